// round 1
// baseline (speedup 1.0000x reference)
#include <cuda_runtime.h>
#include <cstdint>

// ---------------------------------------------------------------------------
// Problem constants (from setup_inputs)
// ---------------------------------------------------------------------------
#define NB 16
// search: 8192 -> 4095 -> 2046 -> 2043 -> 2040
// query : 2048 -> 1023 ->  510 ->  507 ->  504

// ---------------------------------------------------------------------------
// Device scratch (static globals; no runtime allocation)
// ---------------------------------------------------------------------------
__device__ float g_wt  [4 * 320 * 160];   // wide conv weights, [l][(c*4+j)*160 + oc]
__device__ float g_w1t [4 * 80 * 80];     // 1x1 weights, [l][ic*80 + oc]
__device__ float g_wf0t[80 * 80];         // final conv0, [ic*80 + oc]
__device__ float g_wf1t[80 * 80];         // final conv1, [ic*80 + oc]
__device__ float g_e2  [512];             // ||emb_k||^2
__device__ float g_bufA[16 * 80 * 4095];  // ping
__device__ float g_bufB[16 * 80 * 2046];  // pong
__device__ float g_encS[16 * 2040 * 80];  // encoder(search), (N,T,80)
__device__ float g_encQ[16 * 504 * 80];   // encoder(query),  (N,T,80)
__device__ unsigned g_gmax[32];           // ordered-uint max accumulators

// ---------------------------------------------------------------------------
// Weight prep: transpose to oc-fast layouts, ||emb||^2, init gmax
// ---------------------------------------------------------------------------
__global__ void prep_kernel(const float* __restrict__ w_wide,
                            const float* __restrict__ w_1x1,
                            const float* __restrict__ w_f0,
                            const float* __restrict__ w_f1,
                            const float* __restrict__ emb) {
    int g = blockIdx.x * blockDim.x + threadIdx.x;
    int stride = gridDim.x * blockDim.x;
    // w_wide: (4,160,80,4) -> [l][(c*4+j)*160 + oc]
    for (int idx = g; idx < 4 * 160 * 80 * 4; idx += stride) {
        int j  = idx & 3;
        int c  = (idx >> 2) % 80;
        int oc = (idx / 320) % 160;
        int l  = idx / 51200;
        g_wt[l * 51200 + (c * 4 + j) * 160 + oc] = w_wide[idx];
    }
    // w_1x1: (4,80,80,1) -> [l][ic*80 + oc]
    for (int idx = g; idx < 4 * 80 * 80; idx += stride) {
        int ic = idx % 80;
        int oc = (idx / 80) % 80;
        int l  = idx / 6400;
        g_w1t[l * 6400 + ic * 80 + oc] = w_1x1[idx];
    }
    // final convs: (80,80,1) -> [ic*80 + oc]
    for (int idx = g; idx < 6400; idx += stride) {
        int ic = idx % 80;
        int oc = idx / 80;
        g_wf0t[ic * 80 + oc] = w_f0[idx];
        g_wf1t[ic * 80 + oc] = w_f1[idx];
    }
    for (int k = g; k < 512; k += stride) {
        float s = 0.f;
        for (int c = 0; c < 80; c++) { float v = emb[k * 80 + c]; s += v * v; }
        g_e2[k] = s;
    }
    if (g < 32) g_gmax[g] = 0u;
}

// ---------------------------------------------------------------------------
// Fused layer kernel: wide conv(k=4, stride S) + gate + 1x1 + residual
// Tile: 32 output timesteps, all 160 hidden / 80 out channels. 320 threads.
// ---------------------------------------------------------------------------
template <int S, bool FIRST, bool RESID>
__global__ __launch_bounds__(320) void layer_kernel(
    const float* __restrict__ xin,   // FIRST: (N,Tin,80) else (N,80,Tin)
    float* __restrict__ xout,        // (N,80,Tout)
    const float* __restrict__ wt,    // [320*160] k-major, oc fast
    const float* __restrict__ bw,    // [160]
    const float* __restrict__ w1t,   // [80*80] ic-major, oc fast
    const float* __restrict__ b1,    // [80]
    int Tin, int Tout)
{
    constexpr int SPAN  = 32 * S + 3;
    constexpr int PITCH = (S == 2) ? 68 : 36;   // 4-float aligned row pitch
    constexpr int NV    = 3 * S + 4;

    __shared__ __align__(16) float xs[80 * PITCH];
    __shared__ __align__(16) float h [160 * 33];

    const int tid = threadIdx.x;
    const int n   = blockIdx.y;
    const int t0  = blockIdx.x * 32;
    const int ubeg = t0 * S;
    const float* xin_n = xin + (size_t)n * 80 * Tin;

    // ---- stage input tile ----
    for (int i = tid; i < 80 * SPAN; i += 320) {
        int c, u;
        if (FIRST) { u = i / 80;   c = i - u * 80; }
        else       { c = i / SPAN; u = i - c * SPAN; }
        int uu = ubeg + u;
        float v = 0.f;
        if (uu < Tin)
            v = FIRST ? xin_n[(size_t)uu * 80 + c] : xin_n[(size_t)c * Tin + uu];
        xs[c * PITCH + u] = v;
    }
    __syncthreads();

    // ---- phase A: wide conv, 4 oc x 4 t per thread ----
    const int ocg = tid % 40;
    const int tg  = tid / 40;
    const int oc0 = ocg * 4;
    const int tb  = tg * 4;

    float acc[4][4];
    {
        float4 bv = *(const float4*)(bw + oc0);
        #pragma unroll
        for (int tt = 0; tt < 4; tt++) {
            acc[0][tt] = bv.x; acc[1][tt] = bv.y; acc[2][tt] = bv.z; acc[3][tt] = bv.w;
        }
    }

    const float4* wt4 = (const float4*)wt;
    #pragma unroll 2
    for (int c = 0; c < 80; c++) {
        const float* xr = xs + c * PITCH + tb * S;
        float xv[NV];
        if (S == 2) {
            float4 a0 = *(const float4*)(xr);
            float4 a1 = *(const float4*)(xr + 4);
            xv[0]=a0.x; xv[1]=a0.y; xv[2]=a0.z; xv[3]=a0.w;
            xv[4]=a1.x; xv[5]=a1.y; xv[6]=a1.z; xv[7]=a1.w;
            xv[8]=xr[8]; xv[9]=xr[9];
        } else {
            float4 a0 = *(const float4*)(xr);
            xv[0]=a0.x; xv[1]=a0.y; xv[2]=a0.z; xv[3]=a0.w;
            xv[4]=xr[4]; xv[5]=xr[5]; xv[6]=xr[6];
        }
        float4 w[4];
        const float4* wr = wt4 + (size_t)c * 4 * 40 + ocg;
        w[0] = __ldg(wr);       w[1] = __ldg(wr + 40);
        w[2] = __ldg(wr + 80);  w[3] = __ldg(wr + 120);
        #pragma unroll
        for (int j = 0; j < 4; j++) {
            #pragma unroll
            for (int tt = 0; tt < 4; tt++) {
                float x = xv[j + S * tt];
                acc[0][tt] = fmaf(w[j].x, x, acc[0][tt]);
                acc[1][tt] = fmaf(w[j].y, x, acc[1][tt]);
                acc[2][tt] = fmaf(w[j].z, x, acc[2][tt]);
                acc[3][tt] = fmaf(w[j].w, x, acc[3][tt]);
            }
        }
    }
    #pragma unroll
    for (int i = 0; i < 4; i++)
        #pragma unroll
        for (int tt = 0; tt < 4; tt++)
            h[(oc0 + i) * 33 + tb + tt] = acc[i][tt];
    __syncthreads();

    // ---- gate: x2 = tanh(a) * sigmoid(g), in-place into lower half of h ----
    for (int e = tid; e < 80 * 32; e += 320) {
        int oc = e >> 5, tt = e & 31;
        float a  = h[oc * 33 + tt];
        float gg = h[(oc + 80) * 33 + tt];
        float th = 2.f / (1.f + __expf(-2.f * a)) - 1.f;
        float sg = 1.f / (1.f + __expf(-gg));
        h[oc * 33 + tt] = th * sg;
    }
    __syncthreads();

    // ---- phase B: 1x1 conv + residual, 4 oc x 2 t per thread ----
    {
        const int ocg2 = tid % 20;
        const int tg2  = tid / 20;
        const int oc0b = ocg2 * 4;
        const int tt0  = tg2 * 2;

        float4 bb = *(const float4*)(b1 + oc0b);
        float a2[4][2] = {{bb.x, bb.x}, {bb.y, bb.y}, {bb.z, bb.z}, {bb.w, bb.w}};

        const float4* w14 = (const float4*)w1t;
        #pragma unroll 4
        for (int ic = 0; ic < 80; ic++) {
            float4 w = __ldg(&w14[ic * 20 + ocg2]);
            float xa = h[ic * 33 + tt0];
            float xb = h[ic * 33 + tt0 + 1];
            a2[0][0] = fmaf(w.x, xa, a2[0][0]); a2[0][1] = fmaf(w.x, xb, a2[0][1]);
            a2[1][0] = fmaf(w.y, xa, a2[1][0]); a2[1][1] = fmaf(w.y, xb, a2[1][1]);
            a2[2][0] = fmaf(w.z, xa, a2[2][0]); a2[2][1] = fmaf(w.z, xb, a2[2][1]);
            a2[3][0] = fmaf(w.w, xa, a2[3][0]); a2[3][1] = fmaf(w.w, xb, a2[3][1]);
        }
        #pragma unroll
        for (int k = 0; k < 2; k++) {
            int tt = tt0 + k;
            int t  = t0 + tt;
            if (t < Tout) {
                #pragma unroll
                for (int i = 0; i < 4; i++) {
                    float r = 0.f;
                    if (RESID) r = xs[(oc0b + i) * PITCH + tt * S + 3]; // off = skip+S-1 = 3
                    xout[((size_t)n * 80 + oc0b + i) * Tout + t] = a2[i][k] + r;
                }
            }
        }
    }
}

// ---------------------------------------------------------------------------
// Final: conv1x1 -> relu -> conv1x1, output transposed to (N,T,80)
// ---------------------------------------------------------------------------
__global__ __launch_bounds__(320) void final_kernel(
    const float* __restrict__ xin,  // (N,80,T)
    float* __restrict__ enc,        // (N,T,80)
    const float* __restrict__ b0,
    const float* __restrict__ b1,
    int T)
{
    __shared__ __align__(16) float xsf[80 * 33];
    __shared__ __align__(16) float hf [80 * 33];

    const int tid = threadIdx.x;
    const int n   = blockIdx.y;
    const int t0  = blockIdx.x * 32;
    const float* xn = xin + (size_t)n * 80 * T;

    for (int i = tid; i < 80 * 32; i += 320) {
        int c = i >> 5, tt = i & 31;
        int t = t0 + tt;
        xsf[c * 33 + tt] = (t < T) ? xn[(size_t)c * T + t] : 0.f;
    }
    __syncthreads();

    const int ocg = tid % 20;
    const int tg  = tid / 20;
    const int oc0 = ocg * 4;
    const int tt0 = tg * 2;

    // conv0 + relu
    {
        float4 bb = *(const float4*)(b0 + oc0);
        float a2[4][2] = {{bb.x, bb.x}, {bb.y, bb.y}, {bb.z, bb.z}, {bb.w, bb.w}};
        const float4* w4 = (const float4*)g_wf0t;
        #pragma unroll 4
        for (int ic = 0; ic < 80; ic++) {
            float4 w = __ldg(&w4[ic * 20 + ocg]);
            float xa = xsf[ic * 33 + tt0];
            float xb = xsf[ic * 33 + tt0 + 1];
            a2[0][0] = fmaf(w.x, xa, a2[0][0]); a2[0][1] = fmaf(w.x, xb, a2[0][1]);
            a2[1][0] = fmaf(w.y, xa, a2[1][0]); a2[1][1] = fmaf(w.y, xb, a2[1][1]);
            a2[2][0] = fmaf(w.z, xa, a2[2][0]); a2[2][1] = fmaf(w.z, xb, a2[2][1]);
            a2[3][0] = fmaf(w.w, xa, a2[3][0]); a2[3][1] = fmaf(w.w, xb, a2[3][1]);
        }
        #pragma unroll
        for (int k = 0; k < 2; k++)
            #pragma unroll
            for (int i = 0; i < 4; i++)
                hf[(oc0 + i) * 33 + tt0 + k] = fmaxf(a2[i][k], 0.f);
    }
    __syncthreads();

    // conv1
    {
        float4 bb = *(const float4*)(b1 + oc0);
        float a2[4][2] = {{bb.x, bb.x}, {bb.y, bb.y}, {bb.z, bb.z}, {bb.w, bb.w}};
        const float4* w4 = (const float4*)g_wf1t;
        #pragma unroll 4
        for (int ic = 0; ic < 80; ic++) {
            float4 w = __ldg(&w4[ic * 20 + ocg]);
            float xa = hf[ic * 33 + tt0];
            float xb = hf[ic * 33 + tt0 + 1];
            a2[0][0] = fmaf(w.x, xa, a2[0][0]); a2[0][1] = fmaf(w.x, xb, a2[0][1]);
            a2[1][0] = fmaf(w.y, xa, a2[1][0]); a2[1][1] = fmaf(w.y, xb, a2[1][1]);
            a2[2][0] = fmaf(w.z, xa, a2[2][0]); a2[2][1] = fmaf(w.z, xb, a2[2][1]);
            a2[3][0] = fmaf(w.w, xa, a2[3][0]); a2[3][1] = fmaf(w.w, xb, a2[3][1]);
        }
        #pragma unroll
        for (int k = 0; k < 2; k++) {
            int t = t0 + tt0 + k;
            if (t < T)
                #pragma unroll
                for (int i = 0; i < 4; i++)
                    enc[((size_t)n * T + t) * 80 + oc0 + i] = a2[i][k];
        }
    }
}

// ---------------------------------------------------------------------------
// VQ nearest-neighbor + linear head + tanh + per-(n,class) max via atomicMax
// ---------------------------------------------------------------------------
__device__ __forceinline__ unsigned fenc(float f) {
    unsigned u = __float_as_uint(f);
    return (u & 0x80000000u) ? ~u : (u | 0x80000000u);
}

__global__ __launch_bounds__(256) void vq_kernel(
    const float* __restrict__ encS,  // (N,2040,80)
    const float* __restrict__ encQ,  // (N,504,80)
    const float* __restrict__ emb,   // (512,80)
    const float* __restrict__ wlin,  // (2,80)
    const float* __restrict__ blin)  // (2,)
{
    __shared__ __align__(16) float xq[32 * 84];
    __shared__ __align__(16) float eb[64 * 80];
    __shared__ float rd[256];
    __shared__ int   ri[256];

    const int tid = threadIdx.x;
    const int n   = blockIdx.y;
    const int t0  = blockIdx.x * 32;

    for (int i = tid; i < 32 * 80; i += 256) {
        int t = i / 80, c = i - t * 80;
        int tg2 = t0 + t;
        xq[t * 84 + c] = (tg2 < 2040) ? encS[((size_t)n * 2040 + tg2) * 80 + c] : 0.f;
    }

    const int kg = tid >> 5;   // 0..7 class group
    const int lt = tid & 31;   // timestep within tile
    float best = 3.4e38f;
    int   bi   = 0;

    for (int tile = 0; tile < 8; tile++) {
        __syncthreads();
        for (int i = tid; i < 64 * 80; i += 256) {
            int k = i / 80, c = i - k * 80;
            eb[k * 80 + c] = emb[((size_t)(tile * 64 + k)) * 80 + c];
        }
        __syncthreads();
        #pragma unroll 2
        for (int q = 0; q < 8; q++) {
            int kl = kg * 8 + q;
            float4 dv = {0.f, 0.f, 0.f, 0.f};
            #pragma unroll
            for (int c4 = 0; c4 < 20; c4++) {
                float4 xv = *(const float4*)&xq[lt * 84 + c4 * 4];
                float4 ev = *(const float4*)&eb[kl * 80 + c4 * 4];
                dv.x = fmaf(xv.x, ev.x, dv.x);
                dv.y = fmaf(xv.y, ev.y, dv.y);
                dv.z = fmaf(xv.z, ev.z, dv.z);
                dv.w = fmaf(xv.w, ev.w, dv.w);
            }
            float dot = (dv.x + dv.y) + (dv.z + dv.w);
            int kgl = tile * 64 + kl;
            float d = g_e2[kgl] - 2.f * dot;
            if (d < best) { best = d; bi = kgl; }
        }
    }
    rd[tid] = best; ri[tid] = bi;
    __syncthreads();

    if (tid < 32) {
        float bd = rd[tid];
        int  bbi = ri[tid];
        for (int g2 = 1; g2 < 8; g2++) {
            float d = rd[g2 * 32 + tid];
            int  ii = ri[g2 * 32 + tid];
            if (d < bd || (d == bd && ii < bbi)) { bd = d; bbi = ii; }
        }
        int tg2 = t0 + tid;
        if (tg2 < 2040) {
            const float* dv = emb + (size_t)bbi * 80;
            const float* qr = (tg2 < 2016)
                            ? (encQ + ((size_t)n * 504 + (tg2 % 504)) * 80)
                            : nullptr;
            float s0 = blin[0], s1 = blin[1];
            #pragma unroll 4
            for (int c = 0; c < 80; c++) {
                float v = dv[c] + (qr ? qr[c] : 0.f);
                s0 = fmaf(v, wlin[c],      s0);
                s1 = fmaf(v, wlin[80 + c], s1);
            }
            atomicMax(&g_gmax[n * 2 + 0], fenc(tanhf(s0)));
            atomicMax(&g_gmax[n * 2 + 1], fenc(tanhf(s1)));
        }
    }
}

__global__ void finalize_kernel(float* __restrict__ out) {
    int i = threadIdx.x;
    if (i < 32) {
        unsigned e = g_gmax[i];
        out[i] = (e & 0x80000000u) ? __uint_as_float(e ^ 0x80000000u)
                                   : __uint_as_float(~e);
    }
}

// ---------------------------------------------------------------------------
// Host launch
// ---------------------------------------------------------------------------
extern "C" void kernel_launch(void* const* d_in, const int* in_sizes, int n_in,
                              void* d_out, int out_size) {
    const float* search = (const float*)d_in[0];
    const float* query  = (const float*)d_in[1];
    const float* w_wide = (const float*)d_in[2];
    const float* b_wide = (const float*)d_in[3];
    const float* w_1x1  = (const float*)d_in[4];
    const float* b_1x1  = (const float*)d_in[5];
    const float* w_f0   = (const float*)d_in[6];
    const float* b_f0   = (const float*)d_in[7];
    const float* w_f1   = (const float*)d_in[8];
    const float* b_f1   = (const float*)d_in[9];
    const float* emb    = (const float*)d_in[10];
    const float* w_lin  = (const float*)d_in[11];
    const float* b_lin  = (const float*)d_in[12];
    float* out = (float*)d_out;

    void *pA, *pB, *pS, *pQ, *pwt, *pw1;
    cudaGetSymbolAddress(&pA,  g_bufA);
    cudaGetSymbolAddress(&pB,  g_bufB);
    cudaGetSymbolAddress(&pS,  g_encS);
    cudaGetSymbolAddress(&pQ,  g_encQ);
    cudaGetSymbolAddress(&pwt, g_wt);
    cudaGetSymbolAddress(&pw1, g_w1t);
    float* A   = (float*)pA;
    float* B   = (float*)pB;
    float* eS  = (float*)pS;
    float* eQ  = (float*)pQ;
    float* wt  = (float*)pwt;
    float* w1t = (float*)pw1;

    prep_kernel<<<80, 256>>>(w_wide, w_1x1, w_f0, w_f1, emb);

    auto grid = [](int Tout) { return dim3((unsigned)((Tout + 31) / 32), NB); };

    // search pipeline: 8192 -> 4095 -> 2046 -> 2043 -> 2040
    layer_kernel<2, true,  false><<<grid(4095), 320>>>(search, A,
        wt + 0 * 51200, b_wide + 0 * 160, w1t + 0 * 6400, b_1x1 + 0 * 80, 8192, 4095);
    layer_kernel<2, false, true ><<<grid(2046), 320>>>(A, B,
        wt + 1 * 51200, b_wide + 1 * 160, w1t + 1 * 6400, b_1x1 + 1 * 80, 4095, 2046);
    layer_kernel<1, false, true ><<<grid(2043), 320>>>(B, A,
        wt + 2 * 51200, b_wide + 2 * 160, w1t + 2 * 6400, b_1x1 + 2 * 80, 2046, 2043);
    layer_kernel<1, false, true ><<<grid(2040), 320>>>(A, B,
        wt + 3 * 51200, b_wide + 3 * 160, w1t + 3 * 6400, b_1x1 + 3 * 80, 2043, 2040);
    final_kernel<<<grid(2040), 320>>>(B, eS, b_f0, b_f1, 2040);

    // query pipeline: 2048 -> 1023 -> 510 -> 507 -> 504
    layer_kernel<2, true,  false><<<grid(1023), 320>>>(query, A,
        wt + 0 * 51200, b_wide + 0 * 160, w1t + 0 * 6400, b_1x1 + 0 * 80, 2048, 1023);
    layer_kernel<2, false, true ><<<grid(510), 320>>>(A, B,
        wt + 1 * 51200, b_wide + 1 * 160, w1t + 1 * 6400, b_1x1 + 1 * 80, 1023, 510);
    layer_kernel<1, false, true ><<<grid(507), 320>>>(B, A,
        wt + 2 * 51200, b_wide + 2 * 160, w1t + 2 * 6400, b_1x1 + 2 * 80, 510, 507);
    layer_kernel<1, false, true ><<<grid(504), 320>>>(A, B,
        wt + 3 * 51200, b_wide + 3 * 160, w1t + 3 * 6400, b_1x1 + 3 * 80, 507, 504);
    final_kernel<<<grid(504), 320>>>(B, eQ, b_f0, b_f1, 504);

    // VQ + head + max
    vq_kernel<<<dim3(64, NB), 256>>>(eS, eQ, emb, w_lin, b_lin);
    finalize_kernel<<<1, 32>>>(out);
}

// round 2
// speedup vs baseline: 1.0696x; 1.0696x over previous
#include <cuda_runtime.h>
#include <cstdint>

#define NB 16
typedef unsigned long long u64;

// ---------------------------------------------------------------------------
// f32x2 packed-FMA helpers (sm_103a: scalar FFMA is half-rate; FFMA2 is full)
// ---------------------------------------------------------------------------
__device__ __forceinline__ void fma2(u64& d, u64 a, u64 b) {
    asm("fma.rn.f32x2 %0, %1, %2, %0;" : "+l"(d) : "l"(a), "l"(b));
}
__device__ __forceinline__ u64 dup2(float x) {
    u64 r; asm("mov.b64 %0, {%1, %1};" : "=l"(r) : "f"(x)); return r;
}
__device__ __forceinline__ float2 unpack2(u64 v) {
    float2 f; asm("mov.b64 {%0, %1}, %2;" : "=f"(f.x), "=f"(f.y) : "l"(v)); return f;
}

// ---------------------------------------------------------------------------
// Device scratch
// ---------------------------------------------------------------------------
__device__ float g_wt  [4 * 320 * 160];   // wide conv weights, [l][(c*4+j)*160 + oc]
__device__ float g_w1t [4 * 80 * 80];     // 1x1 weights, [l][ic*80 + oc]
__device__ float g_wf0t[80 * 80];
__device__ float g_wf1t[80 * 80];
__device__ float g_e2  [512];
__device__ float g_bufA[16 * 80 * 4095];
__device__ float g_bufB[16 * 80 * 2046];
__device__ float g_encS[16 * 2040 * 80];
__device__ float g_encQ[16 * 504 * 80];
__device__ unsigned g_gmax[32];

// ---------------------------------------------------------------------------
// Weight prep
// ---------------------------------------------------------------------------
__global__ void prep_kernel(const float* __restrict__ w_wide,
                            const float* __restrict__ w_1x1,
                            const float* __restrict__ w_f0,
                            const float* __restrict__ w_f1,
                            const float* __restrict__ emb) {
    int g = blockIdx.x * blockDim.x + threadIdx.x;
    int stride = gridDim.x * blockDim.x;
    for (int idx = g; idx < 4 * 160 * 80 * 4; idx += stride) {
        int j  = idx & 3;
        int c  = (idx >> 2) % 80;
        int oc = (idx / 320) % 160;
        int l  = idx / 51200;
        g_wt[l * 51200 + (c * 4 + j) * 160 + oc] = w_wide[idx];
    }
    for (int idx = g; idx < 4 * 80 * 80; idx += stride) {
        int ic = idx % 80;
        int oc = (idx / 80) % 80;
        int l  = idx / 6400;
        g_w1t[l * 6400 + ic * 80 + oc] = w_1x1[idx];
    }
    for (int idx = g; idx < 6400; idx += stride) {
        int ic = idx % 80;
        int oc = idx / 80;
        g_wf0t[ic * 80 + oc] = w_f0[idx];
        g_wf1t[ic * 80 + oc] = w_f1[idx];
    }
    for (int k = g; k < 512; k += stride) {
        float s = 0.f;
        for (int c = 0; c < 80; c++) { float v = emb[k * 80 + c]; s += v * v; }
        g_e2[k] = s;
    }
    if (g < 32) g_gmax[g] = 0u;
}

// ---------------------------------------------------------------------------
// Fused layer: wide conv(k=4, stride S) + gate + 1x1 + residual. 320 threads.
// All GEMM loops use fma.rn.f32x2 packed over the oc dimension.
// ---------------------------------------------------------------------------
template <int S, bool FIRST, bool RESID>
__global__ __launch_bounds__(320) void layer_kernel(
    const float* __restrict__ xin,
    float* __restrict__ xout,
    const float* __restrict__ wt,
    const float* __restrict__ bw,
    const float* __restrict__ w1t,
    const float* __restrict__ b1,
    int Tin, int Tout)
{
    constexpr int SPAN  = 32 * S + 3;
    constexpr int PITCH = (S == 2) ? 68 : 36;
    constexpr int NV    = 3 * S + 4;

    __shared__ __align__(16) float xs[80 * PITCH];
    __shared__ __align__(16) float h [160 * 33];

    const int tid = threadIdx.x;
    const int n   = blockIdx.y;
    const int t0  = blockIdx.x * 32;
    const int ubeg = t0 * S;
    const float* xin_n = xin + (size_t)n * 80 * Tin;

    for (int i = tid; i < 80 * SPAN; i += 320) {
        int c, u;
        if (FIRST) { u = i / 80;   c = i - u * 80; }
        else       { c = i / SPAN; u = i - c * SPAN; }
        int uu = ubeg + u;
        float v = 0.f;
        if (uu < Tin)
            v = FIRST ? xin_n[(size_t)uu * 80 + c] : xin_n[(size_t)c * Tin + uu];
        xs[c * PITCH + u] = v;
    }
    __syncthreads();

    // ---- phase A: wide conv, 4 oc (2 f32x2 pairs) x 4 t per thread ----
    const int ocg = tid % 40;
    const int tg  = tid / 40;
    const int oc0 = ocg * 4;
    const int tb  = tg * 4;

    u64 acc[2][4];
    {
        ulonglong2 bv = *(const ulonglong2*)(bw + oc0);
        #pragma unroll
        for (int tt = 0; tt < 4; tt++) { acc[0][tt] = bv.x; acc[1][tt] = bv.y; }
    }

    #pragma unroll 2
    for (int c = 0; c < 80; c++) {
        const float* xr = xs + c * PITCH + tb * S;
        float xv[NV];
        if (S == 2) {
            float4 a0 = *(const float4*)(xr);
            float4 a1 = *(const float4*)(xr + 4);
            xv[0]=a0.x; xv[1]=a0.y; xv[2]=a0.z; xv[3]=a0.w;
            xv[4]=a1.x; xv[5]=a1.y; xv[6]=a1.z; xv[7]=a1.w;
            xv[8]=xr[8]; xv[9]=xr[9];
        } else {
            float4 a0 = *(const float4*)(xr);
            xv[0]=a0.x; xv[1]=a0.y; xv[2]=a0.z; xv[3]=a0.w;
            xv[4]=xr[4]; xv[5]=xr[5]; xv[6]=xr[6];
        }
        u64 xd[NV];
        #pragma unroll
        for (int v = 0; v < NV; v++) xd[v] = dup2(xv[v]);

        const ulonglong2* wr = (const ulonglong2*)(wt + (size_t)c * 4 * 160) + ocg;
        ulonglong2 w[4];
        w[0] = __ldg(wr);       w[1] = __ldg(wr + 40);
        w[2] = __ldg(wr + 80);  w[3] = __ldg(wr + 120);
        #pragma unroll
        for (int j = 0; j < 4; j++) {
            #pragma unroll
            for (int tt = 0; tt < 4; tt++) {
                fma2(acc[0][tt], w[j].x, xd[j + S * tt]);
                fma2(acc[1][tt], w[j].y, xd[j + S * tt]);
            }
        }
    }
    #pragma unroll
    for (int tt = 0; tt < 4; tt++) {
        float2 p0 = unpack2(acc[0][tt]);
        float2 p1 = unpack2(acc[1][tt]);
        h[(oc0 + 0) * 33 + tb + tt] = p0.x;
        h[(oc0 + 1) * 33 + tb + tt] = p0.y;
        h[(oc0 + 2) * 33 + tb + tt] = p1.x;
        h[(oc0 + 3) * 33 + tb + tt] = p1.y;
    }
    __syncthreads();

    // ---- gate ----
    for (int e = tid; e < 80 * 32; e += 320) {
        int oc = e >> 5, tt = e & 31;
        float a  = h[oc * 33 + tt];
        float gg = h[(oc + 80) * 33 + tt];
        float th = 2.f / (1.f + __expf(-2.f * a)) - 1.f;
        float sg = 1.f / (1.f + __expf(-gg));
        h[oc * 33 + tt] = th * sg;
    }
    __syncthreads();

    // ---- phase B: 1x1 conv + residual, 4 oc x 2 t per thread ----
    {
        const int ocg2 = tid % 20;
        const int tg2  = tid / 20;
        const int oc0b = ocg2 * 4;
        const int tt0  = tg2 * 2;

        u64 a2[2][2];
        {
            ulonglong2 bb = *(const ulonglong2*)(b1 + oc0b);
            a2[0][0] = bb.x; a2[0][1] = bb.x;
            a2[1][0] = bb.y; a2[1][1] = bb.y;
        }
        const ulonglong2* w14 = (const ulonglong2*)w1t;
        #pragma unroll 4
        for (int ic = 0; ic < 80; ic++) {
            ulonglong2 w = __ldg(&w14[ic * 20 + ocg2]);
            u64 xa = dup2(h[ic * 33 + tt0]);
            u64 xb = dup2(h[ic * 33 + tt0 + 1]);
            fma2(a2[0][0], w.x, xa); fma2(a2[0][1], w.x, xb);
            fma2(a2[1][0], w.y, xa); fma2(a2[1][1], w.y, xb);
        }
        #pragma unroll
        for (int k = 0; k < 2; k++) {
            int tt = tt0 + k;
            int t  = t0 + tt;
            if (t < Tout) {
                float2 p0 = unpack2(a2[0][k]);
                float2 p1 = unpack2(a2[1][k]);
                float v[4] = {p0.x, p0.y, p1.x, p1.y};
                #pragma unroll
                for (int i = 0; i < 4; i++) {
                    float r = 0.f;
                    if (RESID) r = xs[(oc0b + i) * PITCH + tt * S + 3];
                    xout[((size_t)n * 80 + oc0b + i) * Tout + t] = v[i] + r;
                }
            }
        }
    }
}

// ---------------------------------------------------------------------------
// Final: conv1x1 -> relu -> conv1x1, output transposed to (N,T,80)
// ---------------------------------------------------------------------------
__global__ __launch_bounds__(320) void final_kernel(
    const float* __restrict__ xin,
    float* __restrict__ enc,
    const float* __restrict__ b0,
    const float* __restrict__ b1,
    int T)
{
    __shared__ __align__(16) float xsf[80 * 33];
    __shared__ __align__(16) float hf [80 * 33];

    const int tid = threadIdx.x;
    const int n   = blockIdx.y;
    const int t0  = blockIdx.x * 32;
    const float* xn = xin + (size_t)n * 80 * T;

    for (int i = tid; i < 80 * 32; i += 320) {
        int c = i >> 5, tt = i & 31;
        int t = t0 + tt;
        xsf[c * 33 + tt] = (t < T) ? xn[(size_t)c * T + t] : 0.f;
    }
    __syncthreads();

    const int ocg = tid % 20;
    const int tg  = tid / 20;
    const int oc0 = ocg * 4;
    const int tt0 = tg * 2;

    // conv0 + relu
    {
        u64 a2[2][2];
        ulonglong2 bb = *(const ulonglong2*)(b0 + oc0);
        a2[0][0] = bb.x; a2[0][1] = bb.x;
        a2[1][0] = bb.y; a2[1][1] = bb.y;
        const ulonglong2* w4 = (const ulonglong2*)g_wf0t;
        #pragma unroll 4
        for (int ic = 0; ic < 80; ic++) {
            ulonglong2 w = __ldg(&w4[ic * 20 + ocg]);
            u64 xa = dup2(xsf[ic * 33 + tt0]);
            u64 xb = dup2(xsf[ic * 33 + tt0 + 1]);
            fma2(a2[0][0], w.x, xa); fma2(a2[0][1], w.x, xb);
            fma2(a2[1][0], w.y, xa); fma2(a2[1][1], w.y, xb);
        }
        #pragma unroll
        for (int k = 0; k < 2; k++) {
            float2 p0 = unpack2(a2[0][k]);
            float2 p1 = unpack2(a2[1][k]);
            hf[(oc0 + 0) * 33 + tt0 + k] = fmaxf(p0.x, 0.f);
            hf[(oc0 + 1) * 33 + tt0 + k] = fmaxf(p0.y, 0.f);
            hf[(oc0 + 2) * 33 + tt0 + k] = fmaxf(p1.x, 0.f);
            hf[(oc0 + 3) * 33 + tt0 + k] = fmaxf(p1.y, 0.f);
        }
    }
    __syncthreads();

    // conv1
    {
        u64 a2[2][2];
        ulonglong2 bb = *(const ulonglong2*)(b1 + oc0);
        a2[0][0] = bb.x; a2[0][1] = bb.x;
        a2[1][0] = bb.y; a2[1][1] = bb.y;
        const ulonglong2* w4 = (const ulonglong2*)g_wf1t;
        #pragma unroll 4
        for (int ic = 0; ic < 80; ic++) {
            ulonglong2 w = __ldg(&w4[ic * 20 + ocg]);
            u64 xa = dup2(hf[ic * 33 + tt0]);
            u64 xb = dup2(hf[ic * 33 + tt0 + 1]);
            fma2(a2[0][0], w.x, xa); fma2(a2[0][1], w.x, xb);
            fma2(a2[1][0], w.y, xa); fma2(a2[1][1], w.y, xb);
        }
        #pragma unroll
        for (int k = 0; k < 2; k++) {
            int t = t0 + tt0 + k;
            if (t < T) {
                float2 p0 = unpack2(a2[0][k]);
                float2 p1 = unpack2(a2[1][k]);
                float* o = enc + ((size_t)n * T + t) * 80 + oc0;
                o[0] = p0.x; o[1] = p0.y; o[2] = p1.x; o[3] = p1.y;
            }
        }
    }
}

// ---------------------------------------------------------------------------
// VQ nearest-neighbor + linear head + tanh + per-(n,class) max
// ---------------------------------------------------------------------------
__device__ __forceinline__ unsigned fenc(float f) {
    unsigned u = __float_as_uint(f);
    return (u & 0x80000000u) ? ~u : (u | 0x80000000u);
}

__global__ __launch_bounds__(256) void vq_kernel(
    const float* __restrict__ encS,
    const float* __restrict__ encQ,
    const float* __restrict__ emb,
    const float* __restrict__ wlin,
    const float* __restrict__ blin)
{
    __shared__ __align__(16) float xq[32 * 84];
    __shared__ __align__(16) float eb[64 * 80];
    __shared__ float rd[256];
    __shared__ int   ri[256];

    const int tid = threadIdx.x;
    const int n   = blockIdx.y;
    const int t0  = blockIdx.x * 32;

    for (int i = tid; i < 32 * 80; i += 256) {
        int t = i / 80, c = i - t * 80;
        int tg2 = t0 + t;
        xq[t * 84 + c] = (tg2 < 2040) ? encS[((size_t)n * 2040 + tg2) * 80 + c] : 0.f;
    }

    const int kg = tid >> 5;
    const int lt = tid & 31;
    float best = 3.4e38f;
    int   bi   = 0;

    for (int tile = 0; tile < 8; tile++) {
        __syncthreads();
        for (int i = tid; i < 64 * 80; i += 256) {
            int k = i / 80, c = i - k * 80;
            eb[k * 80 + c] = emb[((size_t)(tile * 64 + k)) * 80 + c];
        }
        __syncthreads();
        #pragma unroll 2
        for (int q = 0; q < 8; q++) {
            int kl = kg * 8 + q;
            u64 d0 = 0ull, d1 = 0ull;
            #pragma unroll
            for (int c4 = 0; c4 < 20; c4++) {
                ulonglong2 xv = *(const ulonglong2*)&xq[lt * 84 + c4 * 4];
                ulonglong2 ev = *(const ulonglong2*)&eb[kl * 80 + c4 * 4];
                fma2(d0, xv.x, ev.x);
                fma2(d1, xv.y, ev.y);
            }
            float2 p0 = unpack2(d0), p1 = unpack2(d1);
            float dot = (p0.x + p0.y) + (p1.x + p1.y);
            int kgl = tile * 64 + kl;
            float d = g_e2[kgl] - 2.f * dot;
            if (d < best) { best = d; bi = kgl; }
        }
    }
    rd[tid] = best; ri[tid] = bi;
    __syncthreads();

    if (tid < 32) {
        float bd = rd[tid];
        int  bbi = ri[tid];
        for (int g2 = 1; g2 < 8; g2++) {
            float d = rd[g2 * 32 + tid];
            int  ii = ri[g2 * 32 + tid];
            if (d < bd || (d == bd && ii < bbi)) { bd = d; bbi = ii; }
        }
        int tg2 = t0 + tid;
        if (tg2 < 2040) {
            const float* dv = emb + (size_t)bbi * 80;
            const float* qr = (tg2 < 2016)
                            ? (encQ + ((size_t)n * 504 + (tg2 % 504)) * 80)
                            : nullptr;
            float s0 = blin[0], s1 = blin[1];
            #pragma unroll 4
            for (int c = 0; c < 80; c++) {
                float v = dv[c] + (qr ? qr[c] : 0.f);
                s0 = fmaf(v, wlin[c],      s0);
                s1 = fmaf(v, wlin[80 + c], s1);
            }
            atomicMax(&g_gmax[n * 2 + 0], fenc(tanhf(s0)));
            atomicMax(&g_gmax[n * 2 + 1], fenc(tanhf(s1)));
        }
    }
}

__global__ void finalize_kernel(float* __restrict__ out) {
    int i = threadIdx.x;
    if (i < 32) {
        unsigned e = g_gmax[i];
        out[i] = (e & 0x80000000u) ? __uint_as_float(e ^ 0x80000000u)
                                   : __uint_as_float(~e);
    }
}

// ---------------------------------------------------------------------------
// Host launch
// ---------------------------------------------------------------------------
extern "C" void kernel_launch(void* const* d_in, const int* in_sizes, int n_in,
                              void* d_out, int out_size) {
    const float* search = (const float*)d_in[0];
    const float* query  = (const float*)d_in[1];
    const float* w_wide = (const float*)d_in[2];
    const float* b_wide = (const float*)d_in[3];
    const float* w_1x1  = (const float*)d_in[4];
    const float* b_1x1  = (const float*)d_in[5];
    const float* w_f0   = (const float*)d_in[6];
    const float* b_f0   = (const float*)d_in[7];
    const float* w_f1   = (const float*)d_in[8];
    const float* b_f1   = (const float*)d_in[9];
    const float* emb    = (const float*)d_in[10];
    const float* w_lin  = (const float*)d_in[11];
    const float* b_lin  = (const float*)d_in[12];
    float* out = (float*)d_out;

    void *pA, *pB, *pS, *pQ, *pwt, *pw1;
    cudaGetSymbolAddress(&pA,  g_bufA);
    cudaGetSymbolAddress(&pB,  g_bufB);
    cudaGetSymbolAddress(&pS,  g_encS);
    cudaGetSymbolAddress(&pQ,  g_encQ);
    cudaGetSymbolAddress(&pwt, g_wt);
    cudaGetSymbolAddress(&pw1, g_w1t);
    float* A   = (float*)pA;
    float* B   = (float*)pB;
    float* eS  = (float*)pS;
    float* eQ  = (float*)pQ;
    float* wt  = (float*)pwt;
    float* w1t = (float*)pw1;

    prep_kernel<<<80, 256>>>(w_wide, w_1x1, w_f0, w_f1, emb);

    auto grid = [](int Tout) { return dim3((unsigned)((Tout + 31) / 32), NB); };

    // search pipeline: 8192 -> 4095 -> 2046 -> 2043 -> 2040
    layer_kernel<2, true,  false><<<grid(4095), 320>>>(search, A,
        wt + 0 * 51200, b_wide + 0 * 160, w1t + 0 * 6400, b_1x1 + 0 * 80, 8192, 4095);
    layer_kernel<2, false, true ><<<grid(2046), 320>>>(A, B,
        wt + 1 * 51200, b_wide + 1 * 160, w1t + 1 * 6400, b_1x1 + 1 * 80, 4095, 2046);
    layer_kernel<1, false, true ><<<grid(2043), 320>>>(B, A,
        wt + 2 * 51200, b_wide + 2 * 160, w1t + 2 * 6400, b_1x1 + 2 * 80, 2046, 2043);
    layer_kernel<1, false, true ><<<grid(2040), 320>>>(A, B,
        wt + 3 * 51200, b_wide + 3 * 160, w1t + 3 * 6400, b_1x1 + 3 * 80, 2043, 2040);
    final_kernel<<<grid(2040), 320>>>(B, eS, b_f0, b_f1, 2040);

    // query pipeline: 2048 -> 1023 -> 510 -> 507 -> 504
    layer_kernel<2, true,  false><<<grid(1023), 320>>>(query, A,
        wt + 0 * 51200, b_wide + 0 * 160, w1t + 0 * 6400, b_1x1 + 0 * 80, 2048, 1023);
    layer_kernel<2, false, true ><<<grid(510), 320>>>(A, B,
        wt + 1 * 51200, b_wide + 1 * 160, w1t + 1 * 6400, b_1x1 + 1 * 80, 1023, 510);
    layer_kernel<1, false, true ><<<grid(507), 320>>>(B, A,
        wt + 2 * 51200, b_wide + 2 * 160, w1t + 2 * 6400, b_1x1 + 2 * 80, 510, 507);
    layer_kernel<1, false, true ><<<grid(504), 320>>>(A, B,
        wt + 3 * 51200, b_wide + 3 * 160, w1t + 3 * 6400, b_1x1 + 3 * 80, 507, 504);
    final_kernel<<<grid(504), 320>>>(B, eQ, b_f0, b_f1, 504);

    vq_kernel<<<dim3(64, NB), 256>>>(eS, eQ, emb, w_lin, b_lin);
    finalize_kernel<<<1, 32>>>(out);
}

// round 3
// speedup vs baseline: 1.1268x; 1.0535x over previous
#include <cuda_runtime.h>
#include <cstdint>

#define NB 16
typedef unsigned long long u64;

// ---------------------------------------------------------------------------
// f32x2 packed-FMA helpers
// ---------------------------------------------------------------------------
__device__ __forceinline__ void fma2(u64& d, u64 a, u64 b) {
    asm("fma.rn.f32x2 %0, %1, %2, %0;" : "+l"(d) : "l"(a), "l"(b));
}
__device__ __forceinline__ u64 dup2(float x) {
    u64 r; asm("mov.b64 %0, {%1, %1};" : "=l"(r) : "f"(x)); return r;
}
__device__ __forceinline__ float2 unpack2(u64 v) {
    float2 f; asm("mov.b64 {%0, %1}, %2;" : "=f"(f.x), "=f"(f.y) : "l"(v)); return f;
}

// ---------------------------------------------------------------------------
// Device scratch
// ---------------------------------------------------------------------------
__device__ float g_wt  [4 * 320 * 160];
__device__ float g_w1t [4 * 80 * 80];
__device__ float g_wf0t[80 * 80];
__device__ float g_wf1t[80 * 80];
__device__ float g_e2  [512];
__device__ float g_bufA [16 * 80 * 4095];
__device__ float g_bufB [16 * 80 * 2046];
__device__ float g_bufAq[16 * 80 * 1023];
__device__ float g_bufBq[16 * 80 * 510];
__device__ float g_encS[16 * 2040 * 80];
__device__ float g_encQ[16 * 504 * 80];
__device__ unsigned g_gmax[32];

// ---------------------------------------------------------------------------
// Weight prep
// ---------------------------------------------------------------------------
__global__ void prep_kernel(const float* __restrict__ w_wide,
                            const float* __restrict__ w_1x1,
                            const float* __restrict__ w_f0,
                            const float* __restrict__ w_f1,
                            const float* __restrict__ emb) {
    int g = blockIdx.x * blockDim.x + threadIdx.x;
    int stride = gridDim.x * blockDim.x;
    for (int idx = g; idx < 4 * 160 * 80 * 4; idx += stride) {
        int j  = idx & 3;
        int c  = (idx >> 2) % 80;
        int oc = (idx / 320) % 160;
        int l  = idx / 51200;
        g_wt[l * 51200 + (c * 4 + j) * 160 + oc] = w_wide[idx];
    }
    for (int idx = g; idx < 4 * 80 * 80; idx += stride) {
        int ic = idx % 80;
        int oc = (idx / 80) % 80;
        int l  = idx / 6400;
        g_w1t[l * 6400 + ic * 80 + oc] = w_1x1[idx];
    }
    for (int idx = g; idx < 6400; idx += stride) {
        int ic = idx % 80;
        int oc = idx / 80;
        g_wf0t[ic * 80 + oc] = w_f0[idx];
        g_wf1t[ic * 80 + oc] = w_f1[idx];
    }
    for (int k = g; k < 512; k += stride) {
        float s = 0.f;
        for (int c = 0; c < 80; c++) { float v = emb[k * 80 + c]; s += v * v; }
        g_e2[k] = s;
    }
    if (g < 32) g_gmax[g] = 0u;
}

// ---------------------------------------------------------------------------
// Fused layer: wide conv + gate + 1x1 + residual (+ optional final conv pair)
// Handles BOTH search and query problems in one grid (split on blockIdx.x).
// ---------------------------------------------------------------------------
template <int S, bool FIRST, bool RESID, bool FUSEFINAL>
__global__ __launch_bounds__(320) void layer_kernel(
    const float* __restrict__ xinS, const float* __restrict__ xinQ,
    float* __restrict__ xoutS, float* __restrict__ xoutQ,
    const float* __restrict__ wt,  const float* __restrict__ bw,
    const float* __restrict__ w1t, const float* __restrict__ b1,
    const float* __restrict__ bf0, const float* __restrict__ bf1,
    int TinS, int ToutS, int TinQ, int ToutQ, int blocksS)
{
    constexpr int SPAN  = 32 * S + 3;
    constexpr int PITCH = (S == 2) ? 68 : 36;
    constexpr int NV    = 3 * S + 4;

    __shared__ __align__(16) float xs[80 * PITCH];
    __shared__ __align__(16) float h [160 * 33];

    const int tid = threadIdx.x;
    const int n   = blockIdx.y;
    const int bx  = blockIdx.x;

    const float* xin; float* xout; int Tin, Tout, t0;
    if (bx < blocksS) { xin = xinS; xout = xoutS; Tin = TinS; Tout = ToutS; t0 = bx * 32; }
    else              { xin = xinQ; xout = xoutQ; Tin = TinQ; Tout = ToutQ; t0 = (bx - blocksS) * 32; }

    const int ubeg = t0 * S;
    const float* xin_n = xin + (size_t)n * 80 * Tin;

    for (int i = tid; i < 80 * SPAN; i += 320) {
        int c, u;
        if (FIRST) { u = i / 80;   c = i - u * 80; }
        else       { c = i / SPAN; u = i - c * SPAN; }
        int uu = ubeg + u;
        float v = 0.f;
        if (uu < Tin)
            v = FIRST ? xin_n[(size_t)uu * 80 + c] : xin_n[(size_t)c * Tin + uu];
        xs[c * PITCH + u] = v;
    }
    __syncthreads();

    // ---- phase A: wide conv, 4 oc x 4 t per thread ----
    const int ocg = tid % 40;
    const int tg  = tid / 40;
    const int oc0 = ocg * 4;
    const int tb  = tg * 4;

    u64 acc[2][4];
    {
        ulonglong2 bv = *(const ulonglong2*)(bw + oc0);
        #pragma unroll
        for (int tt = 0; tt < 4; tt++) { acc[0][tt] = bv.x; acc[1][tt] = bv.y; }
    }

    #pragma unroll 2
    for (int c = 0; c < 80; c++) {
        const float* xr = xs + c * PITCH + tb * S;
        float xv[NV];
        if (S == 2) {
            float4 a0 = *(const float4*)(xr);
            float4 a1 = *(const float4*)(xr + 4);
            xv[0]=a0.x; xv[1]=a0.y; xv[2]=a0.z; xv[3]=a0.w;
            xv[4]=a1.x; xv[5]=a1.y; xv[6]=a1.z; xv[7]=a1.w;
            xv[8]=xr[8]; xv[9]=xr[9];
        } else {
            float4 a0 = *(const float4*)(xr);
            xv[0]=a0.x; xv[1]=a0.y; xv[2]=a0.z; xv[3]=a0.w;
            xv[4]=xr[4]; xv[5]=xr[5]; xv[6]=xr[6];
        }
        u64 xd[NV];
        #pragma unroll
        for (int v = 0; v < NV; v++) xd[v] = dup2(xv[v]);

        const ulonglong2* wr = (const ulonglong2*)(wt + (size_t)c * 4 * 160) + ocg;
        ulonglong2 w[4];
        w[0] = __ldg(wr);       w[1] = __ldg(wr + 40);
        w[2] = __ldg(wr + 80);  w[3] = __ldg(wr + 120);
        #pragma unroll
        for (int j = 0; j < 4; j++) {
            #pragma unroll
            for (int tt = 0; tt < 4; tt++) {
                fma2(acc[0][tt], w[j].x, xd[j + S * tt]);
                fma2(acc[1][tt], w[j].y, xd[j + S * tt]);
            }
        }
    }
    #pragma unroll
    for (int tt = 0; tt < 4; tt++) {
        float2 p0 = unpack2(acc[0][tt]);
        float2 p1 = unpack2(acc[1][tt]);
        h[(oc0 + 0) * 33 + tb + tt] = p0.x;
        h[(oc0 + 1) * 33 + tb + tt] = p0.y;
        h[(oc0 + 2) * 33 + tb + tt] = p1.x;
        h[(oc0 + 3) * 33 + tb + tt] = p1.y;
    }
    __syncthreads();

    // ---- gate ----
    #pragma unroll
    for (int r = 0; r < 8; r++) {
        int e = r * 320 + tid;
        int oc = e >> 5, tt = e & 31;
        float a  = h[oc * 33 + tt];
        float gg = h[(oc + 80) * 33 + tt];
        float th = 2.f / (1.f + __expf(-2.f * a)) - 1.f;
        float sg = 1.f / (1.f + __expf(-gg));
        h[oc * 33 + tt] = th * sg;
    }
    __syncthreads();

    // ---- phase B: 1x1 conv + residual ----
    const int ocg2 = tid % 20;
    const int tg2  = tid / 20;
    const int oc0b = ocg2 * 4;
    const int tt0  = tg2 * 2;
    float* hB = h + 80 * 33;   // fused-final staging area (rows 80..159)

    {
        u64 a2[2][2];
        {
            ulonglong2 bb = *(const ulonglong2*)(b1 + oc0b);
            a2[0][0] = bb.x; a2[0][1] = bb.x;
            a2[1][0] = bb.y; a2[1][1] = bb.y;
        }
        const ulonglong2* w14 = (const ulonglong2*)w1t;
        #pragma unroll 4
        for (int ic = 0; ic < 80; ic++) {
            ulonglong2 w = __ldg(&w14[ic * 20 + ocg2]);
            u64 xa = dup2(h[ic * 33 + tt0]);
            u64 xb = dup2(h[ic * 33 + tt0 + 1]);
            fma2(a2[0][0], w.x, xa); fma2(a2[0][1], w.x, xb);
            fma2(a2[1][0], w.y, xa); fma2(a2[1][1], w.y, xb);
        }
        #pragma unroll
        for (int k = 0; k < 2; k++) {
            int tt = tt0 + k;
            int t  = t0 + tt;
            float2 p0 = unpack2(a2[0][k]);
            float2 p1 = unpack2(a2[1][k]);
            float v[4] = {p0.x, p0.y, p1.x, p1.y};
            #pragma unroll
            for (int i = 0; i < 4; i++) {
                float r = 0.f;
                if (RESID) r = xs[(oc0b + i) * PITCH + tt * S + 3];
                float res = v[i] + r;
                if (FUSEFINAL) {
                    hB[(oc0b + i) * 33 + tt] = res;
                } else if (t < Tout) {
                    xout[((size_t)n * 80 + oc0b + i) * Tout + t] = res;
                }
            }
        }
    }

    if (FUSEFINAL) {
        __syncthreads();
        // conv0 + relu: read hB (rows 80..159), write h (rows 0..79)
        {
            u64 a2[2][2];
            ulonglong2 bb = *(const ulonglong2*)(bf0 + oc0b);
            a2[0][0] = bb.x; a2[0][1] = bb.x;
            a2[1][0] = bb.y; a2[1][1] = bb.y;
            const ulonglong2* w4 = (const ulonglong2*)g_wf0t;
            #pragma unroll 4
            for (int ic = 0; ic < 80; ic++) {
                ulonglong2 w = __ldg(&w4[ic * 20 + ocg2]);
                u64 xa = dup2(hB[ic * 33 + tt0]);
                u64 xb = dup2(hB[ic * 33 + tt0 + 1]);
                fma2(a2[0][0], w.x, xa); fma2(a2[0][1], w.x, xb);
                fma2(a2[1][0], w.y, xa); fma2(a2[1][1], w.y, xb);
            }
            #pragma unroll
            for (int k = 0; k < 2; k++) {
                float2 p0 = unpack2(a2[0][k]);
                float2 p1 = unpack2(a2[1][k]);
                h[(oc0b + 0) * 33 + tt0 + k] = fmaxf(p0.x, 0.f);
                h[(oc0b + 1) * 33 + tt0 + k] = fmaxf(p0.y, 0.f);
                h[(oc0b + 2) * 33 + tt0 + k] = fmaxf(p1.x, 0.f);
                h[(oc0b + 3) * 33 + tt0 + k] = fmaxf(p1.y, 0.f);
            }
        }
        __syncthreads();
        // conv1: read h (rows 0..79), write enc (N,T,80)
        {
            u64 a2[2][2];
            ulonglong2 bb = *(const ulonglong2*)(bf1 + oc0b);
            a2[0][0] = bb.x; a2[0][1] = bb.x;
            a2[1][0] = bb.y; a2[1][1] = bb.y;
            const ulonglong2* w4 = (const ulonglong2*)g_wf1t;
            #pragma unroll 4
            for (int ic = 0; ic < 80; ic++) {
                ulonglong2 w = __ldg(&w4[ic * 20 + ocg2]);
                u64 xa = dup2(h[ic * 33 + tt0]);
                u64 xb = dup2(h[ic * 33 + tt0 + 1]);
                fma2(a2[0][0], w.x, xa); fma2(a2[0][1], w.x, xb);
                fma2(a2[1][0], w.y, xa); fma2(a2[1][1], w.y, xb);
            }
            #pragma unroll
            for (int k = 0; k < 2; k++) {
                int t = t0 + tt0 + k;
                if (t < Tout) {
                    float2 p0 = unpack2(a2[0][k]);
                    float2 p1 = unpack2(a2[1][k]);
                    float* o = xout + ((size_t)n * Tout + t) * 80 + oc0b;
                    o[0] = p0.x; o[1] = p0.y; o[2] = p1.x; o[3] = p1.y;
                }
            }
        }
    }
}

// ---------------------------------------------------------------------------
// VQ nearest-neighbor + linear head + tanh + per-(n,class) max
// 64 timesteps per CTA, 512 threads; CTA-level max reduction before atomics.
// ---------------------------------------------------------------------------
__device__ __forceinline__ unsigned fenc(float f) {
    unsigned u = __float_as_uint(f);
    return (u & 0x80000000u) ? ~u : (u | 0x80000000u);
}

__global__ __launch_bounds__(512) void vq_kernel(
    const float* __restrict__ encS,
    const float* __restrict__ encQ,
    const float* __restrict__ emb,
    const float* __restrict__ wlin,
    const float* __restrict__ blin)
{
    __shared__ __align__(16) float xq[64 * 84];
    __shared__ __align__(16) float eb[64 * 80];
    __shared__ float rd[512];
    __shared__ int   ri[512];
    __shared__ unsigned sm0, sm1;

    const int tid = threadIdx.x;
    const int n   = blockIdx.y;
    const int t0  = blockIdx.x * 64;

    if (tid == 0) { sm0 = 0u; sm1 = 0u; }

    {   // stage 64 encS rows (zero-pad tail)
        const float4* src = (const float4*)(encS + (size_t)n * 2040 * 80);
        #pragma unroll
        for (int r = 0; r < 3; r++) {
            int i = r * 512 + tid;   // 0..1279 of 64*20 float4
            if (i < 64 * 20) {
                int t = i / 20, c4 = i % 20;
                int tg2 = t0 + t;
                float4 v = {0.f, 0.f, 0.f, 0.f};
                if (tg2 < 2040) v = src[(size_t)tg2 * 20 + c4];
                *(float4*)&xq[t * 84 + c4 * 4] = v;
            }
        }
    }

    const int kg = tid >> 6;   // 0..7
    const int lt = tid & 63;   // timestep in tile
    float best = 3.4e38f;
    int   bi   = 0;

    for (int tile = 0; tile < 8; tile++) {
        __syncthreads();
        {
            const float4* src = (const float4*)(emb + (size_t)tile * 64 * 80);
            #pragma unroll
            for (int r = 0; r < 3; r++) {
                int i = r * 512 + tid;
                if (i < 64 * 20) *(float4*)&eb[(i / 20) * 80 + (i % 20) * 4] = src[i];
            }
        }
        __syncthreads();
        #pragma unroll 2
        for (int q = 0; q < 8; q++) {
            int kl = kg * 8 + q;
            u64 d0 = 0ull, d1 = 0ull;
            #pragma unroll
            for (int c4 = 0; c4 < 20; c4++) {
                ulonglong2 xv = *(const ulonglong2*)&xq[lt * 84 + c4 * 4];
                ulonglong2 ev = *(const ulonglong2*)&eb[kl * 80 + c4 * 4];
                fma2(d0, xv.x, ev.x);
                fma2(d1, xv.y, ev.y);
            }
            float2 p0 = unpack2(d0), p1 = unpack2(d1);
            float dot = (p0.x + p0.y) + (p1.x + p1.y);
            int kgl = tile * 64 + kl;
            float d = g_e2[kgl] - 2.f * dot;
            if (d < best) { best = d; bi = kgl; }
        }
    }
    rd[tid] = best; ri[tid] = bi;
    __syncthreads();

    if (tid < 64) {
        float bd = rd[tid];
        int  bbi = ri[tid];
        #pragma unroll
        for (int g2 = 1; g2 < 8; g2++) {
            float d = rd[g2 * 64 + tid];
            int  ii = ri[g2 * 64 + tid];
            if (d < bd || (d == bd && ii < bbi)) { bd = d; bbi = ii; }
        }
        int tg2 = t0 + tid;
        if (tg2 < 2040) {
            const float* dv = emb + (size_t)bbi * 80;
            const float* qr = (tg2 < 2016)
                            ? (encQ + ((size_t)n * 504 + (tg2 % 504)) * 80)
                            : nullptr;
            float s0 = blin[0], s1 = blin[1];
            #pragma unroll 4
            for (int c = 0; c < 80; c++) {
                float v = dv[c] + (qr ? qr[c] : 0.f);
                s0 = fmaf(v, wlin[c],      s0);
                s1 = fmaf(v, wlin[80 + c], s1);
            }
            atomicMax(&sm0, fenc(tanhf(s0)));
            atomicMax(&sm1, fenc(tanhf(s1)));
        }
    }
    __syncthreads();
    if (tid == 0) {
        atomicMax(&g_gmax[n * 2 + 0], sm0);
        atomicMax(&g_gmax[n * 2 + 1], sm1);
    }
}

__global__ void finalize_kernel(float* __restrict__ out) {
    int i = threadIdx.x;
    if (i < 32) {
        unsigned e = g_gmax[i];
        out[i] = (e & 0x80000000u) ? __uint_as_float(e ^ 0x80000000u)
                                   : __uint_as_float(~e);
    }
}

// ---------------------------------------------------------------------------
// Host launch
// ---------------------------------------------------------------------------
extern "C" void kernel_launch(void* const* d_in, const int* in_sizes, int n_in,
                              void* d_out, int out_size) {
    const float* search = (const float*)d_in[0];
    const float* query  = (const float*)d_in[1];
    const float* w_wide = (const float*)d_in[2];
    const float* b_wide = (const float*)d_in[3];
    const float* w_1x1  = (const float*)d_in[4];
    const float* b_1x1  = (const float*)d_in[5];
    const float* w_f0   = (const float*)d_in[6];
    const float* b_f0   = (const float*)d_in[7];
    const float* w_f1   = (const float*)d_in[8];
    const float* b_f1   = (const float*)d_in[9];
    const float* emb    = (const float*)d_in[10];
    const float* w_lin  = (const float*)d_in[11];
    const float* b_lin  = (const float*)d_in[12];
    float* out = (float*)d_out;

    void *pA, *pB, *pAq, *pBq, *pS, *pQ, *pwt, *pw1;
    cudaGetSymbolAddress(&pA,  g_bufA);
    cudaGetSymbolAddress(&pB,  g_bufB);
    cudaGetSymbolAddress(&pAq, g_bufAq);
    cudaGetSymbolAddress(&pBq, g_bufBq);
    cudaGetSymbolAddress(&pS,  g_encS);
    cudaGetSymbolAddress(&pQ,  g_encQ);
    cudaGetSymbolAddress(&pwt, g_wt);
    cudaGetSymbolAddress(&pw1, g_w1t);
    float* A   = (float*)pA;
    float* B   = (float*)pB;
    float* Aq  = (float*)pAq;
    float* Bq  = (float*)pBq;
    float* eS  = (float*)pS;
    float* eQ  = (float*)pQ;
    float* wt  = (float*)pwt;
    float* w1t = (float*)pw1;

    prep_kernel<<<80, 256>>>(w_wide, w_1x1, w_f0, w_f1, emb);

    // L0: search 8192->4095 (128 blocks), query 2048->1023 (32 blocks)
    layer_kernel<2, true, false, false><<<dim3(160, NB), 320>>>(
        search, query, A, Aq,
        wt + 0 * 51200, b_wide + 0 * 160, w1t + 0 * 6400, b_1x1 + 0 * 80,
        nullptr, nullptr, 8192, 4095, 2048, 1023, 128);

    // L1: 4095->2046 (64), 1023->510 (16)
    layer_kernel<2, false, true, false><<<dim3(80, NB), 320>>>(
        A, Aq, B, Bq,
        wt + 1 * 51200, b_wide + 1 * 160, w1t + 1 * 6400, b_1x1 + 1 * 80,
        nullptr, nullptr, 4095, 2046, 1023, 510, 64);

    // L2: 2046->2043 (64), 510->507 (16)
    layer_kernel<1, false, true, false><<<dim3(80, NB), 320>>>(
        B, Bq, A, Aq,
        wt + 2 * 51200, b_wide + 2 * 160, w1t + 2 * 6400, b_1x1 + 2 * 80,
        nullptr, nullptr, 2046, 2043, 510, 507, 64);

    // L3 + final convs fused: 2043->2040 (64), 507->504 (16); outputs (N,T,80)
    layer_kernel<1, false, true, true><<<dim3(80, NB), 320>>>(
        A, Aq, eS, eQ,
        wt + 3 * 51200, b_wide + 3 * 160, w1t + 3 * 6400, b_1x1 + 3 * 80,
        b_f0, b_f1, 2043, 2040, 507, 504, 64);

    vq_kernel<<<dim3(32, NB), 512>>>(eS, eQ, emb, w_lin, b_lin);
    finalize_kernel<<<1, 32>>>(out);
}

// round 4
// speedup vs baseline: 1.1293x; 1.0022x over previous
#include <cuda_runtime.h>
#include <cstdint>

#define NB 16
typedef unsigned long long u64;

// ---------------------------------------------------------------------------
// f32x2 packed-FMA helpers
// ---------------------------------------------------------------------------
__device__ __forceinline__ void fma2(u64& d, u64 a, u64 b) {
    asm("fma.rn.f32x2 %0, %1, %2, %0;" : "+l"(d) : "l"(a), "l"(b));
}
__device__ __forceinline__ u64 dup2(float x) {
    u64 r; asm("mov.b64 %0, {%1, %1};" : "=l"(r) : "f"(x)); return r;
}
__device__ __forceinline__ float2 unpack2(u64 v) {
    float2 f; asm("mov.b64 {%0, %1}, %2;" : "=f"(f.x), "=f"(f.y) : "l"(v)); return f;
}

// ---------------------------------------------------------------------------
// Device scratch
// ---------------------------------------------------------------------------
__device__ float g_wt  [4 * 320 * 160];
__device__ float g_w1t [4 * 80 * 80];
__device__ float g_wf0t[80 * 80];
__device__ float g_wf1t[80 * 80];
__device__ float g_e2  [512];
__device__ float g_bufA [16 * 80 * 4095];
__device__ float g_bufB [16 * 80 * 2046];
__device__ float g_bufAq[16 * 80 * 1023];
__device__ float g_bufBq[16 * 80 * 510];
__device__ float g_encS[16 * 2040 * 80];
__device__ float g_encQ[16 * 504 * 80];
__device__ unsigned g_gmax[32];

// ---------------------------------------------------------------------------
// Weight prep
// ---------------------------------------------------------------------------
__global__ void prep_kernel(const float* __restrict__ w_wide,
                            const float* __restrict__ w_1x1,
                            const float* __restrict__ w_f0,
                            const float* __restrict__ w_f1,
                            const float* __restrict__ emb) {
    int g = blockIdx.x * blockDim.x + threadIdx.x;
    int stride = gridDim.x * blockDim.x;
    for (int idx = g; idx < 4 * 160 * 80 * 4; idx += stride) {
        int j  = idx & 3;
        int c  = (idx >> 2) % 80;
        int oc = (idx / 320) % 160;
        int l  = idx / 51200;
        g_wt[l * 51200 + (c * 4 + j) * 160 + oc] = w_wide[idx];
    }
    for (int idx = g; idx < 4 * 80 * 80; idx += stride) {
        int ic = idx % 80;
        int oc = (idx / 80) % 80;
        int l  = idx / 6400;
        g_w1t[l * 6400 + ic * 80 + oc] = w_1x1[idx];
    }
    for (int idx = g; idx < 6400; idx += stride) {
        int ic = idx % 80;
        int oc = idx / 80;
        g_wf0t[ic * 80 + oc] = w_f0[idx];
        g_wf1t[ic * 80 + oc] = w_f1[idx];
    }
    for (int k = g; k < 512; k += stride) {
        float s = 0.f;
        for (int c = 0; c < 80; c++) { float v = emb[k * 80 + c]; s += v * v; }
        g_e2[k] = s;
    }
    if (g < 32) g_gmax[g] = 0u;
}

// ---------------------------------------------------------------------------
// Fused layer: wide conv + gate + 1x1 + residual (+ optional final conv pair)
// Handles BOTH search and query problems in one grid (split on blockIdx.x).
// ---------------------------------------------------------------------------
template <int S, bool FIRST, bool RESID, bool FUSEFINAL>
__global__ __launch_bounds__(320) void layer_kernel(
    const float* __restrict__ xinS, const float* __restrict__ xinQ,
    float* __restrict__ xoutS, float* __restrict__ xoutQ,
    const float* __restrict__ wt,  const float* __restrict__ bw,
    const float* __restrict__ w1t, const float* __restrict__ b1,
    const float* __restrict__ bf0, const float* __restrict__ bf1,
    int TinS, int ToutS, int TinQ, int ToutQ, int blocksS)
{
    constexpr int SPAN  = 32 * S + 3;
    constexpr int PITCH = (S == 2) ? 68 : 36;
    constexpr int NV    = 3 * S + 4;

    __shared__ __align__(16) float xs[80 * PITCH];
    __shared__ __align__(16) float h [160 * 33];

    const int tid = threadIdx.x;
    const int n   = blockIdx.y;
    const int bx  = blockIdx.x;

    const float* xin; float* xout; int Tin, Tout, t0;
    if (bx < blocksS) { xin = xinS; xout = xoutS; Tin = TinS; Tout = ToutS; t0 = bx * 32; }
    else              { xin = xinQ; xout = xoutQ; Tin = TinQ; Tout = ToutQ; t0 = (bx - blocksS) * 32; }

    const int ubeg = t0 * S;
    const float* xin_n = xin + (size_t)n * 80 * Tin;

    for (int i = tid; i < 80 * SPAN; i += 320) {
        int c, u;
        if (FIRST) { u = i / 80;   c = i - u * 80; }
        else       { c = i / SPAN; u = i - c * SPAN; }
        int uu = ubeg + u;
        float v = 0.f;
        if (uu < Tin)
            v = FIRST ? xin_n[(size_t)uu * 80 + c] : xin_n[(size_t)c * Tin + uu];
        xs[c * PITCH + u] = v;
    }
    __syncthreads();

    // ---- phase A: wide conv, 4 oc x 4 t per thread ----
    const int ocg = tid % 40;
    const int tg  = tid / 40;
    const int oc0 = ocg * 4;
    const int tb  = tg * 4;

    u64 acc[2][4];
    {
        ulonglong2 bv = *(const ulonglong2*)(bw + oc0);
        #pragma unroll
        for (int tt = 0; tt < 4; tt++) { acc[0][tt] = bv.x; acc[1][tt] = bv.y; }
    }

    #pragma unroll 2
    for (int c = 0; c < 80; c++) {
        const float* xr = xs + c * PITCH + tb * S;
        float xv[NV];
        if (S == 2) {
            float4 a0 = *(const float4*)(xr);
            float4 a1 = *(const float4*)(xr + 4);
            xv[0]=a0.x; xv[1]=a0.y; xv[2]=a0.z; xv[3]=a0.w;
            xv[4]=a1.x; xv[5]=a1.y; xv[6]=a1.z; xv[7]=a1.w;
            xv[8]=xr[8]; xv[9]=xr[9];
        } else {
            float4 a0 = *(const float4*)(xr);
            xv[0]=a0.x; xv[1]=a0.y; xv[2]=a0.z; xv[3]=a0.w;
            xv[4]=xr[4]; xv[5]=xr[5]; xv[6]=xr[6];
        }
        u64 xd[NV];
        #pragma unroll
        for (int v = 0; v < NV; v++) xd[v] = dup2(xv[v]);

        const ulonglong2* wr = (const ulonglong2*)(wt + (size_t)c * 4 * 160) + ocg;
        ulonglong2 w[4];
        w[0] = __ldg(wr);       w[1] = __ldg(wr + 40);
        w[2] = __ldg(wr + 80);  w[3] = __ldg(wr + 120);
        #pragma unroll
        for (int j = 0; j < 4; j++) {
            #pragma unroll
            for (int tt = 0; tt < 4; tt++) {
                fma2(acc[0][tt], w[j].x, xd[j + S * tt]);
                fma2(acc[1][tt], w[j].y, xd[j + S * tt]);
            }
        }
    }
    #pragma unroll
    for (int tt = 0; tt < 4; tt++) {
        float2 p0 = unpack2(acc[0][tt]);
        float2 p1 = unpack2(acc[1][tt]);
        h[(oc0 + 0) * 33 + tb + tt] = p0.x;
        h[(oc0 + 1) * 33 + tb + tt] = p0.y;
        h[(oc0 + 2) * 33 + tb + tt] = p1.x;
        h[(oc0 + 3) * 33 + tb + tt] = p1.y;
    }
    __syncthreads();

    // ---- gate ----
    #pragma unroll
    for (int r = 0; r < 8; r++) {
        int e = r * 320 + tid;
        int oc = e >> 5, tt = e & 31;
        float a  = h[oc * 33 + tt];
        float gg = h[(oc + 80) * 33 + tt];
        float th = 2.f / (1.f + __expf(-2.f * a)) - 1.f;
        float sg = 1.f / (1.f + __expf(-gg));
        h[oc * 33 + tt] = th * sg;
    }
    __syncthreads();

    // ---- phase B: 1x1 conv + residual ----
    const int ocg2 = tid % 20;
    const int tg2  = tid / 20;
    const int oc0b = ocg2 * 4;
    const int tt0  = tg2 * 2;
    float* hB = h + 80 * 33;   // fused-final staging area (rows 80..159)

    {
        u64 a2[2][2];
        {
            ulonglong2 bb = *(const ulonglong2*)(b1 + oc0b);
            a2[0][0] = bb.x; a2[0][1] = bb.x;
            a2[1][0] = bb.y; a2[1][1] = bb.y;
        }
        const ulonglong2* w14 = (const ulonglong2*)w1t;
        #pragma unroll 4
        for (int ic = 0; ic < 80; ic++) {
            ulonglong2 w = __ldg(&w14[ic * 20 + ocg2]);
            u64 xa = dup2(h[ic * 33 + tt0]);
            u64 xb = dup2(h[ic * 33 + tt0 + 1]);
            fma2(a2[0][0], w.x, xa); fma2(a2[0][1], w.x, xb);
            fma2(a2[1][0], w.y, xa); fma2(a2[1][1], w.y, xb);
        }
        #pragma unroll
        for (int k = 0; k < 2; k++) {
            int tt = tt0 + k;
            int t  = t0 + tt;
            float2 p0 = unpack2(a2[0][k]);
            float2 p1 = unpack2(a2[1][k]);
            float v[4] = {p0.x, p0.y, p1.x, p1.y};
            #pragma unroll
            for (int i = 0; i < 4; i++) {
                float r = 0.f;
                if (RESID) r = xs[(oc0b + i) * PITCH + tt * S + 3];
                float res = v[i] + r;
                if (FUSEFINAL) {
                    hB[(oc0b + i) * 33 + tt] = res;
                } else if (t < Tout) {
                    xout[((size_t)n * 80 + oc0b + i) * Tout + t] = res;
                }
            }
        }
    }

    if (FUSEFINAL) {
        __syncthreads();
        // conv0 + relu: read hB (rows 80..159), write h (rows 0..79)
        {
            u64 a2[2][2];
            ulonglong2 bb = *(const ulonglong2*)(bf0 + oc0b);
            a2[0][0] = bb.x; a2[0][1] = bb.x;
            a2[1][0] = bb.y; a2[1][1] = bb.y;
            const ulonglong2* w4 = (const ulonglong2*)g_wf0t;
            #pragma unroll 4
            for (int ic = 0; ic < 80; ic++) {
                ulonglong2 w = __ldg(&w4[ic * 20 + ocg2]);
                u64 xa = dup2(hB[ic * 33 + tt0]);
                u64 xb = dup2(hB[ic * 33 + tt0 + 1]);
                fma2(a2[0][0], w.x, xa); fma2(a2[0][1], w.x, xb);
                fma2(a2[1][0], w.y, xa); fma2(a2[1][1], w.y, xb);
            }
            #pragma unroll
            for (int k = 0; k < 2; k++) {
                float2 p0 = unpack2(a2[0][k]);
                float2 p1 = unpack2(a2[1][k]);
                h[(oc0b + 0) * 33 + tt0 + k] = fmaxf(p0.x, 0.f);
                h[(oc0b + 1) * 33 + tt0 + k] = fmaxf(p0.y, 0.f);
                h[(oc0b + 2) * 33 + tt0 + k] = fmaxf(p1.x, 0.f);
                h[(oc0b + 3) * 33 + tt0 + k] = fmaxf(p1.y, 0.f);
            }
        }
        __syncthreads();
        // conv1: read h (rows 0..79), write enc (N,T,80)
        {
            u64 a2[2][2];
            ulonglong2 bb = *(const ulonglong2*)(bf1 + oc0b);
            a2[0][0] = bb.x; a2[0][1] = bb.x;
            a2[1][0] = bb.y; a2[1][1] = bb.y;
            const ulonglong2* w4 = (const ulonglong2*)g_wf1t;
            #pragma unroll 4
            for (int ic = 0; ic < 80; ic++) {
                ulonglong2 w = __ldg(&w4[ic * 20 + ocg2]);
                u64 xa = dup2(h[ic * 33 + tt0]);
                u64 xb = dup2(h[ic * 33 + tt0 + 1]);
                fma2(a2[0][0], w.x, xa); fma2(a2[0][1], w.x, xb);
                fma2(a2[1][0], w.y, xa); fma2(a2[1][1], w.y, xb);
            }
            #pragma unroll
            for (int k = 0; k < 2; k++) {
                int t = t0 + tt0 + k;
                if (t < Tout) {
                    float2 p0 = unpack2(a2[0][k]);
                    float2 p1 = unpack2(a2[1][k]);
                    float* o = xout + ((size_t)n * Tout + t) * 80 + oc0b;
                    o[0] = p0.x; o[1] = p0.y; o[2] = p1.x; o[3] = p1.y;
                }
            }
        }
    }
}

// ---------------------------------------------------------------------------
// VQ nearest-neighbor + linear head + tanh + per-(n,class) max
// 64 timesteps per CTA, 512 threads; CTA-level max reduction before atomics.
// ---------------------------------------------------------------------------
__device__ __forceinline__ unsigned fenc(float f) {
    unsigned u = __float_as_uint(f);
    return (u & 0x80000000u) ? ~u : (u | 0x80000000u);
}

__global__ __launch_bounds__(512) void vq_kernel(
    const float* __restrict__ encS,
    const float* __restrict__ encQ,
    const float* __restrict__ emb,
    const float* __restrict__ wlin,
    const float* __restrict__ blin)
{
    __shared__ __align__(16) float xq[64 * 84];
    __shared__ __align__(16) float eb[64 * 80];
    __shared__ float rd[512];
    __shared__ int   ri[512];
    __shared__ unsigned sm0, sm1;

    const int tid = threadIdx.x;
    const int n   = blockIdx.y;
    const int t0  = blockIdx.x * 64;

    if (tid == 0) { sm0 = 0u; sm1 = 0u; }

    {   // stage 64 encS rows (zero-pad tail)
        const float4* src = (const float4*)(encS + (size_t)n * 2040 * 80);
        #pragma unroll
        for (int r = 0; r < 3; r++) {
            int i = r * 512 + tid;   // 0..1279 of 64*20 float4
            if (i < 64 * 20) {
                int t = i / 20, c4 = i % 20;
                int tg2 = t0 + t;
                float4 v = {0.f, 0.f, 0.f, 0.f};
                if (tg2 < 2040) v = src[(size_t)tg2 * 20 + c4];
                *(float4*)&xq[t * 84 + c4 * 4] = v;
            }
        }
    }

    const int kg = tid >> 6;   // 0..7
    const int lt = tid & 63;   // timestep in tile
    float best = 3.4e38f;
    int   bi   = 0;

    for (int tile = 0; tile < 8; tile++) {
        __syncthreads();
        {
            const float4* src = (const float4*)(emb + (size_t)tile * 64 * 80);
            #pragma unroll
            for (int r = 0; r < 3; r++) {
                int i = r * 512 + tid;
                if (i < 64 * 20) *(float4*)&eb[(i / 20) * 80 + (i % 20) * 4] = src[i];
            }
        }
        __syncthreads();
        #pragma unroll 2
        for (int q = 0; q < 8; q++) {
            int kl = kg * 8 + q;
            u64 d0 = 0ull, d1 = 0ull;
            #pragma unroll
            for (int c4 = 0; c4 < 20; c4++) {
                ulonglong2 xv = *(const ulonglong2*)&xq[lt * 84 + c4 * 4];
                ulonglong2 ev = *(const ulonglong2*)&eb[kl * 80 + c4 * 4];
                fma2(d0, xv.x, ev.x);
                fma2(d1, xv.y, ev.y);
            }
            float2 p0 = unpack2(d0), p1 = unpack2(d1);
            float dot = (p0.x + p0.y) + (p1.x + p1.y);
            int kgl = tile * 64 + kl;
            float d = g_e2[kgl] - 2.f * dot;
            if (d < best) { best = d; bi = kgl; }
        }
    }
    rd[tid] = best; ri[tid] = bi;
    __syncthreads();

    if (tid < 64) {
        float bd = rd[tid];
        int  bbi = ri[tid];
        #pragma unroll
        for (int g2 = 1; g2 < 8; g2++) {
            float d = rd[g2 * 64 + tid];
            int  ii = ri[g2 * 64 + tid];
            if (d < bd || (d == bd && ii < bbi)) { bd = d; bbi = ii; }
        }
        int tg2 = t0 + tid;
        if (tg2 < 2040) {
            const float* dv = emb + (size_t)bbi * 80;
            const float* qr = (tg2 < 2016)
                            ? (encQ + ((size_t)n * 504 + (tg2 % 504)) * 80)
                            : nullptr;
            float s0 = blin[0], s1 = blin[1];
            #pragma unroll 4
            for (int c = 0; c < 80; c++) {
                float v = dv[c] + (qr ? qr[c] : 0.f);
                s0 = fmaf(v, wlin[c],      s0);
                s1 = fmaf(v, wlin[80 + c], s1);
            }
            atomicMax(&sm0, fenc(tanhf(s0)));
            atomicMax(&sm1, fenc(tanhf(s1)));
        }
    }
    __syncthreads();
    if (tid == 0) {
        atomicMax(&g_gmax[n * 2 + 0], sm0);
        atomicMax(&g_gmax[n * 2 + 1], sm1);
    }
}

__global__ void finalize_kernel(float* __restrict__ out) {
    int i = threadIdx.x;
    if (i < 32) {
        unsigned e = g_gmax[i];
        out[i] = (e & 0x80000000u) ? __uint_as_float(e ^ 0x80000000u)
                                   : __uint_as_float(~e);
    }
}

// ---------------------------------------------------------------------------
// Host launch
// ---------------------------------------------------------------------------
extern "C" void kernel_launch(void* const* d_in, const int* in_sizes, int n_in,
                              void* d_out, int out_size) {
    const float* search = (const float*)d_in[0];
    const float* query  = (const float*)d_in[1];
    const float* w_wide = (const float*)d_in[2];
    const float* b_wide = (const float*)d_in[3];
    const float* w_1x1  = (const float*)d_in[4];
    const float* b_1x1  = (const float*)d_in[5];
    const float* w_f0   = (const float*)d_in[6];
    const float* b_f0   = (const float*)d_in[7];
    const float* w_f1   = (const float*)d_in[8];
    const float* b_f1   = (const float*)d_in[9];
    const float* emb    = (const float*)d_in[10];
    const float* w_lin  = (const float*)d_in[11];
    const float* b_lin  = (const float*)d_in[12];
    float* out = (float*)d_out;

    void *pA, *pB, *pAq, *pBq, *pS, *pQ, *pwt, *pw1;
    cudaGetSymbolAddress(&pA,  g_bufA);
    cudaGetSymbolAddress(&pB,  g_bufB);
    cudaGetSymbolAddress(&pAq, g_bufAq);
    cudaGetSymbolAddress(&pBq, g_bufBq);
    cudaGetSymbolAddress(&pS,  g_encS);
    cudaGetSymbolAddress(&pQ,  g_encQ);
    cudaGetSymbolAddress(&pwt, g_wt);
    cudaGetSymbolAddress(&pw1, g_w1t);
    float* A   = (float*)pA;
    float* B   = (float*)pB;
    float* Aq  = (float*)pAq;
    float* Bq  = (float*)pBq;
    float* eS  = (float*)pS;
    float* eQ  = (float*)pQ;
    float* wt  = (float*)pwt;
    float* w1t = (float*)pw1;

    prep_kernel<<<80, 256>>>(w_wide, w_1x1, w_f0, w_f1, emb);

    // L0: search 8192->4095 (128 blocks), query 2048->1023 (32 blocks)
    layer_kernel<2, true, false, false><<<dim3(160, NB), 320>>>(
        search, query, A, Aq,
        wt + 0 * 51200, b_wide + 0 * 160, w1t + 0 * 6400, b_1x1 + 0 * 80,
        nullptr, nullptr, 8192, 4095, 2048, 1023, 128);

    // L1: 4095->2046 (64), 1023->510 (16)
    layer_kernel<2, false, true, false><<<dim3(80, NB), 320>>>(
        A, Aq, B, Bq,
        wt + 1 * 51200, b_wide + 1 * 160, w1t + 1 * 6400, b_1x1 + 1 * 80,
        nullptr, nullptr, 4095, 2046, 1023, 510, 64);

    // L2: 2046->2043 (64), 510->507 (16)
    layer_kernel<1, false, true, false><<<dim3(80, NB), 320>>>(
        B, Bq, A, Aq,
        wt + 2 * 51200, b_wide + 2 * 160, w1t + 2 * 6400, b_1x1 + 2 * 80,
        nullptr, nullptr, 2046, 2043, 510, 507, 64);

    // L3 + final convs fused: 2043->2040 (64), 507->504 (16); outputs (N,T,80)
    layer_kernel<1, false, true, true><<<dim3(80, NB), 320>>>(
        A, Aq, eS, eQ,
        wt + 3 * 51200, b_wide + 3 * 160, w1t + 3 * 6400, b_1x1 + 3 * 80,
        b_f0, b_f1, 2043, 2040, 507, 504, 64);

    vq_kernel<<<dim3(32, NB), 512>>>(eS, eQ, emb, w_lin, b_lin);
    finalize_kernel<<<1, 32>>>(out);
}

// round 6
// speedup vs baseline: 1.5529x; 1.3751x over previous
#include <cuda_runtime.h>
#include <cuda_bf16.h>
#include <cstdint>

#define NB 16
typedef unsigned long long u64;

// Arch-specific (sm_103a) feature gate: tcgen05 only exists on the 'a' target.
#if defined(__CUDA_ARCH_FEAT_SM103_ALL) || defined(__CUDA_ARCH_FEAT_SM100_ALL) || \
    (defined(__CUDA_ARCH_SPECIFIC__) && (__CUDA_ARCH_SPECIFIC__ >= 1000))
#define HAS_TC 1
#else
#define HAS_TC 0
#endif

// ---------------------------------------------------------------------------
// PTX helpers
// ---------------------------------------------------------------------------
__device__ __forceinline__ void fma2(u64& d, u64 a, u64 b) {
    asm("fma.rn.f32x2 %0, %1, %2, %0;" : "+l"(d) : "l"(a), "l"(b));
}
__device__ __forceinline__ u64 dup2(float x) {
    u64 r; asm("mov.b64 %0, {%1, %1};" : "=l"(r) : "f"(x)); return r;
}
__device__ __forceinline__ float2 unpack2(u64 v) {
    float2 f; asm("mov.b64 {%0, %1}, %2;" : "=f"(f.x), "=f"(f.y) : "l"(v)); return f;
}
__device__ __forceinline__ uint32_t smem_u32(const void* p) {
    uint32_t a;
    asm("{ .reg .u64 t; cvta.to.shared.u64 t, %1; cvt.u32.u64 %0, t; }" : "=r"(a) : "l"(p));
    return a;
}

#if HAS_TC
__device__ __forceinline__ uint32_t elect_one() {
    uint32_t p;
    asm volatile("{\n\t.reg .pred p;\n\telect.sync _|p, 0xFFFFFFFF;\n\tselp.b32 %0, 1, 0, p;\n\t}" : "=r"(p));
    return p;
}

#define TCGEN05_ALLOC(sm, n) \
    asm volatile("tcgen05.alloc.cta_group::1.sync.aligned.shared::cta.b32 [%0], %1;" \
                 :: "r"((uint32_t)(sm)), "r"((uint32_t)(n)) : "memory")
#define TCGEN05_RELINQ() \
    asm volatile("tcgen05.relinquish_alloc_permit.cta_group::1.sync.aligned;")
#define TCGEN05_DEALLOC(t, n) \
    asm volatile("tcgen05.dealloc.cta_group::1.sync.aligned.b32 %0, %1;" :: "r"(t), "r"((uint32_t)(n)))
#define TCGEN05_COMMIT(mb) \
    asm volatile("tcgen05.commit.cta_group::1.mbarrier::arrive::one.shared::cluster.b64 [%0];" \
                 :: "r"((uint32_t)(mb)) : "memory")
#define TCGEN05_FENCE_AFTER()  asm volatile("tcgen05.fence::after_thread_sync;" ::: "memory")
#define TCGEN05_WAIT_LD()      asm volatile("tcgen05.wait::ld.sync.aligned;" ::: "memory")
#define FENCE_ASYNC_SHARED()   asm volatile("fence.proxy.async.shared::cta;" ::: "memory")
#define MBARRIER_INIT(mb, c) \
    asm volatile("mbarrier.init.shared.b64 [%0], %1;" :: "r"((uint32_t)(mb)), "r"((uint32_t)(c)) : "memory")

#define MBAR_WAIT(mb, ph) do {                                                  \
    uint32_t _m = (uint32_t)(mb), _p = (uint32_t)(ph), _d;                      \
    asm volatile("{\n\t.reg .pred p;\n\t"                                       \
        "mbarrier.try_wait.parity.acquire.cta.shared::cta.b64 p, [%1], %2;\n\t" \
        "selp.b32 %0, 1, 0, p;\n\t}" : "=r"(_d) : "r"(_m), "r"(_p) : "memory"); \
    if (!_d) {                                                                  \
        asm volatile("{\n\t.reg .pred P1;\n\t"                                  \
            "WL_%=:\n\t"                                                        \
            "mbarrier.try_wait.parity.acquire.cta.shared::cta.b64 P1, [%0], %1, 0x989680;\n\t" \
            "@P1 bra.uni WD_%=;\n\t"                                            \
            "bra.uni WL_%=;\n\t"                                                \
            "WD_%=:\n\t}" :: "r"(_m), "r"(_p) : "memory");                      \
    }                                                                           \
} while (0)

#define LDTM_X32(r, a) \
    asm volatile("tcgen05.ld.sync.aligned.32x32b.x32.b32 " \
        "{%0,%1,%2,%3,%4,%5,%6,%7,%8,%9,%10,%11,%12,%13,%14,%15," \
        "%16,%17,%18,%19,%20,%21,%22,%23,%24,%25,%26,%27,%28,%29,%30,%31}, [%32];" \
        : "=r"((r)[0]),"=r"((r)[1]),"=r"((r)[2]),"=r"((r)[3]),"=r"((r)[4]),"=r"((r)[5]),"=r"((r)[6]),"=r"((r)[7]), \
          "=r"((r)[8]),"=r"((r)[9]),"=r"((r)[10]),"=r"((r)[11]),"=r"((r)[12]),"=r"((r)[13]),"=r"((r)[14]),"=r"((r)[15]), \
          "=r"((r)[16]),"=r"((r)[17]),"=r"((r)[18]),"=r"((r)[19]),"=r"((r)[20]),"=r"((r)[21]),"=r"((r)[22]),"=r"((r)[23]), \
          "=r"((r)[24]),"=r"((r)[25]),"=r"((r)[26]),"=r"((r)[27]),"=r"((r)[28]),"=r"((r)[29]),"=r"((r)[30]),"=r"((r)[31]) \
        : "r"(a))

#define LDTM_X16(r, a) \
    asm volatile("tcgen05.ld.sync.aligned.32x32b.x16.b32 " \
        "{%0,%1,%2,%3,%4,%5,%6,%7,%8,%9,%10,%11,%12,%13,%14,%15}, [%16];" \
        : "=r"((r)[0]),"=r"((r)[1]),"=r"((r)[2]),"=r"((r)[3]),"=r"((r)[4]),"=r"((r)[5]),"=r"((r)[6]),"=r"((r)[7]), \
          "=r"((r)[8]),"=r"((r)[9]),"=r"((r)[10]),"=r"((r)[11]),"=r"((r)[12]),"=r"((r)[13]),"=r"((r)[14]),"=r"((r)[15]) \
        : "r"(a))

// SS bf16 MMA, cta_group::1
__device__ __forceinline__ void mma_f16_ss(uint32_t d, u64 ad, u64 bd, uint32_t idesc, uint32_t en) {
    asm volatile("{\n\t.reg .pred p;\n\tsetp.ne.u32 p, %5, 0;\n\t"
        "tcgen05.mma.cta_group::1.kind::f16 [%0], %1, %2, %3, {%4,%4,%4,%4}, p;\n\t}"
        :: "r"(d), "l"(ad), "l"(bd), "r"(idesc), "r"(0u), "r"(en) : "memory");
}

static __device__ __forceinline__ u64 make_desc(uint32_t addr) {
    // SW128, version=1(Blackwell), SBO=64 (1024B 8-row group), LBO=1
    return (u64(2) << 61) | (u64(1) << 46) | (u64(64) << 32) | (u64(1) << 16)
         | ((u64)(addr >> 4) & 0x3FFF);
}

// idesc: fp32 accum, bf16 A/B, K-major both, M=128, N=80
#define IDESC_W ((1u<<4) | (1u<<7) | (1u<<10) | (10u<<17) | (8u<<24))
#endif // HAS_TC

// ---------------------------------------------------------------------------
// Device scratch
// ---------------------------------------------------------------------------
__device__ __align__(16) __nv_bfloat16 g_wbh[4 * 160 * 320];
__device__ __align__(16) __nv_bfloat16 g_wbl[4 * 160 * 320];
__device__ float g_w1t [4 * 80 * 80];
__device__ float g_wf0t[80 * 80];
__device__ float g_wf1t[80 * 80];
__device__ float g_e2  [512];
__device__ float g_bufA [16 * 80 * 4095];
__device__ float g_bufB [16 * 80 * 2046];
__device__ float g_bufAq[16 * 80 * 1023];
__device__ float g_bufBq[16 * 80 * 510];
__device__ float g_encS[16 * 2040 * 80];
__device__ float g_encQ[16 * 504 * 80];
__device__ unsigned g_gmax[32];

// ---------------------------------------------------------------------------
// Weight prep
// ---------------------------------------------------------------------------
__global__ void prep_kernel(const float* __restrict__ w_wide,
                            const float* __restrict__ w_1x1,
                            const float* __restrict__ w_f0,
                            const float* __restrict__ w_f1,
                            const float* __restrict__ emb) {
    int g = blockIdx.x * blockDim.x + threadIdx.x;
    int stride = gridDim.x * blockDim.x;
    // w_wide (4,160,80,4) is already [l][oc][k] linear with k = c*4+j
    for (int idx = g; idx < 4 * 160 * 320; idx += stride) {
        float v = w_wide[idx];
        __nv_bfloat16 h = __float2bfloat16(v);
        g_wbh[idx] = h;
        g_wbl[idx] = __float2bfloat16(v - __bfloat162float(h));
    }
    for (int idx = g; idx < 4 * 80 * 80; idx += stride) {
        int ic = idx % 80;
        int oc = (idx / 80) % 80;
        int l  = idx / 6400;
        g_w1t[l * 6400 + ic * 80 + oc] = w_1x1[idx];
    }
    for (int idx = g; idx < 6400; idx += stride) {
        int ic = idx % 80;
        int oc = idx / 80;
        g_wf0t[ic * 80 + oc] = w_f0[idx];
        g_wf1t[ic * 80 + oc] = w_f1[idx];
    }
    for (int k = g; k < 512; k += stride) {
        float s = 0.f;
        for (int c = 0; c < 80; c++) { float v = emb[k * 80 + c]; s += v * v; }
        g_e2[k] = s;
    }
    if (g < 32) g_gmax[g] = 0u;
}

// ---------------------------------------------------------------------------
// Layer kernel: wide conv (tcgen05 bf16x3 on sm_103a; FFMA fallback on the
// family-PTX pass) + gate + 1x1(+res) [+final]. One CTA = 128 timesteps.
// ---------------------------------------------------------------------------
// smem layout (1024-aligned base):
//   GEMM phase:   A_hi @0 (16KB), A_lo @16K, B_hi @32K (20KB), B_lo @52K
//   Epilogue:     gsm  @0 (80x132 f32 = 42240B), buf2 @42240 (42240B)
#define OFF_A_HI 0
#define OFF_A_LO 16384
#define OFF_B_HI 32768
#define OFF_B_LO 53248
#define OFF_GSM  0
#define OFF_BUF2 42240
#define SMEM_DYN (1024 + 84480)

template <int S, bool FIRST, bool RESID, bool FUSEFINAL>
__global__ __launch_bounds__(320) void gemm_layer_kernel(
    const float* __restrict__ xinS, const float* __restrict__ xinQ,
    float* __restrict__ xoutS, float* __restrict__ xoutQ,
    const __nv_bfloat16* __restrict__ wbh, const __nv_bfloat16* __restrict__ wbl,
    const float* __restrict__ bw,
    const float* __restrict__ w1t, const float* __restrict__ b1,
    const float* __restrict__ bf0, const float* __restrict__ bf1,
    int TinS, int ToutS, int TinQ, int ToutQ, int blocksS)
{
    extern __shared__ char dsm[];

    const int tid = threadIdx.x;
    const int wid = tid >> 5;
    const int n   = blockIdx.y;
    const int bx  = blockIdx.x;

    const float* xin; float* xout; int Tin, Tout, t0;
    if (bx < blocksS) { xin = xinS; xout = xoutS; Tin = TinS; Tout = ToutS; t0 = bx * 128; }
    else              { xin = xinQ; xout = xoutQ; Tin = TinQ; Tout = ToutQ; t0 = (bx - blocksS) * 128; }
    const float* xin_n = xin + (size_t)n * 80 * Tin;

    // 1024-aligned smem base
    uint32_t base_raw = smem_u32(dsm);
    uint32_t ab = (base_raw + 1023u) & ~1023u;
    char* abp = dsm + (ab - base_raw);

    float* gsm  = (float*)(abp + OFF_GSM);   // [80][132] gate output
    float* buf2 = (float*)(abp + OFF_BUF2);  // [80][132] scratch

#if HAS_TC
    __shared__ uint32_t s_tmem;
    __shared__ __align__(8) u64 s_mbar;

    if (tid == 0) MBARRIER_INIT(smem_u32(&s_mbar), 1);
    if (wid == 0) { TCGEN05_ALLOC(smem_u32(&s_tmem), 256); TCGEN05_RELINQ(); }
    __syncthreads();
    const uint32_t tmem = s_tmem;
    const uint32_t mbar = smem_u32(&s_mbar);

    // ---- GEMM: 5 K-chunks of 64 (16 channels each) ----
    for (int kc = 0; kc < 5; kc++) {
        const int k0 = kc * 64;
        if (kc > 0) MBAR_WAIT(mbar, (kc - 1) & 1);
        // A im2col staging: 128 t x 64 k, hi+lo. 1024 granules of 8 bf16.
        #pragma unroll
        for (int r = 0; r < 4; r++) {
            int gi = r * 320 + tid;
            if (gi < 1024) {
                int t  = gi & 127;
                int g8 = gi >> 7;            // 0..7
                int c0 = (k0 >> 2) + g8 * 2; // 2 channels per granule
                int u0 = S * (t0 + t);
                float v[8];
                if (FIRST) {
                    #pragma unroll
                    for (int j = 0; j < 4; j++) {
                        int u = u0 + j;
                        bool ok = u < Tin;
                        v[j]     = ok ? xin_n[(size_t)u * 80 + c0]     : 0.f;
                        v[4 + j] = ok ? xin_n[(size_t)u * 80 + c0 + 1] : 0.f;
                    }
                } else {
                    const float* r0 = xin_n + (size_t)c0 * Tin + u0;
                    #pragma unroll
                    for (int j = 0; j < 4; j++) {
                        bool ok = (u0 + j) < Tin;
                        v[j]     = ok ? __ldg(r0 + j)       : 0.f;
                        v[4 + j] = ok ? __ldg(r0 + Tin + j) : 0.f;
                    }
                }
                __align__(16) __nv_bfloat16 hb[8], lb[8];
                #pragma unroll
                for (int i = 0; i < 8; i++) {
                    __nv_bfloat16 h = __float2bfloat16(v[i]);
                    hb[i] = h;
                    lb[i] = __float2bfloat16(v[i] - __bfloat162float(h));
                }
                uint32_t off = (uint32_t)((t >> 3) * 1024 + (t & 7) * 128 + g8 * 16);
                uint32_t sw  = off ^ ((off >> 3) & 0x70);
                *(uint4*)(abp + OFF_A_HI + sw) = *(const uint4*)hb;
                *(uint4*)(abp + OFF_A_LO + sw) = *(const uint4*)lb;
            }
        }
        // B staging: 160 oc x 64 k, hi+lo. 1280 granules.
        {
            const uint4* srcH = (const uint4*)wbh;
            const uint4* srcL = (const uint4*)wbl;
            #pragma unroll
            for (int r = 0; r < 4; r++) {
                int gi = r * 320 + tid;   // < 1280 always
                int row = gi >> 3, g8 = gi & 7;
                int si  = row * 40 + (k0 >> 3) + g8;
                uint32_t off = (uint32_t)((row >> 3) * 1024 + (row & 7) * 128 + g8 * 16);
                uint32_t sw  = off ^ ((off >> 3) & 0x70);
                *(uint4*)(abp + OFF_B_HI + sw) = __ldg(srcH + si);
                *(uint4*)(abp + OFF_B_LO + sw) = __ldg(srcL + si);
            }
        }
        FENCE_ASYNC_SHARED();
        __syncthreads();

        if (wid == 0 && elect_one()) {
            u64 dAh = make_desc(ab + OFF_A_HI), dAl = make_desc(ab + OFF_A_LO);
            u64 dBh = make_desc(ab + OFF_B_HI), dBl = make_desc(ab + OFF_B_LO);
            u64 pA[3] = {dAh, dAh, dAl};
            u64 pB[3] = {dBh, dBl, dBh};
            #pragma unroll
            for (int p = 0; p < 3; p++) {
                #pragma unroll
                for (int s = 0; s < 4; s++) {
                    uint32_t en = (kc == 0 && p == 0 && s == 0) ? 0u : 1u;
                    u64 ad = pA[p] + s * 2;
                    mma_f16_ss(tmem,      ad, pB[p] + s * 2,       IDESC_W, en);
                    mma_f16_ss(tmem + 80, ad, pB[p] + 640 + s * 2, IDESC_W, en);
                }
            }
            TCGEN05_COMMIT(mbar);
        }
    }
    MBAR_WAIT(mbar, 0);   // 5th commit -> parity 0
    __syncthreads();

    // ---- epilogue: gate (warps 0-3 read TMEM) ----
    if (tid < 128) {
        TCGEN05_FENCE_AFTER();
        uint32_t da[32], dg[32];
        #pragma unroll
        for (int ch = 0; ch < 3; ch++) {
            int a0 = ch * 32;
            int w  = (ch == 2) ? 16 : 32;
            if (w == 32) { LDTM_X32(da, tmem + a0); LDTM_X32(dg, tmem + 80 + a0); }
            else         { LDTM_X16(da, tmem + a0); LDTM_X16(dg, tmem + 80 + a0); }
            TCGEN05_WAIT_LD();
            for (int i = 0; i < w; i++) {
                float a = __uint_as_float(da[i]) + __ldg(bw + a0 + i);
                float g = __uint_as_float(dg[i]) + __ldg(bw + 80 + a0 + i);
                float th = 2.f / (1.f + __expf(-2.f * a)) - 1.f;
                float sg = 1.f / (1.f + __expf(-g));
                gsm[(a0 + i) * 132 + tid] = th * sg;
            }
        }
    }
    __syncthreads();
    if (wid == 0) TCGEN05_DEALLOC(tmem, 256);

#else  // ------- non-'a' PTX pass fallback: plain FFMA wide conv + gate -------
    constexpr int NV = 3 * S + 4;
    const int ocgF = tid % 40;     // 4 oc each
    const int tgF  = tid / 40;     // 8 groups x 4 t = 32 t per subtile
    const int oc0F = ocgF * 4;

    for (int st = 0; st < 4; st++) {
        const int tb = tgF * 4;            // within-subtile t base
        const int tl0 = st * 32 + tb;      // local t 0..127
        float acc[4][4];
        #pragma unroll
        for (int i = 0; i < 4; i++)
            #pragma unroll
            for (int tt = 0; tt < 4; tt++) acc[i][tt] = bw[oc0F + i];

        for (int c = 0; c < 80; c++) {
            float xv[NV];
            int u0 = S * (t0 + tl0);
            #pragma unroll
            for (int v = 0; v < NV; v++) {
                int u = u0 + v;
                bool ok = u < Tin;
                xv[v] = !ok ? 0.f
                      : (FIRST ? xin_n[(size_t)u * 80 + c]
                               : xin_n[(size_t)c * Tin + u]);
            }
            #pragma unroll
            for (int i = 0; i < 4; i++) {
                int oc = oc0F + i;
                #pragma unroll
                for (int j = 0; j < 4; j++) {
                    float w = __bfloat162float(wbh[oc * 320 + c * 4 + j])
                            + __bfloat162float(wbl[oc * 320 + c * 4 + j]);
                    #pragma unroll
                    for (int tt = 0; tt < 4; tt++)
                        acc[i][tt] = fmaf(w, xv[j + S * tt], acc[i][tt]);
                }
            }
        }
        #pragma unroll
        for (int i = 0; i < 4; i++)
            #pragma unroll
            for (int tt = 0; tt < 4; tt++)
                buf2[(oc0F + i) * 33 + tb + tt] = acc[i][tt];
        __syncthreads();
        for (int e = tid; e < 80 * 32; e += 320) {
            int oc = e >> 5, tt = e & 31;
            float a  = buf2[oc * 33 + tt];
            float gg = buf2[(oc + 80) * 33 + tt];
            float th = 2.f / (1.f + __expf(-2.f * a)) - 1.f;
            float sg = 1.f / (1.f + __expf(-gg));
            gsm[oc * 132 + st * 32 + tt] = th * sg;
        }
        __syncthreads();
    }
#endif // HAS_TC

    // ---- 1x1 conv + residual (FFMA2), 4 oc x 8 t per thread ----
    const int ocg = tid % 20;
    const int tg  = tid / 20;      // 0..15
    const int oc0 = ocg * 4;
    const int ts0 = tg * 8;

    {
        u64 a2[2][8];
        {
            ulonglong2 bb = *(const ulonglong2*)(b1 + oc0);
            #pragma unroll
            for (int k = 0; k < 8; k++) { a2[0][k] = bb.x; a2[1][k] = bb.y; }
        }
        const ulonglong2* w14 = (const ulonglong2*)w1t;
        #pragma unroll 4
        for (int ic = 0; ic < 80; ic++) {
            ulonglong2 w = __ldg(&w14[ic * 20 + ocg]);
            #pragma unroll
            for (int k = 0; k < 8; k++) {
                u64 x = dup2(gsm[ic * 132 + ts0 + k]);
                fma2(a2[0][k], w.x, x);
                fma2(a2[1][k], w.y, x);
            }
        }
        #pragma unroll
        for (int k = 0; k < 8; k++) {
            int tl = ts0 + k;
            int t  = t0 + tl;
            float2 p0 = unpack2(a2[0][k]);
            float2 p1 = unpack2(a2[1][k]);
            float v[4] = {p0.x, p0.y, p1.x, p1.y};
            bool valid = (t < Tout);
            if (RESID && valid) {
                #pragma unroll
                for (int i = 0; i < 4; i++)
                    v[i] += __ldg(&xin_n[(size_t)(oc0 + i) * Tin + S * t + 3]);
            }
            if (FUSEFINAL) {
                #pragma unroll
                for (int i = 0; i < 4; i++) buf2[(oc0 + i) * 132 + tl] = v[i];
            } else if (valid) {
                #pragma unroll
                for (int i = 0; i < 4; i++)
                    xout[((size_t)n * 80 + oc0 + i) * Tout + t] = v[i];
            }
        }
    }

    if (FUSEFINAL) {
        __syncthreads();
        // conv0 + relu: buf2 -> gsm
        {
            u64 a2[2][8];
            ulonglong2 bb = *(const ulonglong2*)(bf0 + oc0);
            #pragma unroll
            for (int k = 0; k < 8; k++) { a2[0][k] = bb.x; a2[1][k] = bb.y; }
            const ulonglong2* w4 = (const ulonglong2*)g_wf0t;
            #pragma unroll 4
            for (int ic = 0; ic < 80; ic++) {
                ulonglong2 w = __ldg(&w4[ic * 20 + ocg]);
                #pragma unroll
                for (int k = 0; k < 8; k++) {
                    u64 x = dup2(buf2[ic * 132 + ts0 + k]);
                    fma2(a2[0][k], w.x, x);
                    fma2(a2[1][k], w.y, x);
                }
            }
            __syncthreads();   // all reads of gsm (gate data) done before overwrite
            #pragma unroll
            for (int k = 0; k < 8; k++) {
                float2 p0 = unpack2(a2[0][k]);
                float2 p1 = unpack2(a2[1][k]);
                gsm[(oc0 + 0) * 132 + ts0 + k] = fmaxf(p0.x, 0.f);
                gsm[(oc0 + 1) * 132 + ts0 + k] = fmaxf(p0.y, 0.f);
                gsm[(oc0 + 2) * 132 + ts0 + k] = fmaxf(p1.x, 0.f);
                gsm[(oc0 + 3) * 132 + ts0 + k] = fmaxf(p1.y, 0.f);
            }
        }
        __syncthreads();
        // conv1: gsm -> out (N,T,80)
        {
            u64 a2[2][8];
            ulonglong2 bb = *(const ulonglong2*)(bf1 + oc0);
            #pragma unroll
            for (int k = 0; k < 8; k++) { a2[0][k] = bb.x; a2[1][k] = bb.y; }
            const ulonglong2* w4 = (const ulonglong2*)g_wf1t;
            #pragma unroll 4
            for (int ic = 0; ic < 80; ic++) {
                ulonglong2 w = __ldg(&w4[ic * 20 + ocg]);
                #pragma unroll
                for (int k = 0; k < 8; k++) {
                    u64 x = dup2(gsm[ic * 132 + ts0 + k]);
                    fma2(a2[0][k], w.x, x);
                    fma2(a2[1][k], w.y, x);
                }
            }
            #pragma unroll
            for (int k = 0; k < 8; k++) {
                int t = t0 + ts0 + k;
                if (t < Tout) {
                    float2 p0 = unpack2(a2[0][k]);
                    float2 p1 = unpack2(a2[1][k]);
                    float4 o = {p0.x, p0.y, p1.x, p1.y};
                    *(float4*)(xout + ((size_t)n * Tout + t) * 80 + oc0) = o;
                }
            }
        }
    }
}

// ---------------------------------------------------------------------------
// VQ nearest-neighbor + linear head + tanh + per-(n,class) max
// ---------------------------------------------------------------------------
__device__ __forceinline__ unsigned fenc(float f) {
    unsigned u = __float_as_uint(f);
    return (u & 0x80000000u) ? ~u : (u | 0x80000000u);
}

__global__ __launch_bounds__(512) void vq_kernel(
    const float* __restrict__ encS,
    const float* __restrict__ encQ,
    const float* __restrict__ emb,
    const float* __restrict__ wlin,
    const float* __restrict__ blin)
{
    __shared__ __align__(16) float xq[64 * 84];
    __shared__ __align__(16) float eb[64 * 80];
    __shared__ float rd[512];
    __shared__ int   ri[512];
    __shared__ unsigned sm0, sm1;

    const int tid = threadIdx.x;
    const int n   = blockIdx.y;
    const int t0  = blockIdx.x * 64;

    if (tid == 0) { sm0 = 0u; sm1 = 0u; }

    {
        const float4* src = (const float4*)(encS + (size_t)n * 2040 * 80);
        #pragma unroll
        for (int r = 0; r < 3; r++) {
            int i = r * 512 + tid;
            if (i < 64 * 20) {
                int t = i / 20, c4 = i % 20;
                int tg2 = t0 + t;
                float4 v = {0.f, 0.f, 0.f, 0.f};
                if (tg2 < 2040) v = src[(size_t)tg2 * 20 + c4];
                *(float4*)&xq[t * 84 + c4 * 4] = v;
            }
        }
    }

    const int kg = tid >> 6;
    const int lt = tid & 63;
    float best = 3.4e38f;
    int   bi   = 0;

    for (int tile = 0; tile < 8; tile++) {
        __syncthreads();
        {
            const float4* src = (const float4*)(emb + (size_t)tile * 64 * 80);
            #pragma unroll
            for (int r = 0; r < 3; r++) {
                int i = r * 512 + tid;
                if (i < 64 * 20) *(float4*)&eb[(i / 20) * 80 + (i % 20) * 4] = src[i];
            }
        }
        __syncthreads();
        #pragma unroll 2
        for (int q = 0; q < 8; q++) {
            int kl = kg * 8 + q;
            u64 d0 = 0ull, d1 = 0ull;
            #pragma unroll
            for (int c4 = 0; c4 < 20; c4++) {
                ulonglong2 xv = *(const ulonglong2*)&xq[lt * 84 + c4 * 4];
                ulonglong2 ev = *(const ulonglong2*)&eb[kl * 80 + c4 * 4];
                fma2(d0, xv.x, ev.x);
                fma2(d1, xv.y, ev.y);
            }
            float2 p0 = unpack2(d0), p1 = unpack2(d1);
            float dot = (p0.x + p0.y) + (p1.x + p1.y);
            int kgl = tile * 64 + kl;
            float d = g_e2[kgl] - 2.f * dot;
            if (d < best) { best = d; bi = kgl; }
        }
    }
    rd[tid] = best; ri[tid] = bi;
    __syncthreads();

    if (tid < 64) {
        float bd = rd[tid];
        int  bbi = ri[tid];
        #pragma unroll
        for (int g2 = 1; g2 < 8; g2++) {
            float d = rd[g2 * 64 + tid];
            int  ii = ri[g2 * 64 + tid];
            if (d < bd || (d == bd && ii < bbi)) { bd = d; bbi = ii; }
        }
        int tg2 = t0 + tid;
        if (tg2 < 2040) {
            const float* dv = emb + (size_t)bbi * 80;
            const float* qr = (tg2 < 2016)
                            ? (encQ + ((size_t)n * 504 + (tg2 % 504)) * 80)
                            : nullptr;
            float s0 = blin[0], s1 = blin[1];
            #pragma unroll 4
            for (int c = 0; c < 80; c++) {
                float v = dv[c] + (qr ? qr[c] : 0.f);
                s0 = fmaf(v, wlin[c],      s0);
                s1 = fmaf(v, wlin[80 + c], s1);
            }
            atomicMax(&sm0, fenc(tanhf(s0)));
            atomicMax(&sm1, fenc(tanhf(s1)));
        }
    }
    __syncthreads();
    if (tid == 0) {
        atomicMax(&g_gmax[n * 2 + 0], sm0);
        atomicMax(&g_gmax[n * 2 + 1], sm1);
    }
}

__global__ void finalize_kernel(float* __restrict__ out) {
    int i = threadIdx.x;
    if (i < 32) {
        unsigned e = g_gmax[i];
        out[i] = (e & 0x80000000u) ? __uint_as_float(e ^ 0x80000000u)
                                   : __uint_as_float(~e);
    }
}

// ---------------------------------------------------------------------------
// Host launch
// ---------------------------------------------------------------------------
extern "C" void kernel_launch(void* const* d_in, const int* in_sizes, int n_in,
                              void* d_out, int out_size) {
    const float* search = (const float*)d_in[0];
    const float* query  = (const float*)d_in[1];
    const float* w_wide = (const float*)d_in[2];
    const float* b_wide = (const float*)d_in[3];
    const float* w_1x1  = (const float*)d_in[4];
    const float* b_1x1  = (const float*)d_in[5];
    const float* w_f0   = (const float*)d_in[6];
    const float* b_f0   = (const float*)d_in[7];
    const float* w_f1   = (const float*)d_in[8];
    const float* b_f1   = (const float*)d_in[9];
    const float* emb    = (const float*)d_in[10];
    const float* w_lin  = (const float*)d_in[11];
    const float* b_lin  = (const float*)d_in[12];
    float* out = (float*)d_out;

    void *pA, *pB, *pAq, *pBq, *pS, *pQ, *pwh, *pwl, *pw1;
    cudaGetSymbolAddress(&pA,  g_bufA);
    cudaGetSymbolAddress(&pB,  g_bufB);
    cudaGetSymbolAddress(&pAq, g_bufAq);
    cudaGetSymbolAddress(&pBq, g_bufBq);
    cudaGetSymbolAddress(&pS,  g_encS);
    cudaGetSymbolAddress(&pQ,  g_encQ);
    cudaGetSymbolAddress(&pwh, g_wbh);
    cudaGetSymbolAddress(&pwl, g_wbl);
    cudaGetSymbolAddress(&pw1, g_w1t);
    float* A   = (float*)pA;
    float* B   = (float*)pB;
    float* Aq  = (float*)pAq;
    float* Bq  = (float*)pBq;
    float* eS  = (float*)pS;
    float* eQ  = (float*)pQ;
    __nv_bfloat16* wbh = (__nv_bfloat16*)pwh;
    __nv_bfloat16* wbl = (__nv_bfloat16*)pwl;
    float* w1t = (float*)pw1;

    cudaFuncSetAttribute(gemm_layer_kernel<2, true,  false, false>,
                         cudaFuncAttributeMaxDynamicSharedMemorySize, SMEM_DYN);
    cudaFuncSetAttribute(gemm_layer_kernel<2, false, true,  false>,
                         cudaFuncAttributeMaxDynamicSharedMemorySize, SMEM_DYN);
    cudaFuncSetAttribute(gemm_layer_kernel<1, false, true,  false>,
                         cudaFuncAttributeMaxDynamicSharedMemorySize, SMEM_DYN);
    cudaFuncSetAttribute(gemm_layer_kernel<1, false, true,  true >,
                         cudaFuncAttributeMaxDynamicSharedMemorySize, SMEM_DYN);

    prep_kernel<<<80, 256>>>(w_wide, w_1x1, w_f0, w_f1, emb);

    // L0: search 8192->4095 (32 tiles), query 2048->1023 (8 tiles)
    gemm_layer_kernel<2, true, false, false><<<dim3(40, NB), 320, SMEM_DYN>>>(
        search, query, A, Aq,
        wbh + 0 * 51200, wbl + 0 * 51200, b_wide + 0 * 160,
        w1t + 0 * 6400, b_1x1 + 0 * 80, nullptr, nullptr,
        8192, 4095, 2048, 1023, 32);

    // L1: 4095->2046 (16), 1023->510 (4)
    gemm_layer_kernel<2, false, true, false><<<dim3(20, NB), 320, SMEM_DYN>>>(
        A, Aq, B, Bq,
        wbh + 1 * 51200, wbl + 1 * 51200, b_wide + 1 * 160,
        w1t + 1 * 6400, b_1x1 + 1 * 80, nullptr, nullptr,
        4095, 2046, 1023, 510, 16);

    // L2: 2046->2043 (16), 510->507 (4)
    gemm_layer_kernel<1, false, true, false><<<dim3(20, NB), 320, SMEM_DYN>>>(
        B, Bq, A, Aq,
        wbh + 2 * 51200, wbl + 2 * 51200, b_wide + 2 * 160,
        w1t + 2 * 6400, b_1x1 + 2 * 80, nullptr, nullptr,
        2046, 2043, 510, 507, 16);

    // L3 + final convs: 2043->2040 (16), 507->504 (4); outputs (N,T,80)
    gemm_layer_kernel<1, false, true, true><<<dim3(20, NB), 320, SMEM_DYN>>>(
        A, Aq, eS, eQ,
        wbh + 3 * 51200, wbl + 3 * 51200, b_wide + 3 * 160,
        w1t + 3 * 6400, b_1x1 + 3 * 80, b_f0, b_f1,
        2043, 2040, 507, 504, 16);

    vq_kernel<<<dim3(32, NB), 512>>>(eS, eQ, emb, w_lin, b_lin);
    finalize_kernel<<<1, 32>>>(out);
}

// round 8
// speedup vs baseline: 2.0039x; 1.2904x over previous
#include <cuda_runtime.h>
#include <cuda_bf16.h>
#include <cstdint>

#define NB 16
typedef unsigned long long u64;

// Arch-specific (sm_103a) feature gate: tcgen05 only exists on the 'a' target.
#if defined(__CUDA_ARCH_FEAT_SM103_ALL) || defined(__CUDA_ARCH_FEAT_SM100_ALL) || \
    (defined(__CUDA_ARCH_SPECIFIC__) && (__CUDA_ARCH_SPECIFIC__ >= 1000))
#define HAS_TC 1
#else
#define HAS_TC 0
#endif

// ---------------------------------------------------------------------------
// PTX helpers
// ---------------------------------------------------------------------------
__device__ __forceinline__ void fma2(u64& d, u64 a, u64 b) {
    asm("fma.rn.f32x2 %0, %1, %2, %0;" : "+l"(d) : "l"(a), "l"(b));
}
__device__ __forceinline__ u64 dup2(float x) {
    u64 r; asm("mov.b64 %0, {%1, %1};" : "=l"(r) : "f"(x)); return r;
}
__device__ __forceinline__ float2 unpack2(u64 v) {
    float2 f; asm("mov.b64 {%0, %1}, %2;" : "=f"(f.x), "=f"(f.y) : "l"(v)); return f;
}
__device__ __forceinline__ uint32_t smem_u32(const void* p) {
    uint32_t a;
    asm("{ .reg .u64 t; cvta.to.shared.u64 t, %1; cvt.u32.u64 %0, t; }" : "=r"(a) : "l"(p));
    return a;
}
__device__ __forceinline__ float ex2f(float x) {
    float r; asm("ex2.approx.f32 %0, %1;" : "=f"(r) : "f"(x)); return r;
}
__device__ __forceinline__ float rcpf(float x) {
    float r; asm("rcp.approx.f32 %0, %1;" : "=f"(r) : "f"(x)); return r;
}
__device__ __forceinline__ uint32_t prmt_hi(uint32_t a, uint32_t b) {
    uint32_t r; asm("prmt.b32 %0, %1, %2, 0x7632;" : "=r"(r) : "r"(a), "r"(b)); return r;
}
__device__ __forceinline__ uint32_t cvt_bf16x2(float hi, float lo) {
    uint32_t r; asm("cvt.rn.bf16x2.f32 %0, %1, %2;" : "=r"(r) : "f"(hi), "f"(lo)); return r;
}
// gate: tanh(a) * sigmoid(g), division-free (3 MUFU, no div)
__device__ __forceinline__ float gatef(float a, float g) {
    float e1 = ex2f(fminf(a * -2.885390082f, 80.f));   // e^{-2a}
    float e2 = ex2f(fminf(g * -1.442695041f, 80.f));   // e^{-g}
    float r  = rcpf((1.f + e1) * (1.f + e2));
    return (1.f - e1) * r;
}

#if HAS_TC
__device__ __forceinline__ uint32_t elect_one() {
    uint32_t p;
    asm volatile("{\n\t.reg .pred p;\n\telect.sync _|p, 0xFFFFFFFF;\n\tselp.b32 %0, 1, 0, p;\n\t}" : "=r"(p));
    return p;
}

#define TCGEN05_ALLOC(sm, n) \
    asm volatile("tcgen05.alloc.cta_group::1.sync.aligned.shared::cta.b32 [%0], %1;" \
                 :: "r"((uint32_t)(sm)), "r"((uint32_t)(n)) : "memory")
#define TCGEN05_RELINQ() \
    asm volatile("tcgen05.relinquish_alloc_permit.cta_group::1.sync.aligned;")
#define TCGEN05_DEALLOC(t, n) \
    asm volatile("tcgen05.dealloc.cta_group::1.sync.aligned.b32 %0, %1;" :: "r"(t), "r"((uint32_t)(n)))
#define TCGEN05_COMMIT(mb) \
    asm volatile("tcgen05.commit.cta_group::1.mbarrier::arrive::one.shared::cluster.b64 [%0];" \
                 :: "r"((uint32_t)(mb)) : "memory")
#define TCGEN05_FENCE_AFTER()  asm volatile("tcgen05.fence::after_thread_sync;" ::: "memory")
#define TCGEN05_WAIT_LD()      asm volatile("tcgen05.wait::ld.sync.aligned;" ::: "memory")
#define FENCE_ASYNC_SHARED()   asm volatile("fence.proxy.async.shared::cta;" ::: "memory")
#define MBARRIER_INIT(mb, c) \
    asm volatile("mbarrier.init.shared.b64 [%0], %1;" :: "r"((uint32_t)(mb)), "r"((uint32_t)(c)) : "memory")

#define MBAR_WAIT(mb, ph) do {                                                  \
    uint32_t _m = (uint32_t)(mb), _p = (uint32_t)(ph), _d;                      \
    asm volatile("{\n\t.reg .pred p;\n\t"                                       \
        "mbarrier.try_wait.parity.acquire.cta.shared::cta.b64 p, [%1], %2;\n\t" \
        "selp.b32 %0, 1, 0, p;\n\t}" : "=r"(_d) : "r"(_m), "r"(_p) : "memory"); \
    if (!_d) {                                                                  \
        asm volatile("{\n\t.reg .pred P1;\n\t"                                  \
            "WL_%=:\n\t"                                                        \
            "mbarrier.try_wait.parity.acquire.cta.shared::cta.b64 P1, [%0], %1, 0x989680;\n\t" \
            "@P1 bra.uni WD_%=;\n\t"                                            \
            "bra.uni WL_%=;\n\t"                                                \
            "WD_%=:\n\t}" :: "r"(_m), "r"(_p) : "memory");                      \
    }                                                                           \
} while (0)

#define LDTM_X32(r, a) \
    asm volatile("tcgen05.ld.sync.aligned.32x32b.x32.b32 " \
        "{%0,%1,%2,%3,%4,%5,%6,%7,%8,%9,%10,%11,%12,%13,%14,%15," \
        "%16,%17,%18,%19,%20,%21,%22,%23,%24,%25,%26,%27,%28,%29,%30,%31}, [%32];" \
        : "=r"((r)[0]),"=r"((r)[1]),"=r"((r)[2]),"=r"((r)[3]),"=r"((r)[4]),"=r"((r)[5]),"=r"((r)[6]),"=r"((r)[7]), \
          "=r"((r)[8]),"=r"((r)[9]),"=r"((r)[10]),"=r"((r)[11]),"=r"((r)[12]),"=r"((r)[13]),"=r"((r)[14]),"=r"((r)[15]), \
          "=r"((r)[16]),"=r"((r)[17]),"=r"((r)[18]),"=r"((r)[19]),"=r"((r)[20]),"=r"((r)[21]),"=r"((r)[22]),"=r"((r)[23]), \
          "=r"((r)[24]),"=r"((r)[25]),"=r"((r)[26]),"=r"((r)[27]),"=r"((r)[28]),"=r"((r)[29]),"=r"((r)[30]),"=r"((r)[31]) \
        : "r"(a))

#define LDTM_X16(r, a) \
    asm volatile("tcgen05.ld.sync.aligned.32x32b.x16.b32 " \
        "{%0,%1,%2,%3,%4,%5,%6,%7,%8,%9,%10,%11,%12,%13,%14,%15}, [%16];" \
        : "=r"((r)[0]),"=r"((r)[1]),"=r"((r)[2]),"=r"((r)[3]),"=r"((r)[4]),"=r"((r)[5]),"=r"((r)[6]),"=r"((r)[7]), \
          "=r"((r)[8]),"=r"((r)[9]),"=r"((r)[10]),"=r"((r)[11]),"=r"((r)[12]),"=r"((r)[13]),"=r"((r)[14]),"=r"((r)[15]) \
        : "r"(a))

// SS bf16 MMA, cta_group::1
__device__ __forceinline__ void mma_f16_ss(uint32_t d, u64 ad, u64 bd, uint32_t idesc, uint32_t en) {
    asm volatile("{\n\t.reg .pred p;\n\tsetp.ne.u32 p, %5, 0;\n\t"
        "tcgen05.mma.cta_group::1.kind::f16 [%0], %1, %2, %3, {%4,%4,%4,%4}, p;\n\t}"
        :: "r"(d), "l"(ad), "l"(bd), "r"(idesc), "r"(0u), "r"(en) : "memory");
}

static __device__ __forceinline__ u64 make_desc(uint32_t addr) {
    // SW128, version=1(Blackwell), SBO=64 (1024B 8-row group), LBO=1
    return (u64(2) << 61) | (u64(1) << 46) | (u64(64) << 32) | (u64(1) << 16)
         | ((u64)(addr >> 4) & 0x3FFF);
}

// idesc: fp32 accum, bf16 A/B, K-major both, M=128, N=80
#define IDESC_W ((1u<<4) | (1u<<7) | (1u<<10) | (10u<<17) | (8u<<24))
#endif // HAS_TC

// ---------------------------------------------------------------------------
// Device scratch (intermediate buffers use 4-float padded leading dims)
// ---------------------------------------------------------------------------
__device__ __align__(16) __nv_bfloat16 g_wbh[4 * 160 * 320];
__device__ __align__(16) __nv_bfloat16 g_wbl[4 * 160 * 320];
__device__ __align__(16) float g_w1t [4 * 80 * 80];
__device__ __align__(16) float g_wf0t[80 * 80];
__device__ __align__(16) float g_wf1t[80 * 80];
__device__ __align__(16) float g_e2  [512];
__device__ __align__(16) float g_bufA [16 * 80 * 4096];  // L0 out (ld 4096), L2 out (ld 2044)
__device__ __align__(16) float g_bufB [16 * 80 * 2048];  // L1 out (ld 2048)
__device__ __align__(16) float g_bufAq[16 * 80 * 1024];
__device__ __align__(16) float g_bufBq[16 * 80 * 512];
__device__ __align__(16) float g_encS[16 * 2040 * 80];
__device__ __align__(16) float g_encQ[16 * 504 * 80];
__device__ unsigned g_gmax[32];

// ---------------------------------------------------------------------------
// Weight prep
// ---------------------------------------------------------------------------
__global__ void prep_kernel(const float* __restrict__ w_wide,
                            const float* __restrict__ w_1x1,
                            const float* __restrict__ w_f0,
                            const float* __restrict__ w_f1,
                            const float* __restrict__ emb) {
    int g = blockIdx.x * blockDim.x + threadIdx.x;
    int stride = gridDim.x * blockDim.x;
    // w_wide (4,160,80,4) is already [l][oc][k] linear with k = c*4+j
    for (int idx = g; idx < 4 * 160 * 320; idx += stride) {
        float v = w_wide[idx];
        __nv_bfloat16 h = __float2bfloat16(v);
        g_wbh[idx] = h;
        g_wbl[idx] = __float2bfloat16(v - __bfloat162float(h));
    }
    for (int idx = g; idx < 4 * 80 * 80; idx += stride) {
        int ic = idx % 80;
        int oc = (idx / 80) % 80;
        int l  = idx / 6400;
        g_w1t[l * 6400 + ic * 80 + oc] = w_1x1[idx];
    }
    for (int idx = g; idx < 6400; idx += stride) {
        int ic = idx % 80;
        int oc = idx / 80;
        g_wf0t[ic * 80 + oc] = w_f0[idx];
        g_wf1t[ic * 80 + oc] = w_f1[idx];
    }
    for (int k = g; k < 512; k += stride) {
        float s = 0.f;
        for (int c = 0; c < 80; c++) { float v = emb[k * 80 + c]; s += v * v; }
        g_e2[k] = s;
    }
    if (g < 32) g_gmax[g] = 0u;
}

// ---------------------------------------------------------------------------
// Layer kernel: wide conv (tcgen05 bf16x3 on sm_103a) + gate + 1x1(+res)
// [+final conv pair]. One CTA = 128 output timesteps. 320 threads.
// Non-FIRST inputs are (N,80,Tld); logical length Tin <= Tld (pad never read).
// ---------------------------------------------------------------------------
#define OFF_A_HI 0
#define OFF_A_LO 16384
#define OFF_B_HI 32768
#define OFF_B_LO 53248
#define OFF_GSM  0
#define OFF_BUF2 42240
#define SMEM_NOFUSE (1024 + 73728)
#define SMEM_FUSE   (1024 + 84480)

template <int S, bool FIRST, bool RESID, bool FUSEFINAL>
__global__ __launch_bounds__(320, 2) void gemm_layer_kernel(
    const float* __restrict__ xinS, const float* __restrict__ xinQ,
    float* __restrict__ xoutS, float* __restrict__ xoutQ,
    const __nv_bfloat16* __restrict__ wbh, const __nv_bfloat16* __restrict__ wbl,
    const float* __restrict__ bw,
    const float* __restrict__ w1t, const float* __restrict__ b1,
    const float* __restrict__ bf0, const float* __restrict__ bf1,
    int TinS, int TinLdS, int ToutS, int ToutLdS,
    int TinQ, int TinLdQ, int ToutQ, int ToutLdQ, int blocksS)
{
    extern __shared__ char dsm[];
    __shared__ float s_bias[160];

    const int tid = threadIdx.x;
    const int wid = tid >> 5;
    const int n   = blockIdx.y;
    const int bx  = blockIdx.x;

    const float* xin; float* xout; int Tin, TinLd, Tout, ToutLd, t0;
    if (bx < blocksS) {
        xin = xinS; xout = xoutS; Tin = TinS; TinLd = TinLdS;
        Tout = ToutS; ToutLd = ToutLdS; t0 = bx * 128;
    } else {
        xin = xinQ; xout = xoutQ; Tin = TinQ; TinLd = TinLdQ;
        Tout = ToutQ; ToutLd = ToutLdQ; t0 = (bx - blocksS) * 128;
    }
    const float* xin_n = xin + (size_t)n * 80 * TinLd;

    // 1024-aligned smem base
    uint32_t base_raw = smem_u32(dsm);
    uint32_t ab = (base_raw + 1023u) & ~1023u;
    char* abp = dsm + (ab - base_raw);

    float* gsm  = (float*)(abp + OFF_GSM);   // [80][132] gate output
    float* buf2 = (float*)(abp + OFF_BUF2);  // [80][132] scratch (fused only)

#if HAS_TC
    __shared__ uint32_t s_tmem;
    __shared__ __align__(8) u64 s_mbar;

    if (tid == 0) MBARRIER_INIT(smem_u32(&s_mbar), 1);
    if (wid == 0) { TCGEN05_ALLOC(smem_u32(&s_tmem), 256); TCGEN05_RELINQ(); }
    __syncthreads();
    const uint32_t tmem = s_tmem;
    const uint32_t mbar = smem_u32(&s_mbar);

    // ---- GEMM: 5 K-chunks of 64 (16 channels each) ----
    for (int kc = 0; kc < 5; kc++) {
        const int k0 = kc * 64;
        if (kc > 0) MBAR_WAIT(mbar, (kc - 1) & 1);
        // A im2col staging: 128 t x 64 k, hi+lo via truncation split.
        #pragma unroll
        for (int r = 0; r < 4; r++) {
            int gi = r * 320 + tid;
            if (gi < 1024) {
                int t  = gi & 127;
                int g8 = gi >> 7;            // 0..7
                int c0 = (k0 >> 2) + g8 * 2; // 2 channels per granule
                int u0 = S * (t0 + t);
                float v[8];
                if (FIRST) {
                    #pragma unroll
                    for (int j = 0; j < 4; j++) {
                        int u = u0 + j;
                        if (u < Tin) {
                            float2 p = __ldg((const float2*)&xin_n[(size_t)u * 80 + c0]);
                            v[j] = p.x; v[4 + j] = p.y;
                        } else { v[j] = 0.f; v[4 + j] = 0.f; }
                    }
                } else {
                    const float* r0 = xin_n + (size_t)c0 * TinLd + u0;
                    #pragma unroll
                    for (int j = 0; j < 4; j++) {
                        bool ok = (u0 + j) < Tin;
                        v[j]     = ok ? __ldg(r0 + j)         : 0.f;
                        v[4 + j] = ok ? __ldg(r0 + TinLd + j) : 0.f;
                    }
                }
                // truncation split: hi = trunc-to-bf16, lo = v - hi (rounded)
                uint32_t ub[8]; float lo[8];
                #pragma unroll
                for (int i = 0; i < 8; i++) {
                    ub[i] = __float_as_uint(v[i]);
                    lo[i] = v[i] - __uint_as_float(ub[i] & 0xFFFF0000u);
                }
                uint4 hp, lp;
                hp.x = prmt_hi(ub[0], ub[1]); hp.y = prmt_hi(ub[2], ub[3]);
                hp.z = prmt_hi(ub[4], ub[5]); hp.w = prmt_hi(ub[6], ub[7]);
                lp.x = cvt_bf16x2(lo[1], lo[0]); lp.y = cvt_bf16x2(lo[3], lo[2]);
                lp.z = cvt_bf16x2(lo[5], lo[4]); lp.w = cvt_bf16x2(lo[7], lo[6]);
                uint32_t off = (uint32_t)((t >> 3) * 1024 + (t & 7) * 128 + g8 * 16);
                uint32_t sw  = off ^ ((off >> 3) & 0x70);
                *(uint4*)(abp + OFF_A_HI + sw) = hp;
                *(uint4*)(abp + OFF_A_LO + sw) = lp;
            }
        }
        // B staging: 160 oc x 64 k, hi+lo. 1280 granules.
        {
            const uint4* srcH = (const uint4*)wbh;
            const uint4* srcL = (const uint4*)wbl;
            #pragma unroll
            for (int r = 0; r < 4; r++) {
                int gi = r * 320 + tid;   // < 1280 always
                int row = gi >> 3, g8 = gi & 7;
                int si  = row * 40 + (k0 >> 3) + g8;
                uint32_t off = (uint32_t)((row >> 3) * 1024 + (row & 7) * 128 + g8 * 16);
                uint32_t sw  = off ^ ((off >> 3) & 0x70);
                *(uint4*)(abp + OFF_B_HI + sw) = __ldg(srcH + si);
                *(uint4*)(abp + OFF_B_LO + sw) = __ldg(srcL + si);
            }
        }
        FENCE_ASYNC_SHARED();
        __syncthreads();

        if (wid == 0 && elect_one()) {
            u64 dAh = make_desc(ab + OFF_A_HI), dAl = make_desc(ab + OFF_A_LO);
            u64 dBh = make_desc(ab + OFF_B_HI), dBl = make_desc(ab + OFF_B_LO);
            u64 pA[3] = {dAh, dAh, dAl};
            u64 pB[3] = {dBh, dBl, dBh};
            #pragma unroll
            for (int p = 0; p < 3; p++) {
                #pragma unroll
                for (int s = 0; s < 4; s++) {
                    uint32_t en = (kc == 0 && p == 0 && s == 0) ? 0u : 1u;
                    u64 ad = pA[p] + s * 2;
                    mma_f16_ss(tmem,      ad, pB[p] + s * 2,       IDESC_W, en);
                    mma_f16_ss(tmem + 80, ad, pB[p] + 640 + s * 2, IDESC_W, en);
                }
            }
            TCGEN05_COMMIT(mbar);
        }
    }
    // bias to smem while waiting (idle threads)
    if (tid >= 160) s_bias[tid - 160] = __ldg(bw + tid - 160);
    MBAR_WAIT(mbar, 0);   // 5th commit -> parity 0
    __syncthreads();

    // ---- epilogue: gate (warps 0-3 read TMEM) ----
    if (tid < 128) {
        TCGEN05_FENCE_AFTER();
        uint32_t da[32], dg[32];
        #pragma unroll
        for (int ch = 0; ch < 3; ch++) {
            int a0 = ch * 32;
            int w  = (ch == 2) ? 16 : 32;
            if (w == 32) { LDTM_X32(da, tmem + a0); LDTM_X32(dg, tmem + 80 + a0); }
            else         { LDTM_X16(da, tmem + a0); LDTM_X16(dg, tmem + 80 + a0); }
            TCGEN05_WAIT_LD();
            for (int i = 0; i < w; i++) {
                float a = __uint_as_float(da[i]) + s_bias[a0 + i];
                float g = __uint_as_float(dg[i]) + s_bias[80 + a0 + i];
                gsm[(a0 + i) * 132 + tid] = gatef(a, g);
            }
        }
    }
    __syncthreads();
    if (wid == 0) TCGEN05_DEALLOC(tmem, 256);

#else  // ------- non-'a' PTX pass: safe (slow) scalar fallback -------
    __syncthreads();
    for (int e = tid; e < 80 * 128; e += 320) {
        int oc = e >> 7, tt = e & 127;
        float a = bw[oc], g = bw[oc + 80];
        for (int c = 0; c < 80; c++) {
            #pragma unroll
            for (int j = 0; j < 4; j++) {
                int u = S * (t0 + tt) + j;
                float xv = (u < Tin)
                         ? (FIRST ? xin_n[(size_t)u * 80 + c]
                                  : xin_n[(size_t)c * TinLd + u]) : 0.f;
                float wa = __bfloat162float(wbh[oc * 320 + c * 4 + j])
                         + __bfloat162float(wbl[oc * 320 + c * 4 + j]);
                float wg = __bfloat162float(wbh[(oc + 80) * 320 + c * 4 + j])
                         + __bfloat162float(wbl[(oc + 80) * 320 + c * 4 + j]);
                a = fmaf(wa, xv, a);
                g = fmaf(wg, xv, g);
            }
        }
        gsm[oc * 132 + tt] = gatef(a, g);
    }
    __syncthreads();
#endif // HAS_TC

    // ---- 1x1 conv + residual (FFMA2), 4 oc x 8 t (4 t-pairs) per thread ----
    const int ocg = tid % 20;
    const int tg  = tid / 20;      // 0..15
    const int oc0 = ocg * 4;
    const int ts0 = tg * 8;
    const bool fullTile = (t0 + 128 <= Tout);

    {
        u64 acc[4][4];
        {
            float4 bb = *(const float4*)(b1 + oc0);
            u64 c0 = dup2(bb.x), c1 = dup2(bb.y), c2 = dup2(bb.z), c3 = dup2(bb.w);
            #pragma unroll
            for (int p = 0; p < 4; p++) { acc[0][p] = c0; acc[1][p] = c1; acc[2][p] = c2; acc[3][p] = c3; }
        }
        const float4* w14 = (const float4*)w1t;
        #pragma unroll 4
        for (int ic = 0; ic < 80; ic++) {
            float4 w = __ldg(&w14[ic * 20 + ocg]);
            u64 w0 = dup2(w.x), w1 = dup2(w.y), w2 = dup2(w.z), w3 = dup2(w.w);
            ulonglong2 xa = *(const ulonglong2*)&gsm[ic * 132 + ts0];
            ulonglong2 xb = *(const ulonglong2*)&gsm[ic * 132 + ts0 + 4];
            fma2(acc[0][0], w0, xa.x); fma2(acc[0][1], w0, xa.y); fma2(acc[0][2], w0, xb.x); fma2(acc[0][3], w0, xb.y);
            fma2(acc[1][0], w1, xa.x); fma2(acc[1][1], w1, xa.y); fma2(acc[1][2], w1, xb.x); fma2(acc[1][3], w1, xb.y);
            fma2(acc[2][0], w2, xa.x); fma2(acc[2][1], w2, xa.y); fma2(acc[2][2], w2, xb.x); fma2(acc[2][3], w2, xb.y);
            fma2(acc[3][0], w3, xa.x); fma2(acc[3][1], w3, xa.y); fma2(acc[3][2], w3, xb.x); fma2(acc[3][3], w3, xb.y);
        }
        float v[4][8];
        #pragma unroll
        for (int i = 0; i < 4; i++)
            #pragma unroll
            for (int p = 0; p < 4; p++) {
                float2 f = unpack2(acc[i][p]);
                v[i][2 * p] = f.x; v[i][2 * p + 1] = f.y;
            }
        if (RESID) {
            #pragma unroll
            for (int i = 0; i < 4; i++) {
                const float* rr = xin_n + (size_t)(oc0 + i) * TinLd + S * (t0 + ts0) + 3;
                #pragma unroll
                for (int k = 0; k < 8; k++) {
                    if (fullTile || (t0 + ts0 + k) < Tout) v[i][k] += __ldg(rr + S * k);
                }
            }
        }
        if (FUSEFINAL) {
            #pragma unroll
            for (int i = 0; i < 4; i++) {
                *(float4*)&buf2[(oc0 + i) * 132 + ts0]     = make_float4(v[i][0], v[i][1], v[i][2], v[i][3]);
                *(float4*)&buf2[(oc0 + i) * 132 + ts0 + 4] = make_float4(v[i][4], v[i][5], v[i][6], v[i][7]);
            }
        } else if (fullTile) {
            // ToutLd is a multiple of 4 -> rows are 16B aligned
            #pragma unroll
            for (int i = 0; i < 4; i++) {
                float* row = xout + ((size_t)n * 80 + oc0 + i) * ToutLd + t0 + ts0;
                *(float4*)(row)     = make_float4(v[i][0], v[i][1], v[i][2], v[i][3]);
                *(float4*)(row + 4) = make_float4(v[i][4], v[i][5], v[i][6], v[i][7]);
            }
        } else {
            #pragma unroll
            for (int i = 0; i < 4; i++)
                #pragma unroll
                for (int k = 0; k < 8; k++) {
                    int t = t0 + ts0 + k;
                    if (t < Tout) xout[((size_t)n * 80 + oc0 + i) * ToutLd + t] = v[i][k];
                }
        }
    }

    if (FUSEFINAL) {
        __syncthreads();
        // conv0 + relu: buf2 -> gsm (all gsm reads completed before the sync)
        {
            u64 acc[4][4];
            {
                float4 bb = *(const float4*)(bf0 + oc0);
                u64 c0 = dup2(bb.x), c1 = dup2(bb.y), c2 = dup2(bb.z), c3 = dup2(bb.w);
                #pragma unroll
                for (int p = 0; p < 4; p++) { acc[0][p] = c0; acc[1][p] = c1; acc[2][p] = c2; acc[3][p] = c3; }
            }
            const float4* w4 = (const float4*)g_wf0t;
            #pragma unroll 4
            for (int ic = 0; ic < 80; ic++) {
                float4 w = __ldg(&w4[ic * 20 + ocg]);
                u64 w0 = dup2(w.x), w1 = dup2(w.y), w2 = dup2(w.z), w3 = dup2(w.w);
                ulonglong2 xa = *(const ulonglong2*)&buf2[ic * 132 + ts0];
                ulonglong2 xb = *(const ulonglong2*)&buf2[ic * 132 + ts0 + 4];
                fma2(acc[0][0], w0, xa.x); fma2(acc[0][1], w0, xa.y); fma2(acc[0][2], w0, xb.x); fma2(acc[0][3], w0, xb.y);
                fma2(acc[1][0], w1, xa.x); fma2(acc[1][1], w1, xa.y); fma2(acc[1][2], w1, xb.x); fma2(acc[1][3], w1, xb.y);
                fma2(acc[2][0], w2, xa.x); fma2(acc[2][1], w2, xa.y); fma2(acc[2][2], w2, xb.x); fma2(acc[2][3], w2, xb.y);
                fma2(acc[3][0], w3, xa.x); fma2(acc[3][1], w3, xa.y); fma2(acc[3][2], w3, xb.x); fma2(acc[3][3], w3, xb.y);
            }
            __syncthreads();   // all conv0 reads of buf2 done; also orders gsm writes
            #pragma unroll
            for (int i = 0; i < 4; i++) {
                float o[8];
                #pragma unroll
                for (int p = 0; p < 4; p++) {
                    float2 f = unpack2(acc[i][p]);
                    o[2 * p] = fmaxf(f.x, 0.f); o[2 * p + 1] = fmaxf(f.y, 0.f);
                }
                *(float4*)&gsm[(oc0 + i) * 132 + ts0]     = make_float4(o[0], o[1], o[2], o[3]);
                *(float4*)&gsm[(oc0 + i) * 132 + ts0 + 4] = make_float4(o[4], o[5], o[6], o[7]);
            }
        }
        __syncthreads();
        // conv1: gsm -> out (N,T,80)
        {
            u64 acc[4][4];
            {
                float4 bb = *(const float4*)(bf1 + oc0);
                u64 c0 = dup2(bb.x), c1 = dup2(bb.y), c2 = dup2(bb.z), c3 = dup2(bb.w);
                #pragma unroll
                for (int p = 0; p < 4; p++) { acc[0][p] = c0; acc[1][p] = c1; acc[2][p] = c2; acc[3][p] = c3; }
            }
            const float4* w4 = (const float4*)g_wf1t;
            #pragma unroll 4
            for (int ic = 0; ic < 80; ic++) {
                float4 w = __ldg(&w4[ic * 20 + ocg]);
                u64 w0 = dup2(w.x), w1 = dup2(w.y), w2 = dup2(w.z), w3 = dup2(w.w);
                ulonglong2 xa = *(const ulonglong2*)&gsm[ic * 132 + ts0];
                ulonglong2 xb = *(const ulonglong2*)&gsm[ic * 132 + ts0 + 4];
                fma2(acc[0][0], w0, xa.x); fma2(acc[0][1], w0, xa.y); fma2(acc[0][2], w0, xb.x); fma2(acc[0][3], w0, xb.y);
                fma2(acc[1][0], w1, xa.x); fma2(acc[1][1], w1, xa.y); fma2(acc[1][2], w1, xb.x); fma2(acc[1][3], w1, xb.y);
                fma2(acc[2][0], w2, xa.x); fma2(acc[2][1], w2, xa.y); fma2(acc[2][2], w2, xb.x); fma2(acc[2][3], w2, xb.y);
                fma2(acc[3][0], w3, xa.x); fma2(acc[3][1], w3, xa.y); fma2(acc[3][2], w3, xb.x); fma2(acc[3][3], w3, xb.y);
            }
            #pragma unroll
            for (int p = 0; p < 4; p++) {
                float2 f0 = unpack2(acc[0][p]);
                float2 f1 = unpack2(acc[1][p]);
                float2 f2 = unpack2(acc[2][p]);
                float2 f3 = unpack2(acc[3][p]);
                int t = t0 + ts0 + 2 * p;
                if (t < Tout)
                    *(float4*)(xout + ((size_t)n * Tout + t) * 80 + oc0) =
                        make_float4(f0.x, f1.x, f2.x, f3.x);
                if (t + 1 < Tout)
                    *(float4*)(xout + ((size_t)n * Tout + t + 1) * 80 + oc0) =
                        make_float4(f0.y, f1.y, f2.y, f3.y);
            }
        }
    }
}

// ---------------------------------------------------------------------------
// VQ nearest-neighbor + linear head + tanh + per-(n,class) max
// ---------------------------------------------------------------------------
__device__ __forceinline__ unsigned fenc(float f) {
    unsigned u = __float_as_uint(f);
    return (u & 0x80000000u) ? ~u : (u | 0x80000000u);
}

__global__ __launch_bounds__(512) void vq_kernel(
    const float* __restrict__ encS,
    const float* __restrict__ encQ,
    const float* __restrict__ emb,
    const float* __restrict__ wlin,
    const float* __restrict__ blin)
{
    __shared__ __align__(16) float xq[64 * 84];
    __shared__ __align__(16) float eb[64 * 80];
    __shared__ float rd[512];
    __shared__ int   ri[512];
    __shared__ unsigned sm0, sm1;

    const int tid = threadIdx.x;
    const int n   = blockIdx.y;
    const int t0  = blockIdx.x * 64;

    if (tid == 0) { sm0 = 0u; sm1 = 0u; }

    {
        const float4* src = (const float4*)(encS + (size_t)n * 2040 * 80);
        #pragma unroll
        for (int r = 0; r < 3; r++) {
            int i = r * 512 + tid;
            if (i < 64 * 20) {
                int t = i / 20, c4 = i % 20;
                int tg2 = t0 + t;
                float4 v = {0.f, 0.f, 0.f, 0.f};
                if (tg2 < 2040) v = src[(size_t)tg2 * 20 + c4];
                *(float4*)&xq[t * 84 + c4 * 4] = v;
            }
        }
    }

    const int kg = tid >> 6;
    const int lt = tid & 63;
    float best = 3.4e38f;
    int   bi   = 0;

    for (int tile = 0; tile < 8; tile++) {
        __syncthreads();
        {
            const float4* src = (const float4*)(emb + (size_t)tile * 64 * 80);
            #pragma unroll
            for (int r = 0; r < 3; r++) {
                int i = r * 512 + tid;
                if (i < 64 * 20) *(float4*)&eb[(i / 20) * 80 + (i % 20) * 4] = src[i];
            }
        }
        __syncthreads();
        #pragma unroll
        for (int qb = 0; qb < 2; qb++) {
            int kl0 = kg * 8 + qb * 4;
            u64 a0 = 0ull, a1 = 0ull, a2 = 0ull, a3 = 0ull;
            u64 b0 = 0ull, b1 = 0ull, b2 = 0ull, b3 = 0ull;
            #pragma unroll
            for (int c4 = 0; c4 < 20; c4++) {
                ulonglong2 xv = *(const ulonglong2*)&xq[lt * 84 + c4 * 4];
                ulonglong2 e0 = *(const ulonglong2*)&eb[(kl0 + 0) * 80 + c4 * 4];
                ulonglong2 e1 = *(const ulonglong2*)&eb[(kl0 + 1) * 80 + c4 * 4];
                ulonglong2 e2 = *(const ulonglong2*)&eb[(kl0 + 2) * 80 + c4 * 4];
                ulonglong2 e3 = *(const ulonglong2*)&eb[(kl0 + 3) * 80 + c4 * 4];
                fma2(a0, xv.x, e0.x); fma2(b0, xv.y, e0.y);
                fma2(a1, xv.x, e1.x); fma2(b1, xv.y, e1.y);
                fma2(a2, xv.x, e2.x); fma2(b2, xv.y, e2.y);
                fma2(a3, xv.x, e3.x); fma2(b3, xv.y, e3.y);
            }
            u64 aa[4] = {a0, a1, a2, a3};
            u64 bb[4] = {b0, b1, b2, b3};
            #pragma unroll
            for (int j = 0; j < 4; j++) {
                float2 p0 = unpack2(aa[j]), p1 = unpack2(bb[j]);
                float dot = (p0.x + p0.y) + (p1.x + p1.y);
                int kgl = tile * 64 + kl0 + j;
                float d = g_e2[kgl] - 2.f * dot;
                if (d < best) { best = d; bi = kgl; }
            }
        }
    }
    rd[tid] = best; ri[tid] = bi;
    __syncthreads();

    if (tid < 64) {
        float bd = rd[tid];
        int  bbi = ri[tid];
        #pragma unroll
        for (int g2 = 1; g2 < 8; g2++) {
            float d = rd[g2 * 64 + tid];
            int  ii = ri[g2 * 64 + tid];
            if (d < bd || (d == bd && ii < bbi)) { bd = d; bbi = ii; }
        }
        int tg2 = t0 + tid;
        if (tg2 < 2040) {
            const float* dv = emb + (size_t)bbi * 80;
            const float* qr = (tg2 < 2016)
                            ? (encQ + ((size_t)n * 504 + (tg2 % 504)) * 80)
                            : nullptr;
            float s0 = blin[0], s1 = blin[1];
            #pragma unroll 4
            for (int c = 0; c < 80; c++) {
                float v = dv[c] + (qr ? qr[c] : 0.f);
                s0 = fmaf(v, wlin[c],      s0);
                s1 = fmaf(v, wlin[80 + c], s1);
            }
            atomicMax(&sm0, fenc(tanhf(s0)));
            atomicMax(&sm1, fenc(tanhf(s1)));
        }
    }
    __syncthreads();
    if (tid == 0) {
        atomicMax(&g_gmax[n * 2 + 0], sm0);
        atomicMax(&g_gmax[n * 2 + 1], sm1);
    }
}

__global__ void finalize_kernel(float* __restrict__ out) {
    int i = threadIdx.x;
    if (i < 32) {
        unsigned e = g_gmax[i];
        out[i] = (e & 0x80000000u) ? __uint_as_float(e ^ 0x80000000u)
                                   : __uint_as_float(~e);
    }
}

// ---------------------------------------------------------------------------
// Host launch
// ---------------------------------------------------------------------------
extern "C" void kernel_launch(void* const* d_in, const int* in_sizes, int n_in,
                              void* d_out, int out_size) {
    const float* search = (const float*)d_in[0];
    const float* query  = (const float*)d_in[1];
    const float* w_wide = (const float*)d_in[2];
    const float* b_wide = (const float*)d_in[3];
    const float* w_1x1  = (const float*)d_in[4];
    const float* b_1x1  = (const float*)d_in[5];
    const float* w_f0   = (const float*)d_in[6];
    const float* b_f0   = (const float*)d_in[7];
    const float* w_f1   = (const float*)d_in[8];
    const float* b_f1   = (const float*)d_in[9];
    const float* emb    = (const float*)d_in[10];
    const float* w_lin  = (const float*)d_in[11];
    const float* b_lin  = (const float*)d_in[12];
    float* out = (float*)d_out;

    void *pA, *pB, *pAq, *pBq, *pS, *pQ, *pwh, *pwl, *pw1;
    cudaGetSymbolAddress(&pA,  g_bufA);
    cudaGetSymbolAddress(&pB,  g_bufB);
    cudaGetSymbolAddress(&pAq, g_bufAq);
    cudaGetSymbolAddress(&pBq, g_bufBq);
    cudaGetSymbolAddress(&pS,  g_encS);
    cudaGetSymbolAddress(&pQ,  g_encQ);
    cudaGetSymbolAddress(&pwh, g_wbh);
    cudaGetSymbolAddress(&pwl, g_wbl);
    cudaGetSymbolAddress(&pw1, g_w1t);
    float* A   = (float*)pA;
    float* B   = (float*)pB;
    float* Aq  = (float*)pAq;
    float* Bq  = (float*)pBq;
    float* eS  = (float*)pS;
    float* eQ  = (float*)pQ;
    __nv_bfloat16* wbh = (__nv_bfloat16*)pwh;
    __nv_bfloat16* wbl = (__nv_bfloat16*)pwl;
    float* w1t = (float*)pw1;

    cudaFuncSetAttribute(gemm_layer_kernel<2, true,  false, false>,
                         cudaFuncAttributeMaxDynamicSharedMemorySize, SMEM_NOFUSE);
    cudaFuncSetAttribute(gemm_layer_kernel<2, false, true,  false>,
                         cudaFuncAttributeMaxDynamicSharedMemorySize, SMEM_NOFUSE);
    cudaFuncSetAttribute(gemm_layer_kernel<1, false, true,  false>,
                         cudaFuncAttributeMaxDynamicSharedMemorySize, SMEM_NOFUSE);
    cudaFuncSetAttribute(gemm_layer_kernel<1, false, true,  true >,
                         cudaFuncAttributeMaxDynamicSharedMemorySize, SMEM_FUSE);

    prep_kernel<<<80, 256>>>(w_wide, w_1x1, w_f0, w_f1, emb);

    // L0: search 8192 -> 4095 (ld 4096), query 2048 -> 1023 (ld 1024)
    gemm_layer_kernel<2, true, false, false><<<dim3(40, NB), 320, SMEM_NOFUSE>>>(
        search, query, A, Aq,
        wbh + 0 * 51200, wbl + 0 * 51200, b_wide + 0 * 160,
        w1t + 0 * 6400, b_1x1 + 0 * 80, nullptr, nullptr,
        8192, 8192, 4095, 4096,  2048, 2048, 1023, 1024,  32);

    // L1: 4095 (ld 4096) -> 2046 (ld 2048); 1023 (ld 1024) -> 510 (ld 512)
    gemm_layer_kernel<2, false, true, false><<<dim3(20, NB), 320, SMEM_NOFUSE>>>(
        A, Aq, B, Bq,
        wbh + 1 * 51200, wbl + 1 * 51200, b_wide + 1 * 160,
        w1t + 1 * 6400, b_1x1 + 1 * 80, nullptr, nullptr,
        4095, 4096, 2046, 2048,  1023, 1024, 510, 512,  16);

    // L2: 2046 (ld 2048) -> 2043 (ld 2044); 510 (ld 512) -> 507 (ld 508)
    gemm_layer_kernel<1, false, true, false><<<dim3(20, NB), 320, SMEM_NOFUSE>>>(
        B, Bq, A, Aq,
        wbh + 2 * 51200, wbl + 2 * 51200, b_wide + 2 * 160,
        w1t + 2 * 6400, b_1x1 + 2 * 80, nullptr, nullptr,
        2046, 2048, 2043, 2044,  510, 512, 507, 508,  16);

    // L3 + final convs: 2043 (ld 2044) -> 2040; 507 (ld 508) -> 504; out (N,T,80)
    gemm_layer_kernel<1, false, true, true><<<dim3(20, NB), 320, SMEM_FUSE>>>(
        A, Aq, eS, eQ,
        wbh + 3 * 51200, wbl + 3 * 51200, b_wide + 3 * 160,
        w1t + 3 * 6400, b_1x1 + 3 * 80, b_f0, b_f1,
        2043, 2044, 2040, 2040,  507, 508, 504, 504,  16);

    vq_kernel<<<dim3(32, NB), 512>>>(eS, eQ, emb, w_lin, b_lin);
    finalize_kernel<<<1, 32>>>(out);
}

// round 9
// speedup vs baseline: 2.6239x; 1.3094x over previous
#include <cuda_runtime.h>
#include <cuda_bf16.h>
#include <cstdint>

#define NB 16
typedef unsigned long long u64;

#if defined(__CUDA_ARCH_FEAT_SM103_ALL) || defined(__CUDA_ARCH_FEAT_SM100_ALL) || \
    (defined(__CUDA_ARCH_SPECIFIC__) && (__CUDA_ARCH_SPECIFIC__ >= 1000))
#define HAS_TC 1
#else
#define HAS_TC 0
#endif

// ---------------------------------------------------------------------------
// PTX helpers
// ---------------------------------------------------------------------------
__device__ __forceinline__ void fma2(u64& d, u64 a, u64 b) {
    asm("fma.rn.f32x2 %0, %1, %2, %0;" : "+l"(d) : "l"(a), "l"(b));
}
__device__ __forceinline__ float2 unpack2(u64 v) {
    float2 f; asm("mov.b64 {%0, %1}, %2;" : "=f"(f.x), "=f"(f.y) : "l"(v)); return f;
}
__device__ __forceinline__ uint32_t smem_u32(const void* p) {
    uint32_t a;
    asm("{ .reg .u64 t; cvta.to.shared.u64 t, %1; cvt.u32.u64 %0, t; }" : "=r"(a) : "l"(p));
    return a;
}
__device__ __forceinline__ float ex2f(float x) {
    float r; asm("ex2.approx.f32 %0, %1;" : "=f"(r) : "f"(x)); return r;
}
__device__ __forceinline__ float rcpf(float x) {
    float r; asm("rcp.approx.f32 %0, %1;" : "=f"(r) : "f"(x)); return r;
}
__device__ __forceinline__ uint32_t prmt_hi(uint32_t a, uint32_t b) {
    uint32_t r; asm("prmt.b32 %0, %1, %2, 0x7632;" : "=r"(r) : "r"(a), "r"(b)); return r;
}
__device__ __forceinline__ uint32_t cvt_bf16x2(float hi, float lo) {
    uint32_t r; asm("cvt.rn.bf16x2.f32 %0, %1, %2;" : "=r"(r) : "f"(hi), "f"(lo)); return r;
}
__device__ __forceinline__ float gatef(float a, float g) {
    float e1 = ex2f(fminf(a * -2.885390082f, 80.f));
    float e2 = ex2f(fminf(g * -1.442695041f, 80.f));
    float r  = rcpf((1.f + e1) * (1.f + e2));
    return (1.f - e1) * r;
}

#if HAS_TC
__device__ __forceinline__ uint32_t elect_one() {
    uint32_t p;
    asm volatile("{\n\t.reg .pred p;\n\telect.sync _|p, 0xFFFFFFFF;\n\tselp.b32 %0, 1, 0, p;\n\t}" : "=r"(p));
    return p;
}

#define TCGEN05_ALLOC(sm, n) \
    asm volatile("tcgen05.alloc.cta_group::1.sync.aligned.shared::cta.b32 [%0], %1;" \
                 :: "r"((uint32_t)(sm)), "r"((uint32_t)(n)) : "memory")
#define TCGEN05_RELINQ() \
    asm volatile("tcgen05.relinquish_alloc_permit.cta_group::1.sync.aligned;")
#define TCGEN05_DEALLOC(t, n) \
    asm volatile("tcgen05.dealloc.cta_group::1.sync.aligned.b32 %0, %1;" :: "r"(t), "r"((uint32_t)(n)))
#define TCGEN05_COMMIT(mb) \
    asm volatile("tcgen05.commit.cta_group::1.mbarrier::arrive::one.shared::cluster.b64 [%0];" \
                 :: "r"((uint32_t)(mb)) : "memory")
#define TCGEN05_FENCE_AFTER()  asm volatile("tcgen05.fence::after_thread_sync;" ::: "memory")
#define TCGEN05_WAIT_LD()      asm volatile("tcgen05.wait::ld.sync.aligned;" ::: "memory")
#define FENCE_ASYNC_SHARED()   asm volatile("fence.proxy.async.shared::cta;" ::: "memory")
#define MBARRIER_INIT(mb, c) \
    asm volatile("mbarrier.init.shared.b64 [%0], %1;" :: "r"((uint32_t)(mb)), "r"((uint32_t)(c)) : "memory")

#define MBAR_WAIT(mb, ph) do {                                                  \
    uint32_t _m = (uint32_t)(mb), _p = (uint32_t)(ph), _d;                      \
    asm volatile("{\n\t.reg .pred p;\n\t"                                       \
        "mbarrier.try_wait.parity.acquire.cta.shared::cta.b64 p, [%1], %2;\n\t" \
        "selp.b32 %0, 1, 0, p;\n\t}" : "=r"(_d) : "r"(_m), "r"(_p) : "memory"); \
    if (!_d) {                                                                  \
        asm volatile("{\n\t.reg .pred P1;\n\t"                                  \
            "WL_%=:\n\t"                                                        \
            "mbarrier.try_wait.parity.acquire.cta.shared::cta.b64 P1, [%0], %1, 0x989680;\n\t" \
            "@P1 bra.uni WD_%=;\n\t"                                            \
            "bra.uni WL_%=;\n\t"                                                \
            "WD_%=:\n\t}" :: "r"(_m), "r"(_p) : "memory");                      \
    }                                                                           \
} while (0)

#define LDTM_X32(r, a) \
    asm volatile("tcgen05.ld.sync.aligned.32x32b.x32.b32 " \
        "{%0,%1,%2,%3,%4,%5,%6,%7,%8,%9,%10,%11,%12,%13,%14,%15," \
        "%16,%17,%18,%19,%20,%21,%22,%23,%24,%25,%26,%27,%28,%29,%30,%31}, [%32];" \
        : "=r"((r)[0]),"=r"((r)[1]),"=r"((r)[2]),"=r"((r)[3]),"=r"((r)[4]),"=r"((r)[5]),"=r"((r)[6]),"=r"((r)[7]), \
          "=r"((r)[8]),"=r"((r)[9]),"=r"((r)[10]),"=r"((r)[11]),"=r"((r)[12]),"=r"((r)[13]),"=r"((r)[14]),"=r"((r)[15]), \
          "=r"((r)[16]),"=r"((r)[17]),"=r"((r)[18]),"=r"((r)[19]),"=r"((r)[20]),"=r"((r)[21]),"=r"((r)[22]),"=r"((r)[23]), \
          "=r"((r)[24]),"=r"((r)[25]),"=r"((r)[26]),"=r"((r)[27]),"=r"((r)[28]),"=r"((r)[29]),"=r"((r)[30]),"=r"((r)[31]) \
        : "r"(a))

#define LDTM_X16(r, a) \
    asm volatile("tcgen05.ld.sync.aligned.32x32b.x16.b32 " \
        "{%0,%1,%2,%3,%4,%5,%6,%7,%8,%9,%10,%11,%12,%13,%14,%15}, [%16];" \
        : "=r"((r)[0]),"=r"((r)[1]),"=r"((r)[2]),"=r"((r)[3]),"=r"((r)[4]),"=r"((r)[5]),"=r"((r)[6]),"=r"((r)[7]), \
          "=r"((r)[8]),"=r"((r)[9]),"=r"((r)[10]),"=r"((r)[11]),"=r"((r)[12]),"=r"((r)[13]),"=r"((r)[14]),"=r"((r)[15]) \
        : "r"(a))

__device__ __forceinline__ void mma_f16_ss(uint32_t d, u64 ad, u64 bd, uint32_t idesc, uint32_t en) {
    asm volatile("{\n\t.reg .pred p;\n\tsetp.ne.u32 p, %5, 0;\n\t"
        "tcgen05.mma.cta_group::1.kind::f16 [%0], %1, %2, %3, {%4,%4,%4,%4}, p;\n\t}"
        :: "r"(d), "l"(ad), "l"(bd), "r"(idesc), "r"(0u), "r"(en) : "memory");
}

static __device__ __forceinline__ u64 make_desc(uint32_t addr) {
    return (u64(2) << 61) | (u64(1) << 46) | (u64(64) << 32) | (u64(1) << 16)
         | ((u64)(addr >> 4) & 0x3FFF);
}

#define IDESC_W ((1u<<4) | (1u<<7) | (1u<<10) | (10u<<17) | (8u<<24))
#endif // HAS_TC

// ---------------------------------------------------------------------------
// Device scratch
// ---------------------------------------------------------------------------
__device__ __align__(16) __nv_bfloat16 g_wbh[4 * 160 * 320];
__device__ __align__(16) __nv_bfloat16 g_wbl[4 * 160 * 320];
__device__ __align__(16) char g_w1s [4][2][20480];  // 1x1 weights, swizzled bf16 hi/lo
__device__ __align__(16) char g_wf0s[2][20480];
__device__ __align__(16) char g_wf1s[2][20480];
__device__ __align__(16) float g_w1t [4 * 80 * 80]; // fp32 (fallback only)
__device__ __align__(16) float g_wf0t[80 * 80];
__device__ __align__(16) float g_wf1t[80 * 80];
__device__ __align__(16) float g_e2  [512];
__device__ __align__(16) float g_bufA [16 * 80 * 4096];
__device__ __align__(16) float g_bufB [16 * 80 * 2048];
__device__ __align__(16) float g_bufAq[16 * 80 * 1024];
__device__ __align__(16) float g_bufBq[16 * 80 * 512];
__device__ __align__(16) float g_encS[16 * 2040 * 80];
__device__ __align__(16) float g_encQ[16 * 504 * 80];
__device__ unsigned g_gmax[32];

// ---------------------------------------------------------------------------
// Weight prep
// ---------------------------------------------------------------------------
__global__ void prep_kernel(const float* __restrict__ w_wide,
                            const float* __restrict__ w_1x1,
                            const float* __restrict__ w_f0,
                            const float* __restrict__ w_f1,
                            const float* __restrict__ emb) {
    int g = blockIdx.x * blockDim.x + threadIdx.x;
    int stride = gridDim.x * blockDim.x;
    for (int idx = g; idx < 4 * 160 * 320; idx += stride) {
        float v = w_wide[idx];
        __nv_bfloat16 h = __float2bfloat16(v);
        g_wbh[idx] = h;
        g_wbl[idx] = __float2bfloat16(v - __bfloat162float(h));
    }
    // swizzled bf16 hi/lo images for the N=80,K=128(pad) GEMM-B tiles
    for (int idx = g; idx < 4 * 80 * 128; idx += stride) {
        int l = idx / 10240, r = idx % 10240;
        int oc = r >> 7, k = r & 127;
        float v = (k < 80) ? w_1x1[l * 6400 + oc * 80 + k] : 0.f;
        __nv_bfloat16 h = __float2bfloat16(v);
        __nv_bfloat16 lo = __float2bfloat16(v - __bfloat162float(h));
        uint32_t off = (uint32_t)(((oc >> 3) + (k >> 6) * 10) * 1024 + (oc & 7) * 128 + (k & 63) * 2);
        uint32_t sw  = off ^ ((off >> 3) & 0x70);
        *(__nv_bfloat16*)(g_w1s[l][0] + sw) = h;
        *(__nv_bfloat16*)(g_w1s[l][1] + sw) = lo;
    }
    for (int idx = g; idx < 80 * 128; idx += stride) {
        int oc = idx >> 7, k = idx & 127;
        uint32_t off = (uint32_t)(((oc >> 3) + (k >> 6) * 10) * 1024 + (oc & 7) * 128 + (k & 63) * 2);
        uint32_t sw  = off ^ ((off >> 3) & 0x70);
        float v0 = (k < 80) ? w_f0[oc * 80 + k] : 0.f;
        float v1 = (k < 80) ? w_f1[oc * 80 + k] : 0.f;
        __nv_bfloat16 h0 = __float2bfloat16(v0);
        __nv_bfloat16 h1 = __float2bfloat16(v1);
        *(__nv_bfloat16*)(g_wf0s[0] + sw) = h0;
        *(__nv_bfloat16*)(g_wf0s[1] + sw) = __float2bfloat16(v0 - __bfloat162float(h0));
        *(__nv_bfloat16*)(g_wf1s[0] + sw) = h1;
        *(__nv_bfloat16*)(g_wf1s[1] + sw) = __float2bfloat16(v1 - __bfloat162float(h1));
    }
    // fp32 transposes (fallback path only)
    for (int idx = g; idx < 4 * 80 * 80; idx += stride) {
        int ic = idx % 80, oc = (idx / 80) % 80, l = idx / 6400;
        g_w1t[l * 6400 + ic * 80 + oc] = w_1x1[idx];
    }
    for (int idx = g; idx < 6400; idx += stride) {
        int ic = idx % 80, oc = idx / 80;
        g_wf0t[ic * 80 + oc] = w_f0[idx];
        g_wf1t[ic * 80 + oc] = w_f1[idx];
    }
    for (int k = g; k < 512; k += stride) {
        float s = 0.f;
        for (int c = 0; c < 80; c++) { float v = emb[k * 80 + c]; s += v * v; }
        g_e2[k] = s;
    }
    if (g < 32) g_gmax[g] = 0u;
}

// ---------------------------------------------------------------------------
// smem layout (1024-aligned base):
//   wide GEMM:  A_hi @0 (16K), A_lo @16K, B_hi @32K (20K), B_lo @52K (end 72K)
//   2nd GEMMs:  A2_hi @0 (32K), A2_lo @32K, B2_hi @64K (20K), B2_lo @84K (end 104K)
// ---------------------------------------------------------------------------
#define OFF_A_HI  0
#define OFF_A_LO  16384
#define OFF_B_HI  32768
#define OFF_B_LO  53248
#define OFF2_A_HI 0
#define OFF2_A_LO 32768
#define OFF2_B_HI 65536
#define OFF2_B_LO 86016
#define SMEM_DYN  (1024 + 106496)

#if HAS_TC
// pack 8 consecutive K-values of row t into A2 (hi/lo), granule g8 (0..9)
__device__ __forceinline__ void pack8(char* abp, int t, int g8, const float* v) {
    uint32_t ub[8]; float lo[8];
    #pragma unroll
    for (int i = 0; i < 8; i++) {
        ub[i] = __float_as_uint(v[i]);
        lo[i] = v[i] - __uint_as_float(ub[i] & 0xFFFF0000u);
    }
    uint4 hp, lp;
    hp.x = prmt_hi(ub[0], ub[1]); hp.y = prmt_hi(ub[2], ub[3]);
    hp.z = prmt_hi(ub[4], ub[5]); hp.w = prmt_hi(ub[6], ub[7]);
    lp.x = cvt_bf16x2(lo[1], lo[0]); lp.y = cvt_bf16x2(lo[3], lo[2]);
    lp.z = cvt_bf16x2(lo[5], lo[4]); lp.w = cvt_bf16x2(lo[7], lo[6]);
    uint32_t off = (uint32_t)(((t >> 3) + ((g8 >= 8) ? 16 : 0)) * 1024 + (t & 7) * 128 + (g8 & 7) * 16);
    uint32_t sw  = off ^ ((off >> 3) & 0x70);
    *(uint4*)(abp + OFF2_A_HI + sw) = hp;
    *(uint4*)(abp + OFF2_A_LO + sw) = lp;
}
// copy 20KB hi + 20KB lo weight image into B2 (threads 128..319)
__device__ __forceinline__ void copy_w2(char* abp, const char* hi, const char* lo, int tid) {
    if (tid >= 128) {
        for (int i = tid - 128; i < 1280; i += 192) {
            ((uint4*)(abp + OFF2_B_HI))[i] = __ldg((const uint4*)hi + i);
            ((uint4*)(abp + OFF2_B_LO))[i] = __ldg((const uint4*)lo + i);
        }
    }
}
// issue a 3-pass bf16x3 GEMM: A2(K<=80 in 5 ksteps) x B2 -> tmem cols [dst, dst+80)
__device__ __forceinline__ void issue_gemm2(uint32_t tmem_dst, uint32_t ab, uint32_t mbar) {
    u64 dAh = make_desc(ab + OFF2_A_HI), dAl = make_desc(ab + OFF2_A_LO);
    u64 dBh = make_desc(ab + OFF2_B_HI), dBl = make_desc(ab + OFF2_B_LO);
    u64 pA[3] = {dAh, dAh, dAl};
    u64 pB[3] = {dBh, dBl, dBh};
    #pragma unroll
    for (int p = 0; p < 3; p++) {
        #pragma unroll
        for (int s = 0; s < 5; s++) {
            uint32_t en = (p == 0 && s == 0) ? 0u : 1u;
            u64 ao = (s < 4) ? (u64)(2 * s) : 1024ull;
            u64 bo = (s < 4) ? (u64)(2 * s) : 640ull;
            mma_f16_ss(tmem_dst, pA[p] + ao, pB[p] + bo, IDESC_W, en);
        }
    }
    TCGEN05_COMMIT(mbar);
}
#endif

template <int S, bool FIRST, bool RESID, bool FUSEFINAL>
__global__ __launch_bounds__(320, 2) void gemm_layer_kernel(
    const float* __restrict__ xinS, const float* __restrict__ xinQ,
    float* __restrict__ xoutS, float* __restrict__ xoutQ,
    const __nv_bfloat16* __restrict__ wbh, const __nv_bfloat16* __restrict__ wbl,
    const float* __restrict__ bw,
    const char* __restrict__ w2h, const char* __restrict__ w2l,
    const float* __restrict__ w1t, const float* __restrict__ b1,
    const char* __restrict__ wf0h, const char* __restrict__ wf0l,
    const char* __restrict__ wf1h, const char* __restrict__ wf1l,
    const float* __restrict__ bf0, const float* __restrict__ bf1,
    int TinS, int TinLdS, int ToutS, int ToutLdS,
    int TinQ, int TinLdQ, int ToutQ, int ToutLdQ, int blocksS)
{
    extern __shared__ char dsm[];
    __shared__ float s_bias[400];

    const int tid = threadIdx.x;
    const int wid = tid >> 5;
    const int n   = blockIdx.y;
    const int bx  = blockIdx.x;

    const float* xin; float* xout; int Tin, TinLd, Tout, ToutLd, t0;
    if (bx < blocksS) {
        xin = xinS; xout = xoutS; Tin = TinS; TinLd = TinLdS;
        Tout = ToutS; ToutLd = ToutLdS; t0 = bx * 128;
    } else {
        xin = xinQ; xout = xoutQ; Tin = TinQ; TinLd = TinLdQ;
        Tout = ToutQ; ToutLd = ToutLdQ; t0 = (bx - blocksS) * 128;
    }
    const float* xin_n = xin + (size_t)n * 80 * TinLd;

    uint32_t base_raw = smem_u32(dsm);
    uint32_t ab = (base_raw + 1023u) & ~1023u;
    char* abp = dsm + (ab - base_raw);

    // bias preload
    for (int i = tid; i < 400; i += 320) {
        float v = 0.f;
        if (i < 160) v = __ldg(bw + i);
        else if (i < 240) v = __ldg(b1 + i - 160);
        else if (FUSEFINAL && i < 320) v = __ldg(bf0 + i - 240);
        else if (FUSEFINAL) v = __ldg(bf1 + i - 320);
        s_bias[i] = v;
    }

#if HAS_TC
    __shared__ uint32_t s_tmem;
    __shared__ __align__(8) u64 s_mbar;

    if (tid == 0) MBARRIER_INIT(smem_u32(&s_mbar), 1);
    if (wid == 0) { TCGEN05_ALLOC(smem_u32(&s_tmem), 256); TCGEN05_RELINQ(); }
    __syncthreads();
    const uint32_t tmem = s_tmem;
    const uint32_t mbar = smem_u32(&s_mbar);

    // ---- wide GEMM: 5 K-chunks of 64, D -> tmem cols 0..159 ----
    for (int kc = 0; kc < 5; kc++) {
        const int k0 = kc * 64;
        if (kc > 0) MBAR_WAIT(mbar, (kc - 1) & 1);
        #pragma unroll
        for (int r = 0; r < 4; r++) {
            int gi = r * 320 + tid;
            if (gi < 1024) {
                int t  = gi & 127;
                int g8 = gi >> 7;
                int c0 = (k0 >> 2) + g8 * 2;
                int u0 = S * (t0 + t);
                float v[8];
                if (FIRST) {
                    #pragma unroll
                    for (int j = 0; j < 4; j++) {
                        int u = u0 + j;
                        if (u < Tin) {
                            float2 p = __ldg((const float2*)&xin_n[(size_t)u * 80 + c0]);
                            v[j] = p.x; v[4 + j] = p.y;
                        } else { v[j] = 0.f; v[4 + j] = 0.f; }
                    }
                } else {
                    const float* r0 = xin_n + (size_t)c0 * TinLd + u0;
                    #pragma unroll
                    for (int j = 0; j < 4; j++) {
                        bool ok = (u0 + j) < Tin;
                        v[j]     = ok ? __ldg(r0 + j)         : 0.f;
                        v[4 + j] = ok ? __ldg(r0 + TinLd + j) : 0.f;
                    }
                }
                uint32_t ub[8]; float lo[8];
                #pragma unroll
                for (int i = 0; i < 8; i++) {
                    ub[i] = __float_as_uint(v[i]);
                    lo[i] = v[i] - __uint_as_float(ub[i] & 0xFFFF0000u);
                }
                uint4 hp, lp;
                hp.x = prmt_hi(ub[0], ub[1]); hp.y = prmt_hi(ub[2], ub[3]);
                hp.z = prmt_hi(ub[4], ub[5]); hp.w = prmt_hi(ub[6], ub[7]);
                lp.x = cvt_bf16x2(lo[1], lo[0]); lp.y = cvt_bf16x2(lo[3], lo[2]);
                lp.z = cvt_bf16x2(lo[5], lo[4]); lp.w = cvt_bf16x2(lo[7], lo[6]);
                uint32_t off = (uint32_t)((t >> 3) * 1024 + (t & 7) * 128 + g8 * 16);
                uint32_t sw  = off ^ ((off >> 3) & 0x70);
                *(uint4*)(abp + OFF_A_HI + sw) = hp;
                *(uint4*)(abp + OFF_A_LO + sw) = lp;
            }
        }
        {
            const uint4* srcH = (const uint4*)wbh;
            const uint4* srcL = (const uint4*)wbl;
            #pragma unroll
            for (int r = 0; r < 4; r++) {
                int gi = r * 320 + tid;
                int row = gi >> 3, g8 = gi & 7;
                int si  = row * 40 + (k0 >> 3) + g8;
                uint32_t off = (uint32_t)((row >> 3) * 1024 + (row & 7) * 128 + g8 * 16);
                uint32_t sw  = off ^ ((off >> 3) & 0x70);
                *(uint4*)(abp + OFF_B_HI + sw) = __ldg(srcH + si);
                *(uint4*)(abp + OFF_B_LO + sw) = __ldg(srcL + si);
            }
        }
        FENCE_ASYNC_SHARED();
        __syncthreads();

        if (wid == 0 && elect_one()) {
            u64 dAh = make_desc(ab + OFF_A_HI), dAl = make_desc(ab + OFF_A_LO);
            u64 dBh = make_desc(ab + OFF_B_HI), dBl = make_desc(ab + OFF_B_LO);
            u64 pA[3] = {dAh, dAh, dAl};
            u64 pB[3] = {dBh, dBl, dBh};
            #pragma unroll
            for (int p = 0; p < 3; p++) {
                #pragma unroll
                for (int s = 0; s < 4; s++) {
                    uint32_t en = (kc == 0 && p == 0 && s == 0) ? 0u : 1u;
                    u64 ad = pA[p] + s * 2;
                    mma_f16_ss(tmem,      ad, pB[p] + s * 2,       IDESC_W, en);
                    mma_f16_ss(tmem + 80, ad, pB[p] + 640 + s * 2, IDESC_W, en);
                }
            }
            TCGEN05_COMMIT(mbar);
        }
    }
    MBAR_WAIT(mbar, 0);   // commit #4

    // ---- gate -> bf16 A2 (warps 0-3) ; W1 image copy (warps 4-9) ----
    if (tid < 128) {
        TCGEN05_FENCE_AFTER();
        const int t = tid;
        uint32_t da[32], dg[32];
        #pragma unroll
        for (int ch = 0; ch < 3; ch++) {
            int a0 = ch * 32;
            int w  = (ch == 2) ? 16 : 32;
            if (w == 32) { LDTM_X32(da, tmem + a0); LDTM_X32(dg, tmem + 80 + a0); }
            else         { LDTM_X16(da, tmem + a0); LDTM_X16(dg, tmem + 80 + a0); }
            TCGEN05_WAIT_LD();
            float gv[32];
            for (int i = 0; i < w; i++) {
                float a = __uint_as_float(da[i]) + s_bias[a0 + i];
                float g = __uint_as_float(dg[i]) + s_bias[80 + a0 + i];
                gv[i] = gatef(a, g);
            }
            #pragma unroll
            for (int q = 0; q < 4; q++) {
                if (q * 8 < w) pack8(abp, t, (a0 >> 3) + q, gv + q * 8);
            }
        }
    }
    copy_w2(abp, w2h, w2l, tid);
    FENCE_ASYNC_SHARED();
    __syncthreads();

    // ---- 1x1 GEMM -> cols 160..239 (commit #5, parity 1) ----
    if (wid == 0 && elect_one()) issue_gemm2(tmem + 160, ab, mbar);
    if (FUSEFINAL) { /* nothing yet */ }
    MBAR_WAIT(mbar, 1);

    if (!FUSEFINAL) {
        // readout: +b1 +residual -> gmem (N,80,ToutLd)
        if (tid < 128) {
            TCGEN05_FENCE_AFTER();
            const int t = tid;
            const bool tv = (t0 + t) < Tout;
            uint32_t d[32];
            #pragma unroll
            for (int ch = 0; ch < 3; ch++) {
                int a0 = ch * 32;
                int w  = (ch == 2) ? 16 : 32;
                if (w == 32) LDTM_X32(d, tmem + 160 + a0);
                else         LDTM_X16(d, tmem + 160 + a0);
                TCGEN05_WAIT_LD();
                if (tv) {
                    for (int i = 0; i < w; i++) {
                        int c = a0 + i;
                        float v = __uint_as_float(d[i]) + s_bias[160 + c];
                        if (RESID) v += __ldg(xin_n + (size_t)c * TinLd + S * (t0 + t) + 3);
                        xout[((size_t)n * 80 + c) * ToutLd + t0 + t] = v;
                    }
                }
            }
        }
        __syncthreads();
        if (wid == 0) TCGEN05_DEALLOC(tmem, 256);
    } else {
        // v1 = 1x1 + b1 + res  -> A3 ; Wf0 copy ; GEMM -> cols 0..79
        if (tid < 128) {
            TCGEN05_FENCE_AFTER();
            const int t = tid;
            const bool tv = (t0 + t) < Tout;
            uint32_t d[32];
            #pragma unroll
            for (int ch = 0; ch < 3; ch++) {
                int a0 = ch * 32;
                int w  = (ch == 2) ? 16 : 32;
                if (w == 32) LDTM_X32(d, tmem + 160 + a0);
                else         LDTM_X16(d, tmem + 160 + a0);
                TCGEN05_WAIT_LD();
                float v[32];
                for (int i = 0; i < w; i++) {
                    int c = a0 + i;
                    v[i] = __uint_as_float(d[i]) + s_bias[160 + c];
                    if (RESID && tv) v[i] += __ldg(xin_n + (size_t)c * TinLd + S * (t0 + t) + 3);
                }
                #pragma unroll
                for (int q = 0; q < 4; q++)
                    if (q * 8 < w) pack8(abp, t, (a0 >> 3) + q, v + q * 8);
            }
        }
        copy_w2(abp, wf0h, wf0l, tid);
        FENCE_ASYNC_SHARED();
        __syncthreads();
        if (wid == 0 && elect_one()) issue_gemm2(tmem + 0, ab, mbar);   // commit #6
        MBAR_WAIT(mbar, 0);

        // h = relu(conv0 + bf0) -> A4 ; Wf1 copy ; GEMM -> cols 80..159
        if (tid < 128) {
            TCGEN05_FENCE_AFTER();
            const int t = tid;
            uint32_t d[32];
            #pragma unroll
            for (int ch = 0; ch < 3; ch++) {
                int a0 = ch * 32;
                int w  = (ch == 2) ? 16 : 32;
                if (w == 32) LDTM_X32(d, tmem + a0);
                else         LDTM_X16(d, tmem + a0);
                TCGEN05_WAIT_LD();
                float v[32];
                for (int i = 0; i < w; i++)
                    v[i] = fmaxf(__uint_as_float(d[i]) + s_bias[240 + a0 + i], 0.f);
                #pragma unroll
                for (int q = 0; q < 4; q++)
                    if (q * 8 < w) pack8(abp, t, (a0 >> 3) + q, v + q * 8);
            }
        }
        copy_w2(abp, wf1h, wf1l, tid);
        FENCE_ASYNC_SHARED();
        __syncthreads();
        if (wid == 0 && elect_one()) issue_gemm2(tmem + 80, ab, mbar);  // commit #7
        MBAR_WAIT(mbar, 1);

        // out = conv1 + bf1 -> enc (N,T,80)
        if (tid < 128) {
            TCGEN05_FENCE_AFTER();
            const int t = tid;
            const bool tv = (t0 + t) < Tout;
            uint32_t d[32];
            #pragma unroll
            for (int ch = 0; ch < 3; ch++) {
                int a0 = ch * 32;
                int w  = (ch == 2) ? 16 : 32;
                if (w == 32) LDTM_X32(d, tmem + 80 + a0);
                else         LDTM_X16(d, tmem + 80 + a0);
                TCGEN05_WAIT_LD();
                if (tv) {
                    float* dst = xout + ((size_t)n * Tout + t0 + t) * 80 + a0;
                    for (int i = 0; i < w; i += 4) {
                        float4 o;
                        o.x = __uint_as_float(d[i])     + s_bias[320 + a0 + i];
                        o.y = __uint_as_float(d[i + 1]) + s_bias[320 + a0 + i + 1];
                        o.z = __uint_as_float(d[i + 2]) + s_bias[320 + a0 + i + 2];
                        o.w = __uint_as_float(d[i + 3]) + s_bias[320 + a0 + i + 3];
                        *(float4*)(dst + i) = o;
                    }
                }
            }
        }
        __syncthreads();
        if (wid == 0) TCGEN05_DEALLOC(tmem, 256);
    }

#else  // ------- non-'a' PTX pass: safe scalar fallback (never runs on GB300) -------
    float* gsmF = (float*)(abp);            // [80][132]
    float* bufF = (float*)(abp + 43008);    // [80][132]
    __syncthreads();
    for (int e = tid; e < 80 * 128; e += 320) {
        int oc = e >> 7, tt = e & 127;
        float a = s_bias[oc], g = s_bias[oc + 80];
        for (int c = 0; c < 80; c++) {
            for (int j = 0; j < 4; j++) {
                int u = S * (t0 + tt) + j;
                float xv = (u < Tin)
                         ? (FIRST ? xin_n[(size_t)u * 80 + c]
                                  : xin_n[(size_t)c * TinLd + u]) : 0.f;
                float wa = __bfloat162float(wbh[oc * 320 + c * 4 + j])
                         + __bfloat162float(wbl[oc * 320 + c * 4 + j]);
                float wg = __bfloat162float(wbh[(oc + 80) * 320 + c * 4 + j])
                         + __bfloat162float(wbl[(oc + 80) * 320 + c * 4 + j]);
                a = fmaf(wa, xv, a);
                g = fmaf(wg, xv, g);
            }
        }
        gsmF[oc * 132 + tt] = gatef(a, g);
    }
    __syncthreads();
    for (int e = tid; e < 80 * 128; e += 320) {
        int oc = e >> 7, tt = e & 127;
        int t = t0 + tt;
        float s = s_bias[160 + oc];
        for (int ic = 0; ic < 80; ic++) s = fmaf(w1t[ic * 80 + oc], gsmF[ic * 132 + tt], s);
        if (RESID && t < Tout) s += xin_n[(size_t)oc * TinLd + S * t + 3];
        if (FUSEFINAL) bufF[oc * 132 + tt] = s;
        else if (t < Tout) xout[((size_t)n * 80 + oc) * ToutLd + t] = s;
    }
    if (FUSEFINAL) {
        __syncthreads();
        for (int e = tid; e < 80 * 128; e += 320) {
            int oc = e >> 7, tt = e & 127;
            float s = s_bias[240 + oc];
            for (int ic = 0; ic < 80; ic++) s = fmaf(g_wf0t[ic * 80 + oc], bufF[ic * 132 + tt], s);
            gsmF[oc * 132 + tt] = fmaxf(s, 0.f);
        }
        __syncthreads();
        for (int e = tid; e < 80 * 128; e += 320) {
            int oc = e >> 7, tt = e & 127;
            int t = t0 + tt;
            if (t < Tout) {
                float s = s_bias[320 + oc];
                for (int ic = 0; ic < 80; ic++) s = fmaf(g_wf1t[ic * 80 + oc], gsmF[ic * 132 + tt], s);
                xout[((size_t)n * Tout + t) * 80 + oc] = s;
            }
        }
    }
#endif // HAS_TC
}

// ---------------------------------------------------------------------------
// VQ nearest-neighbor + linear head + tanh + per-(n,class) max
// ---------------------------------------------------------------------------
__device__ __forceinline__ unsigned fenc(float f) {
    unsigned u = __float_as_uint(f);
    return (u & 0x80000000u) ? ~u : (u | 0x80000000u);
}

__global__ __launch_bounds__(512) void vq_kernel(
    const float* __restrict__ encS,
    const float* __restrict__ encQ,
    const float* __restrict__ emb,
    const float* __restrict__ wlin,
    const float* __restrict__ blin)
{
    __shared__ __align__(16) float xq[64 * 84];
    __shared__ __align__(16) float eb[64 * 80];
    __shared__ float rd[512];
    __shared__ int   ri[512];
    __shared__ unsigned sm0, sm1;

    const int tid = threadIdx.x;
    const int n   = blockIdx.y;
    const int t0  = blockIdx.x * 64;

    if (tid == 0) { sm0 = 0u; sm1 = 0u; }

    {
        const float4* src = (const float4*)(encS + (size_t)n * 2040 * 80);
        #pragma unroll
        for (int r = 0; r < 3; r++) {
            int i = r * 512 + tid;
            if (i < 64 * 20) {
                int t = i / 20, c4 = i % 20;
                int tg2 = t0 + t;
                float4 v = {0.f, 0.f, 0.f, 0.f};
                if (tg2 < 2040) v = src[(size_t)tg2 * 20 + c4];
                *(float4*)&xq[t * 84 + c4 * 4] = v;
            }
        }
    }

    const int kg = tid >> 6;
    const int lt = tid & 63;
    float best = 3.4e38f;
    int   bi   = 0;

    for (int tile = 0; tile < 8; tile++) {
        __syncthreads();
        {
            const float4* src = (const float4*)(emb + (size_t)tile * 64 * 80);
            #pragma unroll
            for (int r = 0; r < 3; r++) {
                int i = r * 512 + tid;
                if (i < 64 * 20) *(float4*)&eb[(i / 20) * 80 + (i % 20) * 4] = src[i];
            }
        }
        __syncthreads();
        #pragma unroll
        for (int qb = 0; qb < 2; qb++) {
            int kl0 = kg * 8 + qb * 4;
            u64 a0 = 0ull, a1 = 0ull, a2 = 0ull, a3 = 0ull;
            u64 b0 = 0ull, b1 = 0ull, b2 = 0ull, b3 = 0ull;
            #pragma unroll
            for (int c4 = 0; c4 < 20; c4++) {
                ulonglong2 xv = *(const ulonglong2*)&xq[lt * 84 + c4 * 4];
                ulonglong2 e0 = *(const ulonglong2*)&eb[(kl0 + 0) * 80 + c4 * 4];
                ulonglong2 e1 = *(const ulonglong2*)&eb[(kl0 + 1) * 80 + c4 * 4];
                ulonglong2 e2 = *(const ulonglong2*)&eb[(kl0 + 2) * 80 + c4 * 4];
                ulonglong2 e3 = *(const ulonglong2*)&eb[(kl0 + 3) * 80 + c4 * 4];
                fma2(a0, xv.x, e0.x); fma2(b0, xv.y, e0.y);
                fma2(a1, xv.x, e1.x); fma2(b1, xv.y, e1.y);
                fma2(a2, xv.x, e2.x); fma2(b2, xv.y, e2.y);
                fma2(a3, xv.x, e3.x); fma2(b3, xv.y, e3.y);
            }
            u64 aa[4] = {a0, a1, a2, a3};
            u64 bb[4] = {b0, b1, b2, b3};
            #pragma unroll
            for (int j = 0; j < 4; j++) {
                float2 p0 = unpack2(aa[j]), p1 = unpack2(bb[j]);
                float dot = (p0.x + p0.y) + (p1.x + p1.y);
                int kgl = tile * 64 + kl0 + j;
                float d = g_e2[kgl] - 2.f * dot;
                if (d < best) { best = d; bi = kgl; }
            }
        }
    }
    rd[tid] = best; ri[tid] = bi;
    __syncthreads();

    if (tid < 64) {
        float bd = rd[tid];
        int  bbi = ri[tid];
        #pragma unroll
        for (int g2 = 1; g2 < 8; g2++) {
            float d = rd[g2 * 64 + tid];
            int  ii = ri[g2 * 64 + tid];
            if (d < bd || (d == bd && ii < bbi)) { bd = d; bbi = ii; }
        }
        int tg2 = t0 + tid;
        if (tg2 < 2040) {
            const float* dv = emb + (size_t)bbi * 80;
            const float* qr = (tg2 < 2016)
                            ? (encQ + ((size_t)n * 504 + (tg2 % 504)) * 80)
                            : nullptr;
            float s0 = blin[0], s1 = blin[1];
            #pragma unroll 4
            for (int c = 0; c < 80; c++) {
                float v = dv[c] + (qr ? qr[c] : 0.f);
                s0 = fmaf(v, wlin[c],      s0);
                s1 = fmaf(v, wlin[80 + c], s1);
            }
            atomicMax(&sm0, fenc(tanhf(s0)));
            atomicMax(&sm1, fenc(tanhf(s1)));
        }
    }
    __syncthreads();
    if (tid == 0) {
        atomicMax(&g_gmax[n * 2 + 0], sm0);
        atomicMax(&g_gmax[n * 2 + 1], sm1);
    }
}

__global__ void finalize_kernel(float* __restrict__ out) {
    int i = threadIdx.x;
    if (i < 32) {
        unsigned e = g_gmax[i];
        out[i] = (e & 0x80000000u) ? __uint_as_float(e ^ 0x80000000u)
                                   : __uint_as_float(~e);
    }
}

// ---------------------------------------------------------------------------
// Host launch
// ---------------------------------------------------------------------------
extern "C" void kernel_launch(void* const* d_in, const int* in_sizes, int n_in,
                              void* d_out, int out_size) {
    const float* search = (const float*)d_in[0];
    const float* query  = (const float*)d_in[1];
    const float* w_wide = (const float*)d_in[2];
    const float* b_wide = (const float*)d_in[3];
    const float* w_1x1  = (const float*)d_in[4];
    const float* b_1x1  = (const float*)d_in[5];
    const float* w_f0   = (const float*)d_in[6];
    const float* b_f0   = (const float*)d_in[7];
    const float* w_f1   = (const float*)d_in[8];
    const float* b_f1   = (const float*)d_in[9];
    const float* emb    = (const float*)d_in[10];
    const float* w_lin  = (const float*)d_in[11];
    const float* b_lin  = (const float*)d_in[12];
    float* out = (float*)d_out;

    void *pA, *pB, *pAq, *pBq, *pS, *pQ, *pwh, *pwl, *pw1, *pw1s, *pwf0s, *pwf1s;
    cudaGetSymbolAddress(&pA,   g_bufA);
    cudaGetSymbolAddress(&pB,   g_bufB);
    cudaGetSymbolAddress(&pAq,  g_bufAq);
    cudaGetSymbolAddress(&pBq,  g_bufBq);
    cudaGetSymbolAddress(&pS,   g_encS);
    cudaGetSymbolAddress(&pQ,   g_encQ);
    cudaGetSymbolAddress(&pwh,  g_wbh);
    cudaGetSymbolAddress(&pwl,  g_wbl);
    cudaGetSymbolAddress(&pw1,  g_w1t);
    cudaGetSymbolAddress(&pw1s, g_w1s);
    cudaGetSymbolAddress(&pwf0s, g_wf0s);
    cudaGetSymbolAddress(&pwf1s, g_wf1s);
    float* A   = (float*)pA;
    float* B   = (float*)pB;
    float* Aq  = (float*)pAq;
    float* Bq  = (float*)pBq;
    float* eS  = (float*)pS;
    float* eQ  = (float*)pQ;
    __nv_bfloat16* wbh = (__nv_bfloat16*)pwh;
    __nv_bfloat16* wbl = (__nv_bfloat16*)pwl;
    float* w1t = (float*)pw1;
    const char* w1s  = (const char*)pw1s;   // [4][2][20480]
    const char* wf0s = (const char*)pwf0s;  // [2][20480]
    const char* wf1s = (const char*)pwf1s;

    cudaFuncSetAttribute(gemm_layer_kernel<2, true,  false, false>,
                         cudaFuncAttributeMaxDynamicSharedMemorySize, SMEM_DYN);
    cudaFuncSetAttribute(gemm_layer_kernel<2, false, true,  false>,
                         cudaFuncAttributeMaxDynamicSharedMemorySize, SMEM_DYN);
    cudaFuncSetAttribute(gemm_layer_kernel<1, false, true,  false>,
                         cudaFuncAttributeMaxDynamicSharedMemorySize, SMEM_DYN);
    cudaFuncSetAttribute(gemm_layer_kernel<1, false, true,  true >,
                         cudaFuncAttributeMaxDynamicSharedMemorySize, SMEM_DYN);

    prep_kernel<<<80, 256>>>(w_wide, w_1x1, w_f0, w_f1, emb);

    #define W1S(l)  (w1s + (size_t)(l) * 2 * 20480)
    #define W1SL(l) (w1s + (size_t)(l) * 2 * 20480 + 20480)

    // L0: search 8192 -> 4095 (ld 4096), query 2048 -> 1023 (ld 1024)
    gemm_layer_kernel<2, true, false, false><<<dim3(40, NB), 320, SMEM_DYN>>>(
        search, query, A, Aq,
        wbh + 0 * 51200, wbl + 0 * 51200, b_wide + 0 * 160,
        W1S(0), W1SL(0), w1t + 0 * 6400, b_1x1 + 0 * 80,
        nullptr, nullptr, nullptr, nullptr, nullptr, nullptr,
        8192, 8192, 4095, 4096,  2048, 2048, 1023, 1024,  32);

    // L1
    gemm_layer_kernel<2, false, true, false><<<dim3(20, NB), 320, SMEM_DYN>>>(
        A, Aq, B, Bq,
        wbh + 1 * 51200, wbl + 1 * 51200, b_wide + 1 * 160,
        W1S(1), W1SL(1), w1t + 1 * 6400, b_1x1 + 1 * 80,
        nullptr, nullptr, nullptr, nullptr, nullptr, nullptr,
        4095, 4096, 2046, 2048,  1023, 1024, 510, 512,  16);

    // L2
    gemm_layer_kernel<1, false, true, false><<<dim3(20, NB), 320, SMEM_DYN>>>(
        B, Bq, A, Aq,
        wbh + 2 * 51200, wbl + 2 * 51200, b_wide + 2 * 160,
        W1S(2), W1SL(2), w1t + 2 * 6400, b_1x1 + 2 * 80,
        nullptr, nullptr, nullptr, nullptr, nullptr, nullptr,
        2046, 2048, 2043, 2044,  510, 512, 507, 508,  16);

    // L3 + final convs
    gemm_layer_kernel<1, false, true, true><<<dim3(20, NB), 320, SMEM_DYN>>>(
        A, Aq, eS, eQ,
        wbh + 3 * 51200, wbl + 3 * 51200, b_wide + 3 * 160,
        W1S(3), W1SL(3), w1t + 3 * 6400, b_1x1 + 3 * 80,
        wf0s, wf0s + 20480, wf1s, wf1s + 20480, b_f0, b_f1,
        2043, 2044, 2040, 2040,  507, 508, 504, 504,  16);

    vq_kernel<<<dim3(32, NB), 512>>>(eS, eQ, emb, w_lin, b_lin);
    finalize_kernel<<<1, 32>>>(out);
}

// round 10
// speedup vs baseline: 3.4493x; 1.3145x over previous
#include <cuda_runtime.h>
#include <cuda_bf16.h>
#include <cstdint>

#define NB 16
typedef unsigned long long u64;

#if defined(__CUDA_ARCH_FEAT_SM103_ALL) || defined(__CUDA_ARCH_FEAT_SM100_ALL) || \
    (defined(__CUDA_ARCH_SPECIFIC__) && (__CUDA_ARCH_SPECIFIC__ >= 1000))
#define HAS_TC 1
#else
#define HAS_TC 0
#endif

// ---------------------------------------------------------------------------
// PTX helpers
// ---------------------------------------------------------------------------
__device__ __forceinline__ void fma2(u64& d, u64 a, u64 b) {
    asm("fma.rn.f32x2 %0, %1, %2, %0;" : "+l"(d) : "l"(a), "l"(b));
}
__device__ __forceinline__ float2 unpack2(u64 v) {
    float2 f; asm("mov.b64 {%0, %1}, %2;" : "=f"(f.x), "=f"(f.y) : "l"(v)); return f;
}
__device__ __forceinline__ uint32_t smem_u32(const void* p) {
    uint32_t a;
    asm("{ .reg .u64 t; cvta.to.shared.u64 t, %1; cvt.u32.u64 %0, t; }" : "=r"(a) : "l"(p));
    return a;
}
__device__ __forceinline__ float ex2f(float x) {
    float r; asm("ex2.approx.f32 %0, %1;" : "=f"(r) : "f"(x)); return r;
}
__device__ __forceinline__ float rcpf(float x) {
    float r; asm("rcp.approx.f32 %0, %1;" : "=f"(r) : "f"(x)); return r;
}
__device__ __forceinline__ uint32_t prmt_hi(uint32_t a, uint32_t b) {
    uint32_t r; asm("prmt.b32 %0, %1, %2, 0x7632;" : "=r"(r) : "r"(a), "r"(b)); return r;
}
__device__ __forceinline__ uint32_t cvt_bf16x2(float hi, float lo) {
    uint32_t r; asm("cvt.rn.bf16x2.f32 %0, %1, %2;" : "=r"(r) : "f"(hi), "f"(lo)); return r;
}
__device__ __forceinline__ float gatef(float a, float g) {
    float e1 = ex2f(fminf(a * -2.885390082f, 80.f));
    float e2 = ex2f(fminf(g * -1.442695041f, 80.f));
    float r  = rcpf((1.f + e1) * (1.f + e2));
    return (1.f - e1) * r;
}

#if HAS_TC
__device__ __forceinline__ uint32_t elect_one() {
    uint32_t p;
    asm volatile("{\n\t.reg .pred p;\n\telect.sync _|p, 0xFFFFFFFF;\n\tselp.b32 %0, 1, 0, p;\n\t}" : "=r"(p));
    return p;
}

#define TCGEN05_ALLOC(sm, n) \
    asm volatile("tcgen05.alloc.cta_group::1.sync.aligned.shared::cta.b32 [%0], %1;" \
                 :: "r"((uint32_t)(sm)), "r"((uint32_t)(n)) : "memory")
#define TCGEN05_RELINQ() \
    asm volatile("tcgen05.relinquish_alloc_permit.cta_group::1.sync.aligned;")
#define TCGEN05_DEALLOC(t, n) \
    asm volatile("tcgen05.dealloc.cta_group::1.sync.aligned.b32 %0, %1;" :: "r"(t), "r"((uint32_t)(n)))
#define TCGEN05_COMMIT(mb) \
    asm volatile("tcgen05.commit.cta_group::1.mbarrier::arrive::one.shared::cluster.b64 [%0];" \
                 :: "r"((uint32_t)(mb)) : "memory")
#define TCGEN05_FENCE_AFTER()  asm volatile("tcgen05.fence::after_thread_sync;" ::: "memory")
#define TCGEN05_WAIT_LD()      asm volatile("tcgen05.wait::ld.sync.aligned;" ::: "memory")
#define FENCE_ASYNC_SHARED()   asm volatile("fence.proxy.async.shared::cta;" ::: "memory")
#define MBARRIER_INIT(mb, c) \
    asm volatile("mbarrier.init.shared.b64 [%0], %1;" :: "r"((uint32_t)(mb)), "r"((uint32_t)(c)) : "memory")

#define MBAR_WAIT(mb, ph) do {                                                  \
    uint32_t _m = (uint32_t)(mb), _p = (uint32_t)(ph), _d;                      \
    asm volatile("{\n\t.reg .pred p;\n\t"                                       \
        "mbarrier.try_wait.parity.acquire.cta.shared::cta.b64 p, [%1], %2;\n\t" \
        "selp.b32 %0, 1, 0, p;\n\t}" : "=r"(_d) : "r"(_m), "r"(_p) : "memory"); \
    if (!_d) {                                                                  \
        asm volatile("{\n\t.reg .pred P1;\n\t"                                  \
            "WL_%=:\n\t"                                                        \
            "mbarrier.try_wait.parity.acquire.cta.shared::cta.b64 P1, [%0], %1, 0x989680;\n\t" \
            "@P1 bra.uni WD_%=;\n\t"                                            \
            "bra.uni WL_%=;\n\t"                                                \
            "WD_%=:\n\t}" :: "r"(_m), "r"(_p) : "memory");                      \
    }                                                                           \
} while (0)

#define LDTM_X32(r, a) \
    asm volatile("tcgen05.ld.sync.aligned.32x32b.x32.b32 " \
        "{%0,%1,%2,%3,%4,%5,%6,%7,%8,%9,%10,%11,%12,%13,%14,%15," \
        "%16,%17,%18,%19,%20,%21,%22,%23,%24,%25,%26,%27,%28,%29,%30,%31}, [%32];" \
        : "=r"((r)[0]),"=r"((r)[1]),"=r"((r)[2]),"=r"((r)[3]),"=r"((r)[4]),"=r"((r)[5]),"=r"((r)[6]),"=r"((r)[7]), \
          "=r"((r)[8]),"=r"((r)[9]),"=r"((r)[10]),"=r"((r)[11]),"=r"((r)[12]),"=r"((r)[13]),"=r"((r)[14]),"=r"((r)[15]), \
          "=r"((r)[16]),"=r"((r)[17]),"=r"((r)[18]),"=r"((r)[19]),"=r"((r)[20]),"=r"((r)[21]),"=r"((r)[22]),"=r"((r)[23]), \
          "=r"((r)[24]),"=r"((r)[25]),"=r"((r)[26]),"=r"((r)[27]),"=r"((r)[28]),"=r"((r)[29]),"=r"((r)[30]),"=r"((r)[31]) \
        : "r"(a))

#define LDTM_X16(r, a) \
    asm volatile("tcgen05.ld.sync.aligned.32x32b.x16.b32 " \
        "{%0,%1,%2,%3,%4,%5,%6,%7,%8,%9,%10,%11,%12,%13,%14,%15}, [%16];" \
        : "=r"((r)[0]),"=r"((r)[1]),"=r"((r)[2]),"=r"((r)[3]),"=r"((r)[4]),"=r"((r)[5]),"=r"((r)[6]),"=r"((r)[7]), \
          "=r"((r)[8]),"=r"((r)[9]),"=r"((r)[10]),"=r"((r)[11]),"=r"((r)[12]),"=r"((r)[13]),"=r"((r)[14]),"=r"((r)[15]) \
        : "r"(a))

__device__ __forceinline__ void mma_f16_ss(uint32_t d, u64 ad, u64 bd, uint32_t idesc, uint32_t en) {
    asm volatile("{\n\t.reg .pred p;\n\tsetp.ne.u32 p, %5, 0;\n\t"
        "tcgen05.mma.cta_group::1.kind::f16 [%0], %1, %2, %3, {%4,%4,%4,%4}, p;\n\t}"
        :: "r"(d), "l"(ad), "l"(bd), "r"(idesc), "r"(0u), "r"(en) : "memory");
}

static __device__ __forceinline__ u64 make_desc(uint32_t addr) {
    return (u64(2) << 61) | (u64(1) << 46) | (u64(64) << 32) | (u64(1) << 16)
         | ((u64)(addr >> 4) & 0x3FFF);
}

#define IDESC_W ((1u<<4) | (1u<<7) | (1u<<10) | (10u<<17) | (8u<<24))
#endif // HAS_TC

// ---------------------------------------------------------------------------
// Device scratch
// ---------------------------------------------------------------------------
__device__ __align__(16) __nv_bfloat16 g_wbh[4 * 160 * 320];
__device__ __align__(16) __nv_bfloat16 g_wbl[4 * 160 * 320];
__device__ __align__(16) char g_w1s [4][2][20480];
__device__ __align__(16) char g_wf0s[2][20480];
__device__ __align__(16) char g_wf1s[2][20480];
__device__ __align__(16) float g_w1t [4 * 80 * 80];
__device__ __align__(16) float g_wf0t[80 * 80];
__device__ __align__(16) float g_wf1t[80 * 80];
__device__ __align__(16) float g_e2  [512];
__device__ __align__(16) float g_bufA [16 * 80 * 4096];
__device__ __align__(16) float g_bufB [16 * 80 * 2048];
__device__ __align__(16) float g_bufAq[16 * 80 * 1024];
__device__ __align__(16) float g_bufBq[16 * 80 * 512];
__device__ __align__(16) float g_encS[16 * 2040 * 80];
__device__ __align__(16) float g_encQ[16 * 504 * 80];
__device__ unsigned g_gmax[32];

// ---------------------------------------------------------------------------
// Weight prep
// ---------------------------------------------------------------------------
__global__ void prep_kernel(const float* __restrict__ w_wide,
                            const float* __restrict__ w_1x1,
                            const float* __restrict__ w_f0,
                            const float* __restrict__ w_f1,
                            const float* __restrict__ emb) {
    int g = blockIdx.x * blockDim.x + threadIdx.x;
    int stride = gridDim.x * blockDim.x;
    for (int idx = g; idx < 4 * 160 * 320; idx += stride) {
        float v = w_wide[idx];
        __nv_bfloat16 h = __float2bfloat16(v);
        g_wbh[idx] = h;
        g_wbl[idx] = __float2bfloat16(v - __bfloat162float(h));
    }
    for (int idx = g; idx < 4 * 80 * 128; idx += stride) {
        int l = idx / 10240, r = idx % 10240;
        int oc = r >> 7, k = r & 127;
        float v = (k < 80) ? w_1x1[l * 6400 + oc * 80 + k] : 0.f;
        __nv_bfloat16 h = __float2bfloat16(v);
        __nv_bfloat16 lo = __float2bfloat16(v - __bfloat162float(h));
        uint32_t off = (uint32_t)(((oc >> 3) + (k >> 6) * 10) * 1024 + (oc & 7) * 128 + (k & 63) * 2);
        uint32_t sw  = off ^ ((off >> 3) & 0x70);
        *(__nv_bfloat16*)(g_w1s[l][0] + sw) = h;
        *(__nv_bfloat16*)(g_w1s[l][1] + sw) = lo;
    }
    for (int idx = g; idx < 80 * 128; idx += stride) {
        int oc = idx >> 7, k = idx & 127;
        uint32_t off = (uint32_t)(((oc >> 3) + (k >> 6) * 10) * 1024 + (oc & 7) * 128 + (k & 63) * 2);
        uint32_t sw  = off ^ ((off >> 3) & 0x70);
        float v0 = (k < 80) ? w_f0[oc * 80 + k] : 0.f;
        float v1 = (k < 80) ? w_f1[oc * 80 + k] : 0.f;
        __nv_bfloat16 h0 = __float2bfloat16(v0);
        __nv_bfloat16 h1 = __float2bfloat16(v1);
        *(__nv_bfloat16*)(g_wf0s[0] + sw) = h0;
        *(__nv_bfloat16*)(g_wf0s[1] + sw) = __float2bfloat16(v0 - __bfloat162float(h0));
        *(__nv_bfloat16*)(g_wf1s[0] + sw) = h1;
        *(__nv_bfloat16*)(g_wf1s[1] + sw) = __float2bfloat16(v1 - __bfloat162float(h1));
    }
    for (int idx = g; idx < 4 * 80 * 80; idx += stride) {
        int ic = idx % 80, oc = (idx / 80) % 80, l = idx / 6400;
        g_w1t[l * 6400 + ic * 80 + oc] = w_1x1[idx];
    }
    for (int idx = g; idx < 6400; idx += stride) {
        int ic = idx % 80, oc = idx / 80;
        g_wf0t[ic * 80 + oc] = w_f0[idx];
        g_wf1t[ic * 80 + oc] = w_f1[idx];
    }
    for (int k = g; k < 512; k += stride) {
        float s = 0.f;
        for (int c = 0; c < 80; c++) { float v = emb[k * 80 + c]; s += v * v; }
        g_e2[k] = s;
    }
    if (g < 32) g_gmax[g] = 0u;
}

// ---------------------------------------------------------------------------
// smem layout (1024-aligned base)
// ---------------------------------------------------------------------------
#define OFF_A_HI  0
#define OFF_A_LO  16384
#define OFF_B_HI  32768
#define OFF_B_LO  53248
#define OFF2_A_HI 0
#define OFF2_A_LO 32768
#define OFF2_B_HI 65536
#define OFF2_B_LO 86016
#define SMEM_DYN  (1024 + 106496)

#if HAS_TC
__device__ __forceinline__ void pack8(char* abp, int t, int g8, const float* v) {
    uint32_t ub[8]; float lo[8];
    #pragma unroll
    for (int i = 0; i < 8; i++) {
        ub[i] = __float_as_uint(v[i]);
        lo[i] = v[i] - __uint_as_float(ub[i] & 0xFFFF0000u);
    }
    uint4 hp, lp;
    hp.x = prmt_hi(ub[0], ub[1]); hp.y = prmt_hi(ub[2], ub[3]);
    hp.z = prmt_hi(ub[4], ub[5]); hp.w = prmt_hi(ub[6], ub[7]);
    lp.x = cvt_bf16x2(lo[1], lo[0]); lp.y = cvt_bf16x2(lo[3], lo[2]);
    lp.z = cvt_bf16x2(lo[5], lo[4]); lp.w = cvt_bf16x2(lo[7], lo[6]);
    uint32_t off = (uint32_t)(((t >> 3) + ((g8 >= 8) ? 16 : 0)) * 1024 + (t & 7) * 128 + (g8 & 7) * 16);
    uint32_t sw  = off ^ ((off >> 3) & 0x70);
    *(uint4*)(abp + OFF2_A_HI + sw) = hp;
    *(uint4*)(abp + OFF2_A_LO + sw) = lp;
}
__device__ __forceinline__ void copy_w2(char* abp, const char* hi, const char* lo, int tid) {
    if (tid >= 128) {
        for (int i = tid - 128; i < 1280; i += 192) {
            ((uint4*)(abp + OFF2_B_HI))[i] = __ldg((const uint4*)hi + i);
            ((uint4*)(abp + OFF2_B_LO))[i] = __ldg((const uint4*)lo + i);
        }
    }
}
__device__ __forceinline__ void issue_gemm2(uint32_t tmem_dst, uint32_t ab, uint32_t mbar) {
    u64 dAh = make_desc(ab + OFF2_A_HI), dAl = make_desc(ab + OFF2_A_LO);
    u64 dBh = make_desc(ab + OFF2_B_HI), dBl = make_desc(ab + OFF2_B_LO);
    u64 pA[3] = {dAh, dAh, dAl};
    u64 pB[3] = {dBh, dBl, dBh};
    #pragma unroll
    for (int p = 0; p < 3; p++) {
        #pragma unroll
        for (int s = 0; s < 5; s++) {
            uint32_t en = (p == 0 && s == 0) ? 0u : 1u;
            u64 ao = (s < 4) ? (u64)(2 * s) : 1024ull;
            u64 bo = (s < 4) ? (u64)(2 * s) : 640ull;
            mma_f16_ss(tmem_dst, pA[p] + ao, pB[p] + bo, IDESC_W, en);
        }
    }
    TCGEN05_COMMIT(mbar);
}
#endif

template <int S, bool FIRST, bool RESID, bool FUSEFINAL>
__global__ __launch_bounds__(320, 2) void gemm_layer_kernel(
    const float* __restrict__ xinS, const float* __restrict__ xinQ,
    float* __restrict__ xoutS, float* __restrict__ xoutQ,
    const __nv_bfloat16* __restrict__ wbh, const __nv_bfloat16* __restrict__ wbl,
    const float* __restrict__ bw,
    const char* __restrict__ w2h, const char* __restrict__ w2l,
    const float* __restrict__ w1t, const float* __restrict__ b1,
    const char* __restrict__ wf0h, const char* __restrict__ wf0l,
    const char* __restrict__ wf1h, const char* __restrict__ wf1l,
    const float* __restrict__ bf0, const float* __restrict__ bf1,
    int TinS, int TinLdS, int ToutS, int ToutLdS,
    int TinQ, int TinLdQ, int ToutQ, int ToutLdQ, int blocksS)
{
    extern __shared__ char dsm[];
    __shared__ float s_bias[400];

    const int tid = threadIdx.x;
    const int wid = tid >> 5;
    const int n   = blockIdx.y;
    const int bx  = blockIdx.x;

    const float* xin; float* xout; int Tin, TinLd, Tout, ToutLd, t0;
    if (bx < blocksS) {
        xin = xinS; xout = xoutS; Tin = TinS; TinLd = TinLdS;
        Tout = ToutS; ToutLd = ToutLdS; t0 = bx * 128;
    } else {
        xin = xinQ; xout = xoutQ; Tin = TinQ; TinLd = TinLdQ;
        Tout = ToutQ; ToutLd = ToutLdQ; t0 = (bx - blocksS) * 128;
    }
    const float* xin_n = xin + (size_t)n * 80 * TinLd;

    uint32_t base_raw = smem_u32(dsm);
    uint32_t ab = (base_raw + 1023u) & ~1023u;
    char* abp = dsm + (ab - base_raw);

    for (int i = tid; i < 400; i += 320) {
        float v = 0.f;
        if (i < 160) v = __ldg(bw + i);
        else if (i < 240) v = __ldg(b1 + i - 160);
        else if (FUSEFINAL && i < 320) v = __ldg(bf0 + i - 240);
        else if (FUSEFINAL) v = __ldg(bf1 + i - 320);
        s_bias[i] = v;
    }

#if HAS_TC
    __shared__ uint32_t s_tmem;
    __shared__ __align__(8) u64 s_mbar;

    if (tid == 0) MBARRIER_INIT(smem_u32(&s_mbar), 1);
    if (wid == 0) { TCGEN05_ALLOC(smem_u32(&s_tmem), 256); TCGEN05_RELINQ(); }
    __syncthreads();
    const uint32_t tmem = s_tmem;
    const uint32_t mbar = smem_u32(&s_mbar);

    // ---- wide GEMM: 5 K-chunks of 64, D -> tmem cols 0..159 ----
    for (int kc = 0; kc < 5; kc++) {
        const int k0 = kc * 64;
        if (kc > 0) MBAR_WAIT(mbar, (kc - 1) & 1);
        #pragma unroll
        for (int r = 0; r < 4; r++) {
            int gi = r * 320 + tid;
            if (gi < 1024) {
                int t, g8;
                if (FIRST) { g8 = gi & 7; t = gi >> 3; }      // coalesced on (N,T,80)
                else       { t = gi & 127; g8 = gi >> 7; }    // coalesced on (N,80,T)
                int c0 = (k0 >> 2) + g8 * 2;
                int u0 = S * (t0 + t);
                float v[8];
                if (FIRST) {
                    #pragma unroll
                    for (int j = 0; j < 4; j++) {
                        int u = u0 + j;
                        if (u < Tin) {
                            float2 p = __ldg((const float2*)&xin_n[(size_t)u * 80 + c0]);
                            v[j] = p.x; v[4 + j] = p.y;
                        } else { v[j] = 0.f; v[4 + j] = 0.f; }
                    }
                } else {
                    const float* r0 = xin_n + (size_t)c0 * TinLd + u0;
                    #pragma unroll
                    for (int j = 0; j < 4; j++) {
                        bool ok = (u0 + j) < Tin;
                        v[j]     = ok ? __ldg(r0 + j)         : 0.f;
                        v[4 + j] = ok ? __ldg(r0 + TinLd + j) : 0.f;
                    }
                }
                uint32_t ub[8]; float lo[8];
                #pragma unroll
                for (int i = 0; i < 8; i++) {
                    ub[i] = __float_as_uint(v[i]);
                    lo[i] = v[i] - __uint_as_float(ub[i] & 0xFFFF0000u);
                }
                uint4 hp, lp;
                hp.x = prmt_hi(ub[0], ub[1]); hp.y = prmt_hi(ub[2], ub[3]);
                hp.z = prmt_hi(ub[4], ub[5]); hp.w = prmt_hi(ub[6], ub[7]);
                lp.x = cvt_bf16x2(lo[1], lo[0]); lp.y = cvt_bf16x2(lo[3], lo[2]);
                lp.z = cvt_bf16x2(lo[5], lo[4]); lp.w = cvt_bf16x2(lo[7], lo[6]);
                uint32_t off = (uint32_t)((t >> 3) * 1024 + (t & 7) * 128 + g8 * 16);
                uint32_t sw  = off ^ ((off >> 3) & 0x70);
                *(uint4*)(abp + OFF_A_HI + sw) = hp;
                *(uint4*)(abp + OFF_A_LO + sw) = lp;
            }
        }
        {
            const uint4* srcH = (const uint4*)wbh;
            const uint4* srcL = (const uint4*)wbl;
            #pragma unroll
            for (int r = 0; r < 4; r++) {
                int gi = r * 320 + tid;
                int row = gi >> 3, g8 = gi & 7;
                int si  = row * 40 + (k0 >> 3) + g8;
                uint32_t off = (uint32_t)((row >> 3) * 1024 + (row & 7) * 128 + g8 * 16);
                uint32_t sw  = off ^ ((off >> 3) & 0x70);
                *(uint4*)(abp + OFF_B_HI + sw) = __ldg(srcH + si);
                *(uint4*)(abp + OFF_B_LO + sw) = __ldg(srcL + si);
            }
        }
        FENCE_ASYNC_SHARED();
        __syncthreads();

        if (wid == 0 && elect_one()) {
            u64 dAh = make_desc(ab + OFF_A_HI), dAl = make_desc(ab + OFF_A_LO);
            u64 dBh = make_desc(ab + OFF_B_HI), dBl = make_desc(ab + OFF_B_LO);
            u64 pA[3] = {dAh, dAh, dAl};
            u64 pB[3] = {dBh, dBl, dBh};
            #pragma unroll
            for (int p = 0; p < 3; p++) {
                #pragma unroll
                for (int s = 0; s < 4; s++) {
                    uint32_t en = (kc == 0 && p == 0 && s == 0) ? 0u : 1u;
                    u64 ad = pA[p] + s * 2;
                    mma_f16_ss(tmem,      ad, pB[p] + s * 2,       IDESC_W, en);
                    mma_f16_ss(tmem + 80, ad, pB[p] + 640 + s * 2, IDESC_W, en);
                }
            }
            TCGEN05_COMMIT(mbar);
        }
    }
    MBAR_WAIT(mbar, 0);

    // ---- gate -> bf16 A2 (warps 0-3) ; W1 image copy (warps 4-9) ----
    if (tid < 128) {
        TCGEN05_FENCE_AFTER();
        const int t = tid;
        uint32_t da[32], dg[32];
        #pragma unroll
        for (int ch = 0; ch < 3; ch++) {
            int a0 = ch * 32;
            int w  = (ch == 2) ? 16 : 32;
            if (w == 32) { LDTM_X32(da, tmem + a0); LDTM_X32(dg, tmem + 80 + a0); }
            else         { LDTM_X16(da, tmem + a0); LDTM_X16(dg, tmem + 80 + a0); }
            TCGEN05_WAIT_LD();
            float gv[32];
            for (int i = 0; i < w; i++) {
                float a = __uint_as_float(da[i]) + s_bias[a0 + i];
                float g = __uint_as_float(dg[i]) + s_bias[80 + a0 + i];
                gv[i] = gatef(a, g);
            }
            #pragma unroll
            for (int q = 0; q < 4; q++) {
                if (q * 8 < w) pack8(abp, t, (a0 >> 3) + q, gv + q * 8);
            }
        }
    }
    copy_w2(abp, w2h, w2l, tid);
    FENCE_ASYNC_SHARED();
    __syncthreads();

    if (wid == 0 && elect_one()) issue_gemm2(tmem + 160, ab, mbar);
    MBAR_WAIT(mbar, 1);

    if (!FUSEFINAL) {
        if (tid < 128) {
            TCGEN05_FENCE_AFTER();
            const int t = tid;
            const bool tv = (t0 + t) < Tout;
            uint32_t d[32];
            #pragma unroll
            for (int ch = 0; ch < 3; ch++) {
                int a0 = ch * 32;
                int w  = (ch == 2) ? 16 : 32;
                if (w == 32) LDTM_X32(d, tmem + 160 + a0);
                else         LDTM_X16(d, tmem + 160 + a0);
                TCGEN05_WAIT_LD();
                if (tv) {
                    for (int i = 0; i < w; i++) {
                        int c = a0 + i;
                        float v = __uint_as_float(d[i]) + s_bias[160 + c];
                        if (RESID) v += __ldg(xin_n + (size_t)c * TinLd + S * (t0 + t) + 3);
                        xout[((size_t)n * 80 + c) * ToutLd + t0 + t] = v;
                    }
                }
            }
        }
        __syncthreads();
        if (wid == 0) TCGEN05_DEALLOC(tmem, 256);
    } else {
        if (tid < 128) {
            TCGEN05_FENCE_AFTER();
            const int t = tid;
            const bool tv = (t0 + t) < Tout;
            uint32_t d[32];
            #pragma unroll
            for (int ch = 0; ch < 3; ch++) {
                int a0 = ch * 32;
                int w  = (ch == 2) ? 16 : 32;
                if (w == 32) LDTM_X32(d, tmem + 160 + a0);
                else         LDTM_X16(d, tmem + 160 + a0);
                TCGEN05_WAIT_LD();
                float v[32];
                for (int i = 0; i < w; i++) {
                    int c = a0 + i;
                    v[i] = __uint_as_float(d[i]) + s_bias[160 + c];
                    if (RESID && tv) v[i] += __ldg(xin_n + (size_t)c * TinLd + S * (t0 + t) + 3);
                }
                #pragma unroll
                for (int q = 0; q < 4; q++)
                    if (q * 8 < w) pack8(abp, t, (a0 >> 3) + q, v + q * 8);
            }
        }
        copy_w2(abp, wf0h, wf0l, tid);
        FENCE_ASYNC_SHARED();
        __syncthreads();
        if (wid == 0 && elect_one()) issue_gemm2(tmem + 0, ab, mbar);
        MBAR_WAIT(mbar, 0);

        if (tid < 128) {
            TCGEN05_FENCE_AFTER();
            const int t = tid;
            uint32_t d[32];
            #pragma unroll
            for (int ch = 0; ch < 3; ch++) {
                int a0 = ch * 32;
                int w  = (ch == 2) ? 16 : 32;
                if (w == 32) LDTM_X32(d, tmem + a0);
                else         LDTM_X16(d, tmem + a0);
                TCGEN05_WAIT_LD();
                float v[32];
                for (int i = 0; i < w; i++)
                    v[i] = fmaxf(__uint_as_float(d[i]) + s_bias[240 + a0 + i], 0.f);
                #pragma unroll
                for (int q = 0; q < 4; q++)
                    if (q * 8 < w) pack8(abp, t, (a0 >> 3) + q, v + q * 8);
            }
        }
        copy_w2(abp, wf1h, wf1l, tid);
        FENCE_ASYNC_SHARED();
        __syncthreads();
        if (wid == 0 && elect_one()) issue_gemm2(tmem + 80, ab, mbar);
        MBAR_WAIT(mbar, 1);

        if (tid < 128) {
            TCGEN05_FENCE_AFTER();
            const int t = tid;
            const bool tv = (t0 + t) < Tout;
            uint32_t d[32];
            #pragma unroll
            for (int ch = 0; ch < 3; ch++) {
                int a0 = ch * 32;
                int w  = (ch == 2) ? 16 : 32;
                if (w == 32) LDTM_X32(d, tmem + 80 + a0);
                else         LDTM_X16(d, tmem + 80 + a0);
                TCGEN05_WAIT_LD();
                if (tv) {
                    float* dst = xout + ((size_t)n * Tout + t0 + t) * 80 + a0;
                    for (int i = 0; i < w; i += 4) {
                        float4 o;
                        o.x = __uint_as_float(d[i])     + s_bias[320 + a0 + i];
                        o.y = __uint_as_float(d[i + 1]) + s_bias[320 + a0 + i + 1];
                        o.z = __uint_as_float(d[i + 2]) + s_bias[320 + a0 + i + 2];
                        o.w = __uint_as_float(d[i + 3]) + s_bias[320 + a0 + i + 3];
                        *(float4*)(dst + i) = o;
                    }
                }
            }
        }
        __syncthreads();
        if (wid == 0) TCGEN05_DEALLOC(tmem, 256);
    }

#else  // ------- non-'a' PTX pass: safe scalar fallback (never runs on GB300) -------
    float* gsmF = (float*)(abp);
    float* bufF = (float*)(abp + 43008);
    __syncthreads();
    for (int e = tid; e < 80 * 128; e += 320) {
        int oc = e >> 7, tt = e & 127;
        float a = s_bias[oc], g = s_bias[oc + 80];
        for (int c = 0; c < 80; c++) {
            for (int j = 0; j < 4; j++) {
                int u = S * (t0 + tt) + j;
                float xv = (u < Tin)
                         ? (FIRST ? xin_n[(size_t)u * 80 + c]
                                  : xin_n[(size_t)c * TinLd + u]) : 0.f;
                float wa = __bfloat162float(wbh[oc * 320 + c * 4 + j])
                         + __bfloat162float(wbl[oc * 320 + c * 4 + j]);
                float wg = __bfloat162float(wbh[(oc + 80) * 320 + c * 4 + j])
                         + __bfloat162float(wbl[(oc + 80) * 320 + c * 4 + j]);
                a = fmaf(wa, xv, a);
                g = fmaf(wg, xv, g);
            }
        }
        gsmF[oc * 132 + tt] = gatef(a, g);
    }
    __syncthreads();
    for (int e = tid; e < 80 * 128; e += 320) {
        int oc = e >> 7, tt = e & 127;
        int t = t0 + tt;
        float s = s_bias[160 + oc];
        for (int ic = 0; ic < 80; ic++) s = fmaf(w1t[ic * 80 + oc], gsmF[ic * 132 + tt], s);
        if (RESID && t < Tout) s += xin_n[(size_t)oc * TinLd + S * t + 3];
        if (FUSEFINAL) bufF[oc * 132 + tt] = s;
        else if (t < Tout) xout[((size_t)n * 80 + oc) * ToutLd + t] = s;
    }
    if (FUSEFINAL) {
        __syncthreads();
        for (int e = tid; e < 80 * 128; e += 320) {
            int oc = e >> 7, tt = e & 127;
            float s = s_bias[240 + oc];
            for (int ic = 0; ic < 80; ic++) s = fmaf(g_wf0t[ic * 80 + oc], bufF[ic * 132 + tt], s);
            gsmF[oc * 132 + tt] = fmaxf(s, 0.f);
        }
        __syncthreads();
        for (int e = tid; e < 80 * 128; e += 320) {
            int oc = e >> 7, tt = e & 127;
            int t = t0 + tt;
            if (t < Tout) {
                float s = s_bias[320 + oc];
                for (int ic = 0; ic < 80; ic++) s = fmaf(g_wf1t[ic * 80 + oc], gsmF[ic * 132 + tt], s);
                xout[((size_t)n * Tout + t) * 80 + oc] = s;
            }
        }
    }
#endif // HAS_TC
}

// ---------------------------------------------------------------------------
// VQ v2: 4t x 4k register blocking, 4 class-tiles of 128, warp-shuffle argmin
// ---------------------------------------------------------------------------
__device__ __forceinline__ unsigned fenc(float f) {
    unsigned u = __float_as_uint(f);
    return (u & 0x80000000u) ? ~u : (u | 0x80000000u);
}

__global__ __launch_bounds__(512, 2) void vq_kernel(
    const float* __restrict__ encS,
    const float* __restrict__ encQ,
    const float* __restrict__ emb,
    const float* __restrict__ wlin,
    const float* __restrict__ blin)
{
    __shared__ __align__(16) float xq[64 * 84];
    __shared__ __align__(16) float eb[128 * 84];
    __shared__ int   sbi[64];
    __shared__ unsigned sm0, sm1;

    const int tid = threadIdx.x;
    const int n   = blockIdx.y;
    const int t0  = blockIdx.x * 64;

    if (tid == 0) { sm0 = 0u; sm1 = 0u; }

    {
        const float4* src = (const float4*)(encS + (size_t)n * 2040 * 80);
        #pragma unroll
        for (int r = 0; r < 3; r++) {
            int i = r * 512 + tid;
            if (i < 64 * 20) {
                int t = i / 20, c4 = i % 20;
                int tg2 = t0 + t;
                float4 v = {0.f, 0.f, 0.f, 0.f};
                if (tg2 < 2040) v = src[(size_t)tg2 * 20 + c4];
                *(float4*)&xq[t * 84 + c4 * 4] = v;
            }
        }
    }

    const int kq = tid & 31;   // class lane (one warp = one t-group)
    const int tg = tid >> 5;   // t-group: t = tg*4 .. tg*4+3
    float best[4] = {3.4e38f, 3.4e38f, 3.4e38f, 3.4e38f};
    int   bi[4]   = {0, 0, 0, 0};

    for (int tile = 0; tile < 4; tile++) {
        __syncthreads();
        {
            const float4* src = (const float4*)(emb + (size_t)tile * 128 * 80);
            #pragma unroll
            for (int r = 0; r < 5; r++) {
                int i = r * 512 + tid;   // 128*20 = 2560 = 5*512 exact
                *(float4*)&eb[(i / 20) * 84 + (i % 20) * 4] = src[i];
            }
        }
        __syncthreads();

        u64 acc[4][4];
        #pragma unroll
        for (int i = 0; i < 4; i++)
            #pragma unroll
            for (int j = 0; j < 4; j++) acc[i][j] = 0ull;

        const float* xr = xq + (tg * 4) * 84;
        const float* er = eb + kq * 84;
        #pragma unroll 4
        for (int c4 = 0; c4 < 20; c4++) {
            ulonglong2 ev0 = *(const ulonglong2*)(er + 0 * 32 * 84 + c4 * 4);
            ulonglong2 ev1 = *(const ulonglong2*)(er + 1 * 32 * 84 + c4 * 4);
            ulonglong2 ev2 = *(const ulonglong2*)(er + 2 * 32 * 84 + c4 * 4);
            ulonglong2 ev3 = *(const ulonglong2*)(er + 3 * 32 * 84 + c4 * 4);
            #pragma unroll
            for (int i = 0; i < 4; i++) {
                ulonglong2 xv = *(const ulonglong2*)(xr + i * 84 + c4 * 4);
                fma2(acc[i][0], xv.x, ev0.x); fma2(acc[i][0], xv.y, ev0.y);
                fma2(acc[i][1], xv.x, ev1.x); fma2(acc[i][1], xv.y, ev1.y);
                fma2(acc[i][2], xv.x, ev2.x); fma2(acc[i][2], xv.y, ev2.y);
                fma2(acc[i][3], xv.x, ev3.x); fma2(acc[i][3], xv.y, ev3.y);
            }
        }
        #pragma unroll
        for (int j = 0; j < 4; j++) {
            int k = tile * 128 + j * 32 + kq;
            float e2v = __ldg(&g_e2[k]);
            #pragma unroll
            for (int i = 0; i < 4; i++) {
                float2 p = unpack2(acc[i][j]);
                float d = e2v - 2.f * (p.x + p.y);
                if (d < best[i]) { best[i] = d; bi[i] = k; }
            }
        }
    }

    // warp-level argmin (first-index tie-break)
    #pragma unroll
    for (int off = 16; off > 0; off >>= 1) {
        #pragma unroll
        for (int i = 0; i < 4; i++) {
            float od = __shfl_down_sync(0xFFFFFFFFu, best[i], off);
            int   oi = __shfl_down_sync(0xFFFFFFFFu, bi[i],   off);
            if (od < best[i] || (od == best[i] && oi < bi[i])) { best[i] = od; bi[i] = oi; }
        }
    }
    if (kq == 0) {
        #pragma unroll
        for (int i = 0; i < 4; i++) sbi[tg * 4 + i] = bi[i];
    }
    __syncthreads();

    if (tid < 64) {
        int tg2 = t0 + tid;
        if (tg2 < 2040) {
            const float* dv = emb + (size_t)sbi[tid] * 80;
            const float* qr = (tg2 < 2016)
                            ? (encQ + ((size_t)n * 504 + (tg2 % 504)) * 80)
                            : nullptr;
            float s0 = blin[0], s1 = blin[1];
            #pragma unroll 4
            for (int c = 0; c < 80; c++) {
                float v = dv[c] + (qr ? qr[c] : 0.f);
                s0 = fmaf(v, wlin[c],      s0);
                s1 = fmaf(v, wlin[80 + c], s1);
            }
            atomicMax(&sm0, fenc(tanhf(s0)));
            atomicMax(&sm1, fenc(tanhf(s1)));
        }
    }
    __syncthreads();
    if (tid == 0) {
        atomicMax(&g_gmax[n * 2 + 0], sm0);
        atomicMax(&g_gmax[n * 2 + 1], sm1);
    }
}

__global__ void finalize_kernel(float* __restrict__ out) {
    int i = threadIdx.x;
    if (i < 32) {
        unsigned e = g_gmax[i];
        out[i] = (e & 0x80000000u) ? __uint_as_float(e ^ 0x80000000u)
                                   : __uint_as_float(~e);
    }
}

// ---------------------------------------------------------------------------
// Host launch
// ---------------------------------------------------------------------------
extern "C" void kernel_launch(void* const* d_in, const int* in_sizes, int n_in,
                              void* d_out, int out_size) {
    const float* search = (const float*)d_in[0];
    const float* query  = (const float*)d_in[1];
    const float* w_wide = (const float*)d_in[2];
    const float* b_wide = (const float*)d_in[3];
    const float* w_1x1  = (const float*)d_in[4];
    const float* b_1x1  = (const float*)d_in[5];
    const float* w_f0   = (const float*)d_in[6];
    const float* b_f0   = (const float*)d_in[7];
    const float* w_f1   = (const float*)d_in[8];
    const float* b_f1   = (const float*)d_in[9];
    const float* emb    = (const float*)d_in[10];
    const float* w_lin  = (const float*)d_in[11];
    const float* b_lin  = (const float*)d_in[12];
    float* out = (float*)d_out;

    void *pA, *pB, *pAq, *pBq, *pS, *pQ, *pwh, *pwl, *pw1, *pw1s, *pwf0s, *pwf1s;
    cudaGetSymbolAddress(&pA,   g_bufA);
    cudaGetSymbolAddress(&pB,   g_bufB);
    cudaGetSymbolAddress(&pAq,  g_bufAq);
    cudaGetSymbolAddress(&pBq,  g_bufBq);
    cudaGetSymbolAddress(&pS,   g_encS);
    cudaGetSymbolAddress(&pQ,   g_encQ);
    cudaGetSymbolAddress(&pwh,  g_wbh);
    cudaGetSymbolAddress(&pwl,  g_wbl);
    cudaGetSymbolAddress(&pw1,  g_w1t);
    cudaGetSymbolAddress(&pw1s, g_w1s);
    cudaGetSymbolAddress(&pwf0s, g_wf0s);
    cudaGetSymbolAddress(&pwf1s, g_wf1s);
    float* A   = (float*)pA;
    float* B   = (float*)pB;
    float* Aq  = (float*)pAq;
    float* Bq  = (float*)pBq;
    float* eS  = (float*)pS;
    float* eQ  = (float*)pQ;
    __nv_bfloat16* wbh = (__nv_bfloat16*)pwh;
    __nv_bfloat16* wbl = (__nv_bfloat16*)pwl;
    float* w1t = (float*)pw1;
    const char* w1s  = (const char*)pw1s;
    const char* wf0s = (const char*)pwf0s;
    const char* wf1s = (const char*)pwf1s;

    cudaFuncSetAttribute(gemm_layer_kernel<2, true,  false, false>,
                         cudaFuncAttributeMaxDynamicSharedMemorySize, SMEM_DYN);
    cudaFuncSetAttribute(gemm_layer_kernel<2, false, true,  false>,
                         cudaFuncAttributeMaxDynamicSharedMemorySize, SMEM_DYN);
    cudaFuncSetAttribute(gemm_layer_kernel<1, false, true,  false>,
                         cudaFuncAttributeMaxDynamicSharedMemorySize, SMEM_DYN);
    cudaFuncSetAttribute(gemm_layer_kernel<1, false, true,  true >,
                         cudaFuncAttributeMaxDynamicSharedMemorySize, SMEM_DYN);

    prep_kernel<<<80, 256>>>(w_wide, w_1x1, w_f0, w_f1, emb);

    #define W1S(l)  (w1s + (size_t)(l) * 2 * 20480)
    #define W1SL(l) (w1s + (size_t)(l) * 2 * 20480 + 20480)

    gemm_layer_kernel<2, true, false, false><<<dim3(40, NB), 320, SMEM_DYN>>>(
        search, query, A, Aq,
        wbh + 0 * 51200, wbl + 0 * 51200, b_wide + 0 * 160,
        W1S(0), W1SL(0), w1t + 0 * 6400, b_1x1 + 0 * 80,
        nullptr, nullptr, nullptr, nullptr, nullptr, nullptr,
        8192, 8192, 4095, 4096,  2048, 2048, 1023, 1024,  32);

    gemm_layer_kernel<2, false, true, false><<<dim3(20, NB), 320, SMEM_DYN>>>(
        A, Aq, B, Bq,
        wbh + 1 * 51200, wbl + 1 * 51200, b_wide + 1 * 160,
        W1S(1), W1SL(1), w1t + 1 * 6400, b_1x1 + 1 * 80,
        nullptr, nullptr, nullptr, nullptr, nullptr, nullptr,
        4095, 4096, 2046, 2048,  1023, 1024, 510, 512,  16);

    gemm_layer_kernel<1, false, true, false><<<dim3(20, NB), 320, SMEM_DYN>>>(
        B, Bq, A, Aq,
        wbh + 2 * 51200, wbl + 2 * 51200, b_wide + 2 * 160,
        W1S(2), W1SL(2), w1t + 2 * 6400, b_1x1 + 2 * 80,
        nullptr, nullptr, nullptr, nullptr, nullptr, nullptr,
        2046, 2048, 2043, 2044,  510, 512, 507, 508,  16);

    gemm_layer_kernel<1, false, true, true><<<dim3(20, NB), 320, SMEM_DYN>>>(
        A, Aq, eS, eQ,
        wbh + 3 * 51200, wbl + 3 * 51200, b_wide + 3 * 160,
        W1S(3), W1SL(3), w1t + 3 * 6400, b_1x1 + 3 * 80,
        wf0s, wf0s + 20480, wf1s, wf1s + 20480, b_f0, b_f1,
        2043, 2044, 2040, 2040,  507, 508, 504, 504,  16);

    vq_kernel<<<dim3(32, NB), 512>>>(eS, eQ, emb, w_lin, b_lin);
    finalize_kernel<<<1, 32>>>(out);
}

// round 12
// speedup vs baseline: 4.4298x; 1.2843x over previous
#include <cuda_runtime.h>
#include <cuda_bf16.h>
#include <cstdint>

#define NB 16
typedef unsigned long long u64;

#if defined(__CUDA_ARCH_FEAT_SM103_ALL) || defined(__CUDA_ARCH_FEAT_SM100_ALL) || \
    (defined(__CUDA_ARCH_SPECIFIC__) && (__CUDA_ARCH_SPECIFIC__ >= 1000))
#define HAS_TC 1
#else
#define HAS_TC 0
#endif

// ---------------------------------------------------------------------------
// PTX helpers
// ---------------------------------------------------------------------------
__device__ __forceinline__ void fma2(u64& d, u64 a, u64 b) {
    asm("fma.rn.f32x2 %0, %1, %2, %0;" : "+l"(d) : "l"(a), "l"(b));
}
__device__ __forceinline__ float2 unpack2(u64 v) {
    float2 f; asm("mov.b64 {%0, %1}, %2;" : "=f"(f.x), "=f"(f.y) : "l"(v)); return f;
}
__device__ __forceinline__ uint32_t smem_u32(const void* p) {
    uint32_t a;
    asm("{ .reg .u64 t; cvta.to.shared.u64 t, %1; cvt.u32.u64 %0, t; }" : "=r"(a) : "l"(p));
    return a;
}
__device__ __forceinline__ float ex2f(float x) {
    float r; asm("ex2.approx.f32 %0, %1;" : "=f"(r) : "f"(x)); return r;
}
__device__ __forceinline__ float rcpf(float x) {
    float r; asm("rcp.approx.f32 %0, %1;" : "=f"(r) : "f"(x)); return r;
}
__device__ __forceinline__ uint32_t prmt_hi(uint32_t a, uint32_t b) {
    uint32_t r; asm("prmt.b32 %0, %1, %2, 0x7632;" : "=r"(r) : "r"(a), "r"(b)); return r;
}
__device__ __forceinline__ uint32_t cvt_bf16x2(float hi, float lo) {
    uint32_t r; asm("cvt.rn.bf16x2.f32 %0, %1, %2;" : "=r"(r) : "f"(hi), "f"(lo)); return r;
}
__device__ __forceinline__ float gatef(float a, float g) {
    float e1 = ex2f(fminf(a * -2.885390082f, 80.f));
    float e2 = ex2f(fminf(g * -1.442695041f, 80.f));
    float r  = rcpf((1.f + e1) * (1.f + e2));
    return (1.f - e1) * r;
}

#if HAS_TC
__device__ __forceinline__ uint32_t elect_one() {
    uint32_t p;
    asm volatile("{\n\t.reg .pred p;\n\telect.sync _|p, 0xFFFFFFFF;\n\tselp.b32 %0, 1, 0, p;\n\t}" : "=r"(p));
    return p;
}

#define TCGEN05_ALLOC(sm, n) \
    asm volatile("tcgen05.alloc.cta_group::1.sync.aligned.shared::cta.b32 [%0], %1;" \
                 :: "r"((uint32_t)(sm)), "r"((uint32_t)(n)) : "memory")
#define TCGEN05_RELINQ() \
    asm volatile("tcgen05.relinquish_alloc_permit.cta_group::1.sync.aligned;")
#define TCGEN05_DEALLOC(t, n) \
    asm volatile("tcgen05.dealloc.cta_group::1.sync.aligned.b32 %0, %1;" :: "r"(t), "r"((uint32_t)(n)))
#define TCGEN05_COMMIT(mb) \
    asm volatile("tcgen05.commit.cta_group::1.mbarrier::arrive::one.shared::cluster.b64 [%0];" \
                 :: "r"((uint32_t)(mb)) : "memory")
#define TCGEN05_FENCE_AFTER()  asm volatile("tcgen05.fence::after_thread_sync;" ::: "memory")
#define TCGEN05_FENCE_BEFORE() asm volatile("tcgen05.fence::before_thread_sync;" ::: "memory")
#define TCGEN05_WAIT_LD()      asm volatile("tcgen05.wait::ld.sync.aligned;" ::: "memory")
#define FENCE_ASYNC_SHARED()   asm volatile("fence.proxy.async.shared::cta;" ::: "memory")
#define MBARRIER_INIT(mb, c) \
    asm volatile("mbarrier.init.shared.b64 [%0], %1;" :: "r"((uint32_t)(mb)), "r"((uint32_t)(c)) : "memory")

#define MBAR_WAIT(mb, ph) do {                                                  \
    uint32_t _m = (uint32_t)(mb), _p = (uint32_t)(ph), _d;                      \
    asm volatile("{\n\t.reg .pred p;\n\t"                                       \
        "mbarrier.try_wait.parity.acquire.cta.shared::cta.b64 p, [%1], %2;\n\t" \
        "selp.b32 %0, 1, 0, p;\n\t}" : "=r"(_d) : "r"(_m), "r"(_p) : "memory"); \
    if (!_d) {                                                                  \
        asm volatile("{\n\t.reg .pred P1;\n\t"                                  \
            "WL_%=:\n\t"                                                        \
            "mbarrier.try_wait.parity.acquire.cta.shared::cta.b64 P1, [%0], %1, 0x989680;\n\t" \
            "@P1 bra.uni WD_%=;\n\t"                                            \
            "bra.uni WL_%=;\n\t"                                                \
            "WD_%=:\n\t}" :: "r"(_m), "r"(_p) : "memory");                      \
    }                                                                           \
} while (0)

#define LDTM_X32(r, a) \
    asm volatile("tcgen05.ld.sync.aligned.32x32b.x32.b32 " \
        "{%0,%1,%2,%3,%4,%5,%6,%7,%8,%9,%10,%11,%12,%13,%14,%15," \
        "%16,%17,%18,%19,%20,%21,%22,%23,%24,%25,%26,%27,%28,%29,%30,%31}, [%32];" \
        : "=r"((r)[0]),"=r"((r)[1]),"=r"((r)[2]),"=r"((r)[3]),"=r"((r)[4]),"=r"((r)[5]),"=r"((r)[6]),"=r"((r)[7]), \
          "=r"((r)[8]),"=r"((r)[9]),"=r"((r)[10]),"=r"((r)[11]),"=r"((r)[12]),"=r"((r)[13]),"=r"((r)[14]),"=r"((r)[15]), \
          "=r"((r)[16]),"=r"((r)[17]),"=r"((r)[18]),"=r"((r)[19]),"=r"((r)[20]),"=r"((r)[21]),"=r"((r)[22]),"=r"((r)[23]), \
          "=r"((r)[24]),"=r"((r)[25]),"=r"((r)[26]),"=r"((r)[27]),"=r"((r)[28]),"=r"((r)[29]),"=r"((r)[30]),"=r"((r)[31]) \
        : "r"(a))

#define LDTM_X16(r, a) \
    asm volatile("tcgen05.ld.sync.aligned.32x32b.x16.b32 " \
        "{%0,%1,%2,%3,%4,%5,%6,%7,%8,%9,%10,%11,%12,%13,%14,%15}, [%16];" \
        : "=r"((r)[0]),"=r"((r)[1]),"=r"((r)[2]),"=r"((r)[3]),"=r"((r)[4]),"=r"((r)[5]),"=r"((r)[6]),"=r"((r)[7]), \
          "=r"((r)[8]),"=r"((r)[9]),"=r"((r)[10]),"=r"((r)[11]),"=r"((r)[12]),"=r"((r)[13]),"=r"((r)[14]),"=r"((r)[15]) \
        : "r"(a))

__device__ __forceinline__ void mma_f16_ss(uint32_t d, u64 ad, u64 bd, uint32_t idesc, uint32_t en) {
    asm volatile("{\n\t.reg .pred p;\n\tsetp.ne.u32 p, %5, 0;\n\t"
        "tcgen05.mma.cta_group::1.kind::f16 [%0], %1, %2, %3, {%4,%4,%4,%4}, p;\n\t}"
        :: "r"(d), "l"(ad), "l"(bd), "r"(idesc), "r"(0u), "r"(en) : "memory");
}

static __device__ __forceinline__ u64 make_desc(uint32_t addr) {
    return (u64(2) << 61) | (u64(1) << 46) | (u64(64) << 32) | (u64(1) << 16)
         | ((u64)(addr >> 4) & 0x3FFF);
}

#define IDESC_W ((1u<<4) | (1u<<7) | (1u<<10) | (10u<<17) | (8u<<24))
#define IDESC_V ((1u<<4) | (1u<<7) | (1u<<10) | (8u<<17)  | (8u<<24))
#endif // HAS_TC

// ---------------------------------------------------------------------------
// Device scratch
// ---------------------------------------------------------------------------
__device__ __align__(16) __nv_bfloat16 g_wbh[4 * 160 * 320];
__device__ __align__(16) __nv_bfloat16 g_wbl[4 * 160 * 320];
__device__ __align__(16) char g_w1s [4][2][20480];
__device__ __align__(16) char g_wf0s[2][20480];
__device__ __align__(16) char g_wf1s[2][20480];
__device__ __align__(16) char g_embs[2][8][16384];  // emb, swizzled bf16 hi/lo, 8 chunks of 64 classes
__device__ __align__(16) float g_w1t [4 * 80 * 80];
__device__ __align__(16) float g_wf0t[80 * 80];
__device__ __align__(16) float g_wf1t[80 * 80];
__device__ __align__(16) float g_e2  [512];
__device__ __align__(16) float g_bufA [16 * 80 * 4096];
__device__ __align__(16) float g_bufB [16 * 80 * 2048];
__device__ __align__(16) float g_bufAq[16 * 80 * 1024];
__device__ __align__(16) float g_bufBq[16 * 80 * 512];
__device__ __align__(16) float g_encS[16 * 2040 * 80];
__device__ __align__(16) float g_encQ[16 * 504 * 80];
__device__ unsigned g_gmax[32];

// ---------------------------------------------------------------------------
// Weight prep
// ---------------------------------------------------------------------------
__global__ void prep_kernel(const float* __restrict__ w_wide,
                            const float* __restrict__ w_1x1,
                            const float* __restrict__ w_f0,
                            const float* __restrict__ w_f1,
                            const float* __restrict__ emb) {
    int g = blockIdx.x * blockDim.x + threadIdx.x;
    int stride = gridDim.x * blockDim.x;
    for (int idx = g; idx < 4 * 160 * 320; idx += stride) {
        float v = w_wide[idx];
        __nv_bfloat16 h = __float2bfloat16(v);
        g_wbh[idx] = h;
        g_wbl[idx] = __float2bfloat16(v - __bfloat162float(h));
    }
    for (int idx = g; idx < 4 * 80 * 128; idx += stride) {
        int l = idx / 10240, r = idx % 10240;
        int oc = r >> 7, k = r & 127;
        float v = (k < 80) ? w_1x1[l * 6400 + oc * 80 + k] : 0.f;
        __nv_bfloat16 h = __float2bfloat16(v);
        __nv_bfloat16 lo = __float2bfloat16(v - __bfloat162float(h));
        uint32_t off = (uint32_t)(((oc >> 3) + (k >> 6) * 10) * 1024 + (oc & 7) * 128 + (k & 63) * 2);
        uint32_t sw  = off ^ ((off >> 3) & 0x70);
        *(__nv_bfloat16*)(g_w1s[l][0] + sw) = h;
        *(__nv_bfloat16*)(g_w1s[l][1] + sw) = lo;
    }
    for (int idx = g; idx < 80 * 128; idx += stride) {
        int oc = idx >> 7, k = idx & 127;
        uint32_t off = (uint32_t)(((oc >> 3) + (k >> 6) * 10) * 1024 + (oc & 7) * 128 + (k & 63) * 2);
        uint32_t sw  = off ^ ((off >> 3) & 0x70);
        float v0 = (k < 80) ? w_f0[oc * 80 + k] : 0.f;
        float v1 = (k < 80) ? w_f1[oc * 80 + k] : 0.f;
        __nv_bfloat16 h0 = __float2bfloat16(v0);
        __nv_bfloat16 h1 = __float2bfloat16(v1);
        *(__nv_bfloat16*)(g_wf0s[0] + sw) = h0;
        *(__nv_bfloat16*)(g_wf0s[1] + sw) = __float2bfloat16(v0 - __bfloat162float(h0));
        *(__nv_bfloat16*)(g_wf1s[0] + sw) = h1;
        *(__nv_bfloat16*)(g_wf1s[1] + sw) = __float2bfloat16(v1 - __bfloat162float(h1));
    }
    // emb images: 8 chunks of 64 classes, K padded 80->128, SW128 blocked atoms
    for (int idx = g; idx < 512 * 128; idx += stride) {
        int kc = idx >> 7;       // class 0..511
        int k  = idx & 127;
        int ch = kc >> 6, r = kc & 63;
        float v = (k < 80) ? emb[kc * 80 + k] : 0.f;
        __nv_bfloat16 h = __float2bfloat16(v);
        uint32_t off = (uint32_t)(((r >> 3) + (k >> 6) * 8) * 1024 + (r & 7) * 128 + (k & 63) * 2);
        uint32_t sw  = off ^ ((off >> 3) & 0x70);
        *(__nv_bfloat16*)(g_embs[0][ch] + sw) = h;
        *(__nv_bfloat16*)(g_embs[1][ch] + sw) = __float2bfloat16(v - __bfloat162float(h));
    }
    for (int idx = g; idx < 4 * 80 * 80; idx += stride) {
        int ic = idx % 80, oc = (idx / 80) % 80, l = idx / 6400;
        g_w1t[l * 6400 + ic * 80 + oc] = w_1x1[idx];
    }
    for (int idx = g; idx < 6400; idx += stride) {
        int ic = idx % 80, oc = idx / 80;
        g_wf0t[ic * 80 + oc] = w_f0[idx];
        g_wf1t[ic * 80 + oc] = w_f1[idx];
    }
    for (int k = g; k < 512; k += stride) {
        float s = 0.f;
        for (int c = 0; c < 80; c++) { float v = emb[k * 80 + c]; s += v * v; }
        g_e2[k] = s;
    }
    if (g < 32) g_gmax[g] = 0u;
}

// ---------------------------------------------------------------------------
// smem layout (1024-aligned base)
// ---------------------------------------------------------------------------
#define OFF_A_HI  0
#define OFF_A_LO  16384
#define OFF_B_HI  32768
#define OFF_B_LO  53248
#define OFF2_A_HI 0
#define OFF2_A_LO 32768
#define OFF2_B_HI 65536
#define OFF2_B_LO 86016
#define SMEM_DYN  (1024 + 106496)
// VQ: A_hi @0 (32K), A_lo @32K, B_hi @64K (16K), B_lo @80K (end 96K)
#define VQ_B_HI   65536
#define VQ_B_LO   81920
#define SMEM_VQ   (1024 + 98304)

#if HAS_TC
__device__ __forceinline__ void pack8(char* abp, int t, int g8, const float* v) {
    uint32_t ub[8]; float lo[8];
    #pragma unroll
    for (int i = 0; i < 8; i++) {
        ub[i] = __float_as_uint(v[i]);
        lo[i] = v[i] - __uint_as_float(ub[i] & 0xFFFF0000u);
    }
    uint4 hp, lp;
    hp.x = prmt_hi(ub[0], ub[1]); hp.y = prmt_hi(ub[2], ub[3]);
    hp.z = prmt_hi(ub[4], ub[5]); hp.w = prmt_hi(ub[6], ub[7]);
    lp.x = cvt_bf16x2(lo[1], lo[0]); lp.y = cvt_bf16x2(lo[3], lo[2]);
    lp.z = cvt_bf16x2(lo[5], lo[4]); lp.w = cvt_bf16x2(lo[7], lo[6]);
    uint32_t off = (uint32_t)(((t >> 3) + ((g8 >= 8) ? 16 : 0)) * 1024 + (t & 7) * 128 + (g8 & 7) * 16);
    uint32_t sw  = off ^ ((off >> 3) & 0x70);
    *(uint4*)(abp + OFF2_A_HI + sw) = hp;
    *(uint4*)(abp + OFF2_A_LO + sw) = lp;
}
__device__ __forceinline__ void copy_w2(char* abp, const char* hi, const char* lo, int tid) {
    if (tid >= 128) {
        for (int i = tid - 128; i < 1280; i += 192) {
            ((uint4*)(abp + OFF2_B_HI))[i] = __ldg((const uint4*)hi + i);
            ((uint4*)(abp + OFF2_B_LO))[i] = __ldg((const uint4*)lo + i);
        }
    }
}
__device__ __forceinline__ void issue_gemm2(uint32_t tmem_dst, uint32_t ab, uint32_t mbar) {
    u64 dAh = make_desc(ab + OFF2_A_HI), dAl = make_desc(ab + OFF2_A_LO);
    u64 dBh = make_desc(ab + OFF2_B_HI), dBl = make_desc(ab + OFF2_B_LO);
    u64 pA[3] = {dAh, dAh, dAl};
    u64 pB[3] = {dBh, dBl, dBh};
    #pragma unroll
    for (int p = 0; p < 3; p++) {
        #pragma unroll
        for (int s = 0; s < 5; s++) {
            uint32_t en = (p == 0 && s == 0) ? 0u : 1u;
            u64 ao = (s < 4) ? (u64)(2 * s) : 1024ull;
            u64 bo = (s < 4) ? (u64)(2 * s) : 640ull;
            mma_f16_ss(tmem_dst, pA[p] + ao, pB[p] + bo, IDESC_W, en);
        }
    }
    TCGEN05_COMMIT(mbar);
}
// VQ variant: B = 64 classes, N=64; k 64..79 chunk at +512 units
__device__ __forceinline__ void issue_gemmv(uint32_t tmem_dst, uint32_t ab, uint32_t mbar) {
    u64 dAh = make_desc(ab + OFF2_A_HI), dAl = make_desc(ab + OFF2_A_LO);
    u64 dBh = make_desc(ab + VQ_B_HI),  dBl = make_desc(ab + VQ_B_LO);
    u64 pA[3] = {dAh, dAh, dAl};
    u64 pB[3] = {dBh, dBl, dBh};
    #pragma unroll
    for (int p = 0; p < 3; p++) {
        #pragma unroll
        for (int s = 0; s < 5; s++) {
            uint32_t en = (p == 0 && s == 0) ? 0u : 1u;
            u64 ao = (s < 4) ? (u64)(2 * s) : 1024ull;
            u64 bo = (s < 4) ? (u64)(2 * s) : 512ull;
            mma_f16_ss(tmem_dst, pA[p] + ao, pB[p] + bo, IDESC_V, en);
        }
    }
    TCGEN05_COMMIT(mbar);
}
#endif

template <int S, bool FIRST, bool RESID, bool FUSEFINAL>
__global__ __launch_bounds__(320, 2) void gemm_layer_kernel(
    const float* __restrict__ xinS, const float* __restrict__ xinQ,
    float* __restrict__ xoutS, float* __restrict__ xoutQ,
    const __nv_bfloat16* __restrict__ wbh, const __nv_bfloat16* __restrict__ wbl,
    const float* __restrict__ bw,
    const char* __restrict__ w2h, const char* __restrict__ w2l,
    const float* __restrict__ w1t, const float* __restrict__ b1,
    const char* __restrict__ wf0h, const char* __restrict__ wf0l,
    const char* __restrict__ wf1h, const char* __restrict__ wf1l,
    const float* __restrict__ bf0, const float* __restrict__ bf1,
    int TinS, int TinLdS, int ToutS, int ToutLdS,
    int TinQ, int TinLdQ, int ToutQ, int ToutLdQ, int blocksS)
{
    extern __shared__ char dsm[];
    __shared__ float s_bias[400];

    const int tid = threadIdx.x;
    const int wid = tid >> 5;
    const int n   = blockIdx.y;
    const int bx  = blockIdx.x;

    const float* xin; float* xout; int Tin, TinLd, Tout, ToutLd, t0;
    if (bx < blocksS) {
        xin = xinS; xout = xoutS; Tin = TinS; TinLd = TinLdS;
        Tout = ToutS; ToutLd = ToutLdS; t0 = bx * 128;
    } else {
        xin = xinQ; xout = xoutQ; Tin = TinQ; TinLd = TinLdQ;
        Tout = ToutQ; ToutLd = ToutLdQ; t0 = (bx - blocksS) * 128;
    }
    const float* xin_n = xin + (size_t)n * 80 * TinLd;

    uint32_t base_raw = smem_u32(dsm);
    uint32_t ab = (base_raw + 1023u) & ~1023u;
    char* abp = dsm + (ab - base_raw);

    for (int i = tid; i < 400; i += 320) {
        float v = 0.f;
        if (i < 160) v = __ldg(bw + i);
        else if (i < 240) v = __ldg(b1 + i - 160);
        else if (FUSEFINAL && i < 320) v = __ldg(bf0 + i - 240);
        else if (FUSEFINAL) v = __ldg(bf1 + i - 320);
        s_bias[i] = v;
    }

#if HAS_TC
    __shared__ uint32_t s_tmem;
    __shared__ __align__(8) u64 s_mbar;

    if (tid == 0) MBARRIER_INIT(smem_u32(&s_mbar), 1);
    if (wid == 0) { TCGEN05_ALLOC(smem_u32(&s_tmem), 256); TCGEN05_RELINQ(); }
    __syncthreads();
    const uint32_t tmem = s_tmem;
    const uint32_t mbar = smem_u32(&s_mbar);

    // ---- wide GEMM: 5 K-chunks of 64, D -> tmem cols 0..159 ----
    for (int kc = 0; kc < 5; kc++) {
        const int k0 = kc * 64;
        if (kc > 0) MBAR_WAIT(mbar, (kc - 1) & 1);
        #pragma unroll
        for (int r = 0; r < 4; r++) {
            int gi = r * 320 + tid;
            if (gi < 1024) {
                int t, g8;
                if (FIRST) { g8 = gi & 7; t = gi >> 3; }
                else       { t = gi & 127; g8 = gi >> 7; }
                int c0 = (k0 >> 2) + g8 * 2;
                int u0 = S * (t0 + t);
                float v[8];
                if (FIRST) {
                    #pragma unroll
                    for (int j = 0; j < 4; j++) {
                        int u = u0 + j;
                        if (u < Tin) {
                            float2 p = __ldg((const float2*)&xin_n[(size_t)u * 80 + c0]);
                            v[j] = p.x; v[4 + j] = p.y;
                        } else { v[j] = 0.f; v[4 + j] = 0.f; }
                    }
                } else {
                    const float* r0 = xin_n + (size_t)c0 * TinLd + u0;
                    #pragma unroll
                    for (int j = 0; j < 4; j++) {
                        bool ok = (u0 + j) < Tin;
                        v[j]     = ok ? __ldg(r0 + j)         : 0.f;
                        v[4 + j] = ok ? __ldg(r0 + TinLd + j) : 0.f;
                    }
                }
                uint32_t ub[8]; float lo[8];
                #pragma unroll
                for (int i = 0; i < 8; i++) {
                    ub[i] = __float_as_uint(v[i]);
                    lo[i] = v[i] - __uint_as_float(ub[i] & 0xFFFF0000u);
                }
                uint4 hp, lp;
                hp.x = prmt_hi(ub[0], ub[1]); hp.y = prmt_hi(ub[2], ub[3]);
                hp.z = prmt_hi(ub[4], ub[5]); hp.w = prmt_hi(ub[6], ub[7]);
                lp.x = cvt_bf16x2(lo[1], lo[0]); lp.y = cvt_bf16x2(lo[3], lo[2]);
                lp.z = cvt_bf16x2(lo[5], lo[4]); lp.w = cvt_bf16x2(lo[7], lo[6]);
                uint32_t off = (uint32_t)((t >> 3) * 1024 + (t & 7) * 128 + g8 * 16);
                uint32_t sw  = off ^ ((off >> 3) & 0x70);
                *(uint4*)(abp + OFF_A_HI + sw) = hp;
                *(uint4*)(abp + OFF_A_LO + sw) = lp;
            }
        }
        {
            const uint4* srcH = (const uint4*)wbh;
            const uint4* srcL = (const uint4*)wbl;
            #pragma unroll
            for (int r = 0; r < 4; r++) {
                int gi = r * 320 + tid;
                int row = gi >> 3, g8 = gi & 7;
                int si  = row * 40 + (k0 >> 3) + g8;
                uint32_t off = (uint32_t)((row >> 3) * 1024 + (row & 7) * 128 + g8 * 16);
                uint32_t sw  = off ^ ((off >> 3) & 0x70);
                *(uint4*)(abp + OFF_B_HI + sw) = __ldg(srcH + si);
                *(uint4*)(abp + OFF_B_LO + sw) = __ldg(srcL + si);
            }
        }
        FENCE_ASYNC_SHARED();
        __syncthreads();

        if (wid == 0 && elect_one()) {
            u64 dAh = make_desc(ab + OFF_A_HI), dAl = make_desc(ab + OFF_A_LO);
            u64 dBh = make_desc(ab + OFF_B_HI), dBl = make_desc(ab + OFF_B_LO);
            u64 pA[3] = {dAh, dAh, dAl};
            u64 pB[3] = {dBh, dBl, dBh};
            #pragma unroll
            for (int p = 0; p < 3; p++) {
                #pragma unroll
                for (int s = 0; s < 4; s++) {
                    uint32_t en = (kc == 0 && p == 0 && s == 0) ? 0u : 1u;
                    u64 ad = pA[p] + s * 2;
                    mma_f16_ss(tmem,      ad, pB[p] + s * 2,       IDESC_W, en);
                    mma_f16_ss(tmem + 80, ad, pB[p] + 640 + s * 2, IDESC_W, en);
                }
            }
            TCGEN05_COMMIT(mbar);
        }
    }
    MBAR_WAIT(mbar, 0);

    // ---- gate -> bf16 A2 (warps 0-3) ; W1 image copy (warps 4-9) ----
    if (tid < 128) {
        TCGEN05_FENCE_AFTER();
        const int t = tid;
        uint32_t da[32], dg[32];
        #pragma unroll
        for (int ch = 0; ch < 3; ch++) {
            int a0 = ch * 32;
            int w  = (ch == 2) ? 16 : 32;
            if (w == 32) { LDTM_X32(da, tmem + a0); LDTM_X32(dg, tmem + 80 + a0); }
            else         { LDTM_X16(da, tmem + a0); LDTM_X16(dg, tmem + 80 + a0); }
            TCGEN05_WAIT_LD();
            float gv[32];
            for (int i = 0; i < w; i++) {
                float a = __uint_as_float(da[i]) + s_bias[a0 + i];
                float g = __uint_as_float(dg[i]) + s_bias[80 + a0 + i];
                gv[i] = gatef(a, g);
            }
            #pragma unroll
            for (int q = 0; q < 4; q++) {
                if (q * 8 < w) pack8(abp, t, (a0 >> 3) + q, gv + q * 8);
            }
        }
    }
    copy_w2(abp, w2h, w2l, tid);
    FENCE_ASYNC_SHARED();
    __syncthreads();

    if (wid == 0 && elect_one()) issue_gemm2(tmem + 160, ab, mbar);
    MBAR_WAIT(mbar, 1);

    if (!FUSEFINAL) {
        if (tid < 128) {
            TCGEN05_FENCE_AFTER();
            const int t = tid;
            const bool tv = (t0 + t) < Tout;
            uint32_t d[32];
            #pragma unroll
            for (int ch = 0; ch < 3; ch++) {
                int a0 = ch * 32;
                int w  = (ch == 2) ? 16 : 32;
                if (w == 32) LDTM_X32(d, tmem + 160 + a0);
                else         LDTM_X16(d, tmem + 160 + a0);
                TCGEN05_WAIT_LD();
                if (tv) {
                    for (int i = 0; i < w; i++) {
                        int c = a0 + i;
                        float v = __uint_as_float(d[i]) + s_bias[160 + c];
                        if (RESID) v += __ldg(xin_n + (size_t)c * TinLd + S * (t0 + t) + 3);
                        xout[((size_t)n * 80 + c) * ToutLd + t0 + t] = v;
                    }
                }
            }
        }
        __syncthreads();
        if (wid == 0) TCGEN05_DEALLOC(tmem, 256);
    } else {
        if (tid < 128) {
            TCGEN05_FENCE_AFTER();
            const int t = tid;
            const bool tv = (t0 + t) < Tout;
            uint32_t d[32];
            #pragma unroll
            for (int ch = 0; ch < 3; ch++) {
                int a0 = ch * 32;
                int w  = (ch == 2) ? 16 : 32;
                if (w == 32) LDTM_X32(d, tmem + 160 + a0);
                else         LDTM_X16(d, tmem + 160 + a0);
                TCGEN05_WAIT_LD();
                float v[32];
                for (int i = 0; i < w; i++) {
                    int c = a0 + i;
                    v[i] = __uint_as_float(d[i]) + s_bias[160 + c];
                    if (RESID && tv) v[i] += __ldg(xin_n + (size_t)c * TinLd + S * (t0 + t) + 3);
                }
                #pragma unroll
                for (int q = 0; q < 4; q++)
                    if (q * 8 < w) pack8(abp, t, (a0 >> 3) + q, v + q * 8);
            }
        }
        copy_w2(abp, wf0h, wf0l, tid);
        FENCE_ASYNC_SHARED();
        __syncthreads();
        if (wid == 0 && elect_one()) issue_gemm2(tmem + 0, ab, mbar);
        MBAR_WAIT(mbar, 0);

        if (tid < 128) {
            TCGEN05_FENCE_AFTER();
            const int t = tid;
            uint32_t d[32];
            #pragma unroll
            for (int ch = 0; ch < 3; ch++) {
                int a0 = ch * 32;
                int w  = (ch == 2) ? 16 : 32;
                if (w == 32) LDTM_X32(d, tmem + a0);
                else         LDTM_X16(d, tmem + a0);
                TCGEN05_WAIT_LD();
                float v[32];
                for (int i = 0; i < w; i++)
                    v[i] = fmaxf(__uint_as_float(d[i]) + s_bias[240 + a0 + i], 0.f);
                #pragma unroll
                for (int q = 0; q < 4; q++)
                    if (q * 8 < w) pack8(abp, t, (a0 >> 3) + q, v + q * 8);
            }
        }
        copy_w2(abp, wf1h, wf1l, tid);
        FENCE_ASYNC_SHARED();
        __syncthreads();
        if (wid == 0 && elect_one()) issue_gemm2(tmem + 80, ab, mbar);
        MBAR_WAIT(mbar, 1);

        if (tid < 128) {
            TCGEN05_FENCE_AFTER();
            const int t = tid;
            const bool tv = (t0 + t) < Tout;
            uint32_t d[32];
            #pragma unroll
            for (int ch = 0; ch < 3; ch++) {
                int a0 = ch * 32;
                int w  = (ch == 2) ? 16 : 32;
                if (w == 32) LDTM_X32(d, tmem + 80 + a0);
                else         LDTM_X16(d, tmem + 80 + a0);
                TCGEN05_WAIT_LD();
                if (tv) {
                    float* dst = xout + ((size_t)n * Tout + t0 + t) * 80 + a0;
                    for (int i = 0; i < w; i += 4) {
                        float4 o;
                        o.x = __uint_as_float(d[i])     + s_bias[320 + a0 + i];
                        o.y = __uint_as_float(d[i + 1]) + s_bias[320 + a0 + i + 1];
                        o.z = __uint_as_float(d[i + 2]) + s_bias[320 + a0 + i + 2];
                        o.w = __uint_as_float(d[i + 3]) + s_bias[320 + a0 + i + 3];
                        *(float4*)(dst + i) = o;
                    }
                }
            }
        }
        __syncthreads();
        if (wid == 0) TCGEN05_DEALLOC(tmem, 256);
    }

#else  // ------- non-'a' PTX pass: safe scalar fallback (never runs on GB300) -------
    float* gsmF = (float*)(abp);
    float* bufF = (float*)(abp + 43008);
    __syncthreads();
    for (int e = tid; e < 80 * 128; e += 320) {
        int oc = e >> 7, tt = e & 127;
        float a = s_bias[oc], g = s_bias[oc + 80];
        for (int c = 0; c < 80; c++) {
            for (int j = 0; j < 4; j++) {
                int u = S * (t0 + tt) + j;
                float xv = (u < Tin)
                         ? (FIRST ? xin_n[(size_t)u * 80 + c]
                                  : xin_n[(size_t)c * TinLd + u]) : 0.f;
                float wa = __bfloat162float(wbh[oc * 320 + c * 4 + j])
                         + __bfloat162float(wbl[oc * 320 + c * 4 + j]);
                float wg = __bfloat162float(wbh[(oc + 80) * 320 + c * 4 + j])
                         + __bfloat162float(wbl[(oc + 80) * 320 + c * 4 + j]);
                a = fmaf(wa, xv, a);
                g = fmaf(wg, xv, g);
            }
        }
        gsmF[oc * 132 + tt] = gatef(a, g);
    }
    __syncthreads();
    for (int e = tid; e < 80 * 128; e += 320) {
        int oc = e >> 7, tt = e & 127;
        int t = t0 + tt;
        float s = s_bias[160 + oc];
        for (int ic = 0; ic < 80; ic++) s = fmaf(w1t[ic * 80 + oc], gsmF[ic * 132 + tt], s);
        if (RESID && t < Tout) s += xin_n[(size_t)oc * TinLd + S * t + 3];
        if (FUSEFINAL) bufF[oc * 132 + tt] = s;
        else if (t < Tout) xout[((size_t)n * 80 + oc) * ToutLd + t] = s;
    }
    if (FUSEFINAL) {
        __syncthreads();
        for (int e = tid; e < 80 * 128; e += 320) {
            int oc = e >> 7, tt = e & 127;
            float s = s_bias[240 + oc];
            for (int ic = 0; ic < 80; ic++) s = fmaf(g_wf0t[ic * 80 + oc], bufF[ic * 132 + tt], s);
            gsmF[oc * 132 + tt] = fmaxf(s, 0.f);
        }
        __syncthreads();
        for (int e = tid; e < 80 * 128; e += 320) {
            int oc = e >> 7, tt = e & 127;
            int t = t0 + tt;
            if (t < Tout) {
                float s = s_bias[320 + oc];
                for (int ic = 0; ic < 80; ic++) s = fmaf(g_wf1t[ic * 80 + oc], gsmF[ic * 132 + tt], s);
                xout[((size_t)n * Tout + t) * 80 + oc] = s;
            }
        }
    }
#endif // HAS_TC
}

// ---------------------------------------------------------------------------
// VQ v3: tcgen05 GEMM X[128x80] x Emb^T[80x512] + argmin readout + head
// One CTA = 128 timesteps of one n. 512 threads = 16 warps.
// Readout: quarter = wid>>2 covers 64 of 256 columns; sub = wid&3 picks t-row.
// ---------------------------------------------------------------------------
__device__ __forceinline__ unsigned fenc(float f) {
    unsigned u = __float_as_uint(f);
    return (u & 0x80000000u) ? ~u : (u | 0x80000000u);
}

__global__ __launch_bounds__(512, 2) void vq_kernel(
    const float* __restrict__ encS,
    const float* __restrict__ encQ,
    const float* __restrict__ emb,
    const float* __restrict__ wlin,
    const float* __restrict__ blin)
{
    extern __shared__ char dsm[];
    __shared__ float se2[512];
    __shared__ float sdist[512];
    __shared__ int   sidx[512];
    __shared__ unsigned sm0, sm1;

    const int tid = threadIdx.x;
    const int wid = tid >> 5;
    const int n   = blockIdx.y;
    const int t0  = blockIdx.x * 128;

    if (tid == 0) { sm0 = 0u; sm1 = 0u; }
    se2[tid] = __ldg(&g_e2[tid]);

#if HAS_TC
    __shared__ uint32_t s_tmem;
    __shared__ __align__(8) u64 s_mbar;

    uint32_t base_raw = smem_u32(dsm);
    uint32_t ab = (base_raw + 1023u) & ~1023u;
    char* abp = dsm + (ab - base_raw);

    if (tid == 0) MBARRIER_INIT(smem_u32(&s_mbar), 1);
    if (wid == 0) { TCGEN05_ALLOC(smem_u32(&s_tmem), 256); TCGEN05_RELINQ(); }
    __syncthreads();
    const uint32_t tmem = s_tmem;
    const uint32_t mbar = smem_u32(&s_mbar);

    // ---- stage X as A (128 t x 80 k, hi/lo): 1280 granules ----
    {
        const float4* src = (const float4*)(encS + (size_t)n * 2040 * 80);
        #pragma unroll
        for (int r = 0; r < 3; r++) {
            int gi = r * 512 + tid;
            if (gi < 1280) {
                int t = gi / 10, kg = gi % 10;
                int tg = t0 + t;
                float v[8] = {0.f, 0.f, 0.f, 0.f, 0.f, 0.f, 0.f, 0.f};
                if (tg < 2040) {
                    float4 a = __ldg(src + (size_t)tg * 20 + kg * 2);
                    float4 b = __ldg(src + (size_t)tg * 20 + kg * 2 + 1);
                    v[0] = a.x; v[1] = a.y; v[2] = a.z; v[3] = a.w;
                    v[4] = b.x; v[5] = b.y; v[6] = b.z; v[7] = b.w;
                }
                pack8(abp, t, kg, v);
            }
        }
    }

    // ---- 2 groups x 4 chunks of 64 classes; running argmin in registers ----
    const int sub  = wid & 3;       // subpartition / t-row group
    const int quar = wid >> 2;      // 0..3: column quarter (64 cols each)
    const int t    = sub * 32 + (tid & 31);
    float best = 3.4e38f;
    int   bi   = 0;
    int   cnt  = 0;

    for (int grp = 0; grp < 2; grp++) {
        for (int ch = 0; ch < 4; ch++) {
            int cls = grp * 4 + ch;
            for (int i = tid; i < 1024; i += 512) {
                ((uint4*)(abp + VQ_B_HI))[i] = __ldg((const uint4*)(g_embs[0][cls]) + i);
                ((uint4*)(abp + VQ_B_LO))[i] = __ldg((const uint4*)(g_embs[1][cls]) + i);
            }
            FENCE_ASYNC_SHARED();
            __syncthreads();
            if (wid == 0 && elect_one()) issue_gemmv(tmem + ch * 64, ab, mbar);
            MBAR_WAIT(mbar, cnt & 1);
            cnt++;
        }
        // readout 256 cols, 16 warps: each (sub, quarter) reads 2x32 cols
        TCGEN05_FENCE_AFTER();
        uint32_t d[32];
        #pragma unroll
        for (int cc = 0; cc < 2; cc++) {
            int c0 = quar * 64 + cc * 32;
            LDTM_X32(d, tmem + c0);
            TCGEN05_WAIT_LD();
            for (int i = 0; i < 32; i++) {
                int k = grp * 256 + c0 + i;
                float dd = se2[k] - 2.f * __uint_as_float(d[i]);
                if (dd < best) { best = dd; bi = k; }
            }
        }
        TCGEN05_FENCE_BEFORE();
        __syncthreads();   // all LDTMs done before next group's MMAs overwrite
    }

    sdist[t * 4 + quar] = best;
    sidx [t * 4 + quar] = bi;
    __syncthreads();
    if (wid == 0) TCGEN05_DEALLOC(tmem, 256);

    if (tid < 128) {
        float bd = sdist[tid * 4];
        int  bbi = sidx [tid * 4];
        #pragma unroll
        for (int q = 1; q < 4; q++) {
            float dq = sdist[tid * 4 + q];
            int   iq = sidx [tid * 4 + q];
            if (dq < bd || (dq == bd && iq < bbi)) { bd = dq; bbi = iq; }
        }
        int tg2 = t0 + tid;
        if (tg2 < 2040) {
            const float* dv = emb + (size_t)bbi * 80;
            const float* qr = (tg2 < 2016)
                            ? (encQ + ((size_t)n * 504 + (tg2 % 504)) * 80)
                            : nullptr;
            float s0 = blin[0], s1 = blin[1];
            #pragma unroll 4
            for (int c = 0; c < 80; c++) {
                float v = dv[c] + (qr ? qr[c] : 0.f);
                s0 = fmaf(v, wlin[c],      s0);
                s1 = fmaf(v, wlin[80 + c], s1);
            }
            atomicMax(&sm0, fenc(tanhf(s0)));
            atomicMax(&sm1, fenc(tanhf(s1)));
        }
    }
    __syncthreads();
    if (tid == 0) {
        atomicMax(&g_gmax[n * 2 + 0], sm0);
        atomicMax(&g_gmax[n * 2 + 1], sm1);
    }

#else  // ------- non-'a' PTX pass: safe scalar fallback (never runs on GB300) -------
    __syncthreads();
    if (tid < 128) {
        int tg2 = t0 + tid;
        if (tg2 < 2040) {
            const float* xr = encS + ((size_t)n * 2040 + tg2) * 80;
            float best = 3.4e38f; int bbi = 0;
            for (int k = 0; k < 512; k++) {
                float dot = 0.f;
                for (int c = 0; c < 80; c++) dot = fmaf(xr[c], emb[k * 80 + c], dot);
                float dd = se2[k] - 2.f * dot;
                if (dd < best) { best = dd; bbi = k; }
            }
            const float* dv = emb + (size_t)bbi * 80;
            const float* qr = (tg2 < 2016)
                            ? (encQ + ((size_t)n * 504 + (tg2 % 504)) * 80)
                            : nullptr;
            float s0 = blin[0], s1 = blin[1];
            for (int c = 0; c < 80; c++) {
                float v = dv[c] + (qr ? qr[c] : 0.f);
                s0 = fmaf(v, wlin[c],      s0);
                s1 = fmaf(v, wlin[80 + c], s1);
            }
            atomicMax(&sm0, fenc(tanhf(s0)));
            atomicMax(&sm1, fenc(tanhf(s1)));
        }
    }
    __syncthreads();
    if (tid == 0) {
        atomicMax(&g_gmax[n * 2 + 0], sm0);
        atomicMax(&g_gmax[n * 2 + 1], sm1);
    }
#endif
}

__global__ void finalize_kernel(float* __restrict__ out) {
    int i = threadIdx.x;
    if (i < 32) {
        unsigned e = g_gmax[i];
        out[i] = (e & 0x80000000u) ? __uint_as_float(e ^ 0x80000000u)
                                   : __uint_as_float(~e);
    }
}

// ---------------------------------------------------------------------------
// Host launch
// ---------------------------------------------------------------------------
extern "C" void kernel_launch(void* const* d_in, const int* in_sizes, int n_in,
                              void* d_out, int out_size) {
    const float* search = (const float*)d_in[0];
    const float* query  = (const float*)d_in[1];
    const float* w_wide = (const float*)d_in[2];
    const float* b_wide = (const float*)d_in[3];
    const float* w_1x1  = (const float*)d_in[4];
    const float* b_1x1  = (const float*)d_in[5];
    const float* w_f0   = (const float*)d_in[6];
    const float* b_f0   = (const float*)d_in[7];
    const float* w_f1   = (const float*)d_in[8];
    const float* b_f1   = (const float*)d_in[9];
    const float* emb    = (const float*)d_in[10];
    const float* w_lin  = (const float*)d_in[11];
    const float* b_lin  = (const float*)d_in[12];
    float* out = (float*)d_out;

    void *pA, *pB, *pAq, *pBq, *pS, *pQ, *pwh, *pwl, *pw1, *pw1s, *pwf0s, *pwf1s;
    cudaGetSymbolAddress(&pA,   g_bufA);
    cudaGetSymbolAddress(&pB,   g_bufB);
    cudaGetSymbolAddress(&pAq,  g_bufAq);
    cudaGetSymbolAddress(&pBq,  g_bufBq);
    cudaGetSymbolAddress(&pS,   g_encS);
    cudaGetSymbolAddress(&pQ,   g_encQ);
    cudaGetSymbolAddress(&pwh,  g_wbh);
    cudaGetSymbolAddress(&pwl,  g_wbl);
    cudaGetSymbolAddress(&pw1,  g_w1t);
    cudaGetSymbolAddress(&pw1s, g_w1s);
    cudaGetSymbolAddress(&pwf0s, g_wf0s);
    cudaGetSymbolAddress(&pwf1s, g_wf1s);
    float* A   = (float*)pA;
    float* B   = (float*)pB;
    float* Aq  = (float*)pAq;
    float* Bq  = (float*)pBq;
    float* eS  = (float*)pS;
    float* eQ  = (float*)pQ;
    __nv_bfloat16* wbh = (__nv_bfloat16*)pwh;
    __nv_bfloat16* wbl = (__nv_bfloat16*)pwl;
    float* w1t = (float*)pw1;
    const char* w1s  = (const char*)pw1s;
    const char* wf0s = (const char*)pwf0s;
    const char* wf1s = (const char*)pwf1s;

    cudaFuncSetAttribute(gemm_layer_kernel<2, true,  false, false>,
                         cudaFuncAttributeMaxDynamicSharedMemorySize, SMEM_DYN);
    cudaFuncSetAttribute(gemm_layer_kernel<2, false, true,  false>,
                         cudaFuncAttributeMaxDynamicSharedMemorySize, SMEM_DYN);
    cudaFuncSetAttribute(gemm_layer_kernel<1, false, true,  false>,
                         cudaFuncAttributeMaxDynamicSharedMemorySize, SMEM_DYN);
    cudaFuncSetAttribute(gemm_layer_kernel<1, false, true,  true >,
                         cudaFuncAttributeMaxDynamicSharedMemorySize, SMEM_DYN);
    cudaFuncSetAttribute(vq_kernel,
                         cudaFuncAttributeMaxDynamicSharedMemorySize, SMEM_VQ);

    prep_kernel<<<80, 256>>>(w_wide, w_1x1, w_f0, w_f1, emb);

    #define W1S(l)  (w1s + (size_t)(l) * 2 * 20480)
    #define W1SL(l) (w1s + (size_t)(l) * 2 * 20480 + 20480)

    gemm_layer_kernel<2, true, false, false><<<dim3(40, NB), 320, SMEM_DYN>>>(
        search, query, A, Aq,
        wbh + 0 * 51200, wbl + 0 * 51200, b_wide + 0 * 160,
        W1S(0), W1SL(0), w1t + 0 * 6400, b_1x1 + 0 * 80,
        nullptr, nullptr, nullptr, nullptr, nullptr, nullptr,
        8192, 8192, 4095, 4096,  2048, 2048, 1023, 1024,  32);

    gemm_layer_kernel<2, false, true, false><<<dim3(20, NB), 320, SMEM_DYN>>>(
        A, Aq, B, Bq,
        wbh + 1 * 51200, wbl + 1 * 51200, b_wide + 1 * 160,
        W1S(1), W1SL(1), w1t + 1 * 6400, b_1x1 + 1 * 80,
        nullptr, nullptr, nullptr, nullptr, nullptr, nullptr,
        4095, 4096, 2046, 2048,  1023, 1024, 510, 512,  16);

    gemm_layer_kernel<1, false, true, false><<<dim3(20, NB), 320, SMEM_DYN>>>(
        B, Bq, A, Aq,
        wbh + 2 * 51200, wbl + 2 * 51200, b_wide + 2 * 160,
        W1S(2), W1SL(2), w1t + 2 * 6400, b_1x1 + 2 * 80,
        nullptr, nullptr, nullptr, nullptr, nullptr, nullptr,
        2046, 2048, 2043, 2044,  510, 512, 507, 508,  16);

    gemm_layer_kernel<1, false, true, true><<<dim3(20, NB), 320, SMEM_DYN>>>(
        A, Aq, eS, eQ,
        wbh + 3 * 51200, wbl + 3 * 51200, b_wide + 3 * 160,
        W1S(3), W1SL(3), w1t + 3 * 6400, b_1x1 + 3 * 80,
        wf0s, wf0s + 20480, wf1s, wf1s + 20480, b_f0, b_f1,
        2043, 2044, 2040, 2040,  507, 508, 504, 504,  16);

    vq_kernel<<<dim3(16, NB), 512, SMEM_VQ>>>(eS, eQ, emb, w_lin, b_lin);
    finalize_kernel<<<1, 32>>>(out);
}

// round 13
// speedup vs baseline: 4.5094x; 1.0180x over previous
#include <cuda_runtime.h>
#include <cuda_bf16.h>
#include <cstdint>

#define NB 16
typedef unsigned long long u64;

#if defined(__CUDA_ARCH_FEAT_SM103_ALL) || defined(__CUDA_ARCH_FEAT_SM100_ALL) || \
    (defined(__CUDA_ARCH_SPECIFIC__) && (__CUDA_ARCH_SPECIFIC__ >= 1000))
#define HAS_TC 1
#else
#define HAS_TC 0
#endif

// ---------------------------------------------------------------------------
// PTX helpers
// ---------------------------------------------------------------------------
__device__ __forceinline__ void fma2(u64& d, u64 a, u64 b) {
    asm("fma.rn.f32x2 %0, %1, %2, %0;" : "+l"(d) : "l"(a), "l"(b));
}
__device__ __forceinline__ float2 unpack2(u64 v) {
    float2 f; asm("mov.b64 {%0, %1}, %2;" : "=f"(f.x), "=f"(f.y) : "l"(v)); return f;
}
__device__ __forceinline__ uint32_t smem_u32(const void* p) {
    uint32_t a;
    asm("{ .reg .u64 t; cvta.to.shared.u64 t, %1; cvt.u32.u64 %0, t; }" : "=r"(a) : "l"(p));
    return a;
}
__device__ __forceinline__ float ex2f(float x) {
    float r; asm("ex2.approx.f32 %0, %1;" : "=f"(r) : "f"(x)); return r;
}
__device__ __forceinline__ float rcpf(float x) {
    float r; asm("rcp.approx.f32 %0, %1;" : "=f"(r) : "f"(x)); return r;
}
__device__ __forceinline__ uint32_t prmt_hi(uint32_t a, uint32_t b) {
    uint32_t r; asm("prmt.b32 %0, %1, %2, 0x7632;" : "=r"(r) : "r"(a), "r"(b)); return r;
}
__device__ __forceinline__ uint32_t cvt_bf16x2(float hi, float lo) {
    uint32_t r; asm("cvt.rn.bf16x2.f32 %0, %1, %2;" : "=r"(r) : "f"(hi), "f"(lo)); return r;
}
__device__ __forceinline__ float gatef(float a, float g) {
    float e1 = ex2f(fminf(a * -2.885390082f, 80.f));
    float e2 = ex2f(fminf(g * -1.442695041f, 80.f));
    float r  = rcpf((1.f + e1) * (1.f + e2));
    return (1.f - e1) * r;
}

#if HAS_TC
__device__ __forceinline__ uint32_t elect_one() {
    uint32_t p;
    asm volatile("{\n\t.reg .pred p;\n\telect.sync _|p, 0xFFFFFFFF;\n\tselp.b32 %0, 1, 0, p;\n\t}" : "=r"(p));
    return p;
}

#define TCGEN05_ALLOC(sm, n) \
    asm volatile("tcgen05.alloc.cta_group::1.sync.aligned.shared::cta.b32 [%0], %1;" \
                 :: "r"((uint32_t)(sm)), "r"((uint32_t)(n)) : "memory")
#define TCGEN05_RELINQ() \
    asm volatile("tcgen05.relinquish_alloc_permit.cta_group::1.sync.aligned;")
#define TCGEN05_DEALLOC(t, n) \
    asm volatile("tcgen05.dealloc.cta_group::1.sync.aligned.b32 %0, %1;" :: "r"(t), "r"((uint32_t)(n)))
#define TCGEN05_COMMIT(mb) \
    asm volatile("tcgen05.commit.cta_group::1.mbarrier::arrive::one.shared::cluster.b64 [%0];" \
                 :: "r"((uint32_t)(mb)) : "memory")
#define TCGEN05_FENCE_AFTER()  asm volatile("tcgen05.fence::after_thread_sync;" ::: "memory")
#define TCGEN05_FENCE_BEFORE() asm volatile("tcgen05.fence::before_thread_sync;" ::: "memory")
#define TCGEN05_WAIT_LD()      asm volatile("tcgen05.wait::ld.sync.aligned;" ::: "memory")
#define FENCE_ASYNC_SHARED()   asm volatile("fence.proxy.async.shared::cta;" ::: "memory")
#define MBARRIER_INIT(mb, c) \
    asm volatile("mbarrier.init.shared.b64 [%0], %1;" :: "r"((uint32_t)(mb)), "r"((uint32_t)(c)) : "memory")

#define MBAR_WAIT(mb, ph) do {                                                  \
    uint32_t _m = (uint32_t)(mb), _p = (uint32_t)(ph), _d;                      \
    asm volatile("{\n\t.reg .pred p;\n\t"                                       \
        "mbarrier.try_wait.parity.acquire.cta.shared::cta.b64 p, [%1], %2;\n\t" \
        "selp.b32 %0, 1, 0, p;\n\t}" : "=r"(_d) : "r"(_m), "r"(_p) : "memory"); \
    if (!_d) {                                                                  \
        asm volatile("{\n\t.reg .pred P1;\n\t"                                  \
            "WL_%=:\n\t"                                                        \
            "mbarrier.try_wait.parity.acquire.cta.shared::cta.b64 P1, [%0], %1, 0x989680;\n\t" \
            "@P1 bra.uni WD_%=;\n\t"                                            \
            "bra.uni WL_%=;\n\t"                                                \
            "WD_%=:\n\t}" :: "r"(_m), "r"(_p) : "memory");                      \
    }                                                                           \
} while (0)

#define LDTM_X32(r, a) \
    asm volatile("tcgen05.ld.sync.aligned.32x32b.x32.b32 " \
        "{%0,%1,%2,%3,%4,%5,%6,%7,%8,%9,%10,%11,%12,%13,%14,%15," \
        "%16,%17,%18,%19,%20,%21,%22,%23,%24,%25,%26,%27,%28,%29,%30,%31}, [%32];" \
        : "=r"((r)[0]),"=r"((r)[1]),"=r"((r)[2]),"=r"((r)[3]),"=r"((r)[4]),"=r"((r)[5]),"=r"((r)[6]),"=r"((r)[7]), \
          "=r"((r)[8]),"=r"((r)[9]),"=r"((r)[10]),"=r"((r)[11]),"=r"((r)[12]),"=r"((r)[13]),"=r"((r)[14]),"=r"((r)[15]), \
          "=r"((r)[16]),"=r"((r)[17]),"=r"((r)[18]),"=r"((r)[19]),"=r"((r)[20]),"=r"((r)[21]),"=r"((r)[22]),"=r"((r)[23]), \
          "=r"((r)[24]),"=r"((r)[25]),"=r"((r)[26]),"=r"((r)[27]),"=r"((r)[28]),"=r"((r)[29]),"=r"((r)[30]),"=r"((r)[31]) \
        : "r"(a))

#define LDTM_X16(r, a) \
    asm volatile("tcgen05.ld.sync.aligned.32x32b.x16.b32 " \
        "{%0,%1,%2,%3,%4,%5,%6,%7,%8,%9,%10,%11,%12,%13,%14,%15}, [%16];" \
        : "=r"((r)[0]),"=r"((r)[1]),"=r"((r)[2]),"=r"((r)[3]),"=r"((r)[4]),"=r"((r)[5]),"=r"((r)[6]),"=r"((r)[7]), \
          "=r"((r)[8]),"=r"((r)[9]),"=r"((r)[10]),"=r"((r)[11]),"=r"((r)[12]),"=r"((r)[13]),"=r"((r)[14]),"=r"((r)[15]) \
        : "r"(a))

__device__ __forceinline__ void mma_f16_ss(uint32_t d, u64 ad, u64 bd, uint32_t idesc, uint32_t en) {
    asm volatile("{\n\t.reg .pred p;\n\tsetp.ne.u32 p, %5, 0;\n\t"
        "tcgen05.mma.cta_group::1.kind::f16 [%0], %1, %2, %3, {%4,%4,%4,%4}, p;\n\t}"
        :: "r"(d), "l"(ad), "l"(bd), "r"(idesc), "r"(0u), "r"(en) : "memory");
}

static __device__ __forceinline__ u64 make_desc(uint32_t addr) {
    return (u64(2) << 61) | (u64(1) << 46) | (u64(64) << 32) | (u64(1) << 16)
         | ((u64)(addr >> 4) & 0x3FFF);
}

#define IDESC_W ((1u<<4) | (1u<<7) | (1u<<10) | (10u<<17) | (8u<<24))
#define IDESC_V ((1u<<4) | (1u<<7) | (1u<<10) | (8u<<17)  | (8u<<24))
#endif // HAS_TC

// ---------------------------------------------------------------------------
// Device scratch
// ---------------------------------------------------------------------------
__device__ __align__(16) __nv_bfloat16 g_wbh[4 * 160 * 320];
__device__ __align__(16) __nv_bfloat16 g_wbl[4 * 160 * 320];
__device__ __align__(16) char g_w1s [4][2][20480];
__device__ __align__(16) char g_wf0s[2][20480];
__device__ __align__(16) char g_wf1s[2][20480];
__device__ __align__(16) char g_embs[2][8][16384];
__device__ __align__(16) float g_w1t [4 * 80 * 80];
__device__ __align__(16) float g_wf0t[80 * 80];
__device__ __align__(16) float g_wf1t[80 * 80];
__device__ __align__(16) float g_e2  [512];
__device__ __align__(16) float g_bufA [16 * 80 * 4096];
__device__ __align__(16) float g_bufB [16 * 80 * 2048];
__device__ __align__(16) float g_bufAq[16 * 80 * 1024];
__device__ __align__(16) float g_bufBq[16 * 80 * 512];
__device__ __align__(16) float g_encS[16 * 2040 * 80];
__device__ __align__(16) float g_encQ[16 * 504 * 80];
__device__ unsigned g_gmax[32];
__device__ unsigned g_cnt[16];

// ---------------------------------------------------------------------------
// Weight prep
// ---------------------------------------------------------------------------
__global__ void prep_kernel(const float* __restrict__ w_wide,
                            const float* __restrict__ w_1x1,
                            const float* __restrict__ w_f0,
                            const float* __restrict__ w_f1,
                            const float* __restrict__ emb) {
    int g = blockIdx.x * blockDim.x + threadIdx.x;
    int stride = gridDim.x * blockDim.x;
    for (int idx = g; idx < 4 * 160 * 320; idx += stride) {
        float v = w_wide[idx];
        __nv_bfloat16 h = __float2bfloat16(v);
        g_wbh[idx] = h;
        g_wbl[idx] = __float2bfloat16(v - __bfloat162float(h));
    }
    for (int idx = g; idx < 4 * 80 * 128; idx += stride) {
        int l = idx / 10240, r = idx % 10240;
        int oc = r >> 7, k = r & 127;
        float v = (k < 80) ? w_1x1[l * 6400 + oc * 80 + k] : 0.f;
        __nv_bfloat16 h = __float2bfloat16(v);
        __nv_bfloat16 lo = __float2bfloat16(v - __bfloat162float(h));
        uint32_t off = (uint32_t)(((oc >> 3) + (k >> 6) * 10) * 1024 + (oc & 7) * 128 + (k & 63) * 2);
        uint32_t sw  = off ^ ((off >> 3) & 0x70);
        *(__nv_bfloat16*)(g_w1s[l][0] + sw) = h;
        *(__nv_bfloat16*)(g_w1s[l][1] + sw) = lo;
    }
    for (int idx = g; idx < 80 * 128; idx += stride) {
        int oc = idx >> 7, k = idx & 127;
        uint32_t off = (uint32_t)(((oc >> 3) + (k >> 6) * 10) * 1024 + (oc & 7) * 128 + (k & 63) * 2);
        uint32_t sw  = off ^ ((off >> 3) & 0x70);
        float v0 = (k < 80) ? w_f0[oc * 80 + k] : 0.f;
        float v1 = (k < 80) ? w_f1[oc * 80 + k] : 0.f;
        __nv_bfloat16 h0 = __float2bfloat16(v0);
        __nv_bfloat16 h1 = __float2bfloat16(v1);
        *(__nv_bfloat16*)(g_wf0s[0] + sw) = h0;
        *(__nv_bfloat16*)(g_wf0s[1] + sw) = __float2bfloat16(v0 - __bfloat162float(h0));
        *(__nv_bfloat16*)(g_wf1s[0] + sw) = h1;
        *(__nv_bfloat16*)(g_wf1s[1] + sw) = __float2bfloat16(v1 - __bfloat162float(h1));
    }
    for (int idx = g; idx < 512 * 128; idx += stride) {
        int kc = idx >> 7;
        int k  = idx & 127;
        int ch = kc >> 6, r = kc & 63;
        float v = (k < 80) ? emb[kc * 80 + k] : 0.f;
        __nv_bfloat16 h = __float2bfloat16(v);
        uint32_t off = (uint32_t)(((r >> 3) + (k >> 6) * 8) * 1024 + (r & 7) * 128 + (k & 63) * 2);
        uint32_t sw  = off ^ ((off >> 3) & 0x70);
        *(__nv_bfloat16*)(g_embs[0][ch] + sw) = h;
        *(__nv_bfloat16*)(g_embs[1][ch] + sw) = __float2bfloat16(v - __bfloat162float(h));
    }
    for (int idx = g; idx < 4 * 80 * 80; idx += stride) {
        int ic = idx % 80, oc = (idx / 80) % 80, l = idx / 6400;
        g_w1t[l * 6400 + ic * 80 + oc] = w_1x1[idx];
    }
    for (int idx = g; idx < 6400; idx += stride) {
        int ic = idx % 80, oc = idx / 80;
        g_wf0t[ic * 80 + oc] = w_f0[idx];
        g_wf1t[ic * 80 + oc] = w_f1[idx];
    }
    for (int k = g; k < 512; k += stride) {
        float s = 0.f;
        for (int c = 0; c < 80; c++) { float v = emb[k * 80 + c]; s += v * v; }
        g_e2[k] = s;
    }
    if (g < 32) g_gmax[g] = 0u;
    if (g < 16) g_cnt[g] = 0u;
}

// ---------------------------------------------------------------------------
// smem layout (1024-aligned base)
//   wide:    A0 @0 (32K: hi/lo), A1 @32K (32K), B @64K (hi 20K) / @84K (lo)
//   phase2:  A2_hi @0 (32K), A2_lo @32K, B2_hi @64K (20K), B2_lo @84K
// ---------------------------------------------------------------------------
#define WOFF_A(buf)  ((buf) * 32768)
#define WOFF_B_HI  65536
#define WOFF_B_LO  86016
#define OFF2_A_HI 0
#define OFF2_A_LO 32768
#define OFF2_B_HI 65536
#define OFF2_B_LO 86016
#define SMEM_DYN  (1024 + 106496)
// VQ: A_hi @0 (32K), A_lo @32K, B_hi @64K (16K), B_lo @80K
#define VQ_B_HI   65536
#define VQ_B_LO   81920
#define SMEM_VQ   (1024 + 98304)

#if HAS_TC
__device__ __forceinline__ void pack8(char* abp, int t, int g8, const float* v) {
    uint32_t ub[8]; float lo[8];
    #pragma unroll
    for (int i = 0; i < 8; i++) {
        ub[i] = __float_as_uint(v[i]);
        lo[i] = v[i] - __uint_as_float(ub[i] & 0xFFFF0000u);
    }
    uint4 hp, lp;
    hp.x = prmt_hi(ub[0], ub[1]); hp.y = prmt_hi(ub[2], ub[3]);
    hp.z = prmt_hi(ub[4], ub[5]); hp.w = prmt_hi(ub[6], ub[7]);
    lp.x = cvt_bf16x2(lo[1], lo[0]); lp.y = cvt_bf16x2(lo[3], lo[2]);
    lp.z = cvt_bf16x2(lo[5], lo[4]); lp.w = cvt_bf16x2(lo[7], lo[6]);
    uint32_t off = (uint32_t)(((t >> 3) + ((g8 >= 8) ? 16 : 0)) * 1024 + (t & 7) * 128 + (g8 & 7) * 16);
    uint32_t sw  = off ^ ((off >> 3) & 0x70);
    *(uint4*)(abp + OFF2_A_HI + sw) = hp;
    *(uint4*)(abp + OFF2_A_LO + sw) = lp;
}
__device__ __forceinline__ void copy_w2(char* abp, const char* hi, const char* lo, int tid) {
    if (tid >= 128) {
        for (int i = tid - 128; i < 1280; i += 192) {
            ((uint4*)(abp + OFF2_B_HI))[i] = __ldg((const uint4*)hi + i);
            ((uint4*)(abp + OFF2_B_LO))[i] = __ldg((const uint4*)lo + i);
        }
    }
}
__device__ __forceinline__ void issue_gemm2(uint32_t tmem_dst, uint32_t ab, uint32_t mbar) {
    u64 dAh = make_desc(ab + OFF2_A_HI), dAl = make_desc(ab + OFF2_A_LO);
    u64 dBh = make_desc(ab + OFF2_B_HI), dBl = make_desc(ab + OFF2_B_LO);
    u64 pA[3] = {dAh, dAh, dAl};
    u64 pB[3] = {dBh, dBl, dBh};
    #pragma unroll
    for (int p = 0; p < 3; p++) {
        #pragma unroll
        for (int s = 0; s < 5; s++) {
            uint32_t en = (p == 0 && s == 0) ? 0u : 1u;
            u64 ao = (s < 4) ? (u64)(2 * s) : 1024ull;
            u64 bo = (s < 4) ? (u64)(2 * s) : 640ull;
            mma_f16_ss(tmem_dst, pA[p] + ao, pB[p] + bo, IDESC_W, en);
        }
    }
    TCGEN05_COMMIT(mbar);
}
__device__ __forceinline__ void issue_gemmv(uint32_t tmem_dst, uint32_t ab, uint32_t mbar) {
    u64 dAh = make_desc(ab + OFF2_A_HI), dAl = make_desc(ab + OFF2_A_LO);
    u64 dBh = make_desc(ab + VQ_B_HI),  dBl = make_desc(ab + VQ_B_LO);
    u64 pA[3] = {dAh, dAh, dAl};
    u64 pB[3] = {dBh, dBl, dBh};
    #pragma unroll
    for (int p = 0; p < 3; p++) {
        #pragma unroll
        for (int s = 0; s < 5; s++) {
            uint32_t en = (p == 0 && s == 0) ? 0u : 1u;
            u64 ao = (s < 4) ? (u64)(2 * s) : 1024ull;
            u64 bo = (s < 4) ? (u64)(2 * s) : 512ull;
            mma_f16_ss(tmem_dst, pA[p] + ao, pB[p] + bo, IDESC_V, en);
        }
    }
    TCGEN05_COMMIT(mbar);
}
#endif

template <int S, bool FIRST, bool RESID, bool FUSEFINAL>
__global__ __launch_bounds__(320, 2) void gemm_layer_kernel(
    const float* __restrict__ xinS, const float* __restrict__ xinQ,
    float* __restrict__ xoutS, float* __restrict__ xoutQ,
    const __nv_bfloat16* __restrict__ wbh, const __nv_bfloat16* __restrict__ wbl,
    const float* __restrict__ bw,
    const char* __restrict__ w2h, const char* __restrict__ w2l,
    const float* __restrict__ w1t, const float* __restrict__ b1,
    const char* __restrict__ wf0h, const char* __restrict__ wf0l,
    const char* __restrict__ wf1h, const char* __restrict__ wf1l,
    const float* __restrict__ bf0, const float* __restrict__ bf1,
    int TinS, int TinLdS, int ToutS, int ToutLdS,
    int TinQ, int TinLdQ, int ToutQ, int ToutLdQ, int blocksS)
{
    extern __shared__ char dsm[];
    __shared__ float s_bias[400];

    const int tid = threadIdx.x;
    const int wid = tid >> 5;
    const int n   = blockIdx.y;
    const int bx  = blockIdx.x;

    const float* xin; float* xout; int Tin, TinLd, Tout, ToutLd, t0;
    if (bx < blocksS) {
        xin = xinS; xout = xoutS; Tin = TinS; TinLd = TinLdS;
        Tout = ToutS; ToutLd = ToutLdS; t0 = bx * 128;
    } else {
        xin = xinQ; xout = xoutQ; Tin = TinQ; TinLd = TinLdQ;
        Tout = ToutQ; ToutLd = ToutLdQ; t0 = (bx - blocksS) * 128;
    }
    const float* xin_n = xin + (size_t)n * 80 * TinLd;

    uint32_t base_raw = smem_u32(dsm);
    uint32_t ab = (base_raw + 1023u) & ~1023u;
    char* abp = dsm + (ab - base_raw);

    for (int i = tid; i < 400; i += 320) {
        float v = 0.f;
        if (i < 160) v = __ldg(bw + i);
        else if (i < 240) v = __ldg(b1 + i - 160);
        else if (FUSEFINAL && i < 320) v = __ldg(bf0 + i - 240);
        else if (FUSEFINAL) v = __ldg(bf1 + i - 320);
        s_bias[i] = v;
    }

#if HAS_TC
    __shared__ uint32_t s_tmem;
    __shared__ __align__(8) u64 s_mbar;

    if (tid == 0) MBARRIER_INIT(smem_u32(&s_mbar), 1);
    if (wid == 0) { TCGEN05_ALLOC(smem_u32(&s_tmem), 256); TCGEN05_RELINQ(); }
    __syncthreads();
    const uint32_t tmem = s_tmem;
    const uint32_t mbar = smem_u32(&s_mbar);

    // ---- staging helpers ----
    auto stage_A = [&](int kc, char* aBase) {
        const int k0 = kc * 64;
        #pragma unroll
        for (int r = 0; r < 4; r++) {
            int gi = r * 320 + tid;
            if (gi < 1024) {
                int t, g8;
                if (FIRST) { g8 = gi & 7; t = gi >> 3; }
                else       { t = gi & 127; g8 = gi >> 7; }
                int c0 = (k0 >> 2) + g8 * 2;
                int u0 = S * (t0 + t);
                float v[8];
                if (FIRST) {
                    #pragma unroll
                    for (int j = 0; j < 4; j++) {
                        int u = u0 + j;
                        if (u < Tin) {
                            float2 p = __ldg((const float2*)&xin_n[(size_t)u * 80 + c0]);
                            v[j] = p.x; v[4 + j] = p.y;
                        } else { v[j] = 0.f; v[4 + j] = 0.f; }
                    }
                } else {
                    const float* r0 = xin_n + (size_t)c0 * TinLd + u0;
                    #pragma unroll
                    for (int j = 0; j < 4; j++) {
                        bool ok = (u0 + j) < Tin;
                        v[j]     = ok ? __ldg(r0 + j)         : 0.f;
                        v[4 + j] = ok ? __ldg(r0 + TinLd + j) : 0.f;
                    }
                }
                uint32_t ub[8]; float lo[8];
                #pragma unroll
                for (int i = 0; i < 8; i++) {
                    ub[i] = __float_as_uint(v[i]);
                    lo[i] = v[i] - __uint_as_float(ub[i] & 0xFFFF0000u);
                }
                uint4 hp, lp;
                hp.x = prmt_hi(ub[0], ub[1]); hp.y = prmt_hi(ub[2], ub[3]);
                hp.z = prmt_hi(ub[4], ub[5]); hp.w = prmt_hi(ub[6], ub[7]);
                lp.x = cvt_bf16x2(lo[1], lo[0]); lp.y = cvt_bf16x2(lo[3], lo[2]);
                lp.z = cvt_bf16x2(lo[5], lo[4]); lp.w = cvt_bf16x2(lo[7], lo[6]);
                uint32_t off = (uint32_t)((t >> 3) * 1024 + (t & 7) * 128 + g8 * 16);
                uint32_t sw  = off ^ ((off >> 3) & 0x70);
                *(uint4*)(aBase + sw)         = hp;   // hi
                *(uint4*)(aBase + 16384 + sw) = lp;   // lo
            }
        }
    };
    auto stage_B = [&](int kc) {
        const uint4* srcH = (const uint4*)wbh;
        const uint4* srcL = (const uint4*)wbl;
        #pragma unroll
        for (int r = 0; r < 4; r++) {
            int gi = r * 320 + tid;
            int row = gi >> 3, g8 = gi & 7;
            int si  = row * 40 + (kc << 3) + g8;
            uint32_t off = (uint32_t)((row >> 3) * 1024 + (row & 7) * 128 + g8 * 16);
            uint32_t sw  = off ^ ((off >> 3) & 0x70);
            *(uint4*)(abp + WOFF_B_HI + sw) = __ldg(srcH + si);
            *(uint4*)(abp + WOFF_B_LO + sw) = __ldg(srcL + si);
        }
    };
    auto issue_wide = [&](int kc, uint32_t aAddr) {
        u64 dAh = make_desc(aAddr), dAl = make_desc(aAddr + 16384);
        u64 dBh = make_desc(ab + WOFF_B_HI), dBl = make_desc(ab + WOFF_B_LO);
        u64 pA[3] = {dAh, dAh, dAl};
        u64 pB[3] = {dBh, dBl, dBh};
        #pragma unroll
        for (int p = 0; p < 3; p++) {
            #pragma unroll
            for (int s = 0; s < 4; s++) {
                uint32_t en = (kc == 0 && p == 0 && s == 0) ? 0u : 1u;
                u64 ad = pA[p] + s * 2;
                mma_f16_ss(tmem,      ad, pB[p] + s * 2,       IDESC_W, en);
                mma_f16_ss(tmem + 80, ad, pB[p] + 640 + s * 2, IDESC_W, en);
            }
        }
        TCGEN05_COMMIT(mbar);
    };

    // ---- wide GEMM, A double-buffered: stage A(kc+1) overlaps MMA(kc) ----
    stage_A(0, abp + WOFF_A(0));
    stage_B(0);
    FENCE_ASYNC_SHARED();
    __syncthreads();
    if (wid == 0 && elect_one()) issue_wide(0, ab + WOFF_A(0));

    for (int kc = 1; kc < 5; kc++) {
        stage_A(kc, abp + WOFF_A(kc & 1));      // overlaps MMA(kc-1)
        MBAR_WAIT(mbar, (kc - 1) & 1);          // B buffer free
        stage_B(kc);
        FENCE_ASYNC_SHARED();
        __syncthreads();
        if (wid == 0 && elect_one()) issue_wide(kc, ab + WOFF_A(kc & 1));
    }
    MBAR_WAIT(mbar, 0);   // commit #4

    // ---- gate -> bf16 A2 (warps 0-3) ; W1 image copy (warps 4-9) ----
    if (tid < 128) {
        TCGEN05_FENCE_AFTER();
        const int t = tid;
        uint32_t da[32], dg[32];
        #pragma unroll
        for (int ch = 0; ch < 3; ch++) {
            int a0 = ch * 32;
            int w  = (ch == 2) ? 16 : 32;
            if (w == 32) { LDTM_X32(da, tmem + a0); LDTM_X32(dg, tmem + 80 + a0); }
            else         { LDTM_X16(da, tmem + a0); LDTM_X16(dg, tmem + 80 + a0); }
            TCGEN05_WAIT_LD();
            float gv[32];
            for (int i = 0; i < w; i++) {
                float a = __uint_as_float(da[i]) + s_bias[a0 + i];
                float g = __uint_as_float(dg[i]) + s_bias[80 + a0 + i];
                gv[i] = gatef(a, g);
            }
            #pragma unroll
            for (int q = 0; q < 4; q++) {
                if (q * 8 < w) pack8(abp, t, (a0 >> 3) + q, gv + q * 8);
            }
        }
    }
    copy_w2(abp, w2h, w2l, tid);
    FENCE_ASYNC_SHARED();
    __syncthreads();

    if (wid == 0 && elect_one()) issue_gemm2(tmem + 160, ab, mbar);
    MBAR_WAIT(mbar, 1);

    if (!FUSEFINAL) {
        if (tid < 128) {
            TCGEN05_FENCE_AFTER();
            const int t = tid;
            const bool tv = (t0 + t) < Tout;
            uint32_t d[32];
            #pragma unroll
            for (int ch = 0; ch < 3; ch++) {
                int a0 = ch * 32;
                int w  = (ch == 2) ? 16 : 32;
                if (w == 32) LDTM_X32(d, tmem + 160 + a0);
                else         LDTM_X16(d, tmem + 160 + a0);
                TCGEN05_WAIT_LD();
                if (tv) {
                    for (int i = 0; i < w; i++) {
                        int c = a0 + i;
                        float v = __uint_as_float(d[i]) + s_bias[160 + c];
                        if (RESID) v += __ldg(xin_n + (size_t)c * TinLd + S * (t0 + t) + 3);
                        xout[((size_t)n * 80 + c) * ToutLd + t0 + t] = v;
                    }
                }
            }
        }
        __syncthreads();
        if (wid == 0) TCGEN05_DEALLOC(tmem, 256);
    } else {
        if (tid < 128) {
            TCGEN05_FENCE_AFTER();
            const int t = tid;
            const bool tv = (t0 + t) < Tout;
            uint32_t d[32];
            #pragma unroll
            for (int ch = 0; ch < 3; ch++) {
                int a0 = ch * 32;
                int w  = (ch == 2) ? 16 : 32;
                if (w == 32) LDTM_X32(d, tmem + 160 + a0);
                else         LDTM_X16(d, tmem + 160 + a0);
                TCGEN05_WAIT_LD();
                float v[32];
                for (int i = 0; i < w; i++) {
                    int c = a0 + i;
                    v[i] = __uint_as_float(d[i]) + s_bias[160 + c];
                    if (RESID && tv) v[i] += __ldg(xin_n + (size_t)c * TinLd + S * (t0 + t) + 3);
                }
                #pragma unroll
                for (int q = 0; q < 4; q++)
                    if (q * 8 < w) pack8(abp, t, (a0 >> 3) + q, v + q * 8);
            }
        }
        copy_w2(abp, wf0h, wf0l, tid);
        FENCE_ASYNC_SHARED();
        __syncthreads();
        if (wid == 0 && elect_one()) issue_gemm2(tmem + 0, ab, mbar);
        MBAR_WAIT(mbar, 0);

        if (tid < 128) {
            TCGEN05_FENCE_AFTER();
            const int t = tid;
            uint32_t d[32];
            #pragma unroll
            for (int ch = 0; ch < 3; ch++) {
                int a0 = ch * 32;
                int w  = (ch == 2) ? 16 : 32;
                if (w == 32) LDTM_X32(d, tmem + a0);
                else         LDTM_X16(d, tmem + a0);
                TCGEN05_WAIT_LD();
                float v[32];
                for (int i = 0; i < w; i++)
                    v[i] = fmaxf(__uint_as_float(d[i]) + s_bias[240 + a0 + i], 0.f);
                #pragma unroll
                for (int q = 0; q < 4; q++)
                    if (q * 8 < w) pack8(abp, t, (a0 >> 3) + q, v + q * 8);
            }
        }
        copy_w2(abp, wf1h, wf1l, tid);
        FENCE_ASYNC_SHARED();
        __syncthreads();
        if (wid == 0 && elect_one()) issue_gemm2(tmem + 80, ab, mbar);
        MBAR_WAIT(mbar, 1);

        if (tid < 128) {
            TCGEN05_FENCE_AFTER();
            const int t = tid;
            const bool tv = (t0 + t) < Tout;
            uint32_t d[32];
            #pragma unroll
            for (int ch = 0; ch < 3; ch++) {
                int a0 = ch * 32;
                int w  = (ch == 2) ? 16 : 32;
                if (w == 32) LDTM_X32(d, tmem + 80 + a0);
                else         LDTM_X16(d, tmem + 80 + a0);
                TCGEN05_WAIT_LD();
                if (tv) {
                    float* dst = xout + ((size_t)n * Tout + t0 + t) * 80 + a0;
                    for (int i = 0; i < w; i += 4) {
                        float4 o;
                        o.x = __uint_as_float(d[i])     + s_bias[320 + a0 + i];
                        o.y = __uint_as_float(d[i + 1]) + s_bias[320 + a0 + i + 1];
                        o.z = __uint_as_float(d[i + 2]) + s_bias[320 + a0 + i + 2];
                        o.w = __uint_as_float(d[i + 3]) + s_bias[320 + a0 + i + 3];
                        *(float4*)(dst + i) = o;
                    }
                }
            }
        }
        __syncthreads();
        if (wid == 0) TCGEN05_DEALLOC(tmem, 256);
    }

#else  // ------- non-'a' PTX pass: safe scalar fallback (never runs on GB300) -------
    float* gsmF = (float*)(abp);
    float* bufF = (float*)(abp + 43008);
    __syncthreads();
    for (int e = tid; e < 80 * 128; e += 320) {
        int oc = e >> 7, tt = e & 127;
        float a = s_bias[oc], g = s_bias[oc + 80];
        for (int c = 0; c < 80; c++) {
            for (int j = 0; j < 4; j++) {
                int u = S * (t0 + tt) + j;
                float xv = (u < Tin)
                         ? (FIRST ? xin_n[(size_t)u * 80 + c]
                                  : xin_n[(size_t)c * TinLd + u]) : 0.f;
                float wa = __bfloat162float(wbh[oc * 320 + c * 4 + j])
                         + __bfloat162float(wbl[oc * 320 + c * 4 + j]);
                float wg = __bfloat162float(wbh[(oc + 80) * 320 + c * 4 + j])
                         + __bfloat162float(wbl[(oc + 80) * 320 + c * 4 + j]);
                a = fmaf(wa, xv, a);
                g = fmaf(wg, xv, g);
            }
        }
        gsmF[oc * 132 + tt] = gatef(a, g);
    }
    __syncthreads();
    for (int e = tid; e < 80 * 128; e += 320) {
        int oc = e >> 7, tt = e & 127;
        int t = t0 + tt;
        float s = s_bias[160 + oc];
        for (int ic = 0; ic < 80; ic++) s = fmaf(w1t[ic * 80 + oc], gsmF[ic * 132 + tt], s);
        if (RESID && t < Tout) s += xin_n[(size_t)oc * TinLd + S * t + 3];
        if (FUSEFINAL) bufF[oc * 132 + tt] = s;
        else if (t < Tout) xout[((size_t)n * 80 + oc) * ToutLd + t] = s;
    }
    if (FUSEFINAL) {
        __syncthreads();
        for (int e = tid; e < 80 * 128; e += 320) {
            int oc = e >> 7, tt = e & 127;
            float s = s_bias[240 + oc];
            for (int ic = 0; ic < 80; ic++) s = fmaf(g_wf0t[ic * 80 + oc], bufF[ic * 132 + tt], s);
            gsmF[oc * 132 + tt] = fmaxf(s, 0.f);
        }
        __syncthreads();
        for (int e = tid; e < 80 * 128; e += 320) {
            int oc = e >> 7, tt = e & 127;
            int t = t0 + tt;
            if (t < Tout) {
                float s = s_bias[320 + oc];
                for (int ic = 0; ic < 80; ic++) s = fmaf(g_wf1t[ic * 80 + oc], gsmF[ic * 132 + tt], s);
                xout[((size_t)n * Tout + t) * 80 + oc] = s;
            }
        }
    }
#endif // HAS_TC
}

// ---------------------------------------------------------------------------
// VQ v3 + fused finalize: tcgen05 GEMM X[128x80] x Emb^T + argmin + head + max
// ---------------------------------------------------------------------------
__device__ __forceinline__ unsigned fenc(float f) {
    unsigned u = __float_as_uint(f);
    return (u & 0x80000000u) ? ~u : (u | 0x80000000u);
}
__device__ __forceinline__ float fdec(unsigned e) {
    return (e & 0x80000000u) ? __uint_as_float(e ^ 0x80000000u)
                             : __uint_as_float(~e);
}

__global__ __launch_bounds__(512, 2) void vq_kernel(
    const float* __restrict__ encS,
    const float* __restrict__ encQ,
    const float* __restrict__ emb,
    const float* __restrict__ wlin,
    const float* __restrict__ blin,
    float* __restrict__ out)
{
    extern __shared__ char dsm[];
    __shared__ float se2[512];
    __shared__ float sdist[512];
    __shared__ int   sidx[512];
    __shared__ unsigned sm0, sm1;

    const int tid = threadIdx.x;
    const int wid = tid >> 5;
    const int n   = blockIdx.y;
    const int t0  = blockIdx.x * 128;

    if (tid == 0) { sm0 = 0u; sm1 = 0u; }
    se2[tid] = __ldg(&g_e2[tid]);

#if HAS_TC
    __shared__ uint32_t s_tmem;
    __shared__ __align__(8) u64 s_mbar;

    uint32_t base_raw = smem_u32(dsm);
    uint32_t ab = (base_raw + 1023u) & ~1023u;
    char* abp = dsm + (ab - base_raw);

    if (tid == 0) MBARRIER_INIT(smem_u32(&s_mbar), 1);
    if (wid == 0) { TCGEN05_ALLOC(smem_u32(&s_tmem), 256); TCGEN05_RELINQ(); }
    __syncthreads();
    const uint32_t tmem = s_tmem;
    const uint32_t mbar = smem_u32(&s_mbar);

    {
        const float4* src = (const float4*)(encS + (size_t)n * 2040 * 80);
        #pragma unroll
        for (int r = 0; r < 3; r++) {
            int gi = r * 512 + tid;
            if (gi < 1280) {
                int t = gi / 10, kg = gi % 10;
                int tg = t0 + t;
                float v[8] = {0.f, 0.f, 0.f, 0.f, 0.f, 0.f, 0.f, 0.f};
                if (tg < 2040) {
                    float4 a = __ldg(src + (size_t)tg * 20 + kg * 2);
                    float4 b = __ldg(src + (size_t)tg * 20 + kg * 2 + 1);
                    v[0] = a.x; v[1] = a.y; v[2] = a.z; v[3] = a.w;
                    v[4] = b.x; v[5] = b.y; v[6] = b.z; v[7] = b.w;
                }
                pack8(abp, t, kg, v);
            }
        }
    }

    const int sub  = wid & 3;
    const int quar = wid >> 2;
    const int t    = sub * 32 + (tid & 31);
    float best = 3.4e38f;
    int   bi   = 0;
    int   cnt  = 0;

    for (int grp = 0; grp < 2; grp++) {
        for (int ch = 0; ch < 4; ch++) {
            int cls = grp * 4 + ch;
            for (int i = tid; i < 1024; i += 512) {
                ((uint4*)(abp + VQ_B_HI))[i] = __ldg((const uint4*)(g_embs[0][cls]) + i);
                ((uint4*)(abp + VQ_B_LO))[i] = __ldg((const uint4*)(g_embs[1][cls]) + i);
            }
            FENCE_ASYNC_SHARED();
            __syncthreads();
            if (wid == 0 && elect_one()) issue_gemmv(tmem + ch * 64, ab, mbar);
            MBAR_WAIT(mbar, cnt & 1);
            cnt++;
        }
        TCGEN05_FENCE_AFTER();
        uint32_t d[32];
        #pragma unroll
        for (int cc = 0; cc < 2; cc++) {
            int c0 = quar * 64 + cc * 32;
            LDTM_X32(d, tmem + c0);
            TCGEN05_WAIT_LD();
            for (int i = 0; i < 32; i++) {
                int k = grp * 256 + c0 + i;
                float dd = se2[k] - 2.f * __uint_as_float(d[i]);
                if (dd < best) { best = dd; bi = k; }
            }
        }
        TCGEN05_FENCE_BEFORE();
        __syncthreads();
    }

    sdist[t * 4 + quar] = best;
    sidx [t * 4 + quar] = bi;
    __syncthreads();
    if (wid == 0) TCGEN05_DEALLOC(tmem, 256);

    if (tid < 128) {
        float bd = sdist[tid * 4];
        int  bbi = sidx [tid * 4];
        #pragma unroll
        for (int q = 1; q < 4; q++) {
            float dq = sdist[tid * 4 + q];
            int   iq = sidx [tid * 4 + q];
            if (dq < bd || (dq == bd && iq < bbi)) { bd = dq; bbi = iq; }
        }
        int tg2 = t0 + tid;
        if (tg2 < 2040) {
            const float* dv = emb + (size_t)bbi * 80;
            const float* qr = (tg2 < 2016)
                            ? (encQ + ((size_t)n * 504 + (tg2 % 504)) * 80)
                            : nullptr;
            float s0 = blin[0], s1 = blin[1];
            #pragma unroll 4
            for (int c = 0; c < 80; c++) {
                float v = dv[c] + (qr ? qr[c] : 0.f);
                s0 = fmaf(v, wlin[c],      s0);
                s1 = fmaf(v, wlin[80 + c], s1);
            }
            atomicMax(&sm0, fenc(tanhf(s0)));
            atomicMax(&sm1, fenc(tanhf(s1)));
        }
    }
    __syncthreads();
    if (tid == 0) {
        atomicMax(&g_gmax[n * 2 + 0], sm0);
        atomicMax(&g_gmax[n * 2 + 1], sm1);
        __threadfence();
        unsigned old = atomicAdd(&g_cnt[n], 1u);
        if (old == 15u) {   // last of 16 CTAs for this n: write output
            unsigned e0 = atomicMax(&g_gmax[n * 2 + 0], 0u);
            unsigned e1 = atomicMax(&g_gmax[n * 2 + 1], 0u);
            out[n * 2 + 0] = fdec(e0);
            out[n * 2 + 1] = fdec(e1);
        }
    }

#else  // ------- non-'a' PTX pass: safe scalar fallback (never runs on GB300) -------
    __syncthreads();
    if (tid < 128) {
        int tg2 = t0 + tid;
        if (tg2 < 2040) {
            const float* xr = encS + ((size_t)n * 2040 + tg2) * 80;
            float best = 3.4e38f; int bbi = 0;
            for (int k = 0; k < 512; k++) {
                float dot = 0.f;
                for (int c = 0; c < 80; c++) dot = fmaf(xr[c], emb[k * 80 + c], dot);
                float dd = se2[k] - 2.f * dot;
                if (dd < best) { best = dd; bbi = k; }
            }
            const float* dv = emb + (size_t)bbi * 80;
            const float* qr = (tg2 < 2016)
                            ? (encQ + ((size_t)n * 504 + (tg2 % 504)) * 80)
                            : nullptr;
            float s0 = blin[0], s1 = blin[1];
            for (int c = 0; c < 80; c++) {
                float v = dv[c] + (qr ? qr[c] : 0.f);
                s0 = fmaf(v, wlin[c],      s0);
                s1 = fmaf(v, wlin[80 + c], s1);
            }
            atomicMax(&sm0, fenc(tanhf(s0)));
            atomicMax(&sm1, fenc(tanhf(s1)));
        }
    }
    __syncthreads();
    if (tid == 0) {
        atomicMax(&g_gmax[n * 2 + 0], sm0);
        atomicMax(&g_gmax[n * 2 + 1], sm1);
        __threadfence();
        unsigned old = atomicAdd(&g_cnt[n], 1u);
        if (old == 15u) {
            unsigned e0 = atomicMax(&g_gmax[n * 2 + 0], 0u);
            unsigned e1 = atomicMax(&g_gmax[n * 2 + 1], 0u);
            out[n * 2 + 0] = fdec(e0);
            out[n * 2 + 1] = fdec(e1);
        }
    }
#endif
}

// ---------------------------------------------------------------------------
// Host launch
// ---------------------------------------------------------------------------
extern "C" void kernel_launch(void* const* d_in, const int* in_sizes, int n_in,
                              void* d_out, int out_size) {
    const float* search = (const float*)d_in[0];
    const float* query  = (const float*)d_in[1];
    const float* w_wide = (const float*)d_in[2];
    const float* b_wide = (const float*)d_in[3];
    const float* w_1x1  = (const float*)d_in[4];
    const float* b_1x1  = (const float*)d_in[5];
    const float* w_f0   = (const float*)d_in[6];
    const float* b_f0   = (const float*)d_in[7];
    const float* w_f1   = (const float*)d_in[8];
    const float* b_f1   = (const float*)d_in[9];
    const float* emb    = (const float*)d_in[10];
    const float* w_lin  = (const float*)d_in[11];
    const float* b_lin  = (const float*)d_in[12];
    float* out = (float*)d_out;

    void *pA, *pB, *pAq, *pBq, *pS, *pQ, *pwh, *pwl, *pw1, *pw1s, *pwf0s, *pwf1s;
    cudaGetSymbolAddress(&pA,   g_bufA);
    cudaGetSymbolAddress(&pB,   g_bufB);
    cudaGetSymbolAddress(&pAq,  g_bufAq);
    cudaGetSymbolAddress(&pBq,  g_bufBq);
    cudaGetSymbolAddress(&pS,   g_encS);
    cudaGetSymbolAddress(&pQ,   g_encQ);
    cudaGetSymbolAddress(&pwh,  g_wbh);
    cudaGetSymbolAddress(&pwl,  g_wbl);
    cudaGetSymbolAddress(&pw1,  g_w1t);
    cudaGetSymbolAddress(&pw1s, g_w1s);
    cudaGetSymbolAddress(&pwf0s, g_wf0s);
    cudaGetSymbolAddress(&pwf1s, g_wf1s);
    float* A   = (float*)pA;
    float* B   = (float*)pB;
    float* Aq  = (float*)pAq;
    float* Bq  = (float*)pBq;
    float* eS  = (float*)pS;
    float* eQ  = (float*)pQ;
    __nv_bfloat16* wbh = (__nv_bfloat16*)pwh;
    __nv_bfloat16* wbl = (__nv_bfloat16*)pwl;
    float* w1t = (float*)pw1;
    const char* w1s  = (const char*)pw1s;
    const char* wf0s = (const char*)pwf0s;
    const char* wf1s = (const char*)pwf1s;

    cudaFuncSetAttribute(gemm_layer_kernel<2, true,  false, false>,
                         cudaFuncAttributeMaxDynamicSharedMemorySize, SMEM_DYN);
    cudaFuncSetAttribute(gemm_layer_kernel<2, false, true,  false>,
                         cudaFuncAttributeMaxDynamicSharedMemorySize, SMEM_DYN);
    cudaFuncSetAttribute(gemm_layer_kernel<1, false, true,  false>,
                         cudaFuncAttributeMaxDynamicSharedMemorySize, SMEM_DYN);
    cudaFuncSetAttribute(gemm_layer_kernel<1, false, true,  true >,
                         cudaFuncAttributeMaxDynamicSharedMemorySize, SMEM_DYN);
    cudaFuncSetAttribute(vq_kernel,
                         cudaFuncAttributeMaxDynamicSharedMemorySize, SMEM_VQ);

    prep_kernel<<<80, 256>>>(w_wide, w_1x1, w_f0, w_f1, emb);

    #define W1S(l)  (w1s + (size_t)(l) * 2 * 20480)
    #define W1SL(l) (w1s + (size_t)(l) * 2 * 20480 + 20480)

    gemm_layer_kernel<2, true, false, false><<<dim3(40, NB), 320, SMEM_DYN>>>(
        search, query, A, Aq,
        wbh + 0 * 51200, wbl + 0 * 51200, b_wide + 0 * 160,
        W1S(0), W1SL(0), w1t + 0 * 6400, b_1x1 + 0 * 80,
        nullptr, nullptr, nullptr, nullptr, nullptr, nullptr,
        8192, 8192, 4095, 4096,  2048, 2048, 1023, 1024,  32);

    gemm_layer_kernel<2, false, true, false><<<dim3(20, NB), 320, SMEM_DYN>>>(
        A, Aq, B, Bq,
        wbh + 1 * 51200, wbl + 1 * 51200, b_wide + 1 * 160,
        W1S(1), W1SL(1), w1t + 1 * 6400, b_1x1 + 1 * 80,
        nullptr, nullptr, nullptr, nullptr, nullptr, nullptr,
        4095, 4096, 2046, 2048,  1023, 1024, 510, 512,  16);

    gemm_layer_kernel<1, false, true, false><<<dim3(20, NB), 320, SMEM_DYN>>>(
        B, Bq, A, Aq,
        wbh + 2 * 51200, wbl + 2 * 51200, b_wide + 2 * 160,
        W1S(2), W1SL(2), w1t + 2 * 6400, b_1x1 + 2 * 80,
        nullptr, nullptr, nullptr, nullptr, nullptr, nullptr,
        2046, 2048, 2043, 2044,  510, 512, 507, 508,  16);

    gemm_layer_kernel<1, false, true, true><<<dim3(20, NB), 320, SMEM_DYN>>>(
        A, Aq, eS, eQ,
        wbh + 3 * 51200, wbl + 3 * 51200, b_wide + 3 * 160,
        W1S(3), W1SL(3), w1t + 3 * 6400, b_1x1 + 3 * 80,
        wf0s, wf0s + 20480, wf1s, wf1s + 20480, b_f0, b_f1,
        2043, 2044, 2040, 2040,  507, 508, 504, 504,  16);

    vq_kernel<<<dim3(16, NB), 512, SMEM_VQ>>>(eS, eQ, emb, w_lin, b_lin, out);
}

// round 14
// speedup vs baseline: 4.6673x; 1.0350x over previous
#include <cuda_runtime.h>
#include <cuda_bf16.h>
#include <cstdint>

#define NB 16
typedef unsigned long long u64;

#if defined(__CUDA_ARCH_FEAT_SM103_ALL) || defined(__CUDA_ARCH_FEAT_SM100_ALL) || \
    (defined(__CUDA_ARCH_SPECIFIC__) && (__CUDA_ARCH_SPECIFIC__ >= 1000))
#define HAS_TC 1
#else
#define HAS_TC 0
#endif

// ---------------------------------------------------------------------------
// PTX helpers
// ---------------------------------------------------------------------------
__device__ __forceinline__ uint32_t smem_u32(const void* p) {
    uint32_t a;
    asm("{ .reg .u64 t; cvta.to.shared.u64 t, %1; cvt.u32.u64 %0, t; }" : "=r"(a) : "l"(p));
    return a;
}
__device__ __forceinline__ float ex2f(float x) {
    float r; asm("ex2.approx.f32 %0, %1;" : "=f"(r) : "f"(x)); return r;
}
__device__ __forceinline__ float rcpf(float x) {
    float r; asm("rcp.approx.f32 %0, %1;" : "=f"(r) : "f"(x)); return r;
}
__device__ __forceinline__ uint32_t prmt_hi(uint32_t a, uint32_t b) {
    uint32_t r; asm("prmt.b32 %0, %1, %2, 0x7632;" : "=r"(r) : "r"(a), "r"(b)); return r;
}
__device__ __forceinline__ uint32_t cvt_bf16x2(float hi, float lo) {
    uint32_t r; asm("cvt.rn.bf16x2.f32 %0, %1, %2;" : "=r"(r) : "f"(hi), "f"(lo)); return r;
}
__device__ __forceinline__ float gatef(float a, float g) {
    float e1 = ex2f(fminf(a * -2.885390082f, 80.f));
    float e2 = ex2f(fminf(g * -1.442695041f, 80.f));
    float r  = rcpf((1.f + e1) * (1.f + e2));
    return (1.f - e1) * r;
}

#if HAS_TC
__device__ __forceinline__ uint32_t elect_one() {
    uint32_t p;
    asm volatile("{\n\t.reg .pred p;\n\telect.sync _|p, 0xFFFFFFFF;\n\tselp.b32 %0, 1, 0, p;\n\t}" : "=r"(p));
    return p;
}

#define TCGEN05_ALLOC(sm, n) \
    asm volatile("tcgen05.alloc.cta_group::1.sync.aligned.shared::cta.b32 [%0], %1;" \
                 :: "r"((uint32_t)(sm)), "r"((uint32_t)(n)) : "memory")
#define TCGEN05_RELINQ() \
    asm volatile("tcgen05.relinquish_alloc_permit.cta_group::1.sync.aligned;")
#define TCGEN05_DEALLOC(t, n) \
    asm volatile("tcgen05.dealloc.cta_group::1.sync.aligned.b32 %0, %1;" :: "r"(t), "r"((uint32_t)(n)))
#define TCGEN05_COMMIT(mb) \
    asm volatile("tcgen05.commit.cta_group::1.mbarrier::arrive::one.shared::cluster.b64 [%0];" \
                 :: "r"((uint32_t)(mb)) : "memory")
#define TCGEN05_FENCE_AFTER()  asm volatile("tcgen05.fence::after_thread_sync;" ::: "memory")
#define TCGEN05_FENCE_BEFORE() asm volatile("tcgen05.fence::before_thread_sync;" ::: "memory")
#define TCGEN05_WAIT_LD()      asm volatile("tcgen05.wait::ld.sync.aligned;" ::: "memory")
#define FENCE_ASYNC_SHARED()   asm volatile("fence.proxy.async.shared::cta;" ::: "memory")
#define MBARRIER_INIT(mb, c) \
    asm volatile("mbarrier.init.shared.b64 [%0], %1;" :: "r"((uint32_t)(mb)), "r"((uint32_t)(c)) : "memory")

#define MBAR_WAIT(mb, ph) do {                                                  \
    uint32_t _m = (uint32_t)(mb), _p = (uint32_t)(ph), _d;                      \
    asm volatile("{\n\t.reg .pred p;\n\t"                                       \
        "mbarrier.try_wait.parity.acquire.cta.shared::cta.b64 p, [%1], %2;\n\t" \
        "selp.b32 %0, 1, 0, p;\n\t}" : "=r"(_d) : "r"(_m), "r"(_p) : "memory"); \
    if (!_d) {                                                                  \
        asm volatile("{\n\t.reg .pred P1;\n\t"                                  \
            "WL_%=:\n\t"                                                        \
            "mbarrier.try_wait.parity.acquire.cta.shared::cta.b64 P1, [%0], %1, 0x989680;\n\t" \
            "@P1 bra.uni WD_%=;\n\t"                                            \
            "bra.uni WL_%=;\n\t"                                                \
            "WD_%=:\n\t}" :: "r"(_m), "r"(_p) : "memory");                      \
    }                                                                           \
} while (0)

#define LDTM_X32(r, a) \
    asm volatile("tcgen05.ld.sync.aligned.32x32b.x32.b32 " \
        "{%0,%1,%2,%3,%4,%5,%6,%7,%8,%9,%10,%11,%12,%13,%14,%15," \
        "%16,%17,%18,%19,%20,%21,%22,%23,%24,%25,%26,%27,%28,%29,%30,%31}, [%32];" \
        : "=r"((r)[0]),"=r"((r)[1]),"=r"((r)[2]),"=r"((r)[3]),"=r"((r)[4]),"=r"((r)[5]),"=r"((r)[6]),"=r"((r)[7]), \
          "=r"((r)[8]),"=r"((r)[9]),"=r"((r)[10]),"=r"((r)[11]),"=r"((r)[12]),"=r"((r)[13]),"=r"((r)[14]),"=r"((r)[15]), \
          "=r"((r)[16]),"=r"((r)[17]),"=r"((r)[18]),"=r"((r)[19]),"=r"((r)[20]),"=r"((r)[21]),"=r"((r)[22]),"=r"((r)[23]), \
          "=r"((r)[24]),"=r"((r)[25]),"=r"((r)[26]),"=r"((r)[27]),"=r"((r)[28]),"=r"((r)[29]),"=r"((r)[30]),"=r"((r)[31]) \
        : "r"(a))

#define LDTM_X16(r, a) \
    asm volatile("tcgen05.ld.sync.aligned.32x32b.x16.b32 " \
        "{%0,%1,%2,%3,%4,%5,%6,%7,%8,%9,%10,%11,%12,%13,%14,%15}, [%16];" \
        : "=r"((r)[0]),"=r"((r)[1]),"=r"((r)[2]),"=r"((r)[3]),"=r"((r)[4]),"=r"((r)[5]),"=r"((r)[6]),"=r"((r)[7]), \
          "=r"((r)[8]),"=r"((r)[9]),"=r"((r)[10]),"=r"((r)[11]),"=r"((r)[12]),"=r"((r)[13]),"=r"((r)[14]),"=r"((r)[15]) \
        : "r"(a))

__device__ __forceinline__ void mma_f16_ss(uint32_t d, u64 ad, u64 bd, uint32_t idesc, uint32_t en) {
    asm volatile("{\n\t.reg .pred p;\n\tsetp.ne.u32 p, %5, 0;\n\t"
        "tcgen05.mma.cta_group::1.kind::f16 [%0], %1, %2, %3, {%4,%4,%4,%4}, p;\n\t}"
        :: "r"(d), "l"(ad), "l"(bd), "r"(idesc), "r"(0u), "r"(en) : "memory");
}

static __device__ __forceinline__ u64 make_desc(uint32_t addr) {
    return (u64(2) << 61) | (u64(1) << 46) | (u64(64) << 32) | (u64(1) << 16)
         | ((u64)(addr >> 4) & 0x3FFF);
}

#define IDESC_W ((1u<<4) | (1u<<7) | (1u<<10) | (10u<<17) | (8u<<24))
#define IDESC_V ((1u<<4) | (1u<<7) | (1u<<10) | (8u<<17)  | (8u<<24))
#endif // HAS_TC

// ---------------------------------------------------------------------------
// Device scratch
// ---------------------------------------------------------------------------
__device__ __align__(16) __nv_bfloat16 g_wbh[4 * 160 * 320];
__device__ __align__(16) __nv_bfloat16 g_wbl[4 * 160 * 320];
__device__ __align__(16) char g_w1s [4][2][20480];
__device__ __align__(16) char g_wf0s[2][20480];
__device__ __align__(16) char g_wf1s[2][20480];
__device__ __align__(16) char g_embs[2][8][16384];
__device__ __align__(16) float g_w1t [4 * 80 * 80];
__device__ __align__(16) float g_wf0t[80 * 80];
__device__ __align__(16) float g_wf1t[80 * 80];
__device__ __align__(16) float g_e2  [512];
__device__ __align__(16) float g_bufA [16 * 80 * 4096];   // L0 out AND L2 out (both ld 4096)
__device__ __align__(16) float g_bufB [16 * 80 * 2048];
__device__ __align__(16) float g_bufAq[16 * 80 * 1024];   // L0/L2 Q out (ld 1024)
__device__ __align__(16) float g_bufBq[16 * 80 * 512];
__device__ __align__(16) float g_encS[16 * 2040 * 80];
__device__ __align__(16) float g_encQ[16 * 504 * 80];
__device__ unsigned g_gmax[32];
__device__ unsigned g_cnt[16];
__device__ unsigned g_ticket;
__device__ unsigned g_done[4][16];   // per (layer, n) tile completion counters

// ---------------------------------------------------------------------------
// Weight prep (+ scheduler state reset)
// ---------------------------------------------------------------------------
__global__ void prep_kernel(const float* __restrict__ w_wide,
                            const float* __restrict__ w_1x1,
                            const float* __restrict__ w_f0,
                            const float* __restrict__ w_f1,
                            const float* __restrict__ emb) {
    int g = blockIdx.x * blockDim.x + threadIdx.x;
    int stride = gridDim.x * blockDim.x;
    for (int idx = g; idx < 4 * 160 * 320; idx += stride) {
        float v = w_wide[idx];
        __nv_bfloat16 h = __float2bfloat16(v);
        g_wbh[idx] = h;
        g_wbl[idx] = __float2bfloat16(v - __bfloat162float(h));
    }
    for (int idx = g; idx < 4 * 80 * 128; idx += stride) {
        int l = idx / 10240, r = idx % 10240;
        int oc = r >> 7, k = r & 127;
        float v = (k < 80) ? w_1x1[l * 6400 + oc * 80 + k] : 0.f;
        __nv_bfloat16 h = __float2bfloat16(v);
        __nv_bfloat16 lo = __float2bfloat16(v - __bfloat162float(h));
        uint32_t off = (uint32_t)(((oc >> 3) + (k >> 6) * 10) * 1024 + (oc & 7) * 128 + (k & 63) * 2);
        uint32_t sw  = off ^ ((off >> 3) & 0x70);
        *(__nv_bfloat16*)(g_w1s[l][0] + sw) = h;
        *(__nv_bfloat16*)(g_w1s[l][1] + sw) = lo;
    }
    for (int idx = g; idx < 80 * 128; idx += stride) {
        int oc = idx >> 7, k = idx & 127;
        uint32_t off = (uint32_t)(((oc >> 3) + (k >> 6) * 10) * 1024 + (oc & 7) * 128 + (k & 63) * 2);
        uint32_t sw  = off ^ ((off >> 3) & 0x70);
        float v0 = (k < 80) ? w_f0[oc * 80 + k] : 0.f;
        float v1 = (k < 80) ? w_f1[oc * 80 + k] : 0.f;
        __nv_bfloat16 h0 = __float2bfloat16(v0);
        __nv_bfloat16 h1 = __float2bfloat16(v1);
        *(__nv_bfloat16*)(g_wf0s[0] + sw) = h0;
        *(__nv_bfloat16*)(g_wf0s[1] + sw) = __float2bfloat16(v0 - __bfloat162float(h0));
        *(__nv_bfloat16*)(g_wf1s[0] + sw) = h1;
        *(__nv_bfloat16*)(g_wf1s[1] + sw) = __float2bfloat16(v1 - __bfloat162float(h1));
    }
    for (int idx = g; idx < 512 * 128; idx += stride) {
        int kc = idx >> 7;
        int k  = idx & 127;
        int ch = kc >> 6, r = kc & 63;
        float v = (k < 80) ? emb[kc * 80 + k] : 0.f;
        __nv_bfloat16 h = __float2bfloat16(v);
        uint32_t off = (uint32_t)(((r >> 3) + (k >> 6) * 8) * 1024 + (r & 7) * 128 + (k & 63) * 2);
        uint32_t sw  = off ^ ((off >> 3) & 0x70);
        *(__nv_bfloat16*)(g_embs[0][ch] + sw) = h;
        *(__nv_bfloat16*)(g_embs[1][ch] + sw) = __float2bfloat16(v - __bfloat162float(h));
    }
    for (int idx = g; idx < 4 * 80 * 80; idx += stride) {
        int ic = idx % 80, oc = (idx / 80) % 80, l = idx / 6400;
        g_w1t[l * 6400 + ic * 80 + oc] = w_1x1[idx];
    }
    for (int idx = g; idx < 6400; idx += stride) {
        int ic = idx % 80, oc = idx / 80;
        g_wf0t[ic * 80 + oc] = w_f0[idx];
        g_wf1t[ic * 80 + oc] = w_f1[idx];
    }
    for (int k = g; k < 512; k += stride) {
        float s = 0.f;
        for (int c = 0; c < 80; c++) { float v = emb[k * 80 + c]; s += v * v; }
        g_e2[k] = s;
    }
    if (g < 32) g_gmax[g] = 0u;
    if (g < 16) g_cnt[g] = 0u;
    if (g < 64) ((unsigned*)g_done)[g] = 0u;
    if (g == 64) g_ticket = 0u;
}

// ---------------------------------------------------------------------------
// smem layout (1024-aligned base)
//   wide:   A_hi @0, A_lo @16K, B_hi @32K (20K), B_lo @52K  (end 72K)
//   phase2: A2_hi @0 (32K), A2_lo @32K, B2_hi @64K (20K), B2_lo @84K (end 104K)
//   VQ:     A2 @0..64K, B_hi @64K (16K), B_lo @80K (end 96K)
// ---------------------------------------------------------------------------
#define OFF_A_HI  0
#define OFF_A_LO  16384
#define OFF_B_HI  32768
#define OFF_B_LO  53248
#define OFF2_A_HI 0
#define OFF2_A_LO 32768
#define OFF2_B_HI 65536
#define OFF2_B_LO 86016
#define VQ_B_HI   65536
#define VQ_B_LO   81920
#define SMEM_DYN  (1024 + 106496)

#define N_TICKETS 1856

#if HAS_TC
__device__ __forceinline__ void pack8(char* abp, int t, int g8, const float* v) {
    uint32_t ub[8]; float lo[8];
    #pragma unroll
    for (int i = 0; i < 8; i++) {
        ub[i] = __float_as_uint(v[i]);
        lo[i] = v[i] - __uint_as_float(ub[i] & 0xFFFF0000u);
    }
    uint4 hp, lp;
    hp.x = prmt_hi(ub[0], ub[1]); hp.y = prmt_hi(ub[2], ub[3]);
    hp.z = prmt_hi(ub[4], ub[5]); hp.w = prmt_hi(ub[6], ub[7]);
    lp.x = cvt_bf16x2(lo[1], lo[0]); lp.y = cvt_bf16x2(lo[3], lo[2]);
    lp.z = cvt_bf16x2(lo[5], lo[4]); lp.w = cvt_bf16x2(lo[7], lo[6]);
    uint32_t off = (uint32_t)(((t >> 3) + ((g8 >= 8) ? 16 : 0)) * 1024 + (t & 7) * 128 + (g8 & 7) * 16);
    uint32_t sw  = off ^ ((off >> 3) & 0x70);
    *(uint4*)(abp + OFF2_A_HI + sw) = hp;
    *(uint4*)(abp + OFF2_A_LO + sw) = lp;
}
__device__ __forceinline__ void copy_w2(char* abp, const char* hi, const char* lo, int tid) {
    if (tid >= 128) {
        for (int i = tid - 128; i < 1280; i += 192) {
            ((uint4*)(abp + OFF2_B_HI))[i] = __ldg((const uint4*)hi + i);
            ((uint4*)(abp + OFF2_B_LO))[i] = __ldg((const uint4*)lo + i);
        }
    }
}
__device__ __forceinline__ void issue_gemm2(uint32_t tmem_dst, uint32_t ab, uint32_t mbar) {
    u64 dAh = make_desc(ab + OFF2_A_HI), dAl = make_desc(ab + OFF2_A_LO);
    u64 dBh = make_desc(ab + OFF2_B_HI), dBl = make_desc(ab + OFF2_B_LO);
    u64 pA[3] = {dAh, dAh, dAl};
    u64 pB[3] = {dBh, dBl, dBh};
    #pragma unroll
    for (int p = 0; p < 3; p++) {
        #pragma unroll
        for (int s = 0; s < 5; s++) {
            uint32_t en = (p == 0 && s == 0) ? 0u : 1u;
            u64 ao = (s < 4) ? (u64)(2 * s) : 1024ull;
            u64 bo = (s < 4) ? (u64)(2 * s) : 640ull;
            mma_f16_ss(tmem_dst, pA[p] + ao, pB[p] + bo, IDESC_W, en);
        }
    }
    TCGEN05_COMMIT(mbar);
}
__device__ __forceinline__ void issue_gemmv(uint32_t tmem_dst, uint32_t ab, uint32_t mbar) {
    u64 dAh = make_desc(ab + OFF2_A_HI), dAl = make_desc(ab + OFF2_A_LO);
    u64 dBh = make_desc(ab + VQ_B_HI),  dBl = make_desc(ab + VQ_B_LO);
    u64 pA[3] = {dAh, dAh, dAl};
    u64 pB[3] = {dBh, dBl, dBh};
    #pragma unroll
    for (int p = 0; p < 3; p++) {
        #pragma unroll
        for (int s = 0; s < 5; s++) {
            uint32_t en = (p == 0 && s == 0) ? 0u : 1u;
            u64 ao = (s < 4) ? (u64)(2 * s) : 1024ull;
            u64 bo = (s < 4) ? (u64)(2 * s) : 512ull;
            mma_f16_ss(tmem_dst, pA[p] + ao, pB[p] + bo, IDESC_V, en);
        }
    }
    TCGEN05_COMMIT(mbar);
}
#endif

__device__ __forceinline__ unsigned fenc(float f) {
    unsigned u = __float_as_uint(f);
    return (u & 0x80000000u) ? ~u : (u | 0x80000000u);
}
__device__ __forceinline__ float fdec(unsigned e) {
    return (e & 0x80000000u) ? __uint_as_float(e ^ 0x80000000u)
                             : __uint_as_float(~e);
}

// ---------------------------------------------------------------------------
// Persistent mega-kernel: ordered-ticket scheduler over 1856 tiles
//   tickets [0,640):   layer 0 (n-major, 40 tiles/n: 32 S + 8 Q)
//   [640,960):         layer 1 (20/n: 16 S + 4 Q)
//   [960,1280):        layer 2
//   [1280,1600):       layer 3 (+ fused final convs)
//   [1600,1856):       VQ (16/n)
// ---------------------------------------------------------------------------
__global__ __launch_bounds__(320, 2) void mega_kernel(
    const float* __restrict__ search, const float* __restrict__ query,
    float* __restrict__ A, float* __restrict__ Aq,
    float* __restrict__ B, float* __restrict__ Bq,
    float* __restrict__ eS, float* __restrict__ eQ,
    const __nv_bfloat16* __restrict__ wbh0, const __nv_bfloat16* __restrict__ wbl0,
    const float* __restrict__ b_wide, const float* __restrict__ b_1x1,
    const char* __restrict__ w1s,
    const char* __restrict__ wf0s, const char* __restrict__ wf1s,
    const float* __restrict__ bf0g, const float* __restrict__ bf1g,
    const float* __restrict__ emb, const float* __restrict__ wlin,
    const float* __restrict__ blin, float* __restrict__ out)
{
    extern __shared__ char dsm[];
    __shared__ float s_bias[400];
    __shared__ unsigned s_tk;
    __shared__ float se2[512];
    __shared__ float sdist[256];
    __shared__ int   sidx[256];
    __shared__ unsigned sm0, sm1;

    const int tid = threadIdx.x;
    const int wid = tid >> 5;
    uint32_t base_raw = smem_u32(dsm);
    uint32_t ab = (base_raw + 1023u) & ~1023u;
    char* abp = dsm + (ab - base_raw);

    for (int i = tid; i < 512; i += 320) se2[i] = __ldg(&g_e2[i]);

#if HAS_TC
    __shared__ uint32_t s_tmem;
    __shared__ __align__(8) u64 s_mbar;
    if (tid == 0) MBARRIER_INIT(smem_u32(&s_mbar), 1);
    if (wid == 0) { TCGEN05_ALLOC(smem_u32(&s_tmem), 256); TCGEN05_RELINQ(); }
    __syncthreads();
    const uint32_t tmem = s_tmem;
    const uint32_t mbar = smem_u32(&s_mbar);
#else
    __syncthreads();
#endif
    int mph = 0;
    (void)mph;

    while (true) {
        if (tid == 0) s_tk = atomicAdd(&g_ticket, 1u);
        __syncthreads();
        const unsigned tk = s_tk;
        if (tk >= N_TICKETS) break;

        if (tk < 1600) {
            // ================= layer tile =================
            int l, loc;
            if (tk < 640) { l = 0; loc = (int)tk; }
            else { l = 1 + (int)(tk - 640) / 320; loc = (int)(tk - 640) % 320; }
            const int tilesN = (l == 0) ? 40 : 20;
            const int n = loc / tilesN, idx = loc % tilesN;
            const int blocksS = (l == 0) ? 32 : 16;

            // dependency: previous layer slice n complete
            if (l > 0) {
                const unsigned need = (l == 1) ? 40u : 20u;
                if (tid == 0) {
                    while (atomicAdd(&g_done[l - 1][n], 0u) < need) __nanosleep(200);
                    __threadfence();
                }
                __syncthreads();
            }

            // per-layer dims / pointers
            const int cS[4]       = {2, 2, 1, 1};
            const int cTinS[4]    = {8192, 4095, 2046, 2043};
            const int cTinLdS[4]  = {8192, 4096, 2048, 4096};
            const int cToutS[4]   = {4095, 2046, 2043, 2040};
            const int cToutLdS[4] = {4096, 2048, 4096, 2040};
            const int cTinQ[4]    = {2048, 1023, 510, 507};
            const int cTinLdQ[4]  = {2048, 1024, 512, 1024};
            const int cToutQ[4]   = {1023, 510, 507, 504};
            const int cToutLdQ[4] = {1024, 512, 1024, 504};

            const bool FIRST = (l == 0);
            const bool RESID = (l > 0);
            const bool FUSE  = (l == 3);
            const int  S     = cS[l];

            const float *xinS_, *xinQ_; float *xoutS_, *xoutQ_;
            switch (l) {
                case 0:  xinS_ = search; xinQ_ = query; xoutS_ = A;  xoutQ_ = Aq; break;
                case 1:  xinS_ = A;      xinQ_ = Aq;    xoutS_ = B;  xoutQ_ = Bq; break;
                case 2:  xinS_ = B;      xinQ_ = Bq;    xoutS_ = A;  xoutQ_ = Aq; break;
                default: xinS_ = A;      xinQ_ = Aq;    xoutS_ = eS; xoutQ_ = eQ; break;
            }
            const float* xin; float* xout; int Tin, TinLd, Tout, ToutLd, t0;
            if (idx < blocksS) {
                xin = xinS_; xout = xoutS_; Tin = cTinS[l]; TinLd = cTinLdS[l];
                Tout = cToutS[l]; ToutLd = cToutLdS[l]; t0 = idx * 128;
            } else {
                xin = xinQ_; xout = xoutQ_; Tin = cTinQ[l]; TinLd = cTinLdQ[l];
                Tout = cToutQ[l]; ToutLd = cToutLdQ[l]; t0 = (idx - blocksS) * 128;
            }
            const float* xin_n = xin + (size_t)n * 80 * TinLd;
            const __nv_bfloat16* wbh = wbh0 + l * 51200;
            const __nv_bfloat16* wbl = wbl0 + l * 51200;
            const float* bw = b_wide + l * 160;
            const float* b1 = b_1x1 + l * 80;
            const char* w2h = w1s + (size_t)l * 2 * 20480;
            const char* w2l = w2h + 20480;

            for (int i = tid; i < 400; i += 320) {
                float v = 0.f;
                if (i < 160) v = __ldg(bw + i);
                else if (i < 240) v = __ldg(b1 + i - 160);
                else if (FUSE && i < 320) v = __ldg(bf0g + i - 240);
                else if (FUSE) v = __ldg(bf1g + i - 320);
                s_bias[i] = v;
            }

#if HAS_TC
            // ---- wide GEMM: 5 K-chunks of 64 -> tmem cols 0..159 ----
            for (int kc = 0; kc < 5; kc++) {
                if (kc > 0) { MBAR_WAIT(mbar, mph); mph ^= 1; }
                const int k0 = kc * 64;
                // stage A (im2col, hi/lo trunc split)
                for (int gi = tid; gi < 1024; gi += 320) {
                    int t, g8;
                    if (FIRST) { g8 = gi & 7; t = gi >> 3; }
                    else       { t = gi & 127; g8 = gi >> 7; }
                    int c0 = (k0 >> 2) + g8 * 2;
                    int u0 = S * (t0 + t);
                    float v[8];
                    if (FIRST) {
                        #pragma unroll
                        for (int j = 0; j < 4; j++) {
                            int u = u0 + j;
                            if (u < Tin) {
                                float2 p = __ldg((const float2*)&xin_n[(size_t)u * 80 + c0]);
                                v[j] = p.x; v[4 + j] = p.y;
                            } else { v[j] = 0.f; v[4 + j] = 0.f; }
                        }
                    } else {
                        const float* r0 = xin_n + (size_t)c0 * TinLd + u0;
                        #pragma unroll
                        for (int j = 0; j < 4; j++) {
                            bool ok = (u0 + j) < Tin;
                            v[j]     = ok ? __ldg(r0 + j)         : 0.f;
                            v[4 + j] = ok ? __ldg(r0 + TinLd + j) : 0.f;
                        }
                    }
                    uint32_t ub[8]; float lo[8];
                    #pragma unroll
                    for (int i = 0; i < 8; i++) {
                        ub[i] = __float_as_uint(v[i]);
                        lo[i] = v[i] - __uint_as_float(ub[i] & 0xFFFF0000u);
                    }
                    uint4 hp, lp;
                    hp.x = prmt_hi(ub[0], ub[1]); hp.y = prmt_hi(ub[2], ub[3]);
                    hp.z = prmt_hi(ub[4], ub[5]); hp.w = prmt_hi(ub[6], ub[7]);
                    lp.x = cvt_bf16x2(lo[1], lo[0]); lp.y = cvt_bf16x2(lo[3], lo[2]);
                    lp.z = cvt_bf16x2(lo[5], lo[4]); lp.w = cvt_bf16x2(lo[7], lo[6]);
                    uint32_t off = (uint32_t)((t >> 3) * 1024 + (t & 7) * 128 + g8 * 16);
                    uint32_t sw  = off ^ ((off >> 3) & 0x70);
                    *(uint4*)(abp + OFF_A_HI + sw) = hp;
                    *(uint4*)(abp + OFF_A_LO + sw) = lp;
                }
                // stage B (weights)
                {
                    const uint4* srcH = (const uint4*)wbh;
                    const uint4* srcL = (const uint4*)wbl;
                    #pragma unroll
                    for (int r = 0; r < 4; r++) {
                        int gi = r * 320 + tid;
                        int row = gi >> 3, g8 = gi & 7;
                        int si  = row * 40 + (kc << 3) + g8;
                        uint32_t off = (uint32_t)((row >> 3) * 1024 + (row & 7) * 128 + g8 * 16);
                        uint32_t sw  = off ^ ((off >> 3) & 0x70);
                        *(uint4*)(abp + OFF_B_HI + sw) = __ldg(srcH + si);
                        *(uint4*)(abp + OFF_B_LO + sw) = __ldg(srcL + si);
                    }
                }
                FENCE_ASYNC_SHARED();
                __syncthreads();
                if (wid == 0 && elect_one()) {
                    u64 dAh = make_desc(ab + OFF_A_HI), dAl = make_desc(ab + OFF_A_LO);
                    u64 dBh = make_desc(ab + OFF_B_HI), dBl = make_desc(ab + OFF_B_LO);
                    u64 pA[3] = {dAh, dAh, dAl};
                    u64 pB[3] = {dBh, dBl, dBh};
                    #pragma unroll
                    for (int p = 0; p < 3; p++) {
                        #pragma unroll
                        for (int s = 0; s < 4; s++) {
                            uint32_t en = (kc == 0 && p == 0 && s == 0) ? 0u : 1u;
                            u64 ad = pA[p] + s * 2;
                            mma_f16_ss(tmem,      ad, pB[p] + s * 2,       IDESC_W, en);
                            mma_f16_ss(tmem + 80, ad, pB[p] + 640 + s * 2, IDESC_W, en);
                        }
                    }
                    TCGEN05_COMMIT(mbar);
                }
            }
            MBAR_WAIT(mbar, mph); mph ^= 1;

            // ---- gate -> bf16 A2 (warps 0-3); W1 copy (warps 4-9) ----
            if (tid < 128) {
                TCGEN05_FENCE_AFTER();
                const int t = tid;
                uint32_t da[32], dg[32];
                #pragma unroll
                for (int ch = 0; ch < 3; ch++) {
                    int a0 = ch * 32;
                    int w  = (ch == 2) ? 16 : 32;
                    if (w == 32) { LDTM_X32(da, tmem + a0); LDTM_X32(dg, tmem + 80 + a0); }
                    else         { LDTM_X16(da, tmem + a0); LDTM_X16(dg, tmem + 80 + a0); }
                    TCGEN05_WAIT_LD();
                    float gv[32];
                    for (int i = 0; i < w; i++) {
                        float a = __uint_as_float(da[i]) + s_bias[a0 + i];
                        float g = __uint_as_float(dg[i]) + s_bias[80 + a0 + i];
                        gv[i] = gatef(a, g);
                    }
                    #pragma unroll
                    for (int q = 0; q < 4; q++)
                        if (q * 8 < w) pack8(abp, t, (a0 >> 3) + q, gv + q * 8);
                }
            }
            copy_w2(abp, w2h, w2l, tid);
            FENCE_ASYNC_SHARED();
            __syncthreads();
            if (wid == 0 && elect_one()) issue_gemm2(tmem + 160, ab, mbar);
            MBAR_WAIT(mbar, mph); mph ^= 1;

            if (!FUSE) {
                if (tid < 128) {
                    TCGEN05_FENCE_AFTER();
                    const int t = tid;
                    const bool tv = (t0 + t) < Tout;
                    uint32_t d[32];
                    #pragma unroll
                    for (int ch = 0; ch < 3; ch++) {
                        int a0 = ch * 32;
                        int w  = (ch == 2) ? 16 : 32;
                        if (w == 32) LDTM_X32(d, tmem + 160 + a0);
                        else         LDTM_X16(d, tmem + 160 + a0);
                        TCGEN05_WAIT_LD();
                        if (tv) {
                            for (int i = 0; i < w; i++) {
                                int c = a0 + i;
                                float v = __uint_as_float(d[i]) + s_bias[160 + c];
                                if (RESID) v += __ldg(xin_n + (size_t)c * TinLd + S * (t0 + t) + 3);
                                xout[((size_t)n * 80 + c) * ToutLd + t0 + t] = v;
                            }
                        }
                    }
                }
            } else {
                // v1 = 1x1 + b1 + res -> A3 ; Wf0 ; GEMM -> cols 0..79
                if (tid < 128) {
                    TCGEN05_FENCE_AFTER();
                    const int t = tid;
                    const bool tv = (t0 + t) < Tout;
                    uint32_t d[32];
                    #pragma unroll
                    for (int ch = 0; ch < 3; ch++) {
                        int a0 = ch * 32;
                        int w  = (ch == 2) ? 16 : 32;
                        if (w == 32) LDTM_X32(d, tmem + 160 + a0);
                        else         LDTM_X16(d, tmem + 160 + a0);
                        TCGEN05_WAIT_LD();
                        float v[32];
                        for (int i = 0; i < w; i++) {
                            int c = a0 + i;
                            v[i] = __uint_as_float(d[i]) + s_bias[160 + c];
                            if (tv) v[i] += __ldg(xin_n + (size_t)c * TinLd + S * (t0 + t) + 3);
                        }
                        #pragma unroll
                        for (int q = 0; q < 4; q++)
                            if (q * 8 < w) pack8(abp, t, (a0 >> 3) + q, v + q * 8);
                    }
                }
                copy_w2(abp, wf0s, wf0s + 20480, tid);
                FENCE_ASYNC_SHARED();
                __syncthreads();
                if (wid == 0 && elect_one()) issue_gemm2(tmem + 0, ab, mbar);
                MBAR_WAIT(mbar, mph); mph ^= 1;

                // h = relu(conv0 + bf0) -> A4 ; Wf1 ; GEMM -> cols 80..159
                if (tid < 128) {
                    TCGEN05_FENCE_AFTER();
                    const int t = tid;
                    uint32_t d[32];
                    #pragma unroll
                    for (int ch = 0; ch < 3; ch++) {
                        int a0 = ch * 32;
                        int w  = (ch == 2) ? 16 : 32;
                        if (w == 32) LDTM_X32(d, tmem + a0);
                        else         LDTM_X16(d, tmem + a0);
                        TCGEN05_WAIT_LD();
                        float v[32];
                        for (int i = 0; i < w; i++)
                            v[i] = fmaxf(__uint_as_float(d[i]) + s_bias[240 + a0 + i], 0.f);
                        #pragma unroll
                        for (int q = 0; q < 4; q++)
                            if (q * 8 < w) pack8(abp, t, (a0 >> 3) + q, v + q * 8);
                    }
                }
                copy_w2(abp, wf1s, wf1s + 20480, tid);
                FENCE_ASYNC_SHARED();
                __syncthreads();
                if (wid == 0 && elect_one()) issue_gemm2(tmem + 80, ab, mbar);
                MBAR_WAIT(mbar, mph); mph ^= 1;

                // out = conv1 + bf1 -> enc (N,T,80)
                if (tid < 128) {
                    TCGEN05_FENCE_AFTER();
                    const int t = tid;
                    const bool tv = (t0 + t) < Tout;
                    uint32_t d[32];
                    #pragma unroll
                    for (int ch = 0; ch < 3; ch++) {
                        int a0 = ch * 32;
                        int w  = (ch == 2) ? 16 : 32;
                        if (w == 32) LDTM_X32(d, tmem + 80 + a0);
                        else         LDTM_X16(d, tmem + 80 + a0);
                        TCGEN05_WAIT_LD();
                        if (tv) {
                            float* dst = xout + ((size_t)n * Tout + t0 + t) * 80 + a0;
                            for (int i = 0; i < w; i += 4) {
                                float4 o;
                                o.x = __uint_as_float(d[i])     + s_bias[320 + a0 + i];
                                o.y = __uint_as_float(d[i + 1]) + s_bias[320 + a0 + i + 1];
                                o.z = __uint_as_float(d[i + 2]) + s_bias[320 + a0 + i + 2];
                                o.w = __uint_as_float(d[i + 3]) + s_bias[320 + a0 + i + 3];
                                *(float4*)(dst + i) = o;
                            }
                        }
                    }
                }
            }
#else
            // ------- safe scalar fallback (never runs on GB300) -------
            float* gsmF = (float*)(abp);
            float* bufF = (float*)(abp + 43008);
            __syncthreads();
            for (int e = tid; e < 80 * 128; e += 320) {
                int oc = e >> 7, tt = e & 127;
                float a = s_bias[oc], g = s_bias[oc + 80];
                for (int c = 0; c < 80; c++) {
                    for (int j = 0; j < 4; j++) {
                        int u = S * (t0 + tt) + j;
                        float xv = (u < Tin)
                                 ? (FIRST ? xin_n[(size_t)u * 80 + c]
                                          : xin_n[(size_t)c * TinLd + u]) : 0.f;
                        float wa = __bfloat162float(wbh[oc * 320 + c * 4 + j])
                                 + __bfloat162float(wbl[oc * 320 + c * 4 + j]);
                        float wg = __bfloat162float(wbh[(oc + 80) * 320 + c * 4 + j])
                                 + __bfloat162float(wbl[(oc + 80) * 320 + c * 4 + j]);
                        a = fmaf(wa, xv, a);
                        g = fmaf(wg, xv, g);
                    }
                }
                gsmF[oc * 132 + tt] = gatef(a, g);
            }
            __syncthreads();
            for (int e = tid; e < 80 * 128; e += 320) {
                int oc = e >> 7, tt = e & 127;
                int t = t0 + tt;
                float s = s_bias[160 + oc];
                for (int ic = 0; ic < 80; ic++)
                    s = fmaf(g_w1t[l * 6400 + ic * 80 + oc], gsmF[ic * 132 + tt], s);
                if (RESID && t < Tout) s += xin_n[(size_t)oc * TinLd + S * t + 3];
                if (FUSE) bufF[oc * 132 + tt] = s;
                else if (t < Tout) xout[((size_t)n * 80 + oc) * ToutLd + t] = s;
            }
            if (FUSE) {
                __syncthreads();
                for (int e = tid; e < 80 * 128; e += 320) {
                    int oc = e >> 7, tt = e & 127;
                    float s = s_bias[240 + oc];
                    for (int ic = 0; ic < 80; ic++)
                        s = fmaf(g_wf0t[ic * 80 + oc], bufF[ic * 132 + tt], s);
                    gsmF[oc * 132 + tt] = fmaxf(s, 0.f);
                }
                __syncthreads();
                for (int e = tid; e < 80 * 128; e += 320) {
                    int oc = e >> 7, tt = e & 127;
                    int t = t0 + tt;
                    if (t < Tout) {
                        float s = s_bias[320 + oc];
                        for (int ic = 0; ic < 80; ic++)
                            s = fmaf(g_wf1t[ic * 80 + oc], gsmF[ic * 132 + tt], s);
                        xout[((size_t)n * Tout + t) * 80 + oc] = s;
                    }
                }
            }
#endif
            // publish completion
            __threadfence();
            __syncthreads();
            if (tid == 0) atomicAdd(&g_done[l][n], 1u);

        } else {
            // ================= VQ tile =================
            const int loc = (int)(tk - 1600);
            const int n = loc / 16, bxv = loc % 16;
            const int t0 = bxv * 128;

            if (tid == 0) {
                while (atomicAdd(&g_done[3][n], 0u) < 20u) __nanosleep(200);
                __threadfence();
                sm0 = 0u; sm1 = 0u;
            }
            __syncthreads();

#if HAS_TC
            // stage X as A (128 t x 80 k, hi/lo)
            {
                const float4* src = (const float4*)(eS + (size_t)n * 2040 * 80);
                for (int gi = tid; gi < 1280; gi += 320) {
                    int t = gi / 10, kg = gi % 10;
                    int tg = t0 + t;
                    float v[8] = {0.f, 0.f, 0.f, 0.f, 0.f, 0.f, 0.f, 0.f};
                    if (tg < 2040) {
                        float4 a = __ldg(src + (size_t)tg * 20 + kg * 2);
                        float4 b = __ldg(src + (size_t)tg * 20 + kg * 2 + 1);
                        v[0] = a.x; v[1] = a.y; v[2] = a.z; v[3] = a.w;
                        v[4] = b.x; v[5] = b.y; v[6] = b.z; v[7] = b.w;
                    }
                    pack8(abp, t, kg, v);
                }
            }
            const int sub  = wid & 3;
            const int quar = wid >> 2;    // warps 0..7 used in readout (quar 0/1)
            const int t    = sub * 32 + (tid & 31);
            float best = 3.4e38f;
            int   bi   = 0;

            for (int grp = 0; grp < 2; grp++) {
                for (int ch = 0; ch < 4; ch++) {
                    int cls = grp * 4 + ch;
                    for (int i = tid; i < 1024; i += 320) {
                        ((uint4*)(abp + VQ_B_HI))[i] = __ldg((const uint4*)(g_embs[0][cls]) + i);
                        ((uint4*)(abp + VQ_B_LO))[i] = __ldg((const uint4*)(g_embs[1][cls]) + i);
                    }
                    FENCE_ASYNC_SHARED();
                    __syncthreads();
                    if (wid == 0 && elect_one()) issue_gemmv(tmem + ch * 64, ab, mbar);
                    MBAR_WAIT(mbar, mph); mph ^= 1;
                }
                TCGEN05_FENCE_AFTER();
                if (wid < 8) {
                    uint32_t d[32];
                    #pragma unroll
                    for (int cc = 0; cc < 4; cc++) {
                        int c0 = quar * 128 + cc * 32;
                        LDTM_X32(d, tmem + c0);
                        TCGEN05_WAIT_LD();
                        for (int i = 0; i < 32; i++) {
                            int k = grp * 256 + c0 + i;
                            float dd = se2[k] - 2.f * __uint_as_float(d[i]);
                            if (dd < best) { best = dd; bi = k; }
                        }
                    }
                    TCGEN05_FENCE_BEFORE();
                }
                __syncthreads();   // LDTMs done before next group's MMAs overwrite
            }
            if (wid < 8) {
                sdist[t * 2 + quar] = best;
                sidx [t * 2 + quar] = bi;
            }
            __syncthreads();

            if (tid < 128) {
                float d0 = sdist[tid * 2],     d1 = sdist[tid * 2 + 1];
                int   i0 = sidx [tid * 2],     i1 = sidx [tid * 2 + 1];
                int bbi = (d1 < d0 || (d1 == d0 && i1 < i0)) ? i1 : i0;
                int tg2 = t0 + tid;
                if (tg2 < 2040) {
                    const float* dv = emb + (size_t)bbi * 80;
                    const float* qr = (tg2 < 2016)
                                    ? (eQ + ((size_t)n * 504 + (tg2 % 504)) * 80)
                                    : nullptr;
                    float s0 = blin[0], s1 = blin[1];
                    #pragma unroll 4
                    for (int c = 0; c < 80; c++) {
                        float v = dv[c] + (qr ? qr[c] : 0.f);
                        s0 = fmaf(v, wlin[c],      s0);
                        s1 = fmaf(v, wlin[80 + c], s1);
                    }
                    atomicMax(&sm0, fenc(tanhf(s0)));
                    atomicMax(&sm1, fenc(tanhf(s1)));
                }
            }
            __syncthreads();
#else
            // scalar fallback VQ
            __syncthreads();
            if (tid < 128) {
                int tg2 = t0 + tid;
                if (tg2 < 2040) {
                    const float* xr = eS + ((size_t)n * 2040 + tg2) * 80;
                    float best = 3.4e38f; int bbi = 0;
                    for (int k = 0; k < 512; k++) {
                        float dot = 0.f;
                        for (int c = 0; c < 80; c++) dot = fmaf(xr[c], emb[k * 80 + c], dot);
                        float dd = se2[k] - 2.f * dot;
                        if (dd < best) { best = dd; bbi = k; }
                    }
                    const float* dv = emb + (size_t)bbi * 80;
                    const float* qr = (tg2 < 2016)
                                    ? (eQ + ((size_t)n * 504 + (tg2 % 504)) * 80)
                                    : nullptr;
                    float s0 = blin[0], s1 = blin[1];
                    for (int c = 0; c < 80; c++) {
                        float v = dv[c] + (qr ? qr[c] : 0.f);
                        s0 = fmaf(v, wlin[c],      s0);
                        s1 = fmaf(v, wlin[80 + c], s1);
                    }
                    atomicMax(&sm0, fenc(tanhf(s0)));
                    atomicMax(&sm1, fenc(tanhf(s1)));
                }
            }
            __syncthreads();
#endif
            if (tid == 0) {
                atomicMax(&g_gmax[n * 2 + 0], sm0);
                atomicMax(&g_gmax[n * 2 + 1], sm1);
                __threadfence();
                unsigned old = atomicAdd(&g_cnt[n], 1u);
                if (old == 15u) {
                    unsigned e0 = atomicMax(&g_gmax[n * 2 + 0], 0u);
                    unsigned e1 = atomicMax(&g_gmax[n * 2 + 1], 0u);
                    out[n * 2 + 0] = fdec(e0);
                    out[n * 2 + 1] = fdec(e1);
                }
            }
        }
    }

#if HAS_TC
    __syncthreads();
    if (wid == 0) TCGEN05_DEALLOC(tmem, 256);
#endif
}

// ---------------------------------------------------------------------------
// Host launch
// ---------------------------------------------------------------------------
extern "C" void kernel_launch(void* const* d_in, const int* in_sizes, int n_in,
                              void* d_out, int out_size) {
    const float* search = (const float*)d_in[0];
    const float* query  = (const float*)d_in[1];
    const float* w_wide = (const float*)d_in[2];
    const float* b_wide = (const float*)d_in[3];
    const float* w_1x1  = (const float*)d_in[4];
    const float* b_1x1  = (const float*)d_in[5];
    const float* w_f0   = (const float*)d_in[6];
    const float* b_f0   = (const float*)d_in[7];
    const float* w_f1   = (const float*)d_in[8];
    const float* b_f1   = (const float*)d_in[9];
    const float* emb    = (const float*)d_in[10];
    const float* w_lin  = (const float*)d_in[11];
    const float* b_lin  = (const float*)d_in[12];
    float* out = (float*)d_out;

    void *pA, *pB, *pAq, *pBq, *pS, *pQ, *pwh, *pwl, *pw1s, *pwf0s, *pwf1s;
    cudaGetSymbolAddress(&pA,   g_bufA);
    cudaGetSymbolAddress(&pB,   g_bufB);
    cudaGetSymbolAddress(&pAq,  g_bufAq);
    cudaGetSymbolAddress(&pBq,  g_bufBq);
    cudaGetSymbolAddress(&pS,   g_encS);
    cudaGetSymbolAddress(&pQ,   g_encQ);
    cudaGetSymbolAddress(&pwh,  g_wbh);
    cudaGetSymbolAddress(&pwl,  g_wbl);
    cudaGetSymbolAddress(&pw1s, g_w1s);
    cudaGetSymbolAddress(&pwf0s, g_wf0s);
    cudaGetSymbolAddress(&pwf1s, g_wf1s);
    float* A   = (float*)pA;
    float* B   = (float*)pB;
    float* Aq  = (float*)pAq;
    float* Bq  = (float*)pBq;
    float* eS  = (float*)pS;
    float* eQ  = (float*)pQ;
    __nv_bfloat16* wbh = (__nv_bfloat16*)pwh;
    __nv_bfloat16* wbl = (__nv_bfloat16*)pwl;
    const char* w1s  = (const char*)pw1s;
    const char* wf0s = (const char*)pwf0s;
    const char* wf1s = (const char*)pwf1s;

    cudaFuncSetAttribute(mega_kernel,
                         cudaFuncAttributeMaxDynamicSharedMemorySize, SMEM_DYN);

    prep_kernel<<<80, 256>>>(w_wide, w_1x1, w_f0, w_f1, emb);

    mega_kernel<<<304, 320, SMEM_DYN>>>(
        search, query, A, Aq, B, Bq, eS, eQ,
        wbh, wbl, b_wide, b_1x1,
        w1s, wf0s, wf1s, b_f0, b_f1,
        emb, w_lin, b_lin, out);
}

// round 15
// speedup vs baseline: 4.7111x; 1.0094x over previous
#include <cuda_runtime.h>
#include <cuda_bf16.h>
#include <cstdint>

#define NB 16
typedef unsigned long long u64;

#if defined(__CUDA_ARCH_FEAT_SM103_ALL) || defined(__CUDA_ARCH_FEAT_SM100_ALL) || \
    (defined(__CUDA_ARCH_SPECIFIC__) && (__CUDA_ARCH_SPECIFIC__ >= 1000))
#define HAS_TC 1
#else
#define HAS_TC 0
#endif

// ---------------------------------------------------------------------------
// PTX helpers
// ---------------------------------------------------------------------------
__device__ __forceinline__ uint32_t smem_u32(const void* p) {
    uint32_t a;
    asm("{ .reg .u64 t; cvta.to.shared.u64 t, %1; cvt.u32.u64 %0, t; }" : "=r"(a) : "l"(p));
    return a;
}
__device__ __forceinline__ float ex2f(float x) {
    float r; asm("ex2.approx.f32 %0, %1;" : "=f"(r) : "f"(x)); return r;
}
__device__ __forceinline__ float rcpf(float x) {
    float r; asm("rcp.approx.f32 %0, %1;" : "=f"(r) : "f"(x)); return r;
}
__device__ __forceinline__ uint32_t prmt_hi(uint32_t a, uint32_t b) {
    uint32_t r; asm("prmt.b32 %0, %1, %2, 0x7632;" : "=r"(r) : "r"(a), "r"(b)); return r;
}
__device__ __forceinline__ uint32_t cvt_bf16x2(float hi, float lo) {
    uint32_t r; asm("cvt.rn.bf16x2.f32 %0, %1, %2;" : "=r"(r) : "f"(hi), "f"(lo)); return r;
}
__device__ __forceinline__ float gatef(float a, float g) {
    float e1 = ex2f(fminf(a * -2.885390082f, 80.f));
    float e2 = ex2f(fminf(g * -1.442695041f, 80.f));
    float r  = rcpf((1.f + e1) * (1.f + e2));
    return (1.f - e1) * r;
}

#if HAS_TC
__device__ __forceinline__ uint32_t elect_one() {
    uint32_t p;
    asm volatile("{\n\t.reg .pred p;\n\telect.sync _|p, 0xFFFFFFFF;\n\tselp.b32 %0, 1, 0, p;\n\t}" : "=r"(p));
    return p;
}

#define TCGEN05_ALLOC(sm, n) \
    asm volatile("tcgen05.alloc.cta_group::1.sync.aligned.shared::cta.b32 [%0], %1;" \
                 :: "r"((uint32_t)(sm)), "r"((uint32_t)(n)) : "memory")
#define TCGEN05_RELINQ() \
    asm volatile("tcgen05.relinquish_alloc_permit.cta_group::1.sync.aligned;")
#define TCGEN05_DEALLOC(t, n) \
    asm volatile("tcgen05.dealloc.cta_group::1.sync.aligned.b32 %0, %1;" :: "r"(t), "r"((uint32_t)(n)))
#define TCGEN05_COMMIT(mb) \
    asm volatile("tcgen05.commit.cta_group::1.mbarrier::arrive::one.shared::cluster.b64 [%0];" \
                 :: "r"((uint32_t)(mb)) : "memory")
#define TCGEN05_FENCE_AFTER()  asm volatile("tcgen05.fence::after_thread_sync;" ::: "memory")
#define TCGEN05_FENCE_BEFORE() asm volatile("tcgen05.fence::before_thread_sync;" ::: "memory")
#define TCGEN05_WAIT_LD()      asm volatile("tcgen05.wait::ld.sync.aligned;" ::: "memory")
#define FENCE_ASYNC_SHARED()   asm volatile("fence.proxy.async.shared::cta;" ::: "memory")
#define MBARRIER_INIT(mb, c) \
    asm volatile("mbarrier.init.shared.b64 [%0], %1;" :: "r"((uint32_t)(mb)), "r"((uint32_t)(c)) : "memory")

#define MBAR_WAIT(mb, ph) do {                                                  \
    uint32_t _m = (uint32_t)(mb), _p = (uint32_t)(ph), _d;                      \
    asm volatile("{\n\t.reg .pred p;\n\t"                                       \
        "mbarrier.try_wait.parity.acquire.cta.shared::cta.b64 p, [%1], %2;\n\t" \
        "selp.b32 %0, 1, 0, p;\n\t}" : "=r"(_d) : "r"(_m), "r"(_p) : "memory"); \
    if (!_d) {                                                                  \
        asm volatile("{\n\t.reg .pred P1;\n\t"                                  \
            "WL_%=:\n\t"                                                        \
            "mbarrier.try_wait.parity.acquire.cta.shared::cta.b64 P1, [%0], %1, 0x989680;\n\t" \
            "@P1 bra.uni WD_%=;\n\t"                                            \
            "bra.uni WL_%=;\n\t"                                                \
            "WD_%=:\n\t}" :: "r"(_m), "r"(_p) : "memory");                      \
    }                                                                           \
} while (0)

#define LDTM_X32(r, a) \
    asm volatile("tcgen05.ld.sync.aligned.32x32b.x32.b32 " \
        "{%0,%1,%2,%3,%4,%5,%6,%7,%8,%9,%10,%11,%12,%13,%14,%15," \
        "%16,%17,%18,%19,%20,%21,%22,%23,%24,%25,%26,%27,%28,%29,%30,%31}, [%32];" \
        : "=r"((r)[0]),"=r"((r)[1]),"=r"((r)[2]),"=r"((r)[3]),"=r"((r)[4]),"=r"((r)[5]),"=r"((r)[6]),"=r"((r)[7]), \
          "=r"((r)[8]),"=r"((r)[9]),"=r"((r)[10]),"=r"((r)[11]),"=r"((r)[12]),"=r"((r)[13]),"=r"((r)[14]),"=r"((r)[15]), \
          "=r"((r)[16]),"=r"((r)[17]),"=r"((r)[18]),"=r"((r)[19]),"=r"((r)[20]),"=r"((r)[21]),"=r"((r)[22]),"=r"((r)[23]), \
          "=r"((r)[24]),"=r"((r)[25]),"=r"((r)[26]),"=r"((r)[27]),"=r"((r)[28]),"=r"((r)[29]),"=r"((r)[30]),"=r"((r)[31]) \
        : "r"(a))

#define LDTM_X16(r, a) \
    asm volatile("tcgen05.ld.sync.aligned.32x32b.x16.b32 " \
        "{%0,%1,%2,%3,%4,%5,%6,%7,%8,%9,%10,%11,%12,%13,%14,%15}, [%16];" \
        : "=r"((r)[0]),"=r"((r)[1]),"=r"((r)[2]),"=r"((r)[3]),"=r"((r)[4]),"=r"((r)[5]),"=r"((r)[6]),"=r"((r)[7]), \
          "=r"((r)[8]),"=r"((r)[9]),"=r"((r)[10]),"=r"((r)[11]),"=r"((r)[12]),"=r"((r)[13]),"=r"((r)[14]),"=r"((r)[15]) \
        : "r"(a))

__device__ __forceinline__ void mma_f16_ss(uint32_t d, u64 ad, u64 bd, uint32_t idesc, uint32_t en) {
    asm volatile("{\n\t.reg .pred p;\n\tsetp.ne.u32 p, %5, 0;\n\t"
        "tcgen05.mma.cta_group::1.kind::f16 [%0], %1, %2, %3, {%4,%4,%4,%4}, p;\n\t}"
        :: "r"(d), "l"(ad), "l"(bd), "r"(idesc), "r"(0u), "r"(en) : "memory");
}

static __device__ __forceinline__ u64 make_desc(uint32_t addr) {
    return (u64(2) << 61) | (u64(1) << 46) | (u64(64) << 32) | (u64(1) << 16)
         | ((u64)(addr >> 4) & 0x3FFF);
}

#define IDESC_W ((1u<<4) | (1u<<7) | (1u<<10) | (10u<<17) | (8u<<24))
#define IDESC_V ((1u<<4) | (1u<<7) | (1u<<10) | (8u<<17)  | (8u<<24))
#endif // HAS_TC

// ---------------------------------------------------------------------------
// Device scratch
// ---------------------------------------------------------------------------
__device__ __align__(16) __nv_bfloat16 g_wbh[4 * 160 * 320];
__device__ __align__(16) __nv_bfloat16 g_wbl[4 * 160 * 320];
__device__ __align__(16) char g_w1s [4][2][20480];
__device__ __align__(16) char g_wf0s[2][20480];
__device__ __align__(16) char g_wf1s[2][20480];
__device__ __align__(16) char g_embs[2][8][16384];
__device__ __align__(16) float g_w1t [4 * 80 * 80];
__device__ __align__(16) float g_wf0t[80 * 80];
__device__ __align__(16) float g_wf1t[80 * 80];
__device__ __align__(16) float g_e2  [512];
__device__ __align__(16) float g_bufA [16 * 80 * 4096];   // L0 out AND L2 out (ld 4096)
__device__ __align__(16) float g_bufB [16 * 80 * 2048];
__device__ __align__(16) float g_bufAq[16 * 80 * 1024];
__device__ __align__(16) float g_bufBq[16 * 80 * 512];
__device__ __align__(16) float g_encS[16 * 2040 * 80];
__device__ __align__(16) float g_encQ[16 * 504 * 80];
__device__ unsigned g_gmax[32];
__device__ unsigned g_cnt[16];
__device__ unsigned g_ticket;
__device__ unsigned g_done[4][16];

// ---------------------------------------------------------------------------
// Weight prep (+ scheduler state reset)
// ---------------------------------------------------------------------------
__global__ void prep_kernel(const float* __restrict__ w_wide,
                            const float* __restrict__ w_1x1,
                            const float* __restrict__ w_f0,
                            const float* __restrict__ w_f1,
                            const float* __restrict__ emb) {
    int g = blockIdx.x * blockDim.x + threadIdx.x;
    int stride = gridDim.x * blockDim.x;
    for (int idx = g; idx < 4 * 160 * 320; idx += stride) {
        float v = w_wide[idx];
        __nv_bfloat16 h = __float2bfloat16(v);
        g_wbh[idx] = h;
        g_wbl[idx] = __float2bfloat16(v - __bfloat162float(h));
    }
    for (int idx = g; idx < 4 * 80 * 128; idx += stride) {
        int l = idx / 10240, r = idx % 10240;
        int oc = r >> 7, k = r & 127;
        float v = (k < 80) ? w_1x1[l * 6400 + oc * 80 + k] : 0.f;
        __nv_bfloat16 h = __float2bfloat16(v);
        __nv_bfloat16 lo = __float2bfloat16(v - __bfloat162float(h));
        uint32_t off = (uint32_t)(((oc >> 3) + (k >> 6) * 10) * 1024 + (oc & 7) * 128 + (k & 63) * 2);
        uint32_t sw  = off ^ ((off >> 3) & 0x70);
        *(__nv_bfloat16*)(g_w1s[l][0] + sw) = h;
        *(__nv_bfloat16*)(g_w1s[l][1] + sw) = lo;
    }
    for (int idx = g; idx < 80 * 128; idx += stride) {
        int oc = idx >> 7, k = idx & 127;
        uint32_t off = (uint32_t)(((oc >> 3) + (k >> 6) * 10) * 1024 + (oc & 7) * 128 + (k & 63) * 2);
        uint32_t sw  = off ^ ((off >> 3) & 0x70);
        float v0 = (k < 80) ? w_f0[oc * 80 + k] : 0.f;
        float v1 = (k < 80) ? w_f1[oc * 80 + k] : 0.f;
        __nv_bfloat16 h0 = __float2bfloat16(v0);
        __nv_bfloat16 h1 = __float2bfloat16(v1);
        *(__nv_bfloat16*)(g_wf0s[0] + sw) = h0;
        *(__nv_bfloat16*)(g_wf0s[1] + sw) = __float2bfloat16(v0 - __bfloat162float(h0));
        *(__nv_bfloat16*)(g_wf1s[0] + sw) = h1;
        *(__nv_bfloat16*)(g_wf1s[1] + sw) = __float2bfloat16(v1 - __bfloat162float(h1));
    }
    for (int idx = g; idx < 512 * 128; idx += stride) {
        int kc = idx >> 7;
        int k  = idx & 127;
        int ch = kc >> 6, r = kc & 63;
        float v = (k < 80) ? emb[kc * 80 + k] : 0.f;
        __nv_bfloat16 h = __float2bfloat16(v);
        uint32_t off = (uint32_t)(((r >> 3) + (k >> 6) * 8) * 1024 + (r & 7) * 128 + (k & 63) * 2);
        uint32_t sw  = off ^ ((off >> 3) & 0x70);
        *(__nv_bfloat16*)(g_embs[0][ch] + sw) = h;
        *(__nv_bfloat16*)(g_embs[1][ch] + sw) = __float2bfloat16(v - __bfloat162float(h));
    }
    for (int idx = g; idx < 4 * 80 * 80; idx += stride) {
        int ic = idx % 80, oc = (idx / 80) % 80, l = idx / 6400;
        g_w1t[l * 6400 + ic * 80 + oc] = w_1x1[idx];
    }
    for (int idx = g; idx < 6400; idx += stride) {
        int ic = idx % 80, oc = idx / 80;
        g_wf0t[ic * 80 + oc] = w_f0[idx];
        g_wf1t[ic * 80 + oc] = w_f1[idx];
    }
    for (int k = g; k < 512; k += stride) {
        float s = 0.f;
        for (int c = 0; c < 80; c++) { float v = emb[k * 80 + c]; s += v * v; }
        g_e2[k] = s;
    }
    if (g < 32) g_gmax[g] = 0u;
    if (g < 16) g_cnt[g] = 0u;
    if (g < 64) ((unsigned*)g_done)[g] = 0u;
    if (g == 64) g_ticket = 0u;
}

// ---------------------------------------------------------------------------
// smem layout (1024-aligned base)
// ---------------------------------------------------------------------------
#define OFF_A_HI  0
#define OFF_A_LO  16384
#define OFF_B_HI  32768
#define OFF_B_LO  53248
#define OFF2_A_HI 0
#define OFF2_A_LO 32768
#define OFF2_B_HI 65536
#define OFF2_B_LO 86016
#define VQ_B_HI   65536
#define VQ_B_LO   81920
#define SMEM_DYN  (1024 + 106496)

#define N_TICKETS 1856

#if HAS_TC
__device__ __forceinline__ void pack8(char* abp, int t, int g8, const float* v) {
    uint32_t ub[8]; float lo[8];
    #pragma unroll
    for (int i = 0; i < 8; i++) {
        ub[i] = __float_as_uint(v[i]);
        lo[i] = v[i] - __uint_as_float(ub[i] & 0xFFFF0000u);
    }
    uint4 hp, lp;
    hp.x = prmt_hi(ub[0], ub[1]); hp.y = prmt_hi(ub[2], ub[3]);
    hp.z = prmt_hi(ub[4], ub[5]); hp.w = prmt_hi(ub[6], ub[7]);
    lp.x = cvt_bf16x2(lo[1], lo[0]); lp.y = cvt_bf16x2(lo[3], lo[2]);
    lp.z = cvt_bf16x2(lo[5], lo[4]); lp.w = cvt_bf16x2(lo[7], lo[6]);
    uint32_t off = (uint32_t)(((t >> 3) + ((g8 >= 8) ? 16 : 0)) * 1024 + (t & 7) * 128 + (g8 & 7) * 16);
    uint32_t sw  = off ^ ((off >> 3) & 0x70);
    *(uint4*)(abp + OFF2_A_HI + sw) = hp;
    *(uint4*)(abp + OFF2_A_LO + sw) = lp;
}
// weight-image copy on warps 8-9 (threads 256..319)
__device__ __forceinline__ void copy_w2(char* abp, const char* hi, const char* lo, int tid) {
    if (tid >= 256) {
        for (int i = tid - 256; i < 1280; i += 64) {
            ((uint4*)(abp + OFF2_B_HI))[i] = __ldg((const uint4*)hi + i);
            ((uint4*)(abp + OFF2_B_LO))[i] = __ldg((const uint4*)lo + i);
        }
    }
}
__device__ __forceinline__ void issue_gemm2(uint32_t tmem_dst, uint32_t ab, uint32_t mbar) {
    u64 dAh = make_desc(ab + OFF2_A_HI), dAl = make_desc(ab + OFF2_A_LO);
    u64 dBh = make_desc(ab + OFF2_B_HI), dBl = make_desc(ab + OFF2_B_LO);
    u64 pA[3] = {dAh, dAh, dAl};
    u64 pB[3] = {dBh, dBl, dBh};
    #pragma unroll
    for (int p = 0; p < 3; p++) {
        #pragma unroll
        for (int s = 0; s < 5; s++) {
            uint32_t en = (p == 0 && s == 0) ? 0u : 1u;
            u64 ao = (s < 4) ? (u64)(2 * s) : 1024ull;
            u64 bo = (s < 4) ? (u64)(2 * s) : 640ull;
            mma_f16_ss(tmem_dst, pA[p] + ao, pB[p] + bo, IDESC_W, en);
        }
    }
    TCGEN05_COMMIT(mbar);
}
__device__ __forceinline__ void issue_gemmv(uint32_t tmem_dst, uint32_t ab, uint32_t mbar) {
    u64 dAh = make_desc(ab + OFF2_A_HI), dAl = make_desc(ab + OFF2_A_LO);
    u64 dBh = make_desc(ab + VQ_B_HI),  dBl = make_desc(ab + VQ_B_LO);
    u64 pA[3] = {dAh, dAh, dAl};
    u64 pB[3] = {dBh, dBl, dBh};
    #pragma unroll
    for (int p = 0; p < 3; p++) {
        #pragma unroll
        for (int s = 0; s < 5; s++) {
            uint32_t en = (p == 0 && s == 0) ? 0u : 1u;
            u64 ao = (s < 4) ? (u64)(2 * s) : 1024ull;
            u64 bo = (s < 4) ? (u64)(2 * s) : 512ull;
            mma_f16_ss(tmem_dst, pA[p] + ao, pB[p] + bo, IDESC_V, en);
        }
    }
    TCGEN05_COMMIT(mbar);
}
#endif

__device__ __forceinline__ unsigned fenc(float f) {
    unsigned u = __float_as_uint(f);
    return (u & 0x80000000u) ? ~u : (u | 0x80000000u);
}
__device__ __forceinline__ float fdec(unsigned e) {
    return (e & 0x80000000u) ? __uint_as_float(e ^ 0x80000000u)
                             : __uint_as_float(~e);
}

// ---------------------------------------------------------------------------
// Persistent mega-kernel, ordered-ticket scheduler; 8-warp TMEM readouts
// ---------------------------------------------------------------------------
__global__ __launch_bounds__(320, 2) void mega_kernel(
    const float* __restrict__ search, const float* __restrict__ query,
    float* __restrict__ A, float* __restrict__ Aq,
    float* __restrict__ B, float* __restrict__ Bq,
    float* __restrict__ eS, float* __restrict__ eQ,
    const __nv_bfloat16* __restrict__ wbh0, const __nv_bfloat16* __restrict__ wbl0,
    const float* __restrict__ b_wide, const float* __restrict__ b_1x1,
    const char* __restrict__ w1s,
    const char* __restrict__ wf0s, const char* __restrict__ wf1s,
    const float* __restrict__ bf0g, const float* __restrict__ bf1g,
    const float* __restrict__ emb, const float* __restrict__ wlin,
    const float* __restrict__ blin, float* __restrict__ out)
{
    extern __shared__ char dsm[];
    __shared__ float s_bias[400];
    __shared__ unsigned s_tk;
    __shared__ float se2[512];
    __shared__ float sdist[256];
    __shared__ int   sidx[256];
    __shared__ unsigned sm0, sm1;

    const int tid = threadIdx.x;
    const int wid = tid >> 5;
    uint32_t base_raw = smem_u32(dsm);
    uint32_t ab = (base_raw + 1023u) & ~1023u;
    char* abp = dsm + (ab - base_raw);

    for (int i = tid; i < 512; i += 320) se2[i] = __ldg(&g_e2[i]);

#if HAS_TC
    __shared__ uint32_t s_tmem;
    __shared__ __align__(8) u64 s_mbar;
    if (tid == 0) MBARRIER_INIT(smem_u32(&s_mbar), 1);
    if (wid == 0) { TCGEN05_ALLOC(smem_u32(&s_tmem), 256); TCGEN05_RELINQ(); }
    __syncthreads();
    const uint32_t tmem = s_tmem;
    const uint32_t mbar = smem_u32(&s_mbar);
#else
    __syncthreads();
#endif
    int mph = 0;
    (void)mph;

    while (true) {
        if (tid == 0) s_tk = atomicAdd(&g_ticket, 1u);
        __syncthreads();
        const unsigned tk = s_tk;
        if (tk >= N_TICKETS) break;

        if (tk < 1600) {
            // ================= layer tile =================
            int l, loc;
            if (tk < 640) { l = 0; loc = (int)tk; }
            else { l = 1 + (int)(tk - 640) / 320; loc = (int)(tk - 640) % 320; }
            const int tilesN = (l == 0) ? 40 : 20;
            const int n = loc / tilesN, idx = loc % tilesN;
            const int blocksS = (l == 0) ? 32 : 16;

            if (l > 0) {
                const unsigned need = (l == 1) ? 40u : 20u;
                if (tid == 0) {
                    while (atomicAdd(&g_done[l - 1][n], 0u) < need) __nanosleep(200);
                    __threadfence();
                }
                __syncthreads();
            }

            const int cS[4]       = {2, 2, 1, 1};
            const int cTinS[4]    = {8192, 4095, 2046, 2043};
            const int cTinLdS[4]  = {8192, 4096, 2048, 4096};
            const int cToutS[4]   = {4095, 2046, 2043, 2040};
            const int cToutLdS[4] = {4096, 2048, 4096, 2040};
            const int cTinQ[4]    = {2048, 1023, 510, 507};
            const int cTinLdQ[4]  = {2048, 1024, 512, 1024};
            const int cToutQ[4]   = {1023, 510, 507, 504};
            const int cToutLdQ[4] = {1024, 512, 1024, 504};

            const bool FIRST = (l == 0);
            const bool RESID = (l > 0);
            const bool FUSE  = (l == 3);
            const int  S     = cS[l];

            const float *xinS_, *xinQ_; float *xoutS_, *xoutQ_;
            switch (l) {
                case 0:  xinS_ = search; xinQ_ = query; xoutS_ = A;  xoutQ_ = Aq; break;
                case 1:  xinS_ = A;      xinQ_ = Aq;    xoutS_ = B;  xoutQ_ = Bq; break;
                case 2:  xinS_ = B;      xinQ_ = Bq;    xoutS_ = A;  xoutQ_ = Aq; break;
                default: xinS_ = A;      xinQ_ = Aq;    xoutS_ = eS; xoutQ_ = eQ; break;
            }
            const float* xin; float* xout; int Tin, TinLd, Tout, ToutLd, t0;
            if (idx < blocksS) {
                xin = xinS_; xout = xoutS_; Tin = cTinS[l]; TinLd = cTinLdS[l];
                Tout = cToutS[l]; ToutLd = cToutLdS[l]; t0 = idx * 128;
            } else {
                xin = xinQ_; xout = xoutQ_; Tin = cTinQ[l]; TinLd = cTinLdQ[l];
                Tout = cToutQ[l]; ToutLd = cToutLdQ[l]; t0 = (idx - blocksS) * 128;
            }
            const float* xin_n = xin + (size_t)n * 80 * TinLd;
            const __nv_bfloat16* wbh = wbh0 + l * 51200;
            const __nv_bfloat16* wbl = wbl0 + l * 51200;
            const float* bw = b_wide + l * 160;
            const float* b1 = b_1x1 + l * 80;
            const char* w2h = w1s + (size_t)l * 2 * 20480;
            const char* w2l = w2h + 20480;

            for (int i = tid; i < 400; i += 320) {
                float v = 0.f;
                if (i < 160) v = __ldg(bw + i);
                else if (i < 240) v = __ldg(b1 + i - 160);
                else if (FUSE && i < 320) v = __ldg(bf0g + i - 240);
                else if (FUSE) v = __ldg(bf1g + i - 320);
                s_bias[i] = v;
            }

#if HAS_TC
            // ---- wide GEMM: 5 K-chunks of 64 -> tmem cols 0..159 ----
            for (int kc = 0; kc < 5; kc++) {
                if (kc > 0) { MBAR_WAIT(mbar, mph); mph ^= 1; }
                const int k0 = kc * 64;
                for (int gi = tid; gi < 1024; gi += 320) {
                    int t, g8;
                    if (FIRST) { g8 = gi & 7; t = gi >> 3; }
                    else       { t = gi & 127; g8 = gi >> 7; }
                    int c0 = (k0 >> 2) + g8 * 2;
                    int u0 = S * (t0 + t);
                    float v[8];
                    if (FIRST) {
                        #pragma unroll
                        for (int j = 0; j < 4; j++) {
                            int u = u0 + j;
                            if (u < Tin) {
                                float2 p = __ldg((const float2*)&xin_n[(size_t)u * 80 + c0]);
                                v[j] = p.x; v[4 + j] = p.y;
                            } else { v[j] = 0.f; v[4 + j] = 0.f; }
                        }
                    } else {
                        const float* r0 = xin_n + (size_t)c0 * TinLd + u0;
                        #pragma unroll
                        for (int j = 0; j < 4; j++) {
                            bool ok = (u0 + j) < Tin;
                            v[j]     = ok ? __ldg(r0 + j)         : 0.f;
                            v[4 + j] = ok ? __ldg(r0 + TinLd + j) : 0.f;
                        }
                    }
                    uint32_t ub[8]; float lo[8];
                    #pragma unroll
                    for (int i = 0; i < 8; i++) {
                        ub[i] = __float_as_uint(v[i]);
                        lo[i] = v[i] - __uint_as_float(ub[i] & 0xFFFF0000u);
                    }
                    uint4 hp, lp;
                    hp.x = prmt_hi(ub[0], ub[1]); hp.y = prmt_hi(ub[2], ub[3]);
                    hp.z = prmt_hi(ub[4], ub[5]); hp.w = prmt_hi(ub[6], ub[7]);
                    lp.x = cvt_bf16x2(lo[1], lo[0]); lp.y = cvt_bf16x2(lo[3], lo[2]);
                    lp.z = cvt_bf16x2(lo[5], lo[4]); lp.w = cvt_bf16x2(lo[7], lo[6]);
                    uint32_t off = (uint32_t)((t >> 3) * 1024 + (t & 7) * 128 + g8 * 16);
                    uint32_t sw  = off ^ ((off >> 3) & 0x70);
                    *(uint4*)(abp + OFF_A_HI + sw) = hp;
                    *(uint4*)(abp + OFF_A_LO + sw) = lp;
                }
                {
                    const uint4* srcH = (const uint4*)wbh;
                    const uint4* srcL = (const uint4*)wbl;
                    #pragma unroll
                    for (int r = 0; r < 4; r++) {
                        int gi = r * 320 + tid;
                        int row = gi >> 3, g8 = gi & 7;
                        int si  = row * 40 + (kc << 3) + g8;
                        uint32_t off = (uint32_t)((row >> 3) * 1024 + (row & 7) * 128 + g8 * 16);
                        uint32_t sw  = off ^ ((off >> 3) & 0x70);
                        *(uint4*)(abp + OFF_B_HI + sw) = __ldg(srcH + si);
                        *(uint4*)(abp + OFF_B_LO + sw) = __ldg(srcL + si);
                    }
                }
                FENCE_ASYNC_SHARED();
                __syncthreads();
                if (wid == 0 && elect_one()) {
                    u64 dAh = make_desc(ab + OFF_A_HI), dAl = make_desc(ab + OFF_A_LO);
                    u64 dBh = make_desc(ab + OFF_B_HI), dBl = make_desc(ab + OFF_B_LO);
                    u64 pA[3] = {dAh, dAh, dAl};
                    u64 pB[3] = {dBh, dBl, dBh};
                    #pragma unroll
                    for (int p = 0; p < 3; p++) {
                        #pragma unroll
                        for (int s = 0; s < 4; s++) {
                            uint32_t en = (kc == 0 && p == 0 && s == 0) ? 0u : 1u;
                            u64 ad = pA[p] + s * 2;
                            mma_f16_ss(tmem,      ad, pB[p] + s * 2,       IDESC_W, en);
                            mma_f16_ss(tmem + 80, ad, pB[p] + 640 + s * 2, IDESC_W, en);
                        }
                    }
                    TCGEN05_COMMIT(mbar);
                }
            }
            MBAR_WAIT(mbar, mph); mph ^= 1;

            // ---- gate -> bf16 A2: 8 warps (0-3: cols 0-63, 4-7: cols 64-79) ----
            if (tid < 256) {
                TCGEN05_FENCE_AFTER();
                const int t = tid & 127;
                const int half = tid >> 7;
                uint32_t da[32], dg[32];
                if (half == 0) {
                    #pragma unroll
                    for (int ch = 0; ch < 2; ch++) {
                        int a0 = ch * 32;
                        LDTM_X32(da, tmem + a0); LDTM_X32(dg, tmem + 80 + a0);
                        TCGEN05_WAIT_LD();
                        float gv[32];
                        for (int i = 0; i < 32; i++) {
                            float a = __uint_as_float(da[i]) + s_bias[a0 + i];
                            float g = __uint_as_float(dg[i]) + s_bias[80 + a0 + i];
                            gv[i] = gatef(a, g);
                        }
                        #pragma unroll
                        for (int q = 0; q < 4; q++)
                            pack8(abp, t, (a0 >> 3) + q, gv + q * 8);
                    }
                } else {
                    LDTM_X16(da, tmem + 64); LDTM_X16(dg, tmem + 144);
                    TCGEN05_WAIT_LD();
                    float gv[16];
                    for (int i = 0; i < 16; i++) {
                        float a = __uint_as_float(da[i]) + s_bias[64 + i];
                        float g = __uint_as_float(dg[i]) + s_bias[144 + i];
                        gv[i] = gatef(a, g);
                    }
                    pack8(abp, t, 8, gv);
                    pack8(abp, t, 9, gv + 8);
                }
            }
            copy_w2(abp, w2h, w2l, tid);
            FENCE_ASYNC_SHARED();
            __syncthreads();
            if (wid == 0 && elect_one()) issue_gemm2(tmem + 160, ab, mbar);
            MBAR_WAIT(mbar, mph); mph ^= 1;

            if (!FUSE) {
                if (tid < 256) {
                    TCGEN05_FENCE_AFTER();
                    const int t = tid & 127;
                    const int half = tid >> 7;
                    const bool tv = (t0 + t) < Tout;
                    uint32_t d[32];
                    if (half == 0) {
                        #pragma unroll
                        for (int ch = 0; ch < 2; ch++) {
                            int a0 = ch * 32;
                            LDTM_X32(d, tmem + 160 + a0);
                            TCGEN05_WAIT_LD();
                            if (tv) {
                                for (int i = 0; i < 32; i++) {
                                    int c = a0 + i;
                                    float v = __uint_as_float(d[i]) + s_bias[160 + c];
                                    if (RESID) v += __ldg(xin_n + (size_t)c * TinLd + S * (t0 + t) + 3);
                                    xout[((size_t)n * 80 + c) * ToutLd + t0 + t] = v;
                                }
                            }
                        }
                    } else {
                        LDTM_X16(d, tmem + 160 + 64);
                        TCGEN05_WAIT_LD();
                        if (tv) {
                            for (int i = 0; i < 16; i++) {
                                int c = 64 + i;
                                float v = __uint_as_float(d[i]) + s_bias[160 + c];
                                if (RESID) v += __ldg(xin_n + (size_t)c * TinLd + S * (t0 + t) + 3);
                                xout[((size_t)n * 80 + c) * ToutLd + t0 + t] = v;
                            }
                        }
                    }
                }
            } else {
                // v1 = 1x1 + b1 + res -> A3 ; Wf0 ; GEMM -> cols 0..79
                if (tid < 256) {
                    TCGEN05_FENCE_AFTER();
                    const int t = tid & 127;
                    const int half = tid >> 7;
                    const bool tv = (t0 + t) < Tout;
                    uint32_t d[32];
                    if (half == 0) {
                        #pragma unroll
                        for (int ch = 0; ch < 2; ch++) {
                            int a0 = ch * 32;
                            LDTM_X32(d, tmem + 160 + a0);
                            TCGEN05_WAIT_LD();
                            float v[32];
                            for (int i = 0; i < 32; i++) {
                                int c = a0 + i;
                                v[i] = __uint_as_float(d[i]) + s_bias[160 + c];
                                if (tv) v[i] += __ldg(xin_n + (size_t)c * TinLd + S * (t0 + t) + 3);
                            }
                            #pragma unroll
                            for (int q = 0; q < 4; q++)
                                pack8(abp, t, (a0 >> 3) + q, v + q * 8);
                        }
                    } else {
                        LDTM_X16(d, tmem + 160 + 64);
                        TCGEN05_WAIT_LD();
                        float v[16];
                        for (int i = 0; i < 16; i++) {
                            int c = 64 + i;
                            v[i] = __uint_as_float(d[i]) + s_bias[160 + c];
                            if (tv) v[i] += __ldg(xin_n + (size_t)c * TinLd + S * (t0 + t) + 3);
                        }
                        pack8(abp, t, 8, v);
                        pack8(abp, t, 9, v + 8);
                    }
                }
                copy_w2(abp, wf0s, wf0s + 20480, tid);
                FENCE_ASYNC_SHARED();
                __syncthreads();
                if (wid == 0 && elect_one()) issue_gemm2(tmem + 0, ab, mbar);
                MBAR_WAIT(mbar, mph); mph ^= 1;

                // h = relu(conv0 + bf0) -> A4 ; Wf1 ; GEMM -> cols 80..159
                if (tid < 256) {
                    TCGEN05_FENCE_AFTER();
                    const int t = tid & 127;
                    const int half = tid >> 7;
                    uint32_t d[32];
                    if (half == 0) {
                        #pragma unroll
                        for (int ch = 0; ch < 2; ch++) {
                            int a0 = ch * 32;
                            LDTM_X32(d, tmem + a0);
                            TCGEN05_WAIT_LD();
                            float v[32];
                            for (int i = 0; i < 32; i++)
                                v[i] = fmaxf(__uint_as_float(d[i]) + s_bias[240 + a0 + i], 0.f);
                            #pragma unroll
                            for (int q = 0; q < 4; q++)
                                pack8(abp, t, (a0 >> 3) + q, v + q * 8);
                        }
                    } else {
                        LDTM_X16(d, tmem + 64);
                        TCGEN05_WAIT_LD();
                        float v[16];
                        for (int i = 0; i < 16; i++)
                            v[i] = fmaxf(__uint_as_float(d[i]) + s_bias[240 + 64 + i], 0.f);
                        pack8(abp, t, 8, v);
                        pack8(abp, t, 9, v + 8);
                    }
                }
                copy_w2(abp, wf1s, wf1s + 20480, tid);
                FENCE_ASYNC_SHARED();
                __syncthreads();
                if (wid == 0 && elect_one()) issue_gemm2(tmem + 80, ab, mbar);
                MBAR_WAIT(mbar, mph); mph ^= 1;

                // out = conv1 + bf1 -> enc (N,T,80)
                if (tid < 256) {
                    TCGEN05_FENCE_AFTER();
                    const int t = tid & 127;
                    const int half = tid >> 7;
                    const bool tv = (t0 + t) < Tout;
                    uint32_t d[32];
                    if (half == 0) {
                        #pragma unroll
                        for (int ch = 0; ch < 2; ch++) {
                            int a0 = ch * 32;
                            LDTM_X32(d, tmem + 80 + a0);
                            TCGEN05_WAIT_LD();
                            if (tv) {
                                float* dst = xout + ((size_t)n * Tout + t0 + t) * 80 + a0;
                                for (int i = 0; i < 32; i += 4) {
                                    float4 o;
                                    o.x = __uint_as_float(d[i])     + s_bias[320 + a0 + i];
                                    o.y = __uint_as_float(d[i + 1]) + s_bias[320 + a0 + i + 1];
                                    o.z = __uint_as_float(d[i + 2]) + s_bias[320 + a0 + i + 2];
                                    o.w = __uint_as_float(d[i + 3]) + s_bias[320 + a0 + i + 3];
                                    *(float4*)(dst + i) = o;
                                }
                            }
                        }
                    } else {
                        LDTM_X16(d, tmem + 80 + 64);
                        TCGEN05_WAIT_LD();
                        if (tv) {
                            float* dst = xout + ((size_t)n * Tout + t0 + t) * 80 + 64;
                            for (int i = 0; i < 16; i += 4) {
                                float4 o;
                                o.x = __uint_as_float(d[i])     + s_bias[320 + 64 + i];
                                o.y = __uint_as_float(d[i + 1]) + s_bias[320 + 64 + i + 1];
                                o.z = __uint_as_float(d[i + 2]) + s_bias[320 + 64 + i + 2];
                                o.w = __uint_as_float(d[i + 3]) + s_bias[320 + 64 + i + 3];
                                *(float4*)(dst + i) = o;
                            }
                        }
                    }
                }
            }
#else
            // ------- safe scalar fallback (never runs on GB300) -------
            float* gsmF = (float*)(abp);
            float* bufF = (float*)(abp + 43008);
            __syncthreads();
            for (int e = tid; e < 80 * 128; e += 320) {
                int oc = e >> 7, tt = e & 127;
                float a = s_bias[oc], g = s_bias[oc + 80];
                for (int c = 0; c < 80; c++) {
                    for (int j = 0; j < 4; j++) {
                        int u = S * (t0 + tt) + j;
                        float xv = (u < Tin)
                                 ? (FIRST ? xin_n[(size_t)u * 80 + c]
                                          : xin_n[(size_t)c * TinLd + u]) : 0.f;
                        float wa = __bfloat162float(wbh[oc * 320 + c * 4 + j])
                                 + __bfloat162float(wbl[oc * 320 + c * 4 + j]);
                        float wg = __bfloat162float(wbh[(oc + 80) * 320 + c * 4 + j])
                                 + __bfloat162float(wbl[(oc + 80) * 320 + c * 4 + j]);
                        a = fmaf(wa, xv, a);
                        g = fmaf(wg, xv, g);
                    }
                }
                gsmF[oc * 132 + tt] = gatef(a, g);
            }
            __syncthreads();
            for (int e = tid; e < 80 * 128; e += 320) {
                int oc = e >> 7, tt = e & 127;
                int t = t0 + tt;
                float s = s_bias[160 + oc];
                for (int ic = 0; ic < 80; ic++)
                    s = fmaf(g_w1t[l * 6400 + ic * 80 + oc], gsmF[ic * 132 + tt], s);
                if (RESID && t < Tout) s += xin_n[(size_t)oc * TinLd + S * t + 3];
                if (FUSE) bufF[oc * 132 + tt] = s;
                else if (t < Tout) xout[((size_t)n * 80 + oc) * ToutLd + t] = s;
            }
            if (FUSE) {
                __syncthreads();
                for (int e = tid; e < 80 * 128; e += 320) {
                    int oc = e >> 7, tt = e & 127;
                    float s = s_bias[240 + oc];
                    for (int ic = 0; ic < 80; ic++)
                        s = fmaf(g_wf0t[ic * 80 + oc], bufF[ic * 132 + tt], s);
                    gsmF[oc * 132 + tt] = fmaxf(s, 0.f);
                }
                __syncthreads();
                for (int e = tid; e < 80 * 128; e += 320) {
                    int oc = e >> 7, tt = e & 127;
                    int t = t0 + tt;
                    if (t < Tout) {
                        float s = s_bias[320 + oc];
                        for (int ic = 0; ic < 80; ic++)
                            s = fmaf(g_wf1t[ic * 80 + oc], gsmF[ic * 132 + tt], s);
                        xout[((size_t)n * Tout + t) * 80 + oc] = s;
                    }
                }
            }
#endif
            __threadfence();
            __syncthreads();
            if (tid == 0) atomicAdd(&g_done[l][n], 1u);

        } else {
            // ================= VQ tile =================
            const int loc = (int)(tk - 1600);
            const int n = loc / 16, bxv = loc % 16;
            const int t0 = bxv * 128;

            if (tid == 0) {
                while (atomicAdd(&g_done[3][n], 0u) < 20u) __nanosleep(200);
                __threadfence();
                sm0 = 0u; sm1 = 0u;
            }
            __syncthreads();

#if HAS_TC
            {
                const float4* src = (const float4*)(eS + (size_t)n * 2040 * 80);
                for (int gi = tid; gi < 1280; gi += 320) {
                    int t = gi / 10, kg = gi % 10;
                    int tg = t0 + t;
                    float v[8] = {0.f, 0.f, 0.f, 0.f, 0.f, 0.f, 0.f, 0.f};
                    if (tg < 2040) {
                        float4 a = __ldg(src + (size_t)tg * 20 + kg * 2);
                        float4 b = __ldg(src + (size_t)tg * 20 + kg * 2 + 1);
                        v[0] = a.x; v[1] = a.y; v[2] = a.z; v[3] = a.w;
                        v[4] = b.x; v[5] = b.y; v[6] = b.z; v[7] = b.w;
                    }
                    pack8(abp, t, kg, v);
                }
            }
            const int sub  = wid & 3;
            const int quar = wid >> 2;
            const int t    = sub * 32 + (tid & 31);
            float best = 3.4e38f;
            int   bi   = 0;

            for (int grp = 0; grp < 2; grp++) {
                for (int ch = 0; ch < 4; ch++) {
                    int cls = grp * 4 + ch;
                    for (int i = tid; i < 1024; i += 320) {
                        ((uint4*)(abp + VQ_B_HI))[i] = __ldg((const uint4*)(g_embs[0][cls]) + i);
                        ((uint4*)(abp + VQ_B_LO))[i] = __ldg((const uint4*)(g_embs[1][cls]) + i);
                    }
                    FENCE_ASYNC_SHARED();
                    __syncthreads();
                    if (wid == 0 && elect_one()) issue_gemmv(tmem + ch * 64, ab, mbar);
                    MBAR_WAIT(mbar, mph); mph ^= 1;
                }
                TCGEN05_FENCE_AFTER();
                if (wid < 8) {
                    uint32_t d[32];
                    #pragma unroll
                    for (int cc = 0; cc < 4; cc++) {
                        int c0 = quar * 128 + cc * 32;
                        LDTM_X32(d, tmem + c0);
                        TCGEN05_WAIT_LD();
                        for (int i = 0; i < 32; i++) {
                            int k = grp * 256 + c0 + i;
                            float dd = se2[k] - 2.f * __uint_as_float(d[i]);
                            if (dd < best) { best = dd; bi = k; }
                        }
                    }
                    TCGEN05_FENCE_BEFORE();
                }
                __syncthreads();
            }
            if (wid < 8) {
                sdist[t * 2 + quar] = best;
                sidx [t * 2 + quar] = bi;
            }
            __syncthreads();

            if (tid < 128) {
                float d0 = sdist[tid * 2],     d1 = sdist[tid * 2 + 1];
                int   i0 = sidx [tid * 2],     i1 = sidx [tid * 2 + 1];
                int bbi = (d1 < d0 || (d1 == d0 && i1 < i0)) ? i1 : i0;
                int tg2 = t0 + tid;
                if (tg2 < 2040) {
                    const float* dv = emb + (size_t)bbi * 80;
                    const float* qr = (tg2 < 2016)
                                    ? (eQ + ((size_t)n * 504 + (tg2 % 504)) * 80)
                                    : nullptr;
                    float s0 = blin[0], s1 = blin[1];
                    #pragma unroll 4
                    for (int c = 0; c < 80; c++) {
                        float v = dv[c] + (qr ? qr[c] : 0.f);
                        s0 = fmaf(v, wlin[c],      s0);
                        s1 = fmaf(v, wlin[80 + c], s1);
                    }
                    atomicMax(&sm0, fenc(tanhf(s0)));
                    atomicMax(&sm1, fenc(tanhf(s1)));
                }
            }
            __syncthreads();
#else
            __syncthreads();
            if (tid < 128) {
                int tg2 = t0 + tid;
                if (tg2 < 2040) {
                    const float* xr = eS + ((size_t)n * 2040 + tg2) * 80;
                    float best = 3.4e38f; int bbi = 0;
                    for (int k = 0; k < 512; k++) {
                        float dot = 0.f;
                        for (int c = 0; c < 80; c++) dot = fmaf(xr[c], emb[k * 80 + c], dot);
                        float dd = se2[k] - 2.f * dot;
                        if (dd < best) { best = dd; bbi = k; }
                    }
                    const float* dv = emb + (size_t)bbi * 80;
                    const float* qr = (tg2 < 2016)
                                    ? (eQ + ((size_t)n * 504 + (tg2 % 504)) * 80)
                                    : nullptr;
                    float s0 = blin[0], s1 = blin[1];
                    for (int c = 0; c < 80; c++) {
                        float v = dv[c] + (qr ? qr[c] : 0.f);
                        s0 = fmaf(v, wlin[c],      s0);
                        s1 = fmaf(v, wlin[80 + c], s1);
                    }
                    atomicMax(&sm0, fenc(tanhf(s0)));
                    atomicMax(&sm1, fenc(tanhf(s1)));
                }
            }
            __syncthreads();
#endif
            if (tid == 0) {
                atomicMax(&g_gmax[n * 2 + 0], sm0);
                atomicMax(&g_gmax[n * 2 + 1], sm1);
                __threadfence();
                unsigned old = atomicAdd(&g_cnt[n], 1u);
                if (old == 15u) {
                    unsigned e0 = atomicMax(&g_gmax[n * 2 + 0], 0u);
                    unsigned e1 = atomicMax(&g_gmax[n * 2 + 1], 0u);
                    out[n * 2 + 0] = fdec(e0);
                    out[n * 2 + 1] = fdec(e1);
                }
            }
        }
    }

#if HAS_TC
    __syncthreads();
    if (wid == 0) TCGEN05_DEALLOC(tmem, 256);
#endif
}

// ---------------------------------------------------------------------------
// Host launch
// ---------------------------------------------------------------------------
extern "C" void kernel_launch(void* const* d_in, const int* in_sizes, int n_in,
                              void* d_out, int out_size) {
    const float* search = (const float*)d_in[0];
    const float* query  = (const float*)d_in[1];
    const float* w_wide = (const float*)d_in[2];
    const float* b_wide = (const float*)d_in[3];
    const float* w_1x1  = (const float*)d_in[4];
    const float* b_1x1  = (const float*)d_in[5];
    const float* w_f0   = (const float*)d_in[6];
    const float* b_f0   = (const float*)d_in[7];
    const float* w_f1   = (const float*)d_in[8];
    const float* b_f1   = (const float*)d_in[9];
    const float* emb    = (const float*)d_in[10];
    const float* w_lin  = (const float*)d_in[11];
    const float* b_lin  = (const float*)d_in[12];
    float* out = (float*)d_out;

    void *pA, *pB, *pAq, *pBq, *pS, *pQ, *pwh, *pwl, *pw1s, *pwf0s, *pwf1s;
    cudaGetSymbolAddress(&pA,   g_bufA);
    cudaGetSymbolAddress(&pB,   g_bufB);
    cudaGetSymbolAddress(&pAq,  g_bufAq);
    cudaGetSymbolAddress(&pBq,  g_bufBq);
    cudaGetSymbolAddress(&pS,   g_encS);
    cudaGetSymbolAddress(&pQ,   g_encQ);
    cudaGetSymbolAddress(&pwh,  g_wbh);
    cudaGetSymbolAddress(&pwl,  g_wbl);
    cudaGetSymbolAddress(&pw1s, g_w1s);
    cudaGetSymbolAddress(&pwf0s, g_wf0s);
    cudaGetSymbolAddress(&pwf1s, g_wf1s);
    float* A   = (float*)pA;
    float* B   = (float*)pB;
    float* Aq  = (float*)pAq;
    float* Bq  = (float*)pBq;
    float* eS  = (float*)pS;
    float* eQ  = (float*)pQ;
    __nv_bfloat16* wbh = (__nv_bfloat16*)pwh;
    __nv_bfloat16* wbl = (__nv_bfloat16*)pwl;
    const char* w1s  = (const char*)pw1s;
    const char* wf0s = (const char*)pwf0s;
    const char* wf1s = (const char*)pwf1s;

    cudaFuncSetAttribute(mega_kernel,
                         cudaFuncAttributeMaxDynamicSharedMemorySize, SMEM_DYN);

    prep_kernel<<<80, 256>>>(w_wide, w_1x1, w_f0, w_f1, emb);

    mega_kernel<<<296, 320, SMEM_DYN>>>(
        search, query, A, Aq, B, Bq, eS, eQ,
        wbh, wbl, b_wide, b_1x1,
        w1s, wf0s, wf1s, b_f0, b_f1,
        emb, w_lin, b_lin, out);
}